// round 1
// baseline (speedup 1.0000x reference)
#include <cuda_runtime.h>
#include <math.h>

#define Bdim 128
#define Tdim 24
#define Edim 512
#define Hdim 512
#define Rdim 512
#define NTG 400
#define Vdim 20000
#define TBdim (Tdim*Bdim)   // 3072

// ---------------- scratch (device globals; no allocation allowed) ----------
__device__ float g_xs[TBdim*Edim];          // decoder inputs [T*B, E]
__device__ float g_t2[4*Bdim*Rdim];         // s @ Wb
__device__ float g_t5[4*Bdim*Rdim];         // s @ Ub
__device__ float g_t1[4L*TBdim*Rdim];       // (xs@Wa) * t2
__device__ float g_gx[4L*TBdim*Hdim];       // ((xs@Wa)*t2)@Wc + b
__device__ float g_t6[4*Bdim*Rdim];         // (h@Ua) * t5
__device__ float g_gh[4*Bdim*Hdim];         // t6 @ Uc
__device__ float g_hs[TBdim*Hdim];          // all hidden states
__device__ float g_h[Bdim*Hdim];
__device__ float g_c[Bdim*Hdim];

// ---------------- embedding gather: xs[t] = (t==0)?0:emb[captions[:,t-1]] ---
__global__ void k_gather(const int* __restrict__ caps, const float* __restrict__ emb)
{
    const int b = blockIdx.x, t = blockIdx.y;
    float4 v = make_float4(0.f, 0.f, 0.f, 0.f);
    if (t > 0) {
        int tok = caps[b*Tdim + (t-1)];
        v = ((const float4*)(emb + (long)tok*Edim))[threadIdx.x];
    }
    ((float4*)(g_xs + (long)(t*Bdim + b)*Edim))[threadIdx.x] = v;
}

__global__ void k_init(const float* __restrict__ h0, const float* __restrict__ c0)
{
    int i = blockIdx.x*blockDim.x + threadIdx.x;   // B*H = 65536; h0[0]/c0[0] = first B*H
    g_h[i] = h0[i];
    g_c[i] = c0[i];
}

// ---------------- generic batched tiled SGEMM ------------------------------
// A: row-major [M,K] (+g*sA), B: row-major [K,N] (+g*sB), C: [M,N] (+g*sC)
// MODE 0: C = acc
// MODE 1: C = acc * X[g*sX + (row&127)*N + n]        (SCN factor scaling)
// MODE 2: C = acc + X[g*sX + n]                       (per-gate bias)
// MODE 3: out GEMM: remap row t*128+b -> b*24+t, +X[n] bias, guard n<N
template<int BM,int BN,int BK,int TM,int TN,int MODE>
__global__ void gemm_k(const float* __restrict__ A, const float* __restrict__ Bm,
                       float* __restrict__ C, const float* __restrict__ X,
                       int M, int N, int K,
                       long sA, long sB, long sC, long sX)
{
    constexpr int THREADS = (BM/TM)*(BN/TN);
    __shared__ float As[BK][BM];
    __shared__ float Bs[BK][BN];

    const int g = blockIdx.z;
    const float* Ag = A + (long)g*sA;
    const float* Bg = Bm + (long)g*sB;
    float* Cg = C + (long)g*sC;
    const float* Xg = X + (long)g*sX;

    const int m0 = blockIdx.y*BM;
    const int n0 = blockIdx.x*BN;
    const int tid = threadIdx.x;

    constexpr int AK4 = BK/4;
    const int aRow = tid / AK4;
    const int aCol = (tid % AK4)*4;
    constexpr int AROWS = THREADS/AK4;
    constexpr int BN4 = BN/4;
    const int bRow = tid / BN4;
    const int bCol = (tid % BN4)*4;
    constexpr int BROWS = THREADS/BN4;

    const int tr = (tid/(BN/TN))*TM;
    const int tc = (tid%(BN/TN))*TN;

    float acc[TM][TN];
#pragma unroll
    for (int i = 0; i < TM; i++)
#pragma unroll
        for (int j = 0; j < TN; j++) acc[i][j] = 0.f;

    for (int k0 = 0; k0 < K; k0 += BK) {
#pragma unroll
        for (int i = 0; i < BM; i += AROWS) {
            float4 v = *(const float4*)(Ag + (long)(m0 + aRow + i)*K + (k0 + aCol));
            As[aCol+0][aRow+i] = v.x; As[aCol+1][aRow+i] = v.y;
            As[aCol+2][aRow+i] = v.z; As[aCol+3][aRow+i] = v.w;
        }
#pragma unroll
        for (int i = 0; i < BK; i += BROWS) {
            const int n = n0 + bCol;
            float4 v;
            if (MODE == 3 && n >= N) v = make_float4(0.f,0.f,0.f,0.f);
            else v = *(const float4*)(Bg + (long)(k0 + bRow + i)*N + n);
            *(float4*)&Bs[bRow+i][bCol] = v;
        }
        __syncthreads();
#pragma unroll
        for (int kk = 0; kk < BK; kk++) {
            float rm[TM], rn[TN];
#pragma unroll
            for (int i = 0; i < TM; i++) rm[i] = As[kk][tr+i];
#pragma unroll
            for (int j = 0; j < TN; j++) rn[j] = Bs[kk][tc+j];
#pragma unroll
            for (int i = 0; i < TM; i++)
#pragma unroll
                for (int j = 0; j < TN; j++)
                    acc[i][j] = fmaf(rm[i], rn[j], acc[i][j]);
        }
        __syncthreads();
    }

#pragma unroll
    for (int i = 0; i < TM; i++) {
        const int row = m0 + tr + i;
#pragma unroll
        for (int j = 0; j < TN; j++) {
            const int n = n0 + tc + j;
            float v = acc[i][j];
            if (MODE == 1) v *= Xg[(long)(row & (Bdim-1))*N + n];
            if (MODE == 2) v += Xg[n];
            if (MODE == 3) {
                if (n < N) {
                    const int orow = (row & (Bdim-1))*Tdim + (row >> 7);
                    C[(long)orow*N + n] = v + Xg[n];
                }
            } else {
                Cg[(long)row*N + n] = v;
            }
        }
    }
}

// ---------------- per-step LSTM pointwise -----------------------------------
__global__ void k_lstm(int t)
{
    const int i = blockIdx.x*blockDim.x + threadIdx.x;   // over B*H
    const long so = (long)t*Bdim*Hdim;
    const long GS = (long)TBdim*Hdim;
    const long GH = (long)Bdim*Hdim;

    float pi = g_gx[0*GS + so + i] + g_gh[0*GH + i];
    float pf = g_gx[1*GS + so + i] + g_gh[1*GH + i];
    float po = g_gx[2*GS + so + i] + g_gh[2*GH + i];
    float pc = g_gx[3*GS + so + i] + g_gh[3*GH + i];

    float ig = 1.f/(1.f + expf(-pi));
    float fg = 1.f/(1.f + expf(-pf));
    float og = 1.f/(1.f + expf(-po));
    float ct = tanhf(pc);

    float cn = fg*g_c[i] + ig*ct;
    float hn = og*tanhf(cn);
    g_c[i] = cn;
    g_h[i] = hn;
    g_hs[so + i] = hn;
}

// ---------------- launch ----------------------------------------------------
extern "C" void kernel_launch(void* const* d_in, const int* in_sizes, int n_in,
                              void* d_out, int out_size)
{
    const int*   caps = (const int*)  d_in[0];
    const float* tags = (const float*)d_in[1];
    const float* h0   = (const float*)d_in[2];
    const float* c0   = (const float*)d_in[3];
    const float* Wa   = (const float*)d_in[4];
    const float* Wb   = (const float*)d_in[5];
    const float* Wc   = (const float*)d_in[6];
    const float* Ua   = (const float*)d_in[7];
    const float* Ub   = (const float*)d_in[8];
    const float* Uc   = (const float*)d_in[9];
    const float* bi   = (const float*)d_in[10];
    const float* emb  = (const float*)d_in[11];
    const float* Wout = (const float*)d_in[12];
    const float* bout = (const float*)d_in[13];
    float* out = (float*)d_out;

    float *p_xs, *p_t2, *p_t5, *p_t1, *p_gx, *p_t6, *p_gh, *p_hs, *p_h;
    cudaGetSymbolAddress((void**)&p_xs, g_xs);
    cudaGetSymbolAddress((void**)&p_t2, g_t2);
    cudaGetSymbolAddress((void**)&p_t5, g_t5);
    cudaGetSymbolAddress((void**)&p_t1, g_t1);
    cudaGetSymbolAddress((void**)&p_gx, g_gx);
    cudaGetSymbolAddress((void**)&p_t6, g_t6);
    cudaGetSymbolAddress((void**)&p_gh, g_gh);
    cudaGetSymbolAddress((void**)&p_hs, g_hs);
    cudaGetSymbolAddress((void**)&p_h,  g_h);

    // inputs / state prep
    k_gather<<<dim3(Bdim, Tdim), 128>>>(caps, emb);
    k_init<<<256, 256>>>(h0, c0);

    // temp2[g,b,r] = sum_t s[b,t]*Wb[g,t,r]   (and temp5 with Ub)
    gemm_k<64,64,16,4,4,0><<<dim3(8,2,4), 256>>>(
        tags, Wb, p_t2, p_t2, Bdim, Rdim, NTG, 0, (long)NTG*Rdim, (long)Bdim*Rdim, 0);
    gemm_k<64,64,16,4,4,0><<<dim3(8,2,4), 256>>>(
        tags, Ub, p_t5, p_t5, Bdim, Rdim, NTG, 0, (long)NTG*Rdim, (long)Bdim*Rdim, 0);

    // t1[g,row,r] = (xs @ Wa[g]) * t2[g, row%128, r]       (all T at once)
    gemm_k<128,128,8,8,8,1><<<dim3(4,24,4), 256>>>(
        p_xs, Wa, p_t1, p_t2, TBdim, Rdim, Edim,
        0, (long)Edim*Rdim, (long)TBdim*Rdim, (long)Bdim*Rdim);

    // gx[g,row,h] = t1[g] @ Wc[g] + b[g,h]
    gemm_k<128,128,8,8,8,2><<<dim3(4,24,4), 256>>>(
        p_t1, Wc, p_gx, bi, TBdim, Hdim, Rdim,
        (long)TBdim*Rdim, (long)Rdim*Hdim, (long)TBdim*Hdim, Hdim);

    // recurrence
    for (int t = 0; t < Tdim; t++) {
        // t6[g,b,r] = (h @ Ua[g]) * t5[g,b,r]
        gemm_k<32,64,16,4,4,1><<<dim3(8,4,4), 128>>>(
            p_h, Ua, p_t6, p_t5, Bdim, Rdim, Hdim,
            0, (long)Hdim*Rdim, (long)Bdim*Rdim, (long)Bdim*Rdim);
        // gh[g,b,h] = t6[g] @ Uc[g]
        gemm_k<32,64,16,4,4,0><<<dim3(8,4,4), 128>>>(
            p_t6, Uc, p_gh, p_gh, Bdim, Hdim, Rdim,
            (long)Bdim*Rdim, (long)Rdim*Hdim, (long)Bdim*Hdim, 0);
        // pointwise LSTM update, writes g_hs[t]
        k_lstm<<<256, 256>>>(t);
    }

    // logits: out[b,t,v] = hs[t,b,:] @ Wout + bout
    gemm_k<128,128,8,8,8,3><<<dim3((Vdim + 127)/128, TBdim/128, 1), 256>>>(
        p_hs, Wout, out, bout, TBdim, Vdim, Hdim, 0, 0, 0, 0);
}

// round 3
// speedup vs baseline: 1.3844x; 1.3844x over previous
#include <cuda_runtime.h>
#include <cuda_bf16.h>
#include <math.h>
#include <cstdint>

#define Bdim 128
#define Tdim 24
#define Edim 512
#define Hdim 512
#define Rdim 512
#define NTG 400
#define Vdim 20000
#define TBdim (Tdim*Bdim)   // 3072
#define KP 1536             // split-bf16 K (3 x 512)

// ---------------- scratch (device globals; no allocation allowed) ----------
__device__ float g_xs[TBdim*Edim];
__device__ float g_t2[4*Bdim*Rdim];
__device__ float g_t5[4*Bdim*Rdim];
__device__ float g_t1[4L*TBdim*Rdim];
__device__ float g_gx[4L*TBdim*Hdim];
__device__ float g_t6[4*Bdim*Rdim];
__device__ float g_gh[4*Bdim*Hdim];
__device__ float g_hs[TBdim*Hdim];
__device__ float g_h[Bdim*Hdim];
__device__ float g_c[Bdim*Hdim];
__device__ __nv_bfloat16 g_Abf[(long)TBdim*KP];      // hs split-bf16 [3072,1536]
__device__ __nv_bfloat16 g_Bbf[(long)Vdim*KP];       // Wout^T split-bf16 [20000,1536]

__device__ __forceinline__ uint32_t smem_u32(const void* p) {
    uint32_t a;
    asm("{ .reg .u64 t; cvta.to.shared.u64 t, %1; cvt.u32.u64 %0, t; }" : "=r"(a) : "l"(p));
    return a;
}

// ================= out GEMM: mma.sync bf16, 3-stage cp.async ================
// A': [3072,1536] bf16 row-major;  B': [20000,1536] bf16 row-major ([N,K])
// CTA tile 128x128, BK=64, 8 warps each 64x32 (m16n8k16).
#define OG_STAGES 3
#define OG_STRIDE 144                 // bytes per smem row (64 bf16 + 8 pad)
#define OG_TILEB  (128*OG_STRIDE)     // 18432 B per matrix tile
#define OG_SMEM   (OG_STAGES*2*OG_TILEB)   // 110592

__device__ __forceinline__ void og_load(uint32_t sbase, int stage,
    const __nv_bfloat16* __restrict__ A, const __nv_bfloat16* __restrict__ B,
    int mtile, int ntile, int chunk, int tid)
{
    uint32_t sa = sbase + stage*2*OG_TILEB;
    uint32_t sb = sa + OG_TILEB;
    const char* Ag = (const char*)(A + (long)mtile*128*KP + chunk*64);
    const char* Bg = (const char*)(B + (long)ntile*128*KP + chunk*64);
#pragma unroll
    for (int i = 0; i < 4; i++) {
        int e = tid + i*256;            // 1024 uint4 per tile
        int row = e >> 3, q = e & 7;
        uint32_t d = sa + row*OG_STRIDE + q*16;
        asm volatile("cp.async.cg.shared.global [%0], [%1], 16;"
            :: "r"(d), "l"(Ag + (long)row*KP*2 + q*16) : "memory");
    }
#pragma unroll
    for (int i = 0; i < 4; i++) {
        int e = tid + i*256;
        int row = e >> 3, q = e & 7;
        uint32_t d = sb + row*OG_STRIDE + q*16;
        if (ntile*128 + row < Vdim) {
            asm volatile("cp.async.cg.shared.global [%0], [%1], 16;"
                :: "r"(d), "l"(Bg + (long)row*KP*2 + q*16) : "memory");
        } else {
            asm volatile("st.shared.v4.b32 [%0], {%1,%1,%1,%1};"
                :: "r"(d), "r"(0) : "memory");
        }
    }
}

__device__ __forceinline__ void ldm_x4(uint32_t* r, uint32_t addr)
{
    asm volatile("ldmatrix.sync.aligned.m8n8.x4.shared.b16 {%0,%1,%2,%3}, [%4];"
        : "=r"(r[0]), "=r"(r[1]), "=r"(r[2]), "=r"(r[3]) : "r"(addr));
}

__device__ __forceinline__ void mma16816(float* c, const uint32_t* a, const uint32_t* b)
{
    asm volatile("mma.sync.aligned.m16n8k16.row.col.f32.bf16.bf16.f32 "
        "{%0,%1,%2,%3}, {%4,%5,%6,%7}, {%8,%9}, {%0,%1,%2,%3};"
        : "+f"(c[0]), "+f"(c[1]), "+f"(c[2]), "+f"(c[3])
        : "r"(a[0]), "r"(a[1]), "r"(a[2]), "r"(a[3]), "r"(b[0]), "r"(b[1]));
}

__global__ void __launch_bounds__(256, 1) out_gemm_k(
    const __nv_bfloat16* __restrict__ Abf, const __nv_bfloat16* __restrict__ Bbf,
    const float* __restrict__ bout, float* __restrict__ out)
{
    extern __shared__ char smem[];
    const uint32_t sbase = smem_u32(smem);
    const int tid = threadIdx.x, wid = tid >> 5, lane = tid & 31;
    const int wm = wid & 1, wn = wid >> 1;       // warp tile: 64 x 32
    const int mtile = blockIdx.x, ntile = blockIdx.y;

    float acc[4][4][4];
#pragma unroll
    for (int i = 0; i < 4; i++)
#pragma unroll
        for (int j = 0; j < 4; j++)
#pragma unroll
            for (int q = 0; q < 4; q++) acc[i][j][q] = 0.f;

#pragma unroll
    for (int s = 0; s < OG_STAGES; s++) {
        og_load(sbase, s, Abf, Bbf, mtile, ntile, s, tid);
        asm volatile("cp.async.commit_group;" ::: "memory");
    }

    for (int k = 0; k < 24; k++) {
        asm volatile("cp.async.wait_group 2;" ::: "memory");
        __syncthreads();

        const int st = k % 3;
        uint32_t sa = sbase + st*2*OG_TILEB;
        uint32_t sb = sa + OG_TILEB;
#pragma unroll
        for (int ks = 0; ks < 4; ks++) {
            uint32_t a[4][4];
#pragma unroll
            for (int mi = 0; mi < 4; mi++) {
                uint32_t addr = sa + (wm*64 + mi*16 + (lane & 15))*OG_STRIDE
                              + (ks*16 + (lane >> 4)*8)*2;
                ldm_x4(a[mi], addr);
            }
            uint32_t b[4][2];
#pragma unroll
            for (int np = 0; np < 2; np++) {
                uint32_t row = wn*32 + np*16 + (lane & 7) + ((lane >> 4) & 1)*8;
                uint32_t addr = sb + row*OG_STRIDE + (ks*16 + ((lane >> 3) & 1)*8)*2;
                uint32_t r[4];
                ldm_x4(r, addr);
                b[np*2][0] = r[0];   b[np*2][1] = r[1];
                b[np*2+1][0] = r[2]; b[np*2+1][1] = r[3];
            }
#pragma unroll
            for (int mi = 0; mi < 4; mi++)
#pragma unroll
                for (int ni = 0; ni < 4; ni++)
                    mma16816(acc[mi][ni], a[mi], b[ni]);
        }
        __syncthreads();

        if (k + 3 < 24) og_load(sbase, st, Abf, Bbf, mtile, ntile, k + 3, tid);
        asm volatile("cp.async.commit_group;" ::: "memory");
    }

    // epilogue: bias + [t*128+b] -> [b*24+t] row remap, direct float2 stores
#pragma unroll
    for (int mi = 0; mi < 4; mi++) {
#pragma unroll
        for (int ni = 0; ni < 4; ni++) {
            int n = ntile*128 + wn*32 + ni*8 + (lane & 3)*2;
            if (n < Vdim) {
                float2 bv = *(const float2*)(bout + n);
                int r0 = mtile*128 + wm*64 + mi*16 + (lane >> 2);
                int r1 = r0 + 8;
                long o0 = ((long)(r0 & 127)*Tdim + (r0 >> 7))*Vdim + n;
                long o1 = ((long)(r1 & 127)*Tdim + (r1 >> 7))*Vdim + n;
                float2 v0 = make_float2(acc[mi][ni][0] + bv.x, acc[mi][ni][1] + bv.y);
                float2 v1 = make_float2(acc[mi][ni][2] + bv.x, acc[mi][ni][3] + bv.y);
                *(float2*)(out + o0) = v0;
                *(float2*)(out + o1) = v1;
            }
        }
    }
}

// ---------------- bf16 split conversions ------------------------------------
__global__ void k_convA()      // hs[3072,512] -> A'[3072,1536] = [hi | hi | lo]
{
    long idx = (long)blockIdx.x*blockDim.x + threadIdx.x;
    float v = g_hs[idx];
    long row = idx >> 9;
    int  col = (int)(idx & 511);
    __nv_bfloat16 hi = __float2bfloat16(v);
    __nv_bfloat16 lo = __float2bfloat16(v - __bfloat162float(hi));
    __nv_bfloat16* p = g_Abf + row*KP;
    p[col] = hi; p[512 + col] = hi; p[1024 + col] = lo;
}

__global__ void k_convB(const float* __restrict__ Wout)  // -> B'[n][k] = [hi | lo | hi]
{
    __shared__ float t[32][33];
    int n = blockIdx.x*32 + threadIdx.x;
    int k = blockIdx.y*32 + threadIdx.y;
    t[threadIdx.y][threadIdx.x] = Wout[(long)k*Vdim + n];
    __syncthreads();
    int n2 = blockIdx.x*32 + threadIdx.y;
    int k2 = blockIdx.y*32 + threadIdx.x;
    float v = t[threadIdx.x][threadIdx.y];
    __nv_bfloat16 hi = __float2bfloat16(v);
    __nv_bfloat16 lo = __float2bfloat16(v - __bfloat162float(hi));
    __nv_bfloat16* p = g_Bbf + (long)n2*KP;
    p[k2] = hi; p[512 + k2] = lo; p[1024 + k2] = hi;
}

// ---------------- embedding gather ------------------------------------------
__global__ void k_gather(const int* __restrict__ caps, const float* __restrict__ emb)
{
    const int b = blockIdx.x, t = blockIdx.y;
    float4 v = make_float4(0.f, 0.f, 0.f, 0.f);
    if (t > 0) {
        int tok = caps[b*Tdim + (t-1)];
        v = ((const float4*)(emb + (long)tok*Edim))[threadIdx.x];
    }
    ((float4*)(g_xs + (long)(t*Bdim + b)*Edim))[threadIdx.x] = v;
}

__global__ void k_init(const float* __restrict__ h0, const float* __restrict__ c0)
{
    int i = blockIdx.x*blockDim.x + threadIdx.x;
    g_h[i] = h0[i];
    g_c[i] = c0[i];
}

// ---------------- generic batched tiled SGEMM (fp32 paths) ------------------
template<int BM,int BN,int BK,int TM,int TN,int MODE>
__global__ void gemm_k(const float* __restrict__ A, const float* __restrict__ Bm,
                       float* __restrict__ C, const float* __restrict__ X,
                       int M, int N, int K,
                       long sA, long sB, long sC, long sX)
{
    constexpr int THREADS = (BM/TM)*(BN/TN);
    __shared__ float As[BK][BM];
    __shared__ float Bs[BK][BN];

    const int g = blockIdx.z;
    const float* Ag = A + (long)g*sA;
    const float* Bg = Bm + (long)g*sB;
    float* Cg = C + (long)g*sC;
    const float* Xg = X + (long)g*sX;

    const int m0 = blockIdx.y*BM;
    const int n0 = blockIdx.x*BN;
    const int tid = threadIdx.x;

    constexpr int AK4 = BK/4;
    const int aRow = tid / AK4;
    const int aCol = (tid % AK4)*4;
    constexpr int AROWS = THREADS/AK4;
    constexpr int BN4 = BN/4;
    const int bRow = tid / BN4;
    const int bCol = (tid % BN4)*4;
    constexpr int BROWS = THREADS/BN4;

    const int tr = (tid/(BN/TN))*TM;
    const int tc = (tid%(BN/TN))*TN;

    float acc[TM][TN];
#pragma unroll
    for (int i = 0; i < TM; i++)
#pragma unroll
        for (int j = 0; j < TN; j++) acc[i][j] = 0.f;

    for (int k0 = 0; k0 < K; k0 += BK) {
#pragma unroll
        for (int i = 0; i < BM; i += AROWS) {
            float4 v = *(const float4*)(Ag + (long)(m0 + aRow + i)*K + (k0 + aCol));
            As[aCol+0][aRow+i] = v.x; As[aCol+1][aRow+i] = v.y;
            As[aCol+2][aRow+i] = v.z; As[aCol+3][aRow+i] = v.w;
        }
#pragma unroll
        for (int i = 0; i < BK; i += BROWS) {
            float4 v = *(const float4*)(Bg + (long)(k0 + bRow + i)*N + (n0 + bCol));
            *(float4*)&Bs[bRow+i][bCol] = v;
        }
        __syncthreads();
#pragma unroll
        for (int kk = 0; kk < BK; kk++) {
            float rm[TM], rn[TN];
#pragma unroll
            for (int i = 0; i < TM; i++) rm[i] = As[kk][tr+i];
#pragma unroll
            for (int j = 0; j < TN; j++) rn[j] = Bs[kk][tc+j];
#pragma unroll
            for (int i = 0; i < TM; i++)
#pragma unroll
                for (int j = 0; j < TN; j++)
                    acc[i][j] = fmaf(rm[i], rn[j], acc[i][j]);
        }
        __syncthreads();
    }

#pragma unroll
    for (int i = 0; i < TM; i++) {
        const int row = m0 + tr + i;
#pragma unroll
        for (int j = 0; j < TN; j++) {
            const int n = n0 + tc + j;
            float v = acc[i][j];
            if (MODE == 1) v *= Xg[(long)(row & (Bdim-1))*N + n];
            if (MODE == 2) v += Xg[n];
            Cg[(long)row*N + n] = v;
        }
    }
}

// ---------------- per-step LSTM pointwise -----------------------------------
__global__ void k_lstm(int t)
{
    const int i = blockIdx.x*blockDim.x + threadIdx.x;
    const long so = (long)t*Bdim*Hdim;
    const long GS = (long)TBdim*Hdim;
    const long GH = (long)Bdim*Hdim;

    float pi = g_gx[0*GS + so + i] + g_gh[0*GH + i];
    float pf = g_gx[1*GS + so + i] + g_gh[1*GH + i];
    float po = g_gx[2*GS + so + i] + g_gh[2*GH + i];
    float pc = g_gx[3*GS + so + i] + g_gh[3*GH + i];

    float ig = 1.f/(1.f + expf(-pi));
    float fg = 1.f/(1.f + expf(-pf));
    float og = 1.f/(1.f + expf(-po));
    float ct = tanhf(pc);

    float cn = fg*g_c[i] + ig*ct;
    float hn = og*tanhf(cn);
    g_c[i] = cn;
    g_h[i] = hn;
    g_hs[so + i] = hn;
}

// ---------------- launch ----------------------------------------------------
extern "C" void kernel_launch(void* const* d_in, const int* in_sizes, int n_in,
                              void* d_out, int out_size)
{
    const int*   caps = (const int*)  d_in[0];
    const float* tags = (const float*)d_in[1];
    const float* h0   = (const float*)d_in[2];
    const float* c0   = (const float*)d_in[3];
    const float* Wa   = (const float*)d_in[4];
    const float* Wb   = (const float*)d_in[5];
    const float* Wc   = (const float*)d_in[6];
    const float* Ua   = (const float*)d_in[7];
    const float* Ub   = (const float*)d_in[8];
    const float* Uc   = (const float*)d_in[9];
    const float* bi   = (const float*)d_in[10];
    const float* emb  = (const float*)d_in[11];
    const float* Wout = (const float*)d_in[12];
    const float* bout = (const float*)d_in[13];
    float* out = (float*)d_out;

    float *p_xs, *p_t2, *p_t5, *p_t1, *p_gx, *p_t6, *p_gh, *p_hs, *p_h;
    __nv_bfloat16 *p_Abf, *p_Bbf;
    cudaGetSymbolAddress((void**)&p_xs, g_xs);
    cudaGetSymbolAddress((void**)&p_t2, g_t2);
    cudaGetSymbolAddress((void**)&p_t5, g_t5);
    cudaGetSymbolAddress((void**)&p_t1, g_t1);
    cudaGetSymbolAddress((void**)&p_gx, g_gx);
    cudaGetSymbolAddress((void**)&p_t6, g_t6);
    cudaGetSymbolAddress((void**)&p_gh, g_gh);
    cudaGetSymbolAddress((void**)&p_hs, g_hs);
    cudaGetSymbolAddress((void**)&p_h,  g_h);
    cudaGetSymbolAddress((void**)&p_Abf, g_Abf);
    cudaGetSymbolAddress((void**)&p_Bbf, g_Bbf);

    cudaFuncSetAttribute(out_gemm_k, cudaFuncAttributeMaxDynamicSharedMemorySize, OG_SMEM);

    // prep
    k_gather<<<dim3(Bdim, Tdim), 128>>>(caps, emb);
    k_init<<<256, 256>>>(h0, c0);
    k_convB<<<dim3(Vdim/32, Hdim/32), dim3(32,32)>>>(Wout);   // independent of recurrence

    gemm_k<64,64,16,4,4,0><<<dim3(8,2,4), 256>>>(
        tags, Wb, p_t2, p_t2, Bdim, Rdim, NTG, 0, (long)NTG*Rdim, (long)Bdim*Rdim, 0);
    gemm_k<64,64,16,4,4,0><<<dim3(8,2,4), 256>>>(
        tags, Ub, p_t5, p_t5, Bdim, Rdim, NTG, 0, (long)NTG*Rdim, (long)Bdim*Rdim, 0);

    gemm_k<128,128,8,8,8,1><<<dim3(4,24,4), 256>>>(
        p_xs, Wa, p_t1, p_t2, TBdim, Rdim, Edim,
        0, (long)Edim*Rdim, (long)TBdim*Rdim, (long)Bdim*Rdim);

    gemm_k<128,128,8,8,8,2><<<dim3(4,24,4), 256>>>(
        p_t1, Wc, p_gx, bi, TBdim, Hdim, Rdim,
        (long)TBdim*Rdim, (long)Rdim*Hdim, (long)TBdim*Hdim, Hdim);

    for (int t = 0; t < Tdim; t++) {
        gemm_k<32,64,16,4,4,1><<<dim3(8,4,4), 128>>>(
            p_h, Ua, p_t6, p_t5, Bdim, Rdim, Hdim,
            0, (long)Hdim*Rdim, (long)Bdim*Rdim, (long)Bdim*Rdim);
        gemm_k<32,64,16,4,4,0><<<dim3(8,4,4), 128>>>(
            p_t6, Uc, p_gh, p_gh, Bdim, Hdim, Rdim,
            (long)Bdim*Rdim, (long)Rdim*Hdim, (long)Bdim*Hdim, 0);
        k_lstm<<<256, 256>>>(t);
    }

    // hs -> A' (split bf16), then tensor-core out GEMM
    k_convA<<<(TBdim*Hdim)/256, 256>>>();
    out_gemm_k<<<dim3(TBdim/128, (Vdim + 127)/128), 256, OG_SMEM>>>(p_Abf, p_Bbf, bout, out);
}

// round 4
// speedup vs baseline: 1.6415x; 1.1857x over previous
#include <cuda_runtime.h>
#include <cuda_bf16.h>
#include <math.h>
#include <cstdint>

#define Bdim 128
#define Tdim 24
#define Edim 512
#define Hdim 512
#define Rdim 512
#define NTG 400
#define Vdim 20000
#define TBdim (Tdim*Bdim)   // 3072
#define KP 1536             // split-bf16 K (3 x 512)
#define RC 128              // persistent recurrence CTAs

// ---------------- scratch (device globals; no allocation allowed) ----------
__device__ float g_xs[TBdim*Edim];
__device__ float g_t2[4*Bdim*Rdim];
__device__ float g_t5[4*Bdim*Rdim];
__device__ float g_gx[4L*TBdim*Hdim];
__device__ float g_t6[4*Bdim*Rdim];
__device__ float g_gh[4*Bdim*Hdim];
__device__ float g_hs[TBdim*Hdim];
__device__ float g_h[Bdim*Hdim];
__device__ float g_c[Bdim*Hdim];
__device__ unsigned g_sync;
__device__ __nv_bfloat16 g_Abf[(long)TBdim*KP];      // hs split [3072,1536]
__device__ __nv_bfloat16 g_Bbf[(long)Vdim*KP];       // Wout^T split [20000,1536]
__device__ __nv_bfloat16 g_xbf[(long)TBdim*KP];      // xs split
__device__ __nv_bfloat16 g_t1bf[4L*TBdim*KP];        // t1 split, per gate
__device__ __nv_bfloat16 g_WaT[4L*Rdim*KP];          // Wa^T split, per gate
__device__ __nv_bfloat16 g_WcT[4L*Hdim*KP];          // Wc^T split, per gate

__device__ __forceinline__ uint32_t smem_u32(const void* p) {
    uint32_t a;
    asm("{ .reg .u64 t; cvta.to.shared.u64 t, %1; cvt.u32.u64 %0, t; }" : "=r"(a) : "l"(p));
    return a;
}

// ================= unified split-bf16 MMA GEMM ==============================
// A: [M,KP] bf16 row-major (+z*aS); B: [N,KP] bf16 row-major (+z*bS)
// CTA tile 128x128, BK=64, 3-stage cp.async, 8 warps of 64x32 m16n8k16.
// MODE 0: out logits (bias + [t*128+b]->[b*24+t] remap, N=Vdim guard)
// MODE 1: t1: C_bf16_split = acc * X[(row&127)*512 + n]   (gate z)
// MODE 2: gx: C_f32 = acc + X[z*512 + n]
#define OG_STAGES 3
#define OG_STRIDE 144
#define OG_TILEB  (128*OG_STRIDE)
#define OG_SMEM   (OG_STAGES*2*OG_TILEB)   // 110592

template<int MODE>
__device__ __forceinline__ void og_load(uint32_t sbase, int stage,
    const __nv_bfloat16* __restrict__ A, const __nv_bfloat16* __restrict__ B,
    int mtile, int ntile, int chunk, int tid)
{
    uint32_t sa = sbase + stage*2*OG_TILEB;
    uint32_t sb = sa + OG_TILEB;
    const char* Ag = (const char*)(A + (long)mtile*128*KP + chunk*64);
    const char* Bg = (const char*)(B + (long)ntile*128*KP + chunk*64);
#pragma unroll
    for (int i = 0; i < 4; i++) {
        int e = tid + i*256;
        int row = e >> 3, q = e & 7;
        uint32_t d = sa + row*OG_STRIDE + q*16;
        asm volatile("cp.async.cg.shared.global [%0], [%1], 16;"
            :: "r"(d), "l"(Ag + (long)row*KP*2 + q*16) : "memory");
    }
#pragma unroll
    for (int i = 0; i < 4; i++) {
        int e = tid + i*256;
        int row = e >> 3, q = e & 7;
        uint32_t d = sb + row*OG_STRIDE + q*16;
        if (MODE != 0 || ntile*128 + row < Vdim) {
            asm volatile("cp.async.cg.shared.global [%0], [%1], 16;"
                :: "r"(d), "l"(Bg + (long)row*KP*2 + q*16) : "memory");
        } else {
            asm volatile("st.shared.v4.b32 [%0], {%1,%1,%1,%1};"
                :: "r"(d), "r"(0) : "memory");
        }
    }
}

__device__ __forceinline__ void ldm_x4(uint32_t* r, uint32_t addr)
{
    asm volatile("ldmatrix.sync.aligned.m8n8.x4.shared.b16 {%0,%1,%2,%3}, [%4];"
        : "=r"(r[0]), "=r"(r[1]), "=r"(r[2]), "=r"(r[3]) : "r"(addr));
}

__device__ __forceinline__ void mma16816(float* c, const uint32_t* a, const uint32_t* b)
{
    asm volatile("mma.sync.aligned.m16n8k16.row.col.f32.bf16.bf16.f32 "
        "{%0,%1,%2,%3}, {%4,%5,%6,%7}, {%8,%9}, {%0,%1,%2,%3};"
        : "+f"(c[0]), "+f"(c[1]), "+f"(c[2]), "+f"(c[3])
        : "r"(a[0]), "r"(a[1]), "r"(a[2]), "r"(a[3]), "r"(b[0]), "r"(b[1]));
}

__device__ __forceinline__ void store_split(__nv_bfloat16* p, int col, float v)
{
    __nv_bfloat16 hi = __float2bfloat16(v);
    __nv_bfloat16 lo = __float2bfloat16(v - __bfloat162float(hi));
    p[col] = hi; p[512 + col] = hi; p[1024 + col] = lo;
}

template<int MODE>
__global__ void __launch_bounds__(256, 1) mma_gemm_k(
    const __nv_bfloat16* __restrict__ A, const __nv_bfloat16* __restrict__ B,
    float* __restrict__ Cf, __nv_bfloat16* __restrict__ Cb,
    const float* __restrict__ X, long aS, long bS)
{
    extern __shared__ char smem[];
    const uint32_t sbase = smem_u32(smem);
    const int tid = threadIdx.x, wid = tid >> 5, lane = tid & 31;
    const int wm = wid & 1, wn = wid >> 1;
    const int mtile = blockIdx.x, ntile = blockIdx.y, z = blockIdx.z;

    const __nv_bfloat16* Az = A + (long)z*aS;
    const __nv_bfloat16* Bz = B + (long)z*bS;

    float acc[4][4][4];
#pragma unroll
    for (int i = 0; i < 4; i++)
#pragma unroll
        for (int j = 0; j < 4; j++)
#pragma unroll
            for (int q = 0; q < 4; q++) acc[i][j][q] = 0.f;

#pragma unroll
    for (int s = 0; s < OG_STAGES; s++) {
        og_load<MODE>(sbase, s, Az, Bz, mtile, ntile, s, tid);
        asm volatile("cp.async.commit_group;" ::: "memory");
    }

    for (int k = 0; k < 24; k++) {
        asm volatile("cp.async.wait_group 2;" ::: "memory");
        __syncthreads();

        const int st = k % 3;
        uint32_t sa = sbase + st*2*OG_TILEB;
        uint32_t sb = sa + OG_TILEB;
#pragma unroll
        for (int ks = 0; ks < 4; ks++) {
            uint32_t a[4][4];
#pragma unroll
            for (int mi = 0; mi < 4; mi++) {
                uint32_t addr = sa + (wm*64 + mi*16 + (lane & 15))*OG_STRIDE
                              + (ks*16 + (lane >> 4)*8)*2;
                ldm_x4(a[mi], addr);
            }
            uint32_t b[4][2];
#pragma unroll
            for (int np = 0; np < 2; np++) {
                uint32_t row = wn*32 + np*16 + (lane & 7) + ((lane >> 4) & 1)*8;
                uint32_t addr = sb + row*OG_STRIDE + (ks*16 + ((lane >> 3) & 1)*8)*2;
                uint32_t r[4];
                ldm_x4(r, addr);
                b[np*2][0] = r[0];   b[np*2][1] = r[1];
                b[np*2+1][0] = r[2]; b[np*2+1][1] = r[3];
            }
#pragma unroll
            for (int mi = 0; mi < 4; mi++)
#pragma unroll
                for (int ni = 0; ni < 4; ni++)
                    mma16816(acc[mi][ni], a[mi], b[ni]);
        }
        __syncthreads();

        if (k + 3 < 24) og_load<MODE>(sbase, st, Az, Bz, mtile, ntile, k + 3, tid);
        asm volatile("cp.async.commit_group;" ::: "memory");
    }

#pragma unroll
    for (int mi = 0; mi < 4; mi++) {
#pragma unroll
        for (int ni = 0; ni < 4; ni++) {
            int n = ntile*128 + wn*32 + ni*8 + (lane & 3)*2;
            int gr0 = mtile*128 + wm*64 + mi*16 + (lane >> 2);
            int gr1 = gr0 + 8;
            if (MODE == 0) {
                if (n < Vdim) {
                    float2 bv = *(const float2*)(X + n);
                    long o0 = ((long)(gr0 & 127)*Tdim + (gr0 >> 7))*Vdim + n;
                    long o1 = ((long)(gr1 & 127)*Tdim + (gr1 >> 7))*Vdim + n;
                    *(float2*)(Cf + o0) = make_float2(acc[mi][ni][0] + bv.x, acc[mi][ni][1] + bv.y);
                    *(float2*)(Cf + o1) = make_float2(acc[mi][ni][2] + bv.x, acc[mi][ni][3] + bv.y);
                }
            } else if (MODE == 1) {
                const float* Xg = X + (long)z*Bdim*Rdim;
                __nv_bfloat16* Cz = Cb + (long)z*TBdim*KP;
                float m0a = Xg[(gr0 & 127)*512 + n],   m0b = Xg[(gr0 & 127)*512 + n + 1];
                float m1a = Xg[(gr1 & 127)*512 + n],   m1b = Xg[(gr1 & 127)*512 + n + 1];
                store_split(Cz + (long)gr0*KP, n,     acc[mi][ni][0]*m0a);
                store_split(Cz + (long)gr0*KP, n + 1, acc[mi][ni][1]*m0b);
                store_split(Cz + (long)gr1*KP, n,     acc[mi][ni][2]*m1a);
                store_split(Cz + (long)gr1*KP, n + 1, acc[mi][ni][3]*m1b);
            } else {
                const float* Xg = X + z*512;
                float* Cz = Cf + (long)z*TBdim*512;
                float2 bv = make_float2(Xg[n], Xg[n + 1]);
                *(float2*)(Cz + (long)gr0*512 + n) = make_float2(acc[mi][ni][0] + bv.x, acc[mi][ni][1] + bv.y);
                *(float2*)(Cz + (long)gr1*512 + n) = make_float2(acc[mi][ni][2] + bv.x, acc[mi][ni][3] + bv.y);
            }
        }
    }
}

// ---------------- conversions ------------------------------------------------
__global__ void k_split_rows(const float* __restrict__ src, __nv_bfloat16* __restrict__ dst)
{   // rows of 512 fp32 -> [hi | hi | lo] in KP=1536
    long idx = (long)blockIdx.x*blockDim.x + threadIdx.x;
    float v = src[idx];
    long row = idx >> 9;
    int  col = (int)(idx & 511);
    __nv_bfloat16 hi = __float2bfloat16(v);
    __nv_bfloat16 lo = __float2bfloat16(v - __bfloat162float(hi));
    __nv_bfloat16* p = dst + row*KP;
    p[col] = hi; p[512 + col] = hi; p[1024 + col] = lo;
}

__global__ void k_convW(const float* __restrict__ W, __nv_bfloat16* __restrict__ Bp)
{   // W[g][512,512] (k,n) -> B'[g][n][ hi | lo | hi ]
    __shared__ float t[32][33];
    int g = blockIdx.z;
    int n = blockIdx.x*32 + threadIdx.x;
    int k = blockIdx.y*32 + threadIdx.y;
    t[threadIdx.y][threadIdx.x] = W[(long)g*512*512 + (long)k*512 + n];
    __syncthreads();
    int n2 = blockIdx.x*32 + threadIdx.y;
    int k2 = blockIdx.y*32 + threadIdx.x;
    float v = t[threadIdx.x][threadIdx.y];
    __nv_bfloat16 hi = __float2bfloat16(v);
    __nv_bfloat16 lo = __float2bfloat16(v - __bfloat162float(hi));
    __nv_bfloat16* p = Bp + ((long)g*512 + n2)*KP;
    p[k2] = hi; p[512 + k2] = lo; p[1024 + k2] = hi;
}

__global__ void k_convB(const float* __restrict__ Wout)
{   // Wout[512,20000] -> B'[n][ hi | lo | hi ]
    __shared__ float t[32][33];
    int n = blockIdx.x*32 + threadIdx.x;
    int k = blockIdx.y*32 + threadIdx.y;
    t[threadIdx.y][threadIdx.x] = Wout[(long)k*Vdim + n];
    __syncthreads();
    int n2 = blockIdx.x*32 + threadIdx.y;
    int k2 = blockIdx.y*32 + threadIdx.x;
    float v = t[threadIdx.x][threadIdx.y];
    __nv_bfloat16 hi = __float2bfloat16(v);
    __nv_bfloat16 lo = __float2bfloat16(v - __bfloat162float(hi));
    __nv_bfloat16* p = g_Bbf + (long)n2*KP;
    p[k2] = hi; p[512 + k2] = lo; p[1024 + k2] = hi;
}

// ---------------- embedding gather / init ------------------------------------
__global__ void k_gather(const int* __restrict__ caps, const float* __restrict__ emb)
{
    const int b = blockIdx.x, t = blockIdx.y;
    float4 v = make_float4(0.f, 0.f, 0.f, 0.f);
    if (t > 0) {
        int tok = caps[b*Tdim + (t-1)];
        v = ((const float4*)(emb + (long)tok*Edim))[threadIdx.x];
    }
    ((float4*)(g_xs + (long)(t*Bdim + b)*Edim))[threadIdx.x] = v;
}

__global__ void k_init(const float* __restrict__ h0, const float* __restrict__ c0)
{
    int i = blockIdx.x*blockDim.x + threadIdx.x;
    g_h[i] = h0[i];
    g_c[i] = c0[i];
    if (i == 0) g_sync = 0;
}

// ---------------- fp32 tiled SGEMM (t2/t5 prep only) -------------------------
template<int BM,int BN,int BK,int TM,int TN>
__global__ void gemm_k(const float* __restrict__ A, const float* __restrict__ Bm,
                       float* __restrict__ C, int M, int N, int K, long sB, long sC)
{
    constexpr int THREADS = (BM/TM)*(BN/TN);
    __shared__ float As[BK][BM];
    __shared__ float Bs[BK][BN];
    const int g = blockIdx.z;
    const float* Bg = Bm + (long)g*sB;
    float* Cg = C + (long)g*sC;
    const int m0 = blockIdx.y*BM;
    const int n0 = blockIdx.x*BN;
    const int tid = threadIdx.x;
    constexpr int AK4 = BK/4;
    const int aRow = tid / AK4, aCol = (tid % AK4)*4;
    constexpr int AROWS = THREADS/AK4;
    constexpr int BN4 = BN/4;
    const int bRow = tid / BN4, bCol = (tid % BN4)*4;
    constexpr int BROWS = THREADS/BN4;
    const int tr = (tid/(BN/TN))*TM, tc = (tid%(BN/TN))*TN;

    float acc[TM][TN];
#pragma unroll
    for (int i = 0; i < TM; i++)
#pragma unroll
        for (int j = 0; j < TN; j++) acc[i][j] = 0.f;

    for (int k0 = 0; k0 < K; k0 += BK) {
#pragma unroll
        for (int i = 0; i < BM; i += AROWS) {
            float4 v = *(const float4*)(A + (long)(m0 + aRow + i)*K + (k0 + aCol));
            As[aCol+0][aRow+i] = v.x; As[aCol+1][aRow+i] = v.y;
            As[aCol+2][aRow+i] = v.z; As[aCol+3][aRow+i] = v.w;
        }
#pragma unroll
        for (int i = 0; i < BK; i += BROWS) {
            float4 v = *(const float4*)(Bg + (long)(k0 + bRow + i)*N + (n0 + bCol));
            *(float4*)&Bs[bRow+i][bCol] = v;
        }
        __syncthreads();
#pragma unroll
        for (int kk = 0; kk < BK; kk++) {
            float rm[TM], rn[TN];
#pragma unroll
            for (int i = 0; i < TM; i++) rm[i] = As[kk][tr+i];
#pragma unroll
            for (int j = 0; j < TN; j++) rn[j] = Bs[kk][tc+j];
#pragma unroll
            for (int i = 0; i < TM; i++)
#pragma unroll
                for (int j = 0; j < TN; j++)
                    acc[i][j] = fmaf(rm[i], rn[j], acc[i][j]);
        }
        __syncthreads();
    }
#pragma unroll
    for (int i = 0; i < TM; i++)
#pragma unroll
        for (int j = 0; j < TN; j++)
            Cg[(long)(m0 + tr + i)*N + n0 + tc + j] = acc[i][j];
}

// ---------------- persistent recurrence kernel -------------------------------
__device__ __forceinline__ void gbar(unsigned goal)
{
    __syncthreads();
    __threadfence();
    if (threadIdx.x == 0) {
        atomicAdd(&g_sync, 1u);
        unsigned v;
        do {
            asm volatile("ld.global.acquire.gpu.u32 %0, [%1];" : "=r"(v) : "l"(&g_sync));
        } while (v < goal);
    }
    __syncthreads();
}

__device__ __forceinline__ float sig_f(float x)
{
    return 1.f / (1.f + __expf(-x));
}
__device__ __forceinline__ float tanh_f(float x)
{
    return 2.f / (1.f + __expf(-2.f*x)) - 1.f;
}

__global__ void __launch_bounds__(256, 1) rec_k(const float* __restrict__ Ua,
                                                const float* __restrict__ Uc)
{
    __shared__ float As[32][34];
    __shared__ float Bs[32][64];
    const int tid = threadIdx.x;
    const int bx  = blockIdx.x;
    const int gg  = bx >> 5;          // gate
    const int bt  = (bx >> 3) & 3;    // 32-row b tile
    const int rt  = bx & 7;           // 64-col tile
    const int b0  = bt*32;
    const int c0  = rt*64;
    const int ty  = tid >> 4, tx = tid & 15;
    const int tr  = ty*2,   tc = tx*4;
    const int arow = tid >> 3, acol = (tid & 7)*4;
    const int brow = tid >> 4, bcol = (tid & 15)*4;

    const float* UaG = Ua + (long)gg*512*512;
    const float* UcG = Uc + (long)gg*512*512;
    unsigned goal = RC;

    for (int t = 0; t < Tdim; t++) {
        // ---- phase A: t6[gg, b0.., c0..] = (h @ Ua[gg]) * t5
        {
            float acc[2][4] = {{0.f,0.f,0.f,0.f},{0.f,0.f,0.f,0.f}};
            for (int k0 = 0; k0 < 512; k0 += 32) {
                float4 av = *(const float4*)(g_h + (long)(b0 + arow)*512 + k0 + acol);
                As[acol+0][arow] = av.x; As[acol+1][arow] = av.y;
                As[acol+2][arow] = av.z; As[acol+3][arow] = av.w;
                *(float4*)&Bs[brow][bcol]    = *(const float4*)(UaG + (long)(k0+brow)*512 + c0 + bcol);
                *(float4*)&Bs[brow+16][bcol] = *(const float4*)(UaG + (long)(k0+brow+16)*512 + c0 + bcol);
                __syncthreads();
#pragma unroll
                for (int kk = 0; kk < 32; kk++) {
                    float2 rm = *(const float2*)&As[kk][tr];
                    float4 rn = *(const float4*)&Bs[kk][tc];
                    acc[0][0] = fmaf(rm.x, rn.x, acc[0][0]);
                    acc[0][1] = fmaf(rm.x, rn.y, acc[0][1]);
                    acc[0][2] = fmaf(rm.x, rn.z, acc[0][2]);
                    acc[0][3] = fmaf(rm.x, rn.w, acc[0][3]);
                    acc[1][0] = fmaf(rm.y, rn.x, acc[1][0]);
                    acc[1][1] = fmaf(rm.y, rn.y, acc[1][1]);
                    acc[1][2] = fmaf(rm.y, rn.z, acc[1][2]);
                    acc[1][3] = fmaf(rm.y, rn.w, acc[1][3]);
                }
                __syncthreads();
            }
#pragma unroll
            for (int i = 0; i < 2; i++) {
                long base = ((long)gg*128 + b0 + tr + i)*512 + c0 + tc;
                float4 t5v = *(const float4*)(g_t5 + base);
                float4 o = make_float4(acc[i][0]*t5v.x, acc[i][1]*t5v.y,
                                       acc[i][2]*t5v.z, acc[i][3]*t5v.w);
                *(float4*)(g_t6 + base) = o;
            }
        }
        gbar(goal); goal += RC;

        // ---- phase B: gh[gg, b0.., c0..] = t6[gg] @ Uc[gg]
        {
            const float* Ap = g_t6 + (long)gg*128*512;
            float acc[2][4] = {{0.f,0.f,0.f,0.f},{0.f,0.f,0.f,0.f}};
            for (int k0 = 0; k0 < 512; k0 += 32) {
                float4 av = *(const float4*)(Ap + (long)(b0 + arow)*512 + k0 + acol);
                As[acol+0][arow] = av.x; As[acol+1][arow] = av.y;
                As[acol+2][arow] = av.z; As[acol+3][arow] = av.w;
                *(float4*)&Bs[brow][bcol]    = *(const float4*)(UcG + (long)(k0+brow)*512 + c0 + bcol);
                *(float4*)&Bs[brow+16][bcol] = *(const float4*)(UcG + (long)(k0+brow+16)*512 + c0 + bcol);
                __syncthreads();
#pragma unroll
                for (int kk = 0; kk < 32; kk++) {
                    float2 rm = *(const float2*)&As[kk][tr];
                    float4 rn = *(const float4*)&Bs[kk][tc];
                    acc[0][0] = fmaf(rm.x, rn.x, acc[0][0]);
                    acc[0][1] = fmaf(rm.x, rn.y, acc[0][1]);
                    acc[0][2] = fmaf(rm.x, rn.z, acc[0][2]);
                    acc[0][3] = fmaf(rm.x, rn.w, acc[0][3]);
                    acc[1][0] = fmaf(rm.y, rn.x, acc[1][0]);
                    acc[1][1] = fmaf(rm.y, rn.y, acc[1][1]);
                    acc[1][2] = fmaf(rm.y, rn.z, acc[1][2]);
                    acc[1][3] = fmaf(rm.y, rn.w, acc[1][3]);
                }
                __syncthreads();
            }
#pragma unroll
            for (int i = 0; i < 2; i++) {
                long base = ((long)gg*128 + b0 + tr + i)*512 + c0 + tc;
                *(float4*)(g_gh + base) = make_float4(acc[i][0], acc[i][1], acc[i][2], acc[i][3]);
            }
        }
        gbar(goal); goal += RC;

        // ---- phase C: LSTM pointwise on slice of 512 elements
        {
            const long so = (long)t*Bdim*Hdim;
            const long GS = (long)TBdim*Hdim;
            const long GH = (long)Bdim*Hdim;
            int i0 = bx*512 + tid*2;
#pragma unroll
            for (int u = 0; u < 2; u++) {
                int i = i0 + u;
                float pi = g_gx[0*GS + so + i] + g_gh[0*GH + i];
                float pf = g_gx[1*GS + so + i] + g_gh[1*GH + i];
                float po = g_gx[2*GS + so + i] + g_gh[2*GH + i];
                float pc = g_gx[3*GS + so + i] + g_gh[3*GH + i];
                float ig = sig_f(pi), fg = sig_f(pf), og = sig_f(po);
                float ct = tanh_f(pc);
                float cn = fg*g_c[i] + ig*ct;
                float hn = og*tanh_f(cn);
                g_c[i] = cn;
                g_h[i] = hn;
                g_hs[so + i] = hn;
            }
        }
        gbar(goal); goal += RC;
    }
}

// ---------------- launch ------------------------------------------------------
extern "C" void kernel_launch(void* const* d_in, const int* in_sizes, int n_in,
                              void* d_out, int out_size)
{
    const int*   caps = (const int*)  d_in[0];
    const float* tags = (const float*)d_in[1];
    const float* h0   = (const float*)d_in[2];
    const float* c0   = (const float*)d_in[3];
    const float* Wa   = (const float*)d_in[4];
    const float* Wb   = (const float*)d_in[5];
    const float* Wc   = (const float*)d_in[6];
    const float* Ua   = (const float*)d_in[7];
    const float* Ub   = (const float*)d_in[8];
    const float* Uc   = (const float*)d_in[9];
    const float* bi   = (const float*)d_in[10];
    const float* emb  = (const float*)d_in[11];
    const float* Wout = (const float*)d_in[12];
    const float* bout = (const float*)d_in[13];
    float* out = (float*)d_out;

    float *p_xs, *p_t2, *p_t5, *p_gx, *p_hs;
    __nv_bfloat16 *p_Abf, *p_Bbf, *p_xbf, *p_t1bf, *p_WaT, *p_WcT;
    cudaGetSymbolAddress((void**)&p_xs,  g_xs);
    cudaGetSymbolAddress((void**)&p_t2,  g_t2);
    cudaGetSymbolAddress((void**)&p_t5,  g_t5);
    cudaGetSymbolAddress((void**)&p_gx,  g_gx);
    cudaGetSymbolAddress((void**)&p_hs,  g_hs);
    cudaGetSymbolAddress((void**)&p_Abf, g_Abf);
    cudaGetSymbolAddress((void**)&p_Bbf, g_Bbf);
    cudaGetSymbolAddress((void**)&p_xbf, g_xbf);
    cudaGetSymbolAddress((void**)&p_t1bf, g_t1bf);
    cudaGetSymbolAddress((void**)&p_WaT, g_WaT);
    cudaGetSymbolAddress((void**)&p_WcT, g_WcT);

    cudaFuncSetAttribute(mma_gemm_k<0>, cudaFuncAttributeMaxDynamicSharedMemorySize, OG_SMEM);
    cudaFuncSetAttribute(mma_gemm_k<1>, cudaFuncAttributeMaxDynamicSharedMemorySize, OG_SMEM);
    cudaFuncSetAttribute(mma_gemm_k<2>, cudaFuncAttributeMaxDynamicSharedMemorySize, OG_SMEM);

    // prep (independent of recurrence)
    k_gather<<<dim3(Bdim, Tdim), 128>>>(caps, emb);
    k_init<<<256, 256>>>(h0, c0);
    k_convB<<<dim3(Vdim/32, Hdim/32), dim3(32,32)>>>(Wout);
    k_convW<<<dim3(16,16,4), dim3(32,32)>>>(Wa, p_WaT);
    k_convW<<<dim3(16,16,4), dim3(32,32)>>>(Wc, p_WcT);
    k_split_rows<<<(TBdim*Edim)/256, 256>>>(p_xs, p_xbf);   // after gather (stream-ordered)

    // t2 / t5 (fp32, small)
    gemm_k<64,64,16,4,4><<<dim3(8,2,4), 256>>>(tags, Wb, p_t2, Bdim, Rdim, NTG,
        (long)NTG*Rdim, (long)Bdim*Rdim);
    gemm_k<64,64,16,4,4><<<dim3(8,2,4), 256>>>(tags, Ub, p_t5, Bdim, Rdim, NTG,
        (long)NTG*Rdim, (long)Bdim*Rdim);

    // t1bf = split( (xs @ Wa) * t2 );  gx = t1 @ Wc + b
    mma_gemm_k<1><<<dim3(24,4,4), 256, OG_SMEM>>>(p_xbf, p_WaT, nullptr, p_t1bf, p_t2,
        0L, (long)Rdim*KP);
    mma_gemm_k<2><<<dim3(24,4,4), 256, OG_SMEM>>>(p_t1bf, p_WcT, p_gx, nullptr, bi,
        (long)TBdim*KP, (long)Hdim*KP);

    // persistent recurrence (24 steps, grid-wide barriers)
    rec_k<<<RC, 256>>>(Ua, Uc);

    // hs -> split bf16, then out logits
    k_split_rows<<<(TBdim*Hdim)/256, 256>>>(p_hs, p_Abf);
    mma_gemm_k<0><<<dim3(TBdim/128, (Vdim + 127)/128), 256, OG_SMEM>>>(p_Abf, p_Bbf,
        out, nullptr, bout, 0L, 0L);
}

// round 5
// speedup vs baseline: 2.0418x; 1.2439x over previous
#include <cuda_runtime.h>
#include <cuda_fp16.h>
#include <math.h>
#include <cstdint>

#define Bdim 128
#define Tdim 24
#define Edim 512
#define Hdim 512
#define Rdim 512
#define NTG 400
#define Vdim 20000
#define TBdim (Tdim*Bdim)   // 3072
#define KPA 1024            // fp16 pair K for A ([hi|lo])
#define RC 128              // persistent recurrence CTAs

// ---------------- scratch (device globals; no allocation allowed) ----------
__device__ float g_t2[4*Bdim*Rdim];
__device__ float g_t5[4*Bdim*Rdim];
__device__ float g_gx[4L*TBdim*Hdim];
__device__ float g_t6[4*Bdim*Rdim];
__device__ float g_gh[4*Bdim*Hdim];
__device__ float g_h[Bdim*Hdim];
__device__ float g_c[Bdim*Hdim];
__device__ unsigned g_sync;
__device__ __half g_x2[(long)TBdim*KPA];        // xs pair [3072,1024]
__device__ __half g_t12[4L*TBdim*KPA];          // t1 pair per gate
__device__ __half g_hs2[(long)TBdim*KPA];       // hs pair
__device__ __half g_Wa2[4L*Rdim*Hdim];          // Wa^T hi fp16 [g][r(n)][k]
__device__ __half g_Wc2[4L*Rdim*Hdim];          // Wc^T hi fp16
__device__ __half g_Wo2[(long)Vdim*Hdim];       // Wout^T hi fp16 [20000,512]

__device__ __forceinline__ uint32_t smem_u32(const void* p) {
    uint32_t a;
    asm("{ .reg .u64 t; cvta.to.shared.u64 t, %1; cvt.u32.u64 %0, t; }" : "=r"(a) : "l"(p));
    return a;
}

// ================= unified fp16-pair MMA GEMM ===============================
// A: [M, 1024] fp16 ([hi(512) | lo(512)]) row-major (+z*aS)
// B: [N, 512]  fp16 (hi of fp32)          row-major (+z*bS)
// C = A_hi@B^T + A_lo@B^T  (= A_fp32 @ B_hi^T)
// CTA tile 128x256, BK=64 (8 chunks), 3-stage cp.async, 8 warps of 64x64.
// MODE 0: out logits (bias + [t*128+b]->[b*24+t] remap, n<Vdim guard)
// MODE 1: t1: C_pair = acc * X[z*65536 + (row&127)*512 + n]
// MODE 2: gx: C_f32 = acc + X[z*512 + n]
#define OG_STRIDE 144
#define OG_TILEA  (128*OG_STRIDE)          // 18432
#define OG_TILEB  (256*OG_STRIDE)          // 36864
#define OG_STAGEB (2*OG_TILEA + OG_TILEB)  // 73728
#define OG_SMEM   (3*OG_STAGEB)            // 221184

template<int MODE>
__device__ __forceinline__ void og_load(uint32_t sbase, int stage,
    const __half* __restrict__ A, const __half* __restrict__ B,
    int mtile, int ntile, int k, int tid)
{
    uint32_t sa = sbase + stage*OG_STAGEB;
    uint32_t sl = sa + OG_TILEA;
    uint32_t sb = sa + 2*OG_TILEA;
    const __half* Ag = A + (long)mtile*128*KPA + k*64;
    const __half* Bg = B + (long)ntile*256*512 + k*64;
#pragma unroll
    for (int i = 0; i < 4; i++) {
        int e = tid + i*256;
        int row = e >> 3, q = e & 7;
        uint32_t d = sa + row*OG_STRIDE + q*16;
        asm volatile("cp.async.cg.shared.global [%0], [%1], 16;"
            :: "r"(d), "l"(Ag + (long)row*KPA + q*8) : "memory");
        uint32_t d2 = sl + row*OG_STRIDE + q*16;
        asm volatile("cp.async.cg.shared.global [%0], [%1], 16;"
            :: "r"(d2), "l"(Ag + 512 + (long)row*KPA + q*8) : "memory");
    }
#pragma unroll
    for (int i = 0; i < 8; i++) {
        int e = tid + i*256;
        int row = e >> 3, q = e & 7;
        uint32_t d = sb + row*OG_STRIDE + q*16;
        if (MODE != 0 || ntile*256 + row < Vdim) {
            asm volatile("cp.async.cg.shared.global [%0], [%1], 16;"
                :: "r"(d), "l"(Bg + (long)row*512 + q*8) : "memory");
        } else {
            asm volatile("st.shared.v4.b32 [%0], {%1,%1,%1,%1};"
                :: "r"(d), "r"(0) : "memory");
        }
    }
}

__device__ __forceinline__ void ldm_x4(uint32_t* r, uint32_t addr)
{
    asm volatile("ldmatrix.sync.aligned.m8n8.x4.shared.b16 {%0,%1,%2,%3}, [%4];"
        : "=r"(r[0]), "=r"(r[1]), "=r"(r[2]), "=r"(r[3]) : "r"(addr));
}

__device__ __forceinline__ void mma16816(float* c, const uint32_t* a, const uint32_t* b)
{
    asm volatile("mma.sync.aligned.m16n8k16.row.col.f32.f16.f16.f32 "
        "{%0,%1,%2,%3}, {%4,%5,%6,%7}, {%8,%9}, {%0,%1,%2,%3};"
        : "+f"(c[0]), "+f"(c[1]), "+f"(c[2]), "+f"(c[3])
        : "r"(a[0]), "r"(a[1]), "r"(a[2]), "r"(a[3]), "r"(b[0]), "r"(b[1]));
}

__device__ __forceinline__ void store_pair(__half* p, int col, float v)
{
    __half hi = __float2half_rn(v);
    __half lo = __float2half_rn(v - __half2float(hi));
    p[col] = hi; p[512 + col] = lo;
}

template<int MODE>
__global__ void __launch_bounds__(256, 1) mma_gemm_k(
    const __half* __restrict__ A, const __half* __restrict__ B,
    float* __restrict__ Cf, __half* __restrict__ Cb,
    const float* __restrict__ X, long aS, long bS)
{
    extern __shared__ char smem[];
    const uint32_t sbase = smem_u32(smem);
    const int tid = threadIdx.x, wid = tid >> 5, lane = tid & 31;
    const int wm = wid & 1, wn = wid >> 1;       // 2 x 4 warps, each 64x64
    const int mtile = blockIdx.x, ntile = blockIdx.y, z = blockIdx.z;

    const __half* Az = A + (long)z*aS;
    const __half* Bz = B + (long)z*bS;

    float acc[4][8][4];
#pragma unroll
    for (int i = 0; i < 4; i++)
#pragma unroll
        for (int j = 0; j < 8; j++)
#pragma unroll
            for (int q = 0; q < 4; q++) acc[i][j][q] = 0.f;

#pragma unroll
    for (int s = 0; s < 3; s++) {
        og_load<MODE>(sbase, s, Az, Bz, mtile, ntile, s, tid);
        asm volatile("cp.async.commit_group;" ::: "memory");
    }

    for (int k = 0; k < 8; k++) {
        asm volatile("cp.async.wait_group 2;" ::: "memory");
        __syncthreads();

        uint32_t base = sbase + (k % 3)*OG_STAGEB;
        uint32_t sbB = base + 2*OG_TILEA;
#pragma unroll
        for (int ks = 0; ks < 4; ks++) {
            uint32_t b[8][2];
#pragma unroll
            for (int np = 0; np < 4; np++) {
                uint32_t row = wn*64 + np*16 + (lane & 7) + ((lane >> 4) & 1)*8;
                uint32_t addr = sbB + row*OG_STRIDE + (ks*16 + ((lane >> 3) & 1)*8)*2;
                uint32_t r[4];
                ldm_x4(r, addr);
                b[np*2][0] = r[0];   b[np*2][1] = r[1];
                b[np*2+1][0] = r[2]; b[np*2+1][1] = r[3];
            }
#pragma unroll
            for (int h = 0; h < 2; h++) {
                uint32_t ab = base + h*OG_TILEA;
                uint32_t a[4][4];
#pragma unroll
                for (int mi = 0; mi < 4; mi++) {
                    uint32_t addr = ab + (wm*64 + mi*16 + (lane & 15))*OG_STRIDE
                                  + (ks*16 + (lane >> 4)*8)*2;
                    ldm_x4(a[mi], addr);
                }
#pragma unroll
                for (int mi = 0; mi < 4; mi++)
#pragma unroll
                    for (int ni = 0; ni < 8; ni++)
                        mma16816(acc[mi][ni], a[mi], b[ni]);
            }
        }
        __syncthreads();

        if (k + 3 < 8) og_load<MODE>(sbase, (k + 3) % 3, Az, Bz, mtile, ntile, k + 3, tid);
        asm volatile("cp.async.commit_group;" ::: "memory");
    }

#pragma unroll
    for (int mi = 0; mi < 4; mi++) {
#pragma unroll
        for (int ni = 0; ni < 8; ni++) {
            int n = ntile*256 + wn*64 + ni*8 + (lane & 3)*2;
            int gr0 = mtile*128 + wm*64 + mi*16 + (lane >> 2);
            int gr1 = gr0 + 8;
            if (MODE == 0) {
                if (n < Vdim) {
                    float2 bv = *(const float2*)(X + n);
                    long o0 = ((long)(gr0 & 127)*Tdim + (gr0 >> 7))*Vdim + n;
                    long o1 = ((long)(gr1 & 127)*Tdim + (gr1 >> 7))*Vdim + n;
                    *(float2*)(Cf + o0) = make_float2(acc[mi][ni][0] + bv.x, acc[mi][ni][1] + bv.y);
                    *(float2*)(Cf + o1) = make_float2(acc[mi][ni][2] + bv.x, acc[mi][ni][3] + bv.y);
                }
            } else if (MODE == 1) {
                const float* Xg = X + (long)z*Bdim*Rdim;
                __half* Cz = Cb + (long)z*TBdim*KPA;
                store_pair(Cz + (long)gr0*KPA, n,     acc[mi][ni][0]*Xg[(gr0 & 127)*512 + n]);
                store_pair(Cz + (long)gr0*KPA, n + 1, acc[mi][ni][1]*Xg[(gr0 & 127)*512 + n + 1]);
                store_pair(Cz + (long)gr1*KPA, n,     acc[mi][ni][2]*Xg[(gr1 & 127)*512 + n]);
                store_pair(Cz + (long)gr1*KPA, n + 1, acc[mi][ni][3]*Xg[(gr1 & 127)*512 + n + 1]);
            } else {
                const float* Xg = X + z*512;
                float* Cz = Cf + (long)z*TBdim*512;
                float2 bv = make_float2(Xg[n], Xg[n + 1]);
                *(float2*)(Cz + (long)gr0*512 + n) = make_float2(acc[mi][ni][0] + bv.x, acc[mi][ni][1] + bv.y);
                *(float2*)(Cz + (long)gr1*512 + n) = make_float2(acc[mi][ni][2] + bv.x, acc[mi][ni][3] + bv.y);
            }
        }
    }
}

// ---------------- conversions ------------------------------------------------
__global__ void k_convW(const float* __restrict__ W, __half* __restrict__ Bp)
{   // W[g][512,512] (k,n) -> Bp[g][n][k] hi fp16
    __shared__ float t[32][33];
    int g = blockIdx.z;
    int n = blockIdx.x*32 + threadIdx.x;
    int k = blockIdx.y*32 + threadIdx.y;
    t[threadIdx.y][threadIdx.x] = W[(long)g*512*512 + (long)k*512 + n];
    __syncthreads();
    int n2 = blockIdx.x*32 + threadIdx.y;
    int k2 = blockIdx.y*32 + threadIdx.x;
    Bp[((long)g*512 + n2)*512 + k2] = __float2half_rn(t[threadIdx.x][threadIdx.y]);
}

__global__ void k_convB(const float* __restrict__ Wout)
{   // Wout[512,20000] -> g_Wo2[n][k] hi fp16
    __shared__ float t[32][33];
    int n = blockIdx.x*32 + threadIdx.x;
    int k = blockIdx.y*32 + threadIdx.y;
    t[threadIdx.y][threadIdx.x] = Wout[(long)k*Vdim + n];
    __syncthreads();
    int n2 = blockIdx.x*32 + threadIdx.y;
    int k2 = blockIdx.y*32 + threadIdx.x;
    g_Wo2[(long)n2*512 + k2] = __float2half_rn(t[threadIdx.x][threadIdx.y]);
}

// ---------------- embedding gather (writes fp16 pair directly) ---------------
__global__ void k_gather(const int* __restrict__ caps, const float* __restrict__ emb)
{
    const int b = blockIdx.x, t = blockIdx.y;
    float4 v = make_float4(0.f, 0.f, 0.f, 0.f);
    if (t > 0) {
        int tok = caps[b*Tdim + (t-1)];
        v = ((const float4*)(emb + (long)tok*Edim))[threadIdx.x];
    }
    __half2 h01 = __floats2half2_rn(v.x, v.y);
    __half2 h23 = __floats2half2_rn(v.z, v.w);
    __half2 l01 = __floats2half2_rn(v.x - __half2float(__low2half(h01)),
                                    v.y - __half2float(__high2half(h01)));
    __half2 l23 = __floats2half2_rn(v.z - __half2float(__low2half(h23)),
                                    v.w - __half2float(__high2half(h23)));
    __half* base = g_x2 + (long)(t*Bdim + b)*KPA + threadIdx.x*4;
    *(__half2*)(base)       = h01;
    *(__half2*)(base + 2)   = h23;
    *(__half2*)(base + 512) = l01;
    *(__half2*)(base + 514) = l23;
}

__global__ void k_init(const float* __restrict__ h0, const float* __restrict__ c0)
{
    int i = blockIdx.x*blockDim.x + threadIdx.x;
    g_h[i] = h0[i];
    g_c[i] = c0[i];
    if (i == 0) g_sync = 0;
}

// ---------------- fp32 tiled SGEMM (t2/t5 prep only) -------------------------
template<int BM,int BN,int BK,int TM,int TN>
__global__ void gemm_k(const float* __restrict__ A, const float* __restrict__ Bm,
                       float* __restrict__ C, int M, int N, int K, long sB, long sC)
{
    constexpr int THREADS = (BM/TM)*(BN/TN);
    __shared__ float As[BK][BM];
    __shared__ float Bs[BK][BN];
    const int g = blockIdx.z;
    const float* Bg = Bm + (long)g*sB;
    float* Cg = C + (long)g*sC;
    const int m0 = blockIdx.y*BM;
    const int n0 = blockIdx.x*BN;
    const int tid = threadIdx.x;
    constexpr int AK4 = BK/4;
    const int aRow = tid / AK4, aCol = (tid % AK4)*4;
    constexpr int AROWS = THREADS/AK4;
    constexpr int BN4 = BN/4;
    const int bRow = tid / BN4, bCol = (tid % BN4)*4;
    constexpr int BROWS = THREADS/BN4;
    const int tr = (tid/(BN/TN))*TM, tc = (tid%(BN/TN))*TN;

    float acc[TM][TN];
#pragma unroll
    for (int i = 0; i < TM; i++)
#pragma unroll
        for (int j = 0; j < TN; j++) acc[i][j] = 0.f;

    for (int k0 = 0; k0 < K; k0 += BK) {
#pragma unroll
        for (int i = 0; i < BM; i += AROWS) {
            float4 v = *(const float4*)(A + (long)(m0 + aRow + i)*K + (k0 + aCol));
            As[aCol+0][aRow+i] = v.x; As[aCol+1][aRow+i] = v.y;
            As[aCol+2][aRow+i] = v.z; As[aCol+3][aRow+i] = v.w;
        }
#pragma unroll
        for (int i = 0; i < BK; i += BROWS) {
            float4 v = *(const float4*)(Bg + (long)(k0 + bRow + i)*N + (n0 + bCol));
            *(float4*)&Bs[bRow+i][bCol] = v;
        }
        __syncthreads();
#pragma unroll
        for (int kk = 0; kk < BK; kk++) {
            float rm[TM], rn[TN];
#pragma unroll
            for (int i = 0; i < TM; i++) rm[i] = As[kk][tr+i];
#pragma unroll
            for (int j = 0; j < TN; j++) rn[j] = Bs[kk][tc+j];
#pragma unroll
            for (int i = 0; i < TM; i++)
#pragma unroll
                for (int j = 0; j < TN; j++)
                    acc[i][j] = fmaf(rm[i], rn[j], acc[i][j]);
        }
        __syncthreads();
    }
#pragma unroll
    for (int i = 0; i < TM; i++)
#pragma unroll
        for (int j = 0; j < TN; j++)
            Cg[(long)(m0 + tr + i)*N + n0 + tc + j] = acc[i][j];
}

// ---------------- persistent recurrence kernel -------------------------------
__device__ __forceinline__ void gbar(unsigned goal)
{
    __syncthreads();
    __threadfence();
    if (threadIdx.x == 0) {
        atomicAdd(&g_sync, 1u);
        unsigned v;
        do {
            asm volatile("ld.global.acquire.gpu.u32 %0, [%1];" : "=r"(v) : "l"(&g_sync));
        } while (v < goal);
    }
    __syncthreads();
}

__device__ __forceinline__ float sig_f(float x)
{
    return 1.f / (1.f + __expf(-x));
}
__device__ __forceinline__ float tanh_f(float x)
{
    return 2.f / (1.f + __expf(-2.f*x)) - 1.f;
}

__global__ void __launch_bounds__(256, 1) rec_k(const float* __restrict__ Ua,
                                                const float* __restrict__ Uc)
{
    __shared__ float As[32][34];
    __shared__ float Bs[32][64];
    const int tid = threadIdx.x;
    const int bx  = blockIdx.x;
    const int gg  = bx >> 5;          // gate
    const int bt  = (bx >> 3) & 3;    // 32-row b tile
    const int rt  = bx & 7;           // 64-col tile
    const int b0  = bt*32;
    const int c0  = rt*64;
    const int ty  = tid >> 4, tx = tid & 15;
    const int tr  = ty*2,   tc = tx*4;
    const int arow = tid >> 3, acol = (tid & 7)*4;
    const int brow = tid >> 4, bcol = (tid & 15)*4;

    const float* UaG = Ua + (long)gg*512*512;
    const float* UcG = Uc + (long)gg*512*512;
    unsigned goal = RC;

    for (int t = 0; t < Tdim; t++) {
        // ---- phase A: t6[gg, b0.., c0..] = (h @ Ua[gg]) * t5
        {
            float acc[2][4] = {{0.f,0.f,0.f,0.f},{0.f,0.f,0.f,0.f}};
            for (int k0 = 0; k0 < 512; k0 += 32) {
                float4 av = *(const float4*)(g_h + (long)(b0 + arow)*512 + k0 + acol);
                As[acol+0][arow] = av.x; As[acol+1][arow] = av.y;
                As[acol+2][arow] = av.z; As[acol+3][arow] = av.w;
                *(float4*)&Bs[brow][bcol]    = *(const float4*)(UaG + (long)(k0+brow)*512 + c0 + bcol);
                *(float4*)&Bs[brow+16][bcol] = *(const float4*)(UaG + (long)(k0+brow+16)*512 + c0 + bcol);
                __syncthreads();
#pragma unroll
                for (int kk = 0; kk < 32; kk++) {
                    float2 rm = *(const float2*)&As[kk][tr];
                    float4 rn = *(const float4*)&Bs[kk][tc];
                    acc[0][0] = fmaf(rm.x, rn.x, acc[0][0]);
                    acc[0][1] = fmaf(rm.x, rn.y, acc[0][1]);
                    acc[0][2] = fmaf(rm.x, rn.z, acc[0][2]);
                    acc[0][3] = fmaf(rm.x, rn.w, acc[0][3]);
                    acc[1][0] = fmaf(rm.y, rn.x, acc[1][0]);
                    acc[1][1] = fmaf(rm.y, rn.y, acc[1][1]);
                    acc[1][2] = fmaf(rm.y, rn.z, acc[1][2]);
                    acc[1][3] = fmaf(rm.y, rn.w, acc[1][3]);
                }
                __syncthreads();
            }
#pragma unroll
            for (int i = 0; i < 2; i++) {
                long base = ((long)gg*128 + b0 + tr + i)*512 + c0 + tc;
                float4 t5v = *(const float4*)(g_t5 + base);
                *(float4*)(g_t6 + base) = make_float4(acc[i][0]*t5v.x, acc[i][1]*t5v.y,
                                                      acc[i][2]*t5v.z, acc[i][3]*t5v.w);
            }
        }
        gbar(goal); goal += RC;

        // ---- phase B: gh[gg, b0.., c0..] = t6[gg] @ Uc[gg]
        {
            const float* Ap = g_t6 + (long)gg*128*512;
            float acc[2][4] = {{0.f,0.f,0.f,0.f},{0.f,0.f,0.f,0.f}};
            for (int k0 = 0; k0 < 512; k0 += 32) {
                float4 av = *(const float4*)(Ap + (long)(b0 + arow)*512 + k0 + acol);
                As[acol+0][arow] = av.x; As[acol+1][arow] = av.y;
                As[acol+2][arow] = av.z; As[acol+3][arow] = av.w;
                *(float4*)&Bs[brow][bcol]    = *(const float4*)(UcG + (long)(k0+brow)*512 + c0 + bcol);
                *(float4*)&Bs[brow+16][bcol] = *(const float4*)(UcG + (long)(k0+brow+16)*512 + c0 + bcol);
                __syncthreads();
#pragma unroll
                for (int kk = 0; kk < 32; kk++) {
                    float2 rm = *(const float2*)&As[kk][tr];
                    float4 rn = *(const float4*)&Bs[kk][tc];
                    acc[0][0] = fmaf(rm.x, rn.x, acc[0][0]);
                    acc[0][1] = fmaf(rm.x, rn.y, acc[0][1]);
                    acc[0][2] = fmaf(rm.x, rn.z, acc[0][2]);
                    acc[0][3] = fmaf(rm.x, rn.w, acc[0][3]);
                    acc[1][0] = fmaf(rm.y, rn.x, acc[1][0]);
                    acc[1][1] = fmaf(rm.y, rn.y, acc[1][1]);
                    acc[1][2] = fmaf(rm.y, rn.z, acc[1][2]);
                    acc[1][3] = fmaf(rm.y, rn.w, acc[1][3]);
                }
                __syncthreads();
            }
#pragma unroll
            for (int i = 0; i < 2; i++) {
                long base = ((long)gg*128 + b0 + tr + i)*512 + c0 + tc;
                *(float4*)(g_gh + base) = make_float4(acc[i][0], acc[i][1], acc[i][2], acc[i][3]);
            }
        }
        gbar(goal); goal += RC;

        // ---- phase C: LSTM pointwise; writes h fp32 and hs fp16 pair
        {
            const long GS = (long)TBdim*Hdim;
            const long GH = (long)Bdim*Hdim;
            const long so = (long)t*Bdim*Hdim;
            int i0 = bx*512 + tid*2;
            float hv[2];
#pragma unroll
            for (int u = 0; u < 2; u++) {
                int i = i0 + u;
                float pi = g_gx[0*GS + so + i] + g_gh[0*GH + i];
                float pf = g_gx[1*GS + so + i] + g_gh[1*GH + i];
                float po = g_gx[2*GS + so + i] + g_gh[2*GH + i];
                float pc = g_gx[3*GS + so + i] + g_gh[3*GH + i];
                float ig = sig_f(pi), fg = sig_f(pf), og = sig_f(po);
                float ct = tanh_f(pc);
                float cn = fg*g_c[i] + ig*ct;
                float hn = og*tanh_f(cn);
                g_c[i] = cn;
                g_h[i] = hn;
                hv[u] = hn;
            }
            // hs pair: row = t*128 + bx, col = tid*2
            __half2 hh = __floats2half2_rn(hv[0], hv[1]);
            __half2 ll = __floats2half2_rn(hv[0] - __half2float(__low2half(hh)),
                                           hv[1] - __half2float(__high2half(hh)));
            __half* base = g_hs2 + (long)(t*Bdim + bx)*KPA + tid*2;
            *(__half2*)(base)       = hh;
            *(__half2*)(base + 512) = ll;
        }
        gbar(goal); goal += RC;
    }
}

// ---------------- launch ------------------------------------------------------
extern "C" void kernel_launch(void* const* d_in, const int* in_sizes, int n_in,
                              void* d_out, int out_size)
{
    const int*   caps = (const int*)  d_in[0];
    const float* tags = (const float*)d_in[1];
    const float* h0   = (const float*)d_in[2];
    const float* c0   = (const float*)d_in[3];
    const float* Wa   = (const float*)d_in[4];
    const float* Wb   = (const float*)d_in[5];
    const float* Wc   = (const float*)d_in[6];
    const float* Ua   = (const float*)d_in[7];
    const float* Ub   = (const float*)d_in[8];
    const float* Uc   = (const float*)d_in[9];
    const float* bi   = (const float*)d_in[10];
    const float* emb  = (const float*)d_in[11];
    const float* Wout = (const float*)d_in[12];
    const float* bout = (const float*)d_in[13];
    float* out = (float*)d_out;

    float *p_t2, *p_t5, *p_gx;
    __half *p_x2, *p_t12, *p_hs2, *p_Wa2, *p_Wc2, *p_Wo2;
    cudaGetSymbolAddress((void**)&p_t2,  g_t2);
    cudaGetSymbolAddress((void**)&p_t5,  g_t5);
    cudaGetSymbolAddress((void**)&p_gx,  g_gx);
    cudaGetSymbolAddress((void**)&p_x2,  g_x2);
    cudaGetSymbolAddress((void**)&p_t12, g_t12);
    cudaGetSymbolAddress((void**)&p_hs2, g_hs2);
    cudaGetSymbolAddress((void**)&p_Wa2, g_Wa2);
    cudaGetSymbolAddress((void**)&p_Wc2, g_Wc2);
    cudaGetSymbolAddress((void**)&p_Wo2, g_Wo2);

    cudaFuncSetAttribute(mma_gemm_k<0>, cudaFuncAttributeMaxDynamicSharedMemorySize, OG_SMEM);
    cudaFuncSetAttribute(mma_gemm_k<1>, cudaFuncAttributeMaxDynamicSharedMemorySize, OG_SMEM);
    cudaFuncSetAttribute(mma_gemm_k<2>, cudaFuncAttributeMaxDynamicSharedMemorySize, OG_SMEM);

    // prep (independent of recurrence)
    k_gather<<<dim3(Bdim, Tdim), 128>>>(caps, emb);
    k_init<<<256, 256>>>(h0, c0);
    k_convB<<<dim3(Vdim/32, Hdim/32), dim3(32,32)>>>(Wout);
    k_convW<<<dim3(16,16,4), dim3(32,32)>>>(Wa, p_Wa2);
    k_convW<<<dim3(16,16,4), dim3(32,32)>>>(Wc, p_Wc2);

    // t2 / t5 (fp32, small)
    gemm_k<64,64,16,4,4><<<dim3(8,2,4), 256>>>(tags, Wb, p_t2, Bdim, Rdim, NTG,
        (long)NTG*Rdim, (long)Bdim*Rdim);
    gemm_k<64,64,16,4,4><<<dim3(8,2,4), 256>>>(tags, Ub, p_t5, Bdim, Rdim, NTG,
        (long)NTG*Rdim, (long)Bdim*Rdim);

    // t1 = split-pair( (xs @ Wa) * t2 );  gx = t1 @ Wc + b
    mma_gemm_k<1><<<dim3(24,2,4), 256, OG_SMEM>>>(p_x2, p_Wa2, nullptr, p_t12, p_t2,
        0L, (long)Rdim*Hdim);
    mma_gemm_k<2><<<dim3(24,2,4), 256, OG_SMEM>>>(p_t12, p_Wc2, p_gx, nullptr, bi,
        (long)TBdim*KPA, (long)Rdim*Hdim);

    // persistent recurrence (24 steps, grid-wide barriers), writes hs pair
    rec_k<<<RC, 256>>>(Ua, Uc);

    // out logits
    mma_gemm_k<0><<<dim3(TBdim/128, (Vdim + 255)/256), 256, OG_SMEM>>>(p_hs2, p_Wo2,
        out, nullptr, bout, 0L, 0L);
}

// round 6
// speedup vs baseline: 3.0709x; 1.5040x over previous
#include <cuda_runtime.h>
#include <cuda_fp16.h>
#include <math.h>
#include <cstdint>

#define Bdim 128
#define Tdim 24
#define Edim 512
#define Hdim 512
#define Rdim 512
#define NTG 400
#define Vdim 20000
#define TBdim (Tdim*Bdim)   // 3072
#define KPA 1024            // fp16 pair K ([hi|lo])
#define RC 128              // persistent recurrence CTAs

// ---------------- scratch (device globals; no allocation allowed) ----------
__device__ float g_t2[4*Bdim*Rdim];
__device__ float g_t5[4*Bdim*Rdim];
__device__ float g_gx[4L*TBdim*Hdim];
__device__ float g_gh[4*Bdim*Hdim];
__device__ float g_c[Bdim*Hdim];
__device__ unsigned g_sync;
__device__ __half g_x2[(long)TBdim*KPA];        // xs pair [3072,1024]
__device__ __half g_t12[4L*TBdim*KPA];          // t1 pair per gate
__device__ __half g_hs2[(long)TBdim*KPA];       // hs pair
__device__ __half g_h2[Bdim*KPA];               // h pair [128,1024]
__device__ __half g_t62[4L*Bdim*KPA];           // t6 pair per gate [4][128][1024]
__device__ __half g_Wa2[4L*Rdim*Hdim];          // Wa^T hi fp16 [g][r(n)][k]
__device__ __half g_Wc2[4L*Rdim*Hdim];          // Wc^T hi fp16
__device__ __half g_Wo2[(long)Vdim*Hdim];       // Wout^T hi fp16 [20000,512]

__device__ __forceinline__ uint32_t smem_u32(const void* p) {
    uint32_t a;
    asm("{ .reg .u64 t; cvta.to.shared.u64 t, %1; cvt.u32.u64 %0, t; }" : "=r"(a) : "l"(p));
    return a;
}

__device__ __forceinline__ void ldm_x4(uint32_t* r, uint32_t addr)
{
    asm volatile("ldmatrix.sync.aligned.m8n8.x4.shared.b16 {%0,%1,%2,%3}, [%4];"
        : "=r"(r[0]), "=r"(r[1]), "=r"(r[2]), "=r"(r[3]) : "r"(addr));
}

__device__ __forceinline__ void mma16816(float* c, const uint32_t* a, const uint32_t* b)
{
    asm volatile("mma.sync.aligned.m16n8k16.row.col.f32.f16.f16.f32 "
        "{%0,%1,%2,%3}, {%4,%5,%6,%7}, {%8,%9}, {%0,%1,%2,%3};"
        : "+f"(c[0]), "+f"(c[1]), "+f"(c[2]), "+f"(c[3])
        : "r"(a[0]), "r"(a[1]), "r"(a[2]), "r"(a[3]), "r"(b[0]), "r"(b[1]));
}

__device__ __forceinline__ void store_pair(__half* p, int col, float v)
{
    __half hi = __float2half_rn(v);
    __half lo = __float2half_rn(v - __half2float(hi));
    p[col] = hi; p[512 + col] = lo;
}

// ================= unified fp16-pair MMA GEMM ===============================
// A: [M,1024] fp16 ([hi|lo]); B: [N,512] fp16 hi.  C = A_fp32 @ B_hi^T
// CTA 128x256, BK=64 (8 chunks), 3-stage cp.async, 8 warps of 64x64.
#define OG_STRIDE 144
#define OG_TILEA  (128*OG_STRIDE)
#define OG_TILEB  (256*OG_STRIDE)
#define OG_STAGEB (2*OG_TILEA + OG_TILEB)
#define OG_SMEM   (3*OG_STAGEB)            // 221184

template<int MODE>
__device__ __forceinline__ void og_load(uint32_t sbase, int stage,
    const __half* __restrict__ A, const __half* __restrict__ B,
    int mtile, int ntile, int k, int tid)
{
    uint32_t sa = sbase + stage*OG_STAGEB;
    uint32_t sl = sa + OG_TILEA;
    uint32_t sb = sa + 2*OG_TILEA;
    const __half* Ag = A + (long)mtile*128*KPA + k*64;
    const __half* Bg = B + (long)ntile*256*512 + k*64;
#pragma unroll
    for (int i = 0; i < 4; i++) {
        int e = tid + i*256;
        int row = e >> 3, q = e & 7;
        uint32_t d = sa + row*OG_STRIDE + q*16;
        asm volatile("cp.async.cg.shared.global [%0], [%1], 16;"
            :: "r"(d), "l"(Ag + (long)row*KPA + q*8) : "memory");
        uint32_t d2 = sl + row*OG_STRIDE + q*16;
        asm volatile("cp.async.cg.shared.global [%0], [%1], 16;"
            :: "r"(d2), "l"(Ag + 512 + (long)row*KPA + q*8) : "memory");
    }
#pragma unroll
    for (int i = 0; i < 8; i++) {
        int e = tid + i*256;
        int row = e >> 3, q = e & 7;
        uint32_t d = sb + row*OG_STRIDE + q*16;
        if (MODE != 0 || ntile*256 + row < Vdim) {
            asm volatile("cp.async.cg.shared.global [%0], [%1], 16;"
                :: "r"(d), "l"(Bg + (long)row*512 + q*8) : "memory");
        } else {
            asm volatile("st.shared.v4.b32 [%0], {%1,%1,%1,%1};"
                :: "r"(d), "r"(0) : "memory");
        }
    }
}

template<int MODE>
__global__ void __launch_bounds__(256, 1) mma_gemm_k(
    const __half* __restrict__ A, const __half* __restrict__ B,
    float* __restrict__ Cf, __half* __restrict__ Cb,
    const float* __restrict__ X, long aS, long bS)
{
    extern __shared__ char smem[];
    const uint32_t sbase = smem_u32(smem);
    const int tid = threadIdx.x, wid = tid >> 5, lane = tid & 31;
    const int wm = wid & 1, wn = wid >> 1;
    const int mtile = blockIdx.x, ntile = blockIdx.y, z = blockIdx.z;

    const __half* Az = A + (long)z*aS;
    const __half* Bz = B + (long)z*bS;

    float acc[4][8][4];
#pragma unroll
    for (int i = 0; i < 4; i++)
#pragma unroll
        for (int j = 0; j < 8; j++)
#pragma unroll
            for (int q = 0; q < 4; q++) acc[i][j][q] = 0.f;

#pragma unroll
    for (int s = 0; s < 3; s++) {
        og_load<MODE>(sbase, s, Az, Bz, mtile, ntile, s, tid);
        asm volatile("cp.async.commit_group;" ::: "memory");
    }

    for (int k = 0; k < 8; k++) {
        asm volatile("cp.async.wait_group 2;" ::: "memory");
        __syncthreads();

        uint32_t base = sbase + (k % 3)*OG_STAGEB;
        uint32_t sbB = base + 2*OG_TILEA;
#pragma unroll
        for (int ks = 0; ks < 4; ks++) {
            uint32_t b[8][2];
#pragma unroll
            for (int np = 0; np < 4; np++) {
                uint32_t row = wn*64 + np*16 + (lane & 7) + ((lane >> 4) & 1)*8;
                uint32_t addr = sbB + row*OG_STRIDE + (ks*16 + ((lane >> 3) & 1)*8)*2;
                uint32_t r[4];
                ldm_x4(r, addr);
                b[np*2][0] = r[0];   b[np*2][1] = r[1];
                b[np*2+1][0] = r[2]; b[np*2+1][1] = r[3];
            }
#pragma unroll
            for (int h = 0; h < 2; h++) {
                uint32_t ab = base + h*OG_TILEA;
                uint32_t a[4][4];
#pragma unroll
                for (int mi = 0; mi < 4; mi++) {
                    uint32_t addr = ab + (wm*64 + mi*16 + (lane & 15))*OG_STRIDE
                                  + (ks*16 + (lane >> 4)*8)*2;
                    ldm_x4(a[mi], addr);
                }
#pragma unroll
                for (int mi = 0; mi < 4; mi++)
#pragma unroll
                    for (int ni = 0; ni < 8; ni++)
                        mma16816(acc[mi][ni], a[mi], b[ni]);
            }
        }
        __syncthreads();

        if (k + 3 < 8) og_load<MODE>(sbase, (k + 3) % 3, Az, Bz, mtile, ntile, k + 3, tid);
        asm volatile("cp.async.commit_group;" ::: "memory");
    }

#pragma unroll
    for (int mi = 0; mi < 4; mi++) {
#pragma unroll
        for (int ni = 0; ni < 8; ni++) {
            int n = ntile*256 + wn*64 + ni*8 + (lane & 3)*2;
            int gr0 = mtile*128 + wm*64 + mi*16 + (lane >> 2);
            int gr1 = gr0 + 8;
            if (MODE == 0) {
                if (n < Vdim) {
                    float2 bv = *(const float2*)(X + n);
                    long o0 = ((long)(gr0 & 127)*Tdim + (gr0 >> 7))*Vdim + n;
                    long o1 = ((long)(gr1 & 127)*Tdim + (gr1 >> 7))*Vdim + n;
                    *(float2*)(Cf + o0) = make_float2(acc[mi][ni][0] + bv.x, acc[mi][ni][1] + bv.y);
                    *(float2*)(Cf + o1) = make_float2(acc[mi][ni][2] + bv.x, acc[mi][ni][3] + bv.y);
                }
            } else if (MODE == 1) {
                const float* Xg = X + (long)z*Bdim*Rdim;
                __half* Cz = Cb + (long)z*TBdim*KPA;
                store_pair(Cz + (long)gr0*KPA, n,     acc[mi][ni][0]*Xg[(gr0 & 127)*512 + n]);
                store_pair(Cz + (long)gr0*KPA, n + 1, acc[mi][ni][1]*Xg[(gr0 & 127)*512 + n + 1]);
                store_pair(Cz + (long)gr1*KPA, n,     acc[mi][ni][2]*Xg[(gr1 & 127)*512 + n]);
                store_pair(Cz + (long)gr1*KPA, n + 1, acc[mi][ni][3]*Xg[(gr1 & 127)*512 + n + 1]);
            } else {
                const float* Xg = X + z*512;
                float* Cz = Cf + (long)z*TBdim*512;
                float2 bv = make_float2(Xg[n], Xg[n + 1]);
                *(float2*)(Cz + (long)gr0*512 + n) = make_float2(acc[mi][ni][0] + bv.x, acc[mi][ni][1] + bv.y);
                *(float2*)(Cz + (long)gr1*512 + n) = make_float2(acc[mi][ni][2] + bv.x, acc[mi][ni][3] + bv.y);
            }
        }
    }
}

// ---------------- conversions ------------------------------------------------
__global__ void k_convW(const float* __restrict__ W, __half* __restrict__ Bp)
{
    __shared__ float t[32][33];
    int g = blockIdx.z;
    int n = blockIdx.x*32 + threadIdx.x;
    int k = blockIdx.y*32 + threadIdx.y;
    t[threadIdx.y][threadIdx.x] = W[(long)g*512*512 + (long)k*512 + n];
    __syncthreads();
    int n2 = blockIdx.x*32 + threadIdx.y;
    int k2 = blockIdx.y*32 + threadIdx.x;
    Bp[((long)g*512 + n2)*512 + k2] = __float2half_rn(t[threadIdx.x][threadIdx.y]);
}

__global__ void k_convB(const float* __restrict__ Wout)
{
    __shared__ float t[32][33];
    int n = blockIdx.x*32 + threadIdx.x;
    int k = blockIdx.y*32 + threadIdx.y;
    t[threadIdx.y][threadIdx.x] = Wout[(long)k*Vdim + n];
    __syncthreads();
    int n2 = blockIdx.x*32 + threadIdx.y;
    int k2 = blockIdx.y*32 + threadIdx.x;
    g_Wo2[(long)n2*512 + k2] = __float2half_rn(t[threadIdx.x][threadIdx.y]);
}

// ---------------- embedding gather (fp16 pair) --------------------------------
__global__ void k_gather(const int* __restrict__ caps, const float* __restrict__ emb)
{
    const int b = blockIdx.x, t = blockIdx.y;
    float4 v = make_float4(0.f, 0.f, 0.f, 0.f);
    if (t > 0) {
        int tok = caps[b*Tdim + (t-1)];
        v = ((const float4*)(emb + (long)tok*Edim))[threadIdx.x];
    }
    __half2 h01 = __floats2half2_rn(v.x, v.y);
    __half2 h23 = __floats2half2_rn(v.z, v.w);
    __half2 l01 = __floats2half2_rn(v.x - __half2float(__low2half(h01)),
                                    v.y - __half2float(__high2half(h01)));
    __half2 l23 = __floats2half2_rn(v.z - __half2float(__low2half(h23)),
                                    v.w - __half2float(__high2half(h23)));
    __half* base = g_x2 + (long)(t*Bdim + b)*KPA + threadIdx.x*4;
    *(__half2*)(base)       = h01;
    *(__half2*)(base + 2)   = h23;
    *(__half2*)(base + 512) = l01;
    *(__half2*)(base + 514) = l23;
}

__global__ void k_init(const float* __restrict__ h0, const float* __restrict__ c0)
{
    int i = blockIdx.x*blockDim.x + threadIdx.x;   // 65536
    float v = h0[i];
    __half hi = __float2half_rn(v);
    __half lo = __float2half_rn(v - __half2float(hi));
    __half* p = g_h2 + (long)(i >> 9)*KPA + (i & 511);
    p[0] = hi; p[512] = lo;
    g_c[i] = c0[i];
    if (i == 0) g_sync = 0;
}

// ---------------- fp32 tiled SGEMM (t2/t5 prep only) -------------------------
template<int BM,int BN,int BK,int TM,int TN>
__global__ void gemm_k(const float* __restrict__ A, const float* __restrict__ Bm,
                       float* __restrict__ C, int M, int N, int K, long sB, long sC)
{
    constexpr int THREADS = (BM/TM)*(BN/TN);
    __shared__ float As[BK][BM];
    __shared__ float Bs[BK][BN];
    const int g = blockIdx.z;
    const float* Bg = Bm + (long)g*sB;
    float* Cg = C + (long)g*sC;
    const int m0 = blockIdx.y*BM;
    const int n0 = blockIdx.x*BN;
    const int tid = threadIdx.x;
    constexpr int AK4 = BK/4;
    const int aRow = tid / AK4, aCol = (tid % AK4)*4;
    constexpr int AROWS = THREADS/AK4;
    constexpr int BN4 = BN/4;
    const int bRow = tid / BN4, bCol = (tid % BN4)*4;
    constexpr int BROWS = THREADS/BN4;
    const int tr = (tid/(BN/TN))*TM, tc = (tid%(BN/TN))*TN;

    float acc[TM][TN];
#pragma unroll
    for (int i = 0; i < TM; i++)
#pragma unroll
        for (int j = 0; j < TN; j++) acc[i][j] = 0.f;

    for (int k0 = 0; k0 < K; k0 += BK) {
#pragma unroll
        for (int i = 0; i < BM; i += AROWS) {
            float4 v = *(const float4*)(A + (long)(m0 + aRow + i)*K + (k0 + aCol));
            As[aCol+0][aRow+i] = v.x; As[aCol+1][aRow+i] = v.y;
            As[aCol+2][aRow+i] = v.z; As[aCol+3][aRow+i] = v.w;
        }
#pragma unroll
        for (int i = 0; i < BK; i += BROWS) {
            float4 v = *(const float4*)(Bg + (long)(k0 + bRow + i)*N + (n0 + bCol));
            *(float4*)&Bs[bRow+i][bCol] = v;
        }
        __syncthreads();
#pragma unroll
        for (int kk = 0; kk < BK; kk++) {
            float rm[TM], rn[TN];
#pragma unroll
            for (int i = 0; i < TM; i++) rm[i] = As[kk][tr+i];
#pragma unroll
            for (int j = 0; j < TN; j++) rn[j] = Bs[kk][tc+j];
#pragma unroll
            for (int i = 0; i < TM; i++)
#pragma unroll
                for (int j = 0; j < TN; j++)
                    acc[i][j] = fmaf(rm[i], rn[j], acc[i][j]);
        }
        __syncthreads();
    }
#pragma unroll
    for (int i = 0; i < TM; i++)
#pragma unroll
        for (int j = 0; j < TN; j++)
            Cg[(long)(m0 + tr + i)*N + n0 + tc + j] = acc[i][j];
}

// ---------------- persistent tensor-core recurrence --------------------------
// 128 CTAs: gate gg = bx>>5, col tile ct = bx&31 (16 cols).
// SMEM: 4 weight slabs [16 n][512 k] fp16 (UaHi,UaLo,UcHi,UcLo) persistent,
//       3-stage A pipeline of [128 m][64 k] hi+lo.
#define RW_STRIDE 1040                    // bytes per weight row (520 halfs)
#define RW_SLAB   (16*RW_STRIDE)          // 16640
#define RA_STRIDE 144
#define RA_SLAB   (128*RA_STRIDE)         // 18432
#define RA_BASE   (4*RW_SLAB)             // 66560
#define RA_STAGE  (2*RA_SLAB)             // 36864
#define REC_SMEM  (RA_BASE + 3*RA_STAGE)  // 177152

__device__ __forceinline__ void gbar(unsigned goal)
{
    __syncthreads();
    __threadfence();
    if (threadIdx.x == 0) {
        atomicAdd(&g_sync, 1u);
        unsigned v;
        do {
            asm volatile("ld.global.acquire.gpu.u32 %0, [%1];" : "=r"(v) : "l"(&g_sync));
        } while (v < goal);
    }
    __syncthreads();
}

__device__ __forceinline__ float sig_f(float x)  { return 1.f/(1.f + __expf(-x)); }
__device__ __forceinline__ float tanh_f(float x) { return 2.f/(1.f + __expf(-2.f*x)) - 1.f; }

__device__ __forceinline__ void rec_loadA(uint32_t stg, const __half* __restrict__ Asrc,
                                          int chunk, int tid)
{
    const __half* p = Asrc + chunk*64;
#pragma unroll
    for (int i = 0; i < 4; i++) {
        int e = tid + i*256;
        int row = e >> 3, q = e & 7;
        uint32_t d = stg + row*RA_STRIDE + q*16;
        asm volatile("cp.async.cg.shared.global [%0], [%1], 16;"
            :: "r"(d), "l"(p + (long)row*KPA + q*8) : "memory");
        uint32_t d2 = stg + RA_SLAB + row*RA_STRIDE + q*16;
        asm volatile("cp.async.cg.shared.global [%0], [%1], 16;"
            :: "r"(d2), "l"(p + 512 + (long)row*KPA + q*8) : "memory");
    }
}

// one GEMM phase: acc[2][4] (m16 x n16 per warp) = Asrc_pair @ W_pair^T
__device__ __forceinline__ void rec_phase(uint32_t sbase, uint32_t wbase,
                                          const __half* __restrict__ Asrc,
                                          int tid, int wid, int lane, float acc[2][4])
{
#pragma unroll
    for (int i = 0; i < 2; i++)
#pragma unroll
        for (int q = 0; q < 4; q++) acc[i][q] = 0.f;

#pragma unroll
    for (int s = 0; s < 3; s++) {
        rec_loadA(sbase + RA_BASE + s*RA_STAGE, Asrc, s, tid);
        asm volatile("cp.async.commit_group;" ::: "memory");
    }
    for (int k = 0; k < 8; k++) {
        asm volatile("cp.async.wait_group 2;" ::: "memory");
        __syncthreads();
        uint32_t st = sbase + RA_BASE + (k % 3)*RA_STAGE;
#pragma unroll
        for (int ks = 0; ks < 4; ks++) {
            int krow = k*64 + ks*16 + ((lane >> 3) & 1)*8;
            uint32_t baddr = wbase + ((lane & 7) + ((lane >> 4) & 1)*8)*RW_STRIDE + krow*2;
            uint32_t rhi[4], rlo[4];
            ldm_x4(rhi, baddr);
            ldm_x4(rlo, baddr + RW_SLAB);
            uint32_t bhi[2][2] = {{rhi[0], rhi[1]}, {rhi[2], rhi[3]}};
            uint32_t blo[2][2] = {{rlo[0], rlo[1]}, {rlo[2], rlo[3]}};
            uint32_t aaddr = st + (wid*16 + (lane & 15))*RA_STRIDE + (ks*16 + (lane >> 4)*8)*2;
            uint32_t ahi[4], alo[4];
            ldm_x4(ahi, aaddr);
            ldm_x4(alo, aaddr + RA_SLAB);
#pragma unroll
            for (int ni = 0; ni < 2; ni++) {
                mma16816(acc[ni], ahi, bhi[ni]);
                mma16816(acc[ni], ahi, blo[ni]);
                mma16816(acc[ni], alo, bhi[ni]);
            }
        }
        __syncthreads();
        if (k + 3 < 8) rec_loadA(sbase + RA_BASE + ((k + 3) % 3)*RA_STAGE, Asrc, k + 3, tid);
        asm volatile("cp.async.commit_group;" ::: "memory");
    }
}

__global__ void __launch_bounds__(256, 1) rec_k(const float* __restrict__ Ua,
                                                const float* __restrict__ Uc)
{
    extern __shared__ char smem[];
    const uint32_t sbase = smem_u32(smem);
    const int tid = threadIdx.x, wid = tid >> 5, lane = tid & 31;
    const int bx = blockIdx.x;
    const int gg = bx >> 5;
    const int c0 = (bx & 31)*16;

    // one-time weight slice conversion: W[g][k][c0+j] -> smem [j][k] hi/lo
    {
        const float* UaG = Ua + (long)gg*512*512;
        const float* UcG = Uc + (long)gg*512*512;
        for (int e = tid; e < 512*16; e += 256) {
            int k = e >> 4, j = e & 15;
            float va = UaG[(long)k*512 + c0 + j];
            __half ha = __float2half_rn(va);
            __half la = __float2half_rn(va - __half2float(ha));
            *(__half*)(smem + j*RW_STRIDE + k*2) = ha;
            *(__half*)(smem + RW_SLAB + j*RW_STRIDE + k*2) = la;
            float vc = UcG[(long)k*512 + c0 + j];
            __half hc = __float2half_rn(vc);
            __half lc = __float2half_rn(vc - __half2float(hc));
            *(__half*)(smem + 2*RW_SLAB + j*RW_STRIDE + k*2) = hc;
            *(__half*)(smem + 3*RW_SLAB + j*RW_STRIDE + k*2) = lc;
        }
    }
    __syncthreads();

    unsigned goal = RC;
    const long GS = (long)TBdim*Hdim;
    const long GH = (long)Bdim*Hdim;

    for (int t = 0; t < Tdim; t++) {
        float acc[2][4];

        // ---- phase A: t6[gg][:, c0:c0+16] = (h @ Ua[gg]) * t5, as fp16 pair
        rec_phase(sbase, sbase, g_h2, tid, wid, lane, acc);
        {
            __half* Cz = g_t62 + (long)gg*Bdim*KPA;
            const float* t5g = g_t5 + (long)gg*GH;
#pragma unroll
            for (int ni = 0; ni < 2; ni++) {
                int col = c0 + ni*8 + (lane & 3)*2;
                int r0 = wid*16 + (lane >> 2), r1 = r0 + 8;
                float2 m0 = *(const float2*)(t5g + (long)r0*512 + col);
                float2 m1 = *(const float2*)(t5g + (long)r1*512 + col);
                float v00 = acc[ni][0]*m0.x, v01 = acc[ni][1]*m0.y;
                float v10 = acc[ni][2]*m1.x, v11 = acc[ni][3]*m1.y;
                __half2 h0 = __floats2half2_rn(v00, v01);
                __half2 l0 = __floats2half2_rn(v00 - __half2float(__low2half(h0)),
                                               v01 - __half2float(__high2half(h0)));
                __half2 h1 = __floats2half2_rn(v10, v11);
                __half2 l1 = __floats2half2_rn(v10 - __half2float(__low2half(h1)),
                                               v11 - __half2float(__high2half(h1)));
                *(__half2*)(Cz + (long)r0*KPA + col)       = h0;
                *(__half2*)(Cz + (long)r0*KPA + 512 + col) = l0;
                *(__half2*)(Cz + (long)r1*KPA + col)       = h1;
                *(__half2*)(Cz + (long)r1*KPA + 512 + col) = l1;
            }
        }
        gbar(goal); goal += RC;

        // ---- phase B: gh[gg][:, c0:c0+16] = t6[gg] @ Uc[gg]
        rec_phase(sbase, sbase + 2*RW_SLAB, g_t62 + (long)gg*Bdim*KPA, tid, wid, lane, acc);
        {
            float* Cz = g_gh + (long)gg*GH;
#pragma unroll
            for (int ni = 0; ni < 2; ni++) {
                int col = c0 + ni*8 + (lane & 3)*2;
                int r0 = wid*16 + (lane >> 2), r1 = r0 + 8;
                *(float2*)(Cz + (long)r0*512 + col) = make_float2(acc[ni][0], acc[ni][1]);
                *(float2*)(Cz + (long)r1*512 + col) = make_float2(acc[ni][2], acc[ni][3]);
            }
        }
        gbar(goal); goal += RC;

        // ---- phase C: LSTM pointwise; CTA bx handles batch row b = bx
        {
            const long so = (long)t*Bdim*Hdim;
            int i0 = bx*512 + tid*2;
            float hv[2];
#pragma unroll
            for (int u = 0; u < 2; u++) {
                int i = i0 + u;
                float pi = g_gx[0*GS + so + i] + g_gh[0*GH + i];
                float pf = g_gx[1*GS + so + i] + g_gh[1*GH + i];
                float po = g_gx[2*GS + so + i] + g_gh[2*GH + i];
                float pc = g_gx[3*GS + so + i] + g_gh[3*GH + i];
                float ig = sig_f(pi), fg = sig_f(pf), og = sig_f(po);
                float ct = tanh_f(pc);
                float cn = fg*g_c[i] + ig*ct;
                float hn = og*tanh_f(cn);
                g_c[i] = cn;
                hv[u] = hn;
            }
            __half2 hh = __floats2half2_rn(hv[0], hv[1]);
            __half2 ll = __floats2half2_rn(hv[0] - __half2float(__low2half(hh)),
                                           hv[1] - __half2float(__high2half(hh)));
            // h pair (row b = bx)
            *(__half2*)(g_h2 + (long)bx*KPA + tid*2)       = hh;
            *(__half2*)(g_h2 + (long)bx*KPA + 512 + tid*2) = ll;
            // hs pair (row t*128 + bx)
            __half* hb = g_hs2 + (long)(t*Bdim + bx)*KPA + tid*2;
            *(__half2*)(hb)       = hh;
            *(__half2*)(hb + 512) = ll;
        }
        gbar(goal); goal += RC;
    }
}

// ---------------- launch ------------------------------------------------------
extern "C" void kernel_launch(void* const* d_in, const int* in_sizes, int n_in,
                              void* d_out, int out_size)
{
    const int*   caps = (const int*)  d_in[0];
    const float* tags = (const float*)d_in[1];
    const float* h0   = (const float*)d_in[2];
    const float* c0   = (const float*)d_in[3];
    const float* Wa   = (const float*)d_in[4];
    const float* Wb   = (const float*)d_in[5];
    const float* Wc   = (const float*)d_in[6];
    const float* Ua   = (const float*)d_in[7];
    const float* Ub   = (const float*)d_in[8];
    const float* Uc   = (const float*)d_in[9];
    const float* bi   = (const float*)d_in[10];
    const float* emb  = (const float*)d_in[11];
    const float* Wout = (const float*)d_in[12];
    const float* bout = (const float*)d_in[13];
    float* out = (float*)d_out;

    float *p_t2, *p_t5, *p_gx;
    __half *p_x2, *p_t12, *p_hs2, *p_Wa2, *p_Wc2, *p_Wo2;
    cudaGetSymbolAddress((void**)&p_t2,  g_t2);
    cudaGetSymbolAddress((void**)&p_t5,  g_t5);
    cudaGetSymbolAddress((void**)&p_gx,  g_gx);
    cudaGetSymbolAddress((void**)&p_x2,  g_x2);
    cudaGetSymbolAddress((void**)&p_t12, g_t12);
    cudaGetSymbolAddress((void**)&p_hs2, g_hs2);
    cudaGetSymbolAddress((void**)&p_Wa2, g_Wa2);
    cudaGetSymbolAddress((void**)&p_Wc2, g_Wc2);
    cudaGetSymbolAddress((void**)&p_Wo2, g_Wo2);

    cudaFuncSetAttribute(mma_gemm_k<0>, cudaFuncAttributeMaxDynamicSharedMemorySize, OG_SMEM);
    cudaFuncSetAttribute(mma_gemm_k<1>, cudaFuncAttributeMaxDynamicSharedMemorySize, OG_SMEM);
    cudaFuncSetAttribute(mma_gemm_k<2>, cudaFuncAttributeMaxDynamicSharedMemorySize, OG_SMEM);
    cudaFuncSetAttribute(rec_k, cudaFuncAttributeMaxDynamicSharedMemorySize, REC_SMEM);

    // order chosen so ncu (-s 5 -c 1) profiles mma_gemm_k<1> (6th launch)
    k_gather<<<dim3(Bdim, Tdim), 128>>>(caps, emb);                         // 1
    k_convW<<<dim3(16,16,4), dim3(32,32)>>>(Wa, p_Wa2);                      // 2
    gemm_k<64,64,16,4,4><<<dim3(8,2,4), 256>>>(tags, Wb, p_t2, Bdim, Rdim,   // 3
        NTG, (long)NTG*Rdim, (long)Bdim*Rdim);
    k_init<<<256, 256>>>(h0, c0);                                            // 4
    k_convW<<<dim3(16,16,4), dim3(32,32)>>>(Wc, p_Wc2);                      // 5
    mma_gemm_k<1><<<dim3(24,2,4), 256, OG_SMEM>>>(p_x2, p_Wa2, nullptr,      // 6
        p_t12, p_t2, 0L, (long)Rdim*Hdim);
    gemm_k<64,64,16,4,4><<<dim3(8,2,4), 256>>>(tags, Ub, p_t5, Bdim, Rdim,   // 7
        NTG, (long)NTG*Rdim, (long)Bdim*Rdim);
    mma_gemm_k<2><<<dim3(24,2,4), 256, OG_SMEM>>>(p_t12, p_Wc2, p_gx,        // 8
        nullptr, bi, (long)TBdim*KPA, (long)Rdim*Hdim);
    k_convB<<<dim3(Vdim/32, Hdim/32), dim3(32,32)>>>(Wout);                  // 9
    rec_k<<<RC, 256, REC_SMEM>>>(Ua, Uc);                                    // 10
    mma_gemm_k<0><<<dim3(TBdim/128, (Vdim + 255)/256), 256, OG_SMEM>>>(      // 11
        p_hs2, p_Wo2, out, nullptr, bout, 0L, 0L);
}

// round 7
// speedup vs baseline: 3.5488x; 1.1556x over previous
#include <cuda_runtime.h>
#include <cuda_fp16.h>
#include <math.h>
#include <cstdint>

#define Bdim 128
#define Tdim 24
#define Edim 512
#define Hdim 512
#define Rdim 512
#define NTG 400
#define Vdim 20000
#define TBdim (Tdim*Bdim)   // 3072
#define KPA 1024            // fp16 pair K ([hi|lo])
#define RC 128              // persistent recurrence CTAs

// ---------------- scratch (device globals; no allocation allowed) ----------
__device__ float g_t2[4*Bdim*Rdim];
__device__ float g_t5[4*Bdim*Rdim];
__device__ float g_gx[4L*TBdim*Hdim];
__device__ float g_gh[4*Bdim*Hdim];
__device__ float g_c[Bdim*Hdim];
__device__ unsigned g_sync;
__device__ __half g_x2[(long)TBdim*KPA];        // xs pair [3072,1024]
__device__ __half g_t12[4L*TBdim*KPA];          // t1 pair per gate
__device__ __half g_hs2[(long)TBdim*KPA];       // hs pair
__device__ __half g_h2[Bdim*KPA];               // h pair [128,1024]
__device__ __half g_t62[4L*Bdim*KPA];           // t6 pair per gate
__device__ __half g_Wa2[4L*Rdim*Hdim];          // Wa^T hi fp16 [g][n][k]
__device__ __half g_Wc2[4L*Rdim*Hdim];          // Wc^T hi fp16
__device__ __half g_Wo2[(long)Vdim*Hdim];       // Wout^T hi fp16 [20000,512]

__device__ __forceinline__ uint32_t smem_u32(const void* p) {
    uint32_t a;
    asm("{ .reg .u64 t; cvta.to.shared.u64 t, %1; cvt.u32.u64 %0, t; }" : "=r"(a) : "l"(p));
    return a;
}

__device__ __forceinline__ void ldm_x4(uint32_t* r, uint32_t addr)
{
    asm volatile("ldmatrix.sync.aligned.m8n8.x4.shared.b16 {%0,%1,%2,%3}, [%4];"
        : "=r"(r[0]), "=r"(r[1]), "=r"(r[2]), "=r"(r[3]) : "r"(addr));
}

__device__ __forceinline__ void mma16816(float* c, const uint32_t* a, const uint32_t* b)
{
    asm volatile("mma.sync.aligned.m16n8k16.row.col.f32.f16.f16.f32 "
        "{%0,%1,%2,%3}, {%4,%5,%6,%7}, {%8,%9}, {%0,%1,%2,%3};"
        : "+f"(c[0]), "+f"(c[1]), "+f"(c[2]), "+f"(c[3])
        : "r"(a[0]), "r"(a[1]), "r"(a[2]), "r"(a[3]), "r"(b[0]), "r"(b[1]));
}

__device__ __forceinline__ void store_pair(__half* p, int col, float v)
{
    __half hi = __float2half_rn(v);
    __half lo = __float2half_rn(v - __half2float(hi));
    p[col] = hi; p[512 + col] = lo;
}

// ================= unified fp16 MMA GEMM ====================================
// A: [M,1024] fp16 pair layout ([hi|lo]); AH=1 uses hi only, AH=2 both.
// B: [N,512] fp16 hi.  C = A @ B^T (fp32 acc)
// CTA 128x256, BK=64 (8 chunks), 3-stage cp.async, 8 warps of 64x64.
// MODE 0: out logits (bias + row remap, n<Vdim guard)
// MODE 1: t1: C_pair = acc * X[z*65536 + (row&127)*512 + n]
// MODE 2: gx: C_f32 = acc + X[z*512 + n]
#define OG_STRIDE 144
#define OG_TILEA  (128*OG_STRIDE)          // 18432
#define OG_TILEB  (256*OG_STRIDE)          // 36864

template<int MODE, int AH>
__device__ __forceinline__ void og_load(uint32_t sbase, int stage,
    const __half* __restrict__ A, const __half* __restrict__ B,
    int mtile, int ntile, int k, int tid)
{
    constexpr int STAGEB = AH*OG_TILEA + OG_TILEB;
    uint32_t sa = sbase + stage*STAGEB;
    uint32_t sb = sa + AH*OG_TILEA;
    const __half* Ag = A + (long)mtile*128*KPA + k*64;
    const __half* Bg = B + (long)ntile*256*512 + k*64;
#pragma unroll
    for (int i = 0; i < 4; i++) {
        int e = tid + i*256;
        int row = e >> 3, q = e & 7;
        uint32_t d = sa + row*OG_STRIDE + q*16;
        asm volatile("cp.async.cg.shared.global [%0], [%1], 16;"
            :: "r"(d), "l"(Ag + (long)row*KPA + q*8) : "memory");
        if (AH == 2) {
            uint32_t d2 = sa + OG_TILEA + row*OG_STRIDE + q*16;
            asm volatile("cp.async.cg.shared.global [%0], [%1], 16;"
                :: "r"(d2), "l"(Ag + 512 + (long)row*KPA + q*8) : "memory");
        }
    }
#pragma unroll
    for (int i = 0; i < 8; i++) {
        int e = tid + i*256;
        int row = e >> 3, q = e & 7;
        uint32_t d = sb + row*OG_STRIDE + q*16;
        if (MODE != 0 || ntile*256 + row < Vdim) {
            asm volatile("cp.async.cg.shared.global [%0], [%1], 16;"
                :: "r"(d), "l"(Bg + (long)row*512 + q*8) : "memory");
        } else {
            asm volatile("st.shared.v4.b32 [%0], {%1,%1,%1,%1};"
                :: "r"(d), "r"(0) : "memory");
        }
    }
}

template<int MODE, int AH>
__global__ void __launch_bounds__(256, 1) mma_gemm_k(
    const __half* __restrict__ A, const __half* __restrict__ B,
    float* __restrict__ Cf, __half* __restrict__ Cb,
    const float* __restrict__ X, long aS, long bS)
{
    constexpr int STAGEB = AH*OG_TILEA + OG_TILEB;
    extern __shared__ char smem[];
    const uint32_t sbase = smem_u32(smem);
    const int tid = threadIdx.x, wid = tid >> 5, lane = tid & 31;
    const int wm = wid & 1, wn = wid >> 1;
    const int mtile = blockIdx.x, ntile = blockIdx.y, z = blockIdx.z;

    const __half* Az = A + (long)z*aS;
    const __half* Bz = B + (long)z*bS;

    float acc[4][8][4];
#pragma unroll
    for (int i = 0; i < 4; i++)
#pragma unroll
        for (int j = 0; j < 8; j++)
#pragma unroll
            for (int q = 0; q < 4; q++) acc[i][j][q] = 0.f;

#pragma unroll
    for (int s = 0; s < 3; s++) {
        og_load<MODE, AH>(sbase, s, Az, Bz, mtile, ntile, s, tid);
        asm volatile("cp.async.commit_group;" ::: "memory");
    }

    for (int k = 0; k < 8; k++) {
        asm volatile("cp.async.wait_group 2;" ::: "memory");
        __syncthreads();

        uint32_t base = sbase + (k % 3)*STAGEB;
        uint32_t sbB = base + AH*OG_TILEA;
#pragma unroll
        for (int ks = 0; ks < 4; ks++) {
            uint32_t b[8][2];
#pragma unroll
            for (int np = 0; np < 4; np++) {
                uint32_t row = wn*64 + np*16 + (lane & 7) + ((lane >> 4) & 1)*8;
                uint32_t addr = sbB + row*OG_STRIDE + (ks*16 + ((lane >> 3) & 1)*8)*2;
                uint32_t r[4];
                ldm_x4(r, addr);
                b[np*2][0] = r[0];   b[np*2][1] = r[1];
                b[np*2+1][0] = r[2]; b[np*2+1][1] = r[3];
            }
#pragma unroll
            for (int h = 0; h < AH; h++) {
                uint32_t ab = base + h*OG_TILEA;
                uint32_t a[4][4];
#pragma unroll
                for (int mi = 0; mi < 4; mi++) {
                    uint32_t addr = ab + (wm*64 + mi*16 + (lane & 15))*OG_STRIDE
                                  + (ks*16 + (lane >> 4)*8)*2;
                    ldm_x4(a[mi], addr);
                }
#pragma unroll
                for (int mi = 0; mi < 4; mi++)
#pragma unroll
                    for (int ni = 0; ni < 8; ni++)
                        mma16816(acc[mi][ni], a[mi], b[ni]);
            }
        }
        __syncthreads();

        if (k + 3 < 8) og_load<MODE, AH>(sbase, (k + 3) % 3, Az, Bz, mtile, ntile, k + 3, tid);
        asm volatile("cp.async.commit_group;" ::: "memory");
    }

#pragma unroll
    for (int mi = 0; mi < 4; mi++) {
#pragma unroll
        for (int ni = 0; ni < 8; ni++) {
            int n = ntile*256 + wn*64 + ni*8 + (lane & 3)*2;
            int gr0 = mtile*128 + wm*64 + mi*16 + (lane >> 2);
            int gr1 = gr0 + 8;
            if (MODE == 0) {
                if (n < Vdim) {
                    float2 bv = *(const float2*)(X + n);
                    long o0 = ((long)(gr0 & 127)*Tdim + (gr0 >> 7))*Vdim + n;
                    long o1 = ((long)(gr1 & 127)*Tdim + (gr1 >> 7))*Vdim + n;
                    *(float2*)(Cf + o0) = make_float2(acc[mi][ni][0] + bv.x, acc[mi][ni][1] + bv.y);
                    *(float2*)(Cf + o1) = make_float2(acc[mi][ni][2] + bv.x, acc[mi][ni][3] + bv.y);
                }
            } else if (MODE == 1) {
                const float* Xg = X + (long)z*Bdim*Rdim;
                __half* Cz = Cb + (long)z*TBdim*KPA;
                store_pair(Cz + (long)gr0*KPA, n,     acc[mi][ni][0]*Xg[(gr0 & 127)*512 + n]);
                store_pair(Cz + (long)gr0*KPA, n + 1, acc[mi][ni][1]*Xg[(gr0 & 127)*512 + n + 1]);
                store_pair(Cz + (long)gr1*KPA, n,     acc[mi][ni][2]*Xg[(gr1 & 127)*512 + n]);
                store_pair(Cz + (long)gr1*KPA, n + 1, acc[mi][ni][3]*Xg[(gr1 & 127)*512 + n + 1]);
            } else {
                const float* Xg = X + z*512;
                float* Cz = Cf + (long)z*TBdim*512;
                float2 bv = make_float2(Xg[n], Xg[n + 1]);
                *(float2*)(Cz + (long)gr0*512 + n) = make_float2(acc[mi][ni][0] + bv.x, acc[mi][ni][1] + bv.y);
                *(float2*)(Cz + (long)gr1*512 + n) = make_float2(acc[mi][ni][2] + bv.x, acc[mi][ni][3] + bv.y);
            }
        }
    }
}

#define OG_SMEM_P (3*(2*OG_TILEA + OG_TILEB))   // AH=2: 221184
#define OG_SMEM_H (3*(1*OG_TILEA + OG_TILEB))   // AH=1: 165888

// ---------------- conversions ------------------------------------------------
__global__ void k_convW(const float* __restrict__ W, __half* __restrict__ Bp)
{
    __shared__ float t[32][33];
    int g = blockIdx.z;
    int n = blockIdx.x*32 + threadIdx.x;
    int k = blockIdx.y*32 + threadIdx.y;
    t[threadIdx.y][threadIdx.x] = W[(long)g*512*512 + (long)k*512 + n];
    __syncthreads();
    int n2 = blockIdx.x*32 + threadIdx.y;
    int k2 = blockIdx.y*32 + threadIdx.x;
    Bp[((long)g*512 + n2)*512 + k2] = __float2half_rn(t[threadIdx.x][threadIdx.y]);
}

__global__ void k_convB(const float* __restrict__ Wout)
{
    __shared__ float t[32][33];
    int n = blockIdx.x*32 + threadIdx.x;
    int k = blockIdx.y*32 + threadIdx.y;
    t[threadIdx.y][threadIdx.x] = Wout[(long)k*Vdim + n];
    __syncthreads();
    int n2 = blockIdx.x*32 + threadIdx.y;
    int k2 = blockIdx.y*32 + threadIdx.x;
    g_Wo2[(long)n2*512 + k2] = __float2half_rn(t[threadIdx.x][threadIdx.y]);
}

// ---------------- embedding gather (fp16 pair) --------------------------------
__global__ void k_gather(const int* __restrict__ caps, const float* __restrict__ emb)
{
    const int b = blockIdx.x, t = blockIdx.y;
    float4 v = make_float4(0.f, 0.f, 0.f, 0.f);
    if (t > 0) {
        int tok = caps[b*Tdim + (t-1)];
        v = ((const float4*)(emb + (long)tok*Edim))[threadIdx.x];
    }
    __half2 h01 = __floats2half2_rn(v.x, v.y);
    __half2 h23 = __floats2half2_rn(v.z, v.w);
    __half2 l01 = __floats2half2_rn(v.x - __half2float(__low2half(h01)),
                                    v.y - __half2float(__high2half(h01)));
    __half2 l23 = __floats2half2_rn(v.z - __half2float(__low2half(h23)),
                                    v.w - __half2float(__high2half(h23)));
    __half* base = g_x2 + (long)(t*Bdim + b)*KPA + threadIdx.x*4;
    *(__half2*)(base)       = h01;
    *(__half2*)(base + 2)   = h23;
    *(__half2*)(base + 512) = l01;
    *(__half2*)(base + 514) = l23;
}

__global__ void k_init(const float* __restrict__ h0, const float* __restrict__ c0)
{
    int i = blockIdx.x*blockDim.x + threadIdx.x;
    float v = h0[i];
    __half hi = __float2half_rn(v);
    __half lo = __float2half_rn(v - __half2float(hi));
    __half* p = g_h2 + (long)(i >> 9)*KPA + (i & 511);
    p[0] = hi; p[512] = lo;
    g_c[i] = c0[i];
    if (i == 0) g_sync = 0;
}

// ---------------- fp32 tiled SGEMM (t2/t5 prep only) -------------------------
template<int BM,int BN,int BK,int TM,int TN>
__global__ void gemm_k(const float* __restrict__ A, const float* __restrict__ Bm,
                       float* __restrict__ C, int M, int N, int K, long sB, long sC)
{
    constexpr int THREADS = (BM/TM)*(BN/TN);
    __shared__ float As[BK][BM];
    __shared__ float Bs[BK][BN];
    const int g = blockIdx.z;
    const float* Bg = Bm + (long)g*sB;
    float* Cg = C + (long)g*sC;
    const int m0 = blockIdx.y*BM;
    const int n0 = blockIdx.x*BN;
    const int tid = threadIdx.x;
    constexpr int AK4 = BK/4;
    const int aRow = tid / AK4, aCol = (tid % AK4)*4;
    constexpr int AROWS = THREADS/AK4;
    constexpr int BN4 = BN/4;
    const int bRow = tid / BN4, bCol = (tid % BN4)*4;
    constexpr int BROWS = THREADS/BN4;
    const int tr = (tid/(BN/TN))*TM, tc = (tid%(BN/TN))*TN;

    float acc[TM][TN];
#pragma unroll
    for (int i = 0; i < TM; i++)
#pragma unroll
        for (int j = 0; j < TN; j++) acc[i][j] = 0.f;

    for (int k0 = 0; k0 < K; k0 += BK) {
#pragma unroll
        for (int i = 0; i < BM; i += AROWS) {
            float4 v = *(const float4*)(A + (long)(m0 + aRow + i)*K + (k0 + aCol));
            As[aCol+0][aRow+i] = v.x; As[aCol+1][aRow+i] = v.y;
            As[aCol+2][aRow+i] = v.z; As[aCol+3][aRow+i] = v.w;
        }
#pragma unroll
        for (int i = 0; i < BK; i += BROWS) {
            float4 v = *(const float4*)(Bg + (long)(k0 + bRow + i)*N + (n0 + bCol));
            *(float4*)&Bs[bRow+i][bCol] = v;
        }
        __syncthreads();
#pragma unroll
        for (int kk = 0; kk < BK; kk++) {
            float rm[TM], rn[TN];
#pragma unroll
            for (int i = 0; i < TM; i++) rm[i] = As[kk][tr+i];
#pragma unroll
            for (int j = 0; j < TN; j++) rn[j] = Bs[kk][tc+j];
#pragma unroll
            for (int i = 0; i < TM; i++)
#pragma unroll
                for (int j = 0; j < TN; j++)
                    acc[i][j] = fmaf(rm[i], rn[j], acc[i][j]);
        }
        __syncthreads();
    }
#pragma unroll
    for (int i = 0; i < TM; i++)
#pragma unroll
        for (int j = 0; j < TN; j++)
            Cg[(long)(m0 + tr + i)*N + n0 + tc + j] = acc[i][j];
}

// ---------------- persistent tensor-core recurrence --------------------------
#define RW_STRIDE 1040
#define RW_SLAB   (16*RW_STRIDE)
#define RA_STRIDE 144
#define RA_SLAB   (128*RA_STRIDE)
#define RA_BASE   (4*RW_SLAB)
#define RA_STAGE  (2*RA_SLAB)
#define REC_SMEM  (RA_BASE + 3*RA_STAGE)

__device__ __forceinline__ void gbar(unsigned goal)
{
    __syncthreads();
    __threadfence();
    if (threadIdx.x == 0) {
        atomicAdd(&g_sync, 1u);
        unsigned v;
        do {
            asm volatile("ld.global.acquire.gpu.u32 %0, [%1];" : "=r"(v) : "l"(&g_sync));
        } while (v < goal);
    }
    __syncthreads();
}

__device__ __forceinline__ float sig_f(float x)  { return 1.f/(1.f + __expf(-x)); }
__device__ __forceinline__ float tanh_f(float x) { return 2.f/(1.f + __expf(-2.f*x)) - 1.f; }

__device__ __forceinline__ void rec_loadA(uint32_t stg, const __half* __restrict__ Asrc,
                                          int chunk, int tid)
{
    const __half* p = Asrc + chunk*64;
#pragma unroll
    for (int i = 0; i < 4; i++) {
        int e = tid + i*256;
        int row = e >> 3, q = e & 7;
        uint32_t d = stg + row*RA_STRIDE + q*16;
        asm volatile("cp.async.cg.shared.global [%0], [%1], 16;"
            :: "r"(d), "l"(p + (long)row*KPA + q*8) : "memory");
        uint32_t d2 = stg + RA_SLAB + row*RA_STRIDE + q*16;
        asm volatile("cp.async.cg.shared.global [%0], [%1], 16;"
            :: "r"(d2), "l"(p + 512 + (long)row*KPA + q*8) : "memory");
    }
}

__device__ __forceinline__ void rec_phase(uint32_t sbase, uint32_t wbase,
                                          const __half* __restrict__ Asrc,
                                          int tid, int wid, int lane, float acc[2][4])
{
#pragma unroll
    for (int i = 0; i < 2; i++)
#pragma unroll
        for (int q = 0; q < 4; q++) acc[i][q] = 0.f;

#pragma unroll
    for (int s = 0; s < 3; s++) {
        rec_loadA(sbase + RA_BASE + s*RA_STAGE, Asrc, s, tid);
        asm volatile("cp.async.commit_group;" ::: "memory");
    }
    for (int k = 0; k < 8; k++) {
        asm volatile("cp.async.wait_group 2;" ::: "memory");
        __syncthreads();
        uint32_t st = sbase + RA_BASE + (k % 3)*RA_STAGE;
#pragma unroll
        for (int ks = 0; ks < 4; ks++) {
            int krow = k*64 + ks*16 + ((lane >> 3) & 1)*8;
            uint32_t baddr = wbase + ((lane & 7) + ((lane >> 4) & 1)*8)*RW_STRIDE + krow*2;
            uint32_t rhi[4], rlo[4];
            ldm_x4(rhi, baddr);
            ldm_x4(rlo, baddr + RW_SLAB);
            uint32_t bhi[2][2] = {{rhi[0], rhi[1]}, {rhi[2], rhi[3]}};
            uint32_t blo[2][2] = {{rlo[0], rlo[1]}, {rlo[2], rlo[3]}};
            uint32_t aaddr = st + (wid*16 + (lane & 15))*RA_STRIDE + (ks*16 + (lane >> 4)*8)*2;
            uint32_t ahi[4], alo[4];
            ldm_x4(ahi, aaddr);
            ldm_x4(alo, aaddr + RA_SLAB);
#pragma unroll
            for (int ni = 0; ni < 2; ni++) {
                mma16816(acc[ni], ahi, bhi[ni]);
                mma16816(acc[ni], ahi, blo[ni]);
                mma16816(acc[ni], alo, bhi[ni]);
            }
        }
        __syncthreads();
        if (k + 3 < 8) rec_loadA(sbase + RA_BASE + ((k + 3) % 3)*RA_STAGE, Asrc, k + 3, tid);
        asm volatile("cp.async.commit_group;" ::: "memory");
    }
}

__global__ void __launch_bounds__(256, 1) rec_k(const float* __restrict__ Ua,
                                                const float* __restrict__ Uc)
{
    extern __shared__ char smem[];
    const uint32_t sbase = smem_u32(smem);
    const int tid = threadIdx.x, wid = tid >> 5, lane = tid & 31;
    const int bx = blockIdx.x;
    const int gg = bx >> 5;
    const int c0 = (bx & 31)*16;

    {
        const float* UaG = Ua + (long)gg*512*512;
        const float* UcG = Uc + (long)gg*512*512;
        for (int e = tid; e < 512*16; e += 256) {
            int k = e >> 4, j = e & 15;
            float va = UaG[(long)k*512 + c0 + j];
            __half ha = __float2half_rn(va);
            __half la = __float2half_rn(va - __half2float(ha));
            *(__half*)(smem + j*RW_STRIDE + k*2) = ha;
            *(__half*)(smem + RW_SLAB + j*RW_STRIDE + k*2) = la;
            float vc = UcG[(long)k*512 + c0 + j];
            __half hc = __float2half_rn(vc);
            __half lc = __float2half_rn(vc - __half2float(hc));
            *(__half*)(smem + 2*RW_SLAB + j*RW_STRIDE + k*2) = hc;
            *(__half*)(smem + 3*RW_SLAB + j*RW_STRIDE + k*2) = lc;
        }
    }
    __syncthreads();

    unsigned goal = RC;
    const long GS = (long)TBdim*Hdim;
    const long GH = (long)Bdim*Hdim;

    for (int t = 0; t < Tdim; t++) {
        float acc[2][4];

        // phase A: t6[gg][:, c0..] = (h @ Ua[gg]) * t5, stored as fp16 pair
        rec_phase(sbase, sbase, g_h2, tid, wid, lane, acc);
        {
            __half* Cz = g_t62 + (long)gg*Bdim*KPA;
            const float* t5g = g_t5 + (long)gg*GH;
#pragma unroll
            for (int ni = 0; ni < 2; ni++) {
                int col = c0 + ni*8 + (lane & 3)*2;
                int r0 = wid*16 + (lane >> 2), r1 = r0 + 8;
                float2 m0 = *(const float2*)(t5g + (long)r0*512 + col);
                float2 m1 = *(const float2*)(t5g + (long)r1*512 + col);
                float v00 = acc[ni][0]*m0.x, v01 = acc[ni][1]*m0.y;
                float v10 = acc[ni][2]*m1.x, v11 = acc[ni][3]*m1.y;
                __half2 h0 = __floats2half2_rn(v00, v01);
                __half2 l0 = __floats2half2_rn(v00 - __half2float(__low2half(h0)),
                                               v01 - __half2float(__high2half(h0)));
                __half2 h1 = __floats2half2_rn(v10, v11);
                __half2 l1 = __floats2half2_rn(v10 - __half2float(__low2half(h1)),
                                               v11 - __half2float(__high2half(h1)));
                *(__half2*)(Cz + (long)r0*KPA + col)       = h0;
                *(__half2*)(Cz + (long)r0*KPA + 512 + col) = l0;
                *(__half2*)(Cz + (long)r1*KPA + col)       = h1;
                *(__half2*)(Cz + (long)r1*KPA + 512 + col) = l1;
            }
        }
        gbar(goal); goal += RC;

        // phase B: gh[gg][:, c0..] = t6[gg] @ Uc[gg]
        rec_phase(sbase, sbase + 2*RW_SLAB, g_t62 + (long)gg*Bdim*KPA, tid, wid, lane, acc);
        {
            float* Cz = g_gh + (long)gg*GH;
#pragma unroll
            for (int ni = 0; ni < 2; ni++) {
                int col = c0 + ni*8 + (lane & 3)*2;
                int r0 = wid*16 + (lane >> 2), r1 = r0 + 8;
                *(float2*)(Cz + (long)r0*512 + col) = make_float2(acc[ni][0], acc[ni][1]);
                *(float2*)(Cz + (long)r1*512 + col) = make_float2(acc[ni][2], acc[ni][3]);
            }
        }
        gbar(goal); goal += RC;

        // phase C: LSTM pointwise on batch row bx
        {
            const long so = (long)t*Bdim*Hdim;
            int i0 = bx*512 + tid*2;
            float hv[2];
#pragma unroll
            for (int u = 0; u < 2; u++) {
                int i = i0 + u;
                float pi = g_gx[0*GS + so + i] + g_gh[0*GH + i];
                float pf = g_gx[1*GS + so + i] + g_gh[1*GH + i];
                float po = g_gx[2*GS + so + i] + g_gh[2*GH + i];
                float pc = g_gx[3*GS + so + i] + g_gh[3*GH + i];
                float ig = sig_f(pi), fg = sig_f(pf), og = sig_f(po);
                float ct = tanh_f(pc);
                float cn = fg*g_c[i] + ig*ct;
                float hn = og*tanh_f(cn);
                g_c[i] = cn;
                hv[u] = hn;
            }
            __half2 hh = __floats2half2_rn(hv[0], hv[1]);
            __half2 ll = __floats2half2_rn(hv[0] - __half2float(__low2half(hh)),
                                           hv[1] - __half2float(__high2half(hh)));
            *(__half2*)(g_h2 + (long)bx*KPA + tid*2)       = hh;
            *(__half2*)(g_h2 + (long)bx*KPA + 512 + tid*2) = ll;
            __half* hb = g_hs2 + (long)(t*Bdim + bx)*KPA + tid*2;
            *(__half2*)(hb)       = hh;
            *(__half2*)(hb + 512) = ll;
        }
        gbar(goal); goal += RC;
    }
}

// ---------------- launch ------------------------------------------------------
extern "C" void kernel_launch(void* const* d_in, const int* in_sizes, int n_in,
                              void* d_out, int out_size)
{
    const int*   caps = (const int*)  d_in[0];
    const float* tags = (const float*)d_in[1];
    const float* h0   = (const float*)d_in[2];
    const float* c0   = (const float*)d_in[3];
    const float* Wa   = (const float*)d_in[4];
    const float* Wb   = (const float*)d_in[5];
    const float* Wc   = (const float*)d_in[6];
    const float* Ua   = (const float*)d_in[7];
    const float* Ub   = (const float*)d_in[8];
    const float* Uc   = (const float*)d_in[9];
    const float* bi   = (const float*)d_in[10];
    const float* emb  = (const float*)d_in[11];
    const float* Wout = (const float*)d_in[12];
    const float* bout = (const float*)d_in[13];
    float* out = (float*)d_out;

    float *p_t2, *p_t5, *p_gx;
    __half *p_x2, *p_t12, *p_hs2, *p_Wa2, *p_Wc2, *p_Wo2;
    cudaGetSymbolAddress((void**)&p_t2,  g_t2);
    cudaGetSymbolAddress((void**)&p_t5,  g_t5);
    cudaGetSymbolAddress((void**)&p_gx,  g_gx);
    cudaGetSymbolAddress((void**)&p_x2,  g_x2);
    cudaGetSymbolAddress((void**)&p_t12, g_t12);
    cudaGetSymbolAddress((void**)&p_hs2, g_hs2);
    cudaGetSymbolAddress((void**)&p_Wa2, g_Wa2);
    cudaGetSymbolAddress((void**)&p_Wc2, g_Wc2);
    cudaGetSymbolAddress((void**)&p_Wo2, g_Wo2);

    cudaFuncSetAttribute((const void*)mma_gemm_k<0,1>, cudaFuncAttributeMaxDynamicSharedMemorySize, OG_SMEM_H);
    cudaFuncSetAttribute((const void*)mma_gemm_k<1,2>, cudaFuncAttributeMaxDynamicSharedMemorySize, OG_SMEM_P);
    cudaFuncSetAttribute((const void*)mma_gemm_k<2,2>, cudaFuncAttributeMaxDynamicSharedMemorySize, OG_SMEM_P);
    cudaFuncSetAttribute((const void*)rec_k, cudaFuncAttributeMaxDynamicSharedMemorySize, REC_SMEM);

    k_gather<<<dim3(Bdim, Tdim), 128>>>(caps, emb);
    k_convW<<<dim3(16,16,4), dim3(32,32)>>>(Wa, p_Wa2);
    gemm_k<32,64,16,4,4><<<dim3(8,4,4), 128>>>(tags, Wb, p_t2, Bdim, Rdim,
        NTG, (long)NTG*Rdim, (long)Bdim*Rdim);
    k_init<<<256, 256>>>(h0, c0);
    k_convW<<<dim3(16,16,4), dim3(32,32)>>>(Wc, p_Wc2);
    mma_gemm_k<1,2><<<dim3(24,2,4), 256, OG_SMEM_P>>>(p_x2, p_Wa2, nullptr,
        p_t12, p_t2, 0L, (long)Rdim*Hdim);
    gemm_k<32,64,16,4,4><<<dim3(8,4,4), 128>>>(tags, Ub, p_t5, Bdim, Rdim,
        NTG, (long)NTG*Rdim, (long)Bdim*Rdim);
    mma_gemm_k<2,2><<<dim3(24,2,4), 256, OG_SMEM_P>>>(p_t12, p_Wc2, p_gx,
        nullptr, bi, (long)TBdim*KPA, (long)Rdim*Hdim);
    k_convB<<<dim3(Vdim/32, Hdim/32), dim3(32,32)>>>(Wout);
    rec_k<<<RC, 256, REC_SMEM>>>(Ua, Uc);
    mma_gemm_k<0,1><<<dim3(TBdim/128, (Vdim + 255)/256), 256, OG_SMEM_H>>>(
        p_hs2, p_Wo2, out, nullptr, bout, 0L, 0L);
}

// round 8
// speedup vs baseline: 3.8559x; 1.0865x over previous
#include <cuda_runtime.h>
#include <cuda_fp16.h>
#include <math.h>
#include <cstdint>

#define Bdim 128
#define Tdim 24
#define Edim 512
#define Hdim 512
#define Rdim 512
#define NTG 400
#define Vdim 20000
#define NPAD 20224          // 79*256
#define TBdim (Tdim*Bdim)   // 3072
#define KPA 1024            // fp16 pair K ([hi|lo])
#define RC 128              // persistent recurrence CTAs

// ---------------- scratch (device globals; no allocation allowed) ----------
__device__ float g_t2[4*Bdim*Rdim];
__device__ float g_t5[4*Bdim*Rdim];
__device__ float g_gx[4L*TBdim*Hdim];
__device__ float g_gh[4*Bdim*Hdim];
__device__ float g_c[Bdim*Hdim];
__device__ unsigned g_sync;
__device__ __half g_x2[(long)TBdim*KPA];        // xs pair [3072,1024]
__device__ __half g_t12[4L*TBdim*KPA];          // t1 pair per gate
__device__ __half g_h2[Bdim*KPA];               // h pair [128,1024]
__device__ __half g_t62[4L*Bdim*KPA];           // t6 pair per gate
__device__ __half g_Wa2[4L*Rdim*Hdim];          // Wa^T hi fp16 [g][n][k]
__device__ __half g_Wc2[4L*Rdim*Hdim];          // Wc^T hi fp16
__device__ __half g_hsC[8L*TBdim*64];           // hs hi, chunk-major swizzled
__device__ __half g_WoC[8L*NPAD*64];            // Wout^T hi, chunk-major swizzled

__device__ __forceinline__ uint32_t smem_u32(const void* p) {
    uint32_t a;
    asm("{ .reg .u64 t; cvta.to.shared.u64 t, %1; cvt.u32.u64 %0, t; }" : "=r"(a) : "l"(p));
    return a;
}

__device__ __forceinline__ void ldm_x4(uint32_t* r, uint32_t addr)
{
    asm volatile("ldmatrix.sync.aligned.m8n8.x4.shared.b16 {%0,%1,%2,%3}, [%4];"
        : "=r"(r[0]), "=r"(r[1]), "=r"(r[2]), "=r"(r[3]) : "r"(addr));
}

__device__ __forceinline__ void mma16816(float* c, const uint32_t* a, const uint32_t* b)
{
    asm volatile("mma.sync.aligned.m16n8k16.row.col.f32.f16.f16.f32 "
        "{%0,%1,%2,%3}, {%4,%5,%6,%7}, {%8,%9}, {%0,%1,%2,%3};"
        : "+f"(c[0]), "+f"(c[1]), "+f"(c[2]), "+f"(c[3])
        : "r"(a[0]), "r"(a[1]), "r"(a[2]), "r"(a[3]), "r"(b[0]), "r"(b[1]));
}

__device__ __forceinline__ void store_pair(__half* p, int col, float v)
{
    __half hi = __float2half_rn(v);
    __half lo = __float2half_rn(v - __half2float(hi));
    p[col] = hi; p[512 + col] = lo;
}

#define MBARRIER_INIT(mbar, cnt) \
    asm volatile("mbarrier.init.shared.b64 [%0], %1;" :: "r"((uint32_t)(mbar)), "r"((uint32_t)(cnt)) : "memory")
#define MBARRIER_WAIT_PARITY(mbar, par) do { \
    uint32_t _m = (uint32_t)(mbar), _p = (uint32_t)(par), _d; \
    asm volatile("{\n\t.reg .pred p;\n\t" \
        "mbarrier.try_wait.parity.acquire.cta.shared::cta.b64 p, [%1], %2;\n\t" \
        "selp.b32 %0, 1, 0, p;\n\t}" : "=r"(_d) : "r"(_m), "r"(_p) : "memory"); \
    if (!_d) { \
        asm volatile("{\n\t.reg .pred P1;\n\t" \
            "WL_%=:\n\t" \
            "mbarrier.try_wait.parity.acquire.cta.shared::cta.b64 P1, [%0], %1, 0x989680;\n\t" \
            "@P1 bra.uni WD_%=;\n\t" \
            "bra.uni WL_%=;\n\t" \
            "WD_%=:\n\t}" :: "r"(_m), "r"(_p) : "memory"); \
    } \
} while (0)

// ================= out GEMM: bulk-TMA + mma.sync ============================
// A: g_hsC [chunk][3072 rows][64 halfs] (swizzled); B: g_WoC [chunk][20224][64]
// CTA 128x256, 3 stages of (16K A + 32K B), 8 warps of 64x64.
#define TO_STAGE 49152
#define TO_SMEM  (3*TO_STAGE + 32)

__device__ __forceinline__ void out_issue(uint32_t sb, uint32_t mb, int k,
                                          const __half* Ac, const __half* Bc,
                                          int mtile, int ntile)
{
    int slot = k % 3;
    uint32_t dst = sb + slot*TO_STAGE;
    uint32_t bar = mb + slot*8;
    asm volatile("mbarrier.arrive.expect_tx.shared.b64 _, [%0], %1;"
        :: "r"(bar), "r"(49152u) : "memory");
    const __half* As = Ac + ((long)k*TBdim + mtile*128)*64;
    asm volatile("cp.async.bulk.shared::cluster.global.mbarrier::complete_tx::bytes "
        "[%0], [%1], %2, [%3];"
        :: "r"(dst), "l"(As), "r"(16384u), "r"(bar) : "memory");
    const __half* Bs = Bc + ((long)k*NPAD + ntile*256)*64;
    asm volatile("cp.async.bulk.shared::cluster.global.mbarrier::complete_tx::bytes "
        "[%0], [%1], %2, [%3];"
        :: "r"(dst + 16384), "l"(Bs), "r"(32768u), "r"(bar) : "memory");
}

__global__ void __launch_bounds__(256, 1) out_gemm_tma(
    const __half* __restrict__ Ac, const __half* __restrict__ Bc,
    const float* __restrict__ bout, float* __restrict__ out)
{
    extern __shared__ char smem[];
    const uint32_t sb = smem_u32(smem);
    const uint32_t mb = sb + 3*TO_STAGE;
    const int tid = threadIdx.x, wid = tid >> 5, lane = tid & 31;
    const int wm = wid & 1, wn = wid >> 1;
    const int mtile = blockIdx.x, ntile = blockIdx.y;

    if (tid == 0) {
        MBARRIER_INIT(mb, 1); MBARRIER_INIT(mb + 8, 1); MBARRIER_INIT(mb + 16, 1);
    }
    __syncthreads();
    if (tid == 0) {
        out_issue(sb, mb, 0, Ac, Bc, mtile, ntile);
        out_issue(sb, mb, 1, Ac, Bc, mtile, ntile);
    }

    float acc[4][8][4];
#pragma unroll
    for (int i = 0; i < 4; i++)
#pragma unroll
        for (int j = 0; j < 8; j++)
#pragma unroll
            for (int q = 0; q < 4; q++) acc[i][j][q] = 0.f;

    for (int k = 0; k < 8; k++) {
        int slot = k % 3;
        MBARRIER_WAIT_PARITY(mb + slot*8, (k/3) & 1);
        __syncthreads();                 // all threads past wait => stage k-1 fully consumed
        if (tid == 0 && k + 2 < 8) out_issue(sb, mb, k + 2, Ac, Bc, mtile, ntile);

        uint32_t sA = sb + slot*TO_STAGE;
        uint32_t sB = sA + 16384;
#pragma unroll
        for (int ks = 0; ks < 4; ks++) {
            uint32_t b[8][2];
#pragma unroll
            for (int np = 0; np < 4; np++) {
                uint32_t n = wn*64 + np*16 + (lane & 7) + ((lane >> 4) & 1)*8;
                uint32_t q = ks*2 + ((lane >> 3) & 1);
                uint32_t r[4];
                ldm_x4(r, sB + n*128 + (q ^ (n & 7))*16);
                b[np*2][0] = r[0];   b[np*2][1] = r[1];
                b[np*2+1][0] = r[2]; b[np*2+1][1] = r[3];
            }
            uint32_t a[4][4];
#pragma unroll
            for (int mi = 0; mi < 4; mi++) {
                uint32_t m = wm*64 + mi*16 + (lane & 15);
                uint32_t q = ks*2 + (lane >> 4);
                ldm_x4(a[mi], sA + m*128 + (q ^ (m & 7))*16);
            }
#pragma unroll
            for (int mi = 0; mi < 4; mi++)
#pragma unroll
                for (int ni = 0; ni < 8; ni++)
                    mma16816(acc[mi][ni], a[mi], b[ni]);
        }
    }

#pragma unroll
    for (int mi = 0; mi < 4; mi++) {
#pragma unroll
        for (int ni = 0; ni < 8; ni++) {
            int n = ntile*256 + wn*64 + ni*8 + (lane & 3)*2;
            if (n < Vdim) {
                float2 bv = *(const float2*)(bout + n);
                int gr0 = mtile*128 + wm*64 + mi*16 + (lane >> 2);
                int gr1 = gr0 + 8;
                long o0 = ((long)(gr0 & 127)*Tdim + (gr0 >> 7))*Vdim + n;
                long o1 = ((long)(gr1 & 127)*Tdim + (gr1 >> 7))*Vdim + n;
                *(float2*)(out + o0) = make_float2(acc[mi][ni][0] + bv.x, acc[mi][ni][1] + bv.y);
                *(float2*)(out + o1) = make_float2(acc[mi][ni][2] + bv.x, acc[mi][ni][3] + bv.y);
            }
        }
    }
}

// ================= fp16-pair MMA GEMM (prep: t1, gx) ========================
#define OG_STRIDE 144
#define OG_TILEA  (128*OG_STRIDE)
#define OG_TILEB  (256*OG_STRIDE)
#define OG_STAGEB (2*OG_TILEA + OG_TILEB)
#define OG_SMEM_P (3*OG_STAGEB)

template<int MODE>
__device__ __forceinline__ void og_load(uint32_t sbase, int stage,
    const __half* __restrict__ A, const __half* __restrict__ B,
    int mtile, int ntile, int k, int tid)
{
    uint32_t sa = sbase + stage*OG_STAGEB;
    uint32_t sb = sa + 2*OG_TILEA;
    const __half* Ag = A + (long)mtile*128*KPA + k*64;
    const __half* Bg = B + (long)ntile*256*512 + k*64;
#pragma unroll
    for (int i = 0; i < 4; i++) {
        int e = tid + i*256;
        int row = e >> 3, q = e & 7;
        uint32_t d = sa + row*OG_STRIDE + q*16;
        asm volatile("cp.async.cg.shared.global [%0], [%1], 16;"
            :: "r"(d), "l"(Ag + (long)row*KPA + q*8) : "memory");
        uint32_t d2 = sa + OG_TILEA + row*OG_STRIDE + q*16;
        asm volatile("cp.async.cg.shared.global [%0], [%1], 16;"
            :: "r"(d2), "l"(Ag + 512 + (long)row*KPA + q*8) : "memory");
    }
#pragma unroll
    for (int i = 0; i < 8; i++) {
        int e = tid + i*256;
        int row = e >> 3, q = e & 7;
        uint32_t d = sb + row*OG_STRIDE + q*16;
        asm volatile("cp.async.cg.shared.global [%0], [%1], 16;"
            :: "r"(d), "l"(Bg + (long)row*512 + q*8) : "memory");
    }
}

template<int MODE>
__global__ void __launch_bounds__(256, 1) mma_gemm_k(
    const __half* __restrict__ A, const __half* __restrict__ B,
    float* __restrict__ Cf, __half* __restrict__ Cb,
    const float* __restrict__ X, long aS, long bS)
{
    extern __shared__ char smem[];
    const uint32_t sbase = smem_u32(smem);
    const int tid = threadIdx.x, wid = tid >> 5, lane = tid & 31;
    const int wm = wid & 1, wn = wid >> 1;
    const int mtile = blockIdx.x, ntile = blockIdx.y, z = blockIdx.z;

    const __half* Az = A + (long)z*aS;
    const __half* Bz = B + (long)z*bS;

    float acc[4][8][4];
#pragma unroll
    for (int i = 0; i < 4; i++)
#pragma unroll
        for (int j = 0; j < 8; j++)
#pragma unroll
            for (int q = 0; q < 4; q++) acc[i][j][q] = 0.f;

#pragma unroll
    for (int s = 0; s < 3; s++) {
        og_load<MODE>(sbase, s, Az, Bz, mtile, ntile, s, tid);
        asm volatile("cp.async.commit_group;" ::: "memory");
    }

    for (int k = 0; k < 8; k++) {
        asm volatile("cp.async.wait_group 2;" ::: "memory");
        __syncthreads();

        uint32_t base = sbase + (k % 3)*OG_STAGEB;
        uint32_t sbB = base + 2*OG_TILEA;
#pragma unroll
        for (int ks = 0; ks < 4; ks++) {
            uint32_t b[8][2];
#pragma unroll
            for (int np = 0; np < 4; np++) {
                uint32_t row = wn*64 + np*16 + (lane & 7) + ((lane >> 4) & 1)*8;
                uint32_t addr = sbB + row*OG_STRIDE + (ks*16 + ((lane >> 3) & 1)*8)*2;
                uint32_t r[4];
                ldm_x4(r, addr);
                b[np*2][0] = r[0];   b[np*2][1] = r[1];
                b[np*2+1][0] = r[2]; b[np*2+1][1] = r[3];
            }
#pragma unroll
            for (int h = 0; h < 2; h++) {
                uint32_t ab = base + h*OG_TILEA;
                uint32_t a[4][4];
#pragma unroll
                for (int mi = 0; mi < 4; mi++) {
                    uint32_t addr = ab + (wm*64 + mi*16 + (lane & 15))*OG_STRIDE
                                  + (ks*16 + (lane >> 4)*8)*2;
                    ldm_x4(a[mi], addr);
                }
#pragma unroll
                for (int mi = 0; mi < 4; mi++)
#pragma unroll
                    for (int ni = 0; ni < 8; ni++)
                        mma16816(acc[mi][ni], a[mi], b[ni]);
            }
        }
        __syncthreads();

        if (k + 3 < 8) og_load<MODE>(sbase, (k + 3) % 3, Az, Bz, mtile, ntile, k + 3, tid);
        asm volatile("cp.async.commit_group;" ::: "memory");
    }

#pragma unroll
    for (int mi = 0; mi < 4; mi++) {
#pragma unroll
        for (int ni = 0; ni < 8; ni++) {
            int n = ntile*256 + wn*64 + ni*8 + (lane & 3)*2;
            int gr0 = mtile*128 + wm*64 + mi*16 + (lane >> 2);
            int gr1 = gr0 + 8;
            if (MODE == 1) {
                const float* Xg = X + (long)z*Bdim*Rdim;
                __half* Cz = Cb + (long)z*TBdim*KPA;
                store_pair(Cz + (long)gr0*KPA, n,     acc[mi][ni][0]*Xg[(gr0 & 127)*512 + n]);
                store_pair(Cz + (long)gr0*KPA, n + 1, acc[mi][ni][1]*Xg[(gr0 & 127)*512 + n + 1]);
                store_pair(Cz + (long)gr1*KPA, n,     acc[mi][ni][2]*Xg[(gr1 & 127)*512 + n]);
                store_pair(Cz + (long)gr1*KPA, n + 1, acc[mi][ni][3]*Xg[(gr1 & 127)*512 + n + 1]);
            } else {
                const float* Xg = X + z*512;
                float* Cz = Cf + (long)z*TBdim*512;
                float2 bv = make_float2(Xg[n], Xg[n + 1]);
                *(float2*)(Cz + (long)gr0*512 + n) = make_float2(acc[mi][ni][0] + bv.x, acc[mi][ni][1] + bv.y);
                *(float2*)(Cz + (long)gr1*512 + n) = make_float2(acc[mi][ni][2] + bv.x, acc[mi][ni][3] + bv.y);
            }
        }
    }
}

// ---------------- conversions ------------------------------------------------
__global__ void k_convW(const float* __restrict__ W, __half* __restrict__ Bp)
{
    __shared__ float t[32][33];
    int g = blockIdx.z;
    int n = blockIdx.x*32 + threadIdx.x;
    int k = blockIdx.y*32 + threadIdx.y;
    t[threadIdx.y][threadIdx.x] = W[(long)g*512*512 + (long)k*512 + n];
    __syncthreads();
    int n2 = blockIdx.x*32 + threadIdx.y;
    int k2 = blockIdx.y*32 + threadIdx.x;
    Bp[((long)g*512 + n2)*512 + k2] = __float2half_rn(t[threadIdx.x][threadIdx.y]);
}

__global__ void __launch_bounds__(256) k_convB(const float* __restrict__ Wout)
{   // Wout[512,20000] -> g_WoC[chunk][n][64] swizzled, n padded to NPAD (zeros)
    __shared__ float t[64][33];
    const int tid = threadIdx.x;
    const int n0 = blockIdx.x*32;
    const int k0 = blockIdx.y*64;
    for (int e = tid; e < 64*32; e += 256) {
        int kk = e >> 5, nn = e & 31;
        int n = n0 + nn;
        t[kk][nn] = (n < Vdim) ? Wout[(long)(k0 + kk)*Vdim + n] : 0.f;
    }
    __syncthreads();
    int nn = tid >> 3, q = tid & 7;
    int n = n0 + nn;
    __half h[8];
#pragma unroll
    for (int i = 0; i < 8; i++) h[i] = __float2half_rn(t[q*8 + i][nn]);
    int qs = q ^ (n & 7);
    *(uint4*)(g_WoC + ((long)blockIdx.y*NPAD + n)*64 + qs*8) = *(uint4*)h;
}

// ---------------- embedding gather (fp16 pair) --------------------------------
__global__ void k_gather(const int* __restrict__ caps, const float* __restrict__ emb)
{
    const int b = blockIdx.x, t = blockIdx.y;
    float4 v = make_float4(0.f, 0.f, 0.f, 0.f);
    if (t > 0) {
        int tok = caps[b*Tdim + (t-1)];
        v = ((const float4*)(emb + (long)tok*Edim))[threadIdx.x];
    }
    __half2 h01 = __floats2half2_rn(v.x, v.y);
    __half2 h23 = __floats2half2_rn(v.z, v.w);
    __half2 l01 = __floats2half2_rn(v.x - __half2float(__low2half(h01)),
                                    v.y - __half2float(__high2half(h01)));
    __half2 l23 = __floats2half2_rn(v.z - __half2float(__low2half(h23)),
                                    v.w - __half2float(__high2half(h23)));
    __half* base = g_x2 + (long)(t*Bdim + b)*KPA + threadIdx.x*4;
    *(__half2*)(base)       = h01;
    *(__half2*)(base + 2)   = h23;
    *(__half2*)(base + 512) = l01;
    *(__half2*)(base + 514) = l23;
}

__global__ void k_init(const float* __restrict__ h0, const float* __restrict__ c0)
{
    int i = blockIdx.x*blockDim.x + threadIdx.x;
    float v = h0[i];
    __half hi = __float2half_rn(v);
    __half lo = __float2half_rn(v - __half2float(hi));
    __half* p = g_h2 + (long)(i >> 9)*KPA + (i & 511);
    p[0] = hi; p[512] = lo;
    g_c[i] = c0[i];
    if (i == 0) g_sync = 0;
}

// ---------------- fp32 tiled SGEMM (t2 and t5 in one launch) -----------------
template<int BM,int BN,int BK,int TM,int TN>
__global__ void gemm_k(const float* __restrict__ A,
                       const float* __restrict__ Bm, const float* __restrict__ Bm2,
                       float* __restrict__ C, float* __restrict__ C2,
                       int M, int N, int K, long sB, long sC)
{
    constexpr int THREADS = (BM/TM)*(BN/TN);
    __shared__ float As[BK][BM];
    __shared__ float Bs[BK][BN];
    const int z = blockIdx.z;
    const int g = z & 3;
    const float* Bg = (z < 4 ? Bm : Bm2) + (long)g*sB;
    float* Cg = (z < 4 ? C : C2) + (long)g*sC;
    const int m0 = blockIdx.y*BM;
    const int n0 = blockIdx.x*BN;
    const int tid = threadIdx.x;
    constexpr int AK4 = BK/4;
    const int aRow = tid / AK4, aCol = (tid % AK4)*4;
    constexpr int AROWS = THREADS/AK4;
    constexpr int BN4 = BN/4;
    const int bRow = tid / BN4, bCol = (tid % BN4)*4;
    constexpr int BROWS = THREADS/BN4;
    const int tr = (tid/(BN/TN))*TM, tc = (tid%(BN/TN))*TN;

    float acc[TM][TN];
#pragma unroll
    for (int i = 0; i < TM; i++)
#pragma unroll
        for (int j = 0; j < TN; j++) acc[i][j] = 0.f;

    for (int k0 = 0; k0 < K; k0 += BK) {
#pragma unroll
        for (int i = 0; i < BM; i += AROWS) {
            float4 v = *(const float4*)(A + (long)(m0 + aRow + i)*K + (k0 + aCol));
            As[aCol+0][aRow+i] = v.x; As[aCol+1][aRow+i] = v.y;
            As[aCol+2][aRow+i] = v.z; As[aCol+3][aRow+i] = v.w;
        }
#pragma unroll
        for (int i = 0; i < BK; i += BROWS) {
            float4 v = *(const float4*)(Bg + (long)(k0 + bRow + i)*N + (n0 + bCol));
            *(float4*)&Bs[bRow+i][bCol] = v;
        }
        __syncthreads();
#pragma unroll
        for (int kk = 0; kk < BK; kk++) {
            float rm[TM], rn[TN];
#pragma unroll
            for (int i = 0; i < TM; i++) rm[i] = As[kk][tr+i];
#pragma unroll
            for (int j = 0; j < TN; j++) rn[j] = Bs[kk][tc+j];
#pragma unroll
            for (int i = 0; i < TM; i++)
#pragma unroll
                for (int j = 0; j < TN; j++)
                    acc[i][j] = fmaf(rm[i], rn[j], acc[i][j]);
        }
        __syncthreads();
    }
#pragma unroll
    for (int i = 0; i < TM; i++)
#pragma unroll
        for (int j = 0; j < TN; j++)
            Cg[(long)(m0 + tr + i)*N + n0 + tc + j] = acc[i][j];
}

// ---------------- persistent tensor-core recurrence --------------------------
#define RW_STRIDE 1040
#define RW_SLAB   (16*RW_STRIDE)
#define RA_STRIDE 144
#define RA_SLAB   (128*RA_STRIDE)
#define RA_BASE   (4*RW_SLAB)
#define RA_STAGE  (2*RA_SLAB)
#define REC_SMEM  (RA_BASE + 3*RA_STAGE)

__device__ __forceinline__ void gbar(unsigned goal)
{
    __syncthreads();
    __threadfence();
    if (threadIdx.x == 0) {
        atomicAdd(&g_sync, 1u);
        unsigned v;
        do {
            asm volatile("ld.global.acquire.gpu.u32 %0, [%1];" : "=r"(v) : "l"(&g_sync));
        } while (v < goal);
    }
    __syncthreads();
}

__device__ __forceinline__ float sig_f(float x)  { return 1.f/(1.f + __expf(-x)); }
__device__ __forceinline__ float tanh_f(float x) { return 2.f/(1.f + __expf(-2.f*x)) - 1.f; }

__device__ __forceinline__ void rec_loadA(uint32_t stg, const __half* __restrict__ Asrc,
                                          int chunk, int tid)
{
    const __half* p = Asrc + chunk*64;
#pragma unroll
    for (int i = 0; i < 4; i++) {
        int e = tid + i*256;
        int row = e >> 3, q = e & 7;
        uint32_t d = stg + row*RA_STRIDE + q*16;
        asm volatile("cp.async.cg.shared.global [%0], [%1], 16;"
            :: "r"(d), "l"(p + (long)row*KPA + q*8) : "memory");
        uint32_t d2 = stg + RA_SLAB + row*RA_STRIDE + q*16;
        asm volatile("cp.async.cg.shared.global [%0], [%1], 16;"
            :: "r"(d2), "l"(p + 512 + (long)row*KPA + q*8) : "memory");
    }
}

__device__ __forceinline__ void rec_phase(uint32_t sbase, uint32_t wbase,
                                          const __half* __restrict__ Asrc,
                                          int tid, int wid, int lane, float acc[2][4])
{
#pragma unroll
    for (int i = 0; i < 2; i++)
#pragma unroll
        for (int q = 0; q < 4; q++) acc[i][q] = 0.f;

#pragma unroll
    for (int s = 0; s < 3; s++) {
        rec_loadA(sbase + RA_BASE + s*RA_STAGE, Asrc, s, tid);
        asm volatile("cp.async.commit_group;" ::: "memory");
    }
    for (int k = 0; k < 8; k++) {
        asm volatile("cp.async.wait_group 2;" ::: "memory");
        __syncthreads();
        uint32_t st = sbase + RA_BASE + (k % 3)*RA_STAGE;
#pragma unroll
        for (int ks = 0; ks < 4; ks++) {
            int krow = k*64 + ks*16 + ((lane >> 3) & 1)*8;
            uint32_t baddr = wbase + ((lane & 7) + ((lane >> 4) & 1)*8)*RW_STRIDE + krow*2;
            uint32_t rhi[4], rlo[4];
            ldm_x4(rhi, baddr);
            ldm_x4(rlo, baddr + RW_SLAB);
            uint32_t bhi[2][2] = {{rhi[0], rhi[1]}, {rhi[2], rhi[3]}};
            uint32_t blo[2][2] = {{rlo[0], rlo[1]}, {rlo[2], rlo[3]}};
            uint32_t aaddr = st + (wid*16 + (lane & 15))*RA_STRIDE + (ks*16 + (lane >> 4)*8)*2;
            uint32_t ahi[4], alo[4];
            ldm_x4(ahi, aaddr);
            ldm_x4(alo, aaddr + RA_SLAB);
#pragma unroll
            for (int ni = 0; ni < 2; ni++) {
                mma16816(acc[ni], ahi, bhi[ni]);
                mma16816(acc[ni], ahi, blo[ni]);
                mma16816(acc[ni], alo, bhi[ni]);
            }
        }
        __syncthreads();
        if (k + 3 < 8) rec_loadA(sbase + RA_BASE + ((k + 3) % 3)*RA_STAGE, Asrc, k + 3, tid);
        asm volatile("cp.async.commit_group;" ::: "memory");
    }
}

__global__ void __launch_bounds__(256, 1) rec_k(const float* __restrict__ Ua,
                                                const float* __restrict__ Uc)
{
    extern __shared__ char smem[];
    const uint32_t sbase = smem_u32(smem);
    const int tid = threadIdx.x, wid = tid >> 5, lane = tid & 31;
    const int bx = blockIdx.x;
    const int gg = bx >> 5;
    const int c0 = (bx & 31)*16;

    {
        const float* UaG = Ua + (long)gg*512*512;
        const float* UcG = Uc + (long)gg*512*512;
        for (int e = tid; e < 512*16; e += 256) {
            int k = e >> 4, j = e & 15;
            float va = UaG[(long)k*512 + c0 + j];
            __half ha = __float2half_rn(va);
            __half la = __float2half_rn(va - __half2float(ha));
            *(__half*)(smem + j*RW_STRIDE + k*2) = ha;
            *(__half*)(smem + RW_SLAB + j*RW_STRIDE + k*2) = la;
            float vc = UcG[(long)k*512 + c0 + j];
            __half hc = __float2half_rn(vc);
            __half lc = __float2half_rn(vc - __half2float(hc));
            *(__half*)(smem + 2*RW_SLAB + j*RW_STRIDE + k*2) = hc;
            *(__half*)(smem + 3*RW_SLAB + j*RW_STRIDE + k*2) = lc;
        }
    }
    __syncthreads();

    unsigned goal = RC;
    const long GS = (long)TBdim*Hdim;
    const long GH = (long)Bdim*Hdim;

    for (int t = 0; t < Tdim; t++) {
        float acc[2][4];

        // phase A: t6[gg][:, c0..] = (h @ Ua[gg]) * t5, stored as fp16 pair
        rec_phase(sbase, sbase, g_h2, tid, wid, lane, acc);
        {
            __half* Cz = g_t62 + (long)gg*Bdim*KPA;
            const float* t5g = g_t5 + (long)gg*GH;
#pragma unroll
            for (int ni = 0; ni < 2; ni++) {
                int col = c0 + ni*8 + (lane & 3)*2;
                int r0 = wid*16 + (lane >> 2), r1 = r0 + 8;
                float2 m0 = *(const float2*)(t5g + (long)r0*512 + col);
                float2 m1 = *(const float2*)(t5g + (long)r1*512 + col);
                float v00 = acc[ni][0]*m0.x, v01 = acc[ni][1]*m0.y;
                float v10 = acc[ni][2]*m1.x, v11 = acc[ni][3]*m1.y;
                __half2 h0 = __floats2half2_rn(v00, v01);
                __half2 l0 = __floats2half2_rn(v00 - __half2float(__low2half(h0)),
                                               v01 - __half2float(__high2half(h0)));
                __half2 h1 = __floats2half2_rn(v10, v11);
                __half2 l1 = __floats2half2_rn(v10 - __half2float(__low2half(h1)),
                                               v11 - __half2float(__high2half(h1)));
                *(__half2*)(Cz + (long)r0*KPA + col)       = h0;
                *(__half2*)(Cz + (long)r0*KPA + 512 + col) = l0;
                *(__half2*)(Cz + (long)r1*KPA + col)       = h1;
                *(__half2*)(Cz + (long)r1*KPA + 512 + col) = l1;
            }
        }
        gbar(goal); goal += RC;

        // phase B: gh[gg][:, c0..] = t6[gg] @ Uc[gg]
        rec_phase(sbase, sbase + 2*RW_SLAB, g_t62 + (long)gg*Bdim*KPA, tid, wid, lane, acc);
        {
            float* Cz = g_gh + (long)gg*GH;
#pragma unroll
            for (int ni = 0; ni < 2; ni++) {
                int col = c0 + ni*8 + (lane & 3)*2;
                int r0 = wid*16 + (lane >> 2), r1 = r0 + 8;
                *(float2*)(Cz + (long)r0*512 + col) = make_float2(acc[ni][0], acc[ni][1]);
                *(float2*)(Cz + (long)r1*512 + col) = make_float2(acc[ni][2], acc[ni][3]);
            }
        }
        gbar(goal); goal += RC;

        // phase C: LSTM pointwise on batch row bx
        {
            const long so = (long)t*Bdim*Hdim;
            int i0 = bx*512 + tid*2;
            float hv[2];
#pragma unroll
            for (int u = 0; u < 2; u++) {
                int i = i0 + u;
                float pi = g_gx[0*GS + so + i] + g_gh[0*GH + i];
                float pf = g_gx[1*GS + so + i] + g_gh[1*GH + i];
                float po = g_gx[2*GS + so + i] + g_gh[2*GH + i];
                float pc = g_gx[3*GS + so + i] + g_gh[3*GH + i];
                float ig = sig_f(pi), fg = sig_f(pf), og = sig_f(po);
                float ct = tanh_f(pc);
                float cn = fg*g_c[i] + ig*ct;
                float hn = og*tanh_f(cn);
                g_c[i] = cn;
                hv[u] = hn;
            }
            __half2 hh = __floats2half2_rn(hv[0], hv[1]);
            __half2 ll = __floats2half2_rn(hv[0] - __half2float(__low2half(hh)),
                                           hv[1] - __half2float(__high2half(hh)));
            // h pair for next step's phase A
            *(__half2*)(g_h2 + (long)bx*KPA + tid*2)       = hh;
            *(__half2*)(g_h2 + (long)bx*KPA + 512 + tid*2) = ll;
            // hs hi into chunk-major swizzled layout for the TMA out-GEMM
            int kcol = tid*2;
            int row = t*Bdim + bx;
            int chunk = kcol >> 6;
            int q = (kcol & 63) >> 3;
            int qs = q ^ (row & 7);
            *(__half2*)(g_hsC + ((long)chunk*TBdim + row)*64 + qs*8 + (kcol & 7)) = hh;
        }
        gbar(goal); goal += RC;
    }
}

// ---------------- launch ------------------------------------------------------
extern "C" void kernel_launch(void* const* d_in, const int* in_sizes, int n_in,
                              void* d_out, int out_size)
{
    const int*   caps = (const int*)  d_in[0];
    const float* tags = (const float*)d_in[1];
    const float* h0   = (const float*)d_in[2];
    const float* c0   = (const float*)d_in[3];
    const float* Wa   = (const float*)d_in[4];
    const float* Wb   = (const float*)d_in[5];
    const float* Wc   = (const float*)d_in[6];
    const float* Ua   = (const float*)d_in[7];
    const float* Ub   = (const float*)d_in[8];
    const float* Uc   = (const float*)d_in[9];
    const float* bi   = (const float*)d_in[10];
    const float* emb  = (const float*)d_in[11];
    const float* Wout = (const float*)d_in[12];
    const float* bout = (const float*)d_in[13];
    float* out = (float*)d_out;

    float *p_t2, *p_t5, *p_gx;
    __half *p_x2, *p_t12, *p_Wa2, *p_Wc2, *p_hsC, *p_WoC;
    cudaGetSymbolAddress((void**)&p_t2,  g_t2);
    cudaGetSymbolAddress((void**)&p_t5,  g_t5);
    cudaGetSymbolAddress((void**)&p_gx,  g_gx);
    cudaGetSymbolAddress((void**)&p_x2,  g_x2);
    cudaGetSymbolAddress((void**)&p_t12, g_t12);
    cudaGetSymbolAddress((void**)&p_Wa2, g_Wa2);
    cudaGetSymbolAddress((void**)&p_Wc2, g_Wc2);
    cudaGetSymbolAddress((void**)&p_hsC, g_hsC);
    cudaGetSymbolAddress((void**)&p_WoC, g_WoC);

    cudaFuncSetAttribute((const void*)mma_gemm_k<1>, cudaFuncAttributeMaxDynamicSharedMemorySize, OG_SMEM_P);
    cudaFuncSetAttribute((const void*)mma_gemm_k<2>, cudaFuncAttributeMaxDynamicSharedMemorySize, OG_SMEM_P);
    cudaFuncSetAttribute((const void*)rec_k, cudaFuncAttributeMaxDynamicSharedMemorySize, REC_SMEM);
    cudaFuncSetAttribute((const void*)out_gemm_tma, cudaFuncAttributeMaxDynamicSharedMemorySize, TO_SMEM);

    // launch order: slot 4 is the ncu-profiled launch -> mma_gemm_k<1>
    k_gather<<<dim3(Bdim, Tdim), 128>>>(caps, emb);                          // 1
    k_convW<<<dim3(16,16,4), dim3(32,32)>>>(Wa, p_Wa2);                       // 2
    gemm_k<32,64,16,4,4><<<dim3(8,4,8), 128>>>(tags, Wb, Ub, p_t2, p_t5,      // 3
        Bdim, Rdim, NTG, (long)NTG*Rdim, (long)Bdim*Rdim);
    mma_gemm_k<1><<<dim3(24,2,4), 256, OG_SMEM_P>>>(p_x2, p_Wa2, nullptr,     // 4 (profiled)
        p_t12, p_t2, 0L, (long)Rdim*Hdim);
    k_convW<<<dim3(16,16,4), dim3(32,32)>>>(Wc, p_Wc2);                       // 5
    k_init<<<256, 256>>>(h0, c0);                                             // 6
    mma_gemm_k<2><<<dim3(24,2,4), 256, OG_SMEM_P>>>(p_t12, p_Wc2, p_gx,       // 7
        nullptr, bi, (long)TBdim*KPA, (long)Rdim*Hdim);
    k_convB<<<dim3(NPAD/32, 8), 256>>>(Wout);                                 // 8
    rec_k<<<RC, 256, REC_SMEM>>>(Ua, Uc);                                     // 9
    out_gemm_tma<<<dim3(TBdim/128, NPAD/256), 256, TO_SMEM>>>(                // 10
        p_hsC, p_WoC, bout, out);
}

// round 9
// speedup vs baseline: 4.6856x; 1.2152x over previous
#include <cuda_runtime.h>
#include <cuda_fp16.h>
#include <math.h>
#include <cstdint>

#define Bdim 128
#define Tdim 24
#define Edim 512
#define Hdim 512
#define Rdim 512
#define NTG 400
#define Vdim 20000
#define NPAD 20224          // 79*256
#define TBdim (Tdim*Bdim)   // 3072
#define RC 128              // persistent recurrence CTAs

// ---------------- scratch (device globals; no allocation allowed) ----------
__device__ float g_t2[4*Bdim*Rdim];
__device__ float g_t5[4*Bdim*Rdim];
__device__ float g_gx[4L*TBdim*Hdim];
__device__ float g_c[Bdim*Hdim];
__device__ unsigned g_sync;
// chunk-major swizzled fp16 layouts: [chunk][ (slab) ][rows][64]
__device__ __half g_x2C[8L*2*TBdim*64];         // xs pair
__device__ __half g_t1C[4L*8*2*TBdim*64];       // t1 pair per gate
__device__ __half g_hC[8L*2*Bdim*64];           // h pair
__device__ __half g_t6C[4L*8*2*Bdim*64];        // t6 pair per gate
__device__ __half g_WaC[4L*8*Rdim*64];          // Wa^T hi per gate
__device__ __half g_WcC[4L*8*Rdim*64];          // Wc^T hi per gate
__device__ __half g_hsC[8L*TBdim*64];           // hs hi (out GEMM A)
__device__ __half g_WoC[8L*NPAD*64];            // Wout^T hi (out GEMM B)

__device__ __forceinline__ uint32_t smem_u32(const void* p) {
    uint32_t a;
    asm("{ .reg .u64 t; cvta.to.shared.u64 t, %1; cvt.u32.u64 %0, t; }" : "=r"(a) : "l"(p));
    return a;
}

__device__ __forceinline__ void ldm_x4(uint32_t* r, uint32_t addr)
{
    asm volatile("ldmatrix.sync.aligned.m8n8.x4.shared.b16 {%0,%1,%2,%3}, [%4];"
        : "=r"(r[0]), "=r"(r[1]), "=r"(r[2]), "=r"(r[3]) : "r"(addr));
}

__device__ __forceinline__ void mma16816(float* c, const uint32_t* a, const uint32_t* b)
{
    asm volatile("mma.sync.aligned.m16n8k16.row.col.f32.f16.f16.f32 "
        "{%0,%1,%2,%3}, {%4,%5,%6,%7}, {%8,%9}, {%0,%1,%2,%3};"
        : "+f"(c[0]), "+f"(c[1]), "+f"(c[2]), "+f"(c[3])
        : "r"(a[0]), "r"(a[1]), "r"(a[2]), "r"(a[3]), "r"(b[0]), "r"(b[1]));
}

#define MBARRIER_INIT(mbar, cnt) \
    asm volatile("mbarrier.init.shared.b64 [%0], %1;" :: "r"((uint32_t)(mbar)), "r"((uint32_t)(cnt)) : "memory")
#define MBARRIER_WAIT_PARITY(mbar, par) do { \
    uint32_t _m = (uint32_t)(mbar), _p = (uint32_t)(par), _d; \
    asm volatile("{\n\t.reg .pred p;\n\t" \
        "mbarrier.try_wait.parity.acquire.cta.shared::cta.b64 p, [%1], %2;\n\t" \
        "selp.b32 %0, 1, 0, p;\n\t}" : "=r"(_d) : "r"(_m), "r"(_p) : "memory"); \
    if (!_d) { \
        asm volatile("{\n\t.reg .pred P1;\n\t" \
            "WL_%=:\n\t" \
            "mbarrier.try_wait.parity.acquire.cta.shared::cta.b64 P1, [%0], %1, 0x989680;\n\t" \
            "@P1 bra.uni WD_%=;\n\t" \
            "bra.uni WL_%=;\n\t" \
            "WD_%=:\n\t}" :: "r"(_m), "r"(_p) : "memory"); \
    } \
} while (0)
#define BULK_CP(dst, src, bytes, bar) \
    asm volatile("cp.async.bulk.shared::cluster.global.mbarrier::complete_tx::bytes " \
        "[%0], [%1], %2, [%3];" :: "r"(dst), "l"(src), "r"((uint32_t)(bytes)), "r"(bar) : "memory")
#define BAR_EXPECT(bar, bytes) \
    asm volatile("mbarrier.arrive.expect_tx.shared.b64 _, [%0], %1;" \
        :: "r"(bar), "r"((uint32_t)(bytes)) : "memory")

// ================= out GEMM: bulk-TMA + mma.sync (proven R8) ================
#define TO_STAGE 49152
#define TO_SMEM  (3*TO_STAGE + 32)

__device__ __forceinline__ void out_issue(uint32_t sb, uint32_t mb, int k,
                                          const __half* Ac, const __half* Bc,
                                          int mtile, int ntile)
{
    int slot = k % 3;
    uint32_t dst = sb + slot*TO_STAGE;
    uint32_t bar = mb + slot*8;
    BAR_EXPECT(bar, 49152u);
    BULK_CP(dst, Ac + ((long)k*TBdim + mtile*128)*64, 16384u, bar);
    BULK_CP(dst + 16384, Bc + ((long)k*NPAD + ntile*256)*64, 32768u, bar);
}

__global__ void __launch_bounds__(256, 1) out_gemm_tma(
    const __half* __restrict__ Ac, const __half* __restrict__ Bc,
    const float* __restrict__ bout, float* __restrict__ out)
{
    extern __shared__ char smem[];
    const uint32_t sb = smem_u32(smem);
    const uint32_t mb = sb + 3*TO_STAGE;
    const int tid = threadIdx.x, wid = tid >> 5, lane = tid & 31;
    const int wm = wid & 1, wn = wid >> 1;
    const int mtile = blockIdx.x, ntile = blockIdx.y;

    if (tid == 0) {
        MBARRIER_INIT(mb, 1); MBARRIER_INIT(mb + 8, 1); MBARRIER_INIT(mb + 16, 1);
    }
    __syncthreads();
    if (tid == 0) {
        out_issue(sb, mb, 0, Ac, Bc, mtile, ntile);
        out_issue(sb, mb, 1, Ac, Bc, mtile, ntile);
    }

    float acc[4][8][4];
#pragma unroll
    for (int i = 0; i < 4; i++)
#pragma unroll
        for (int j = 0; j < 8; j++)
#pragma unroll
            for (int q = 0; q < 4; q++) acc[i][j][q] = 0.f;

    for (int k = 0; k < 8; k++) {
        int slot = k % 3;
        MBARRIER_WAIT_PARITY(mb + slot*8, (k/3) & 1);
        __syncthreads();
        if (tid == 0 && k + 2 < 8) out_issue(sb, mb, k + 2, Ac, Bc, mtile, ntile);

        uint32_t sA = sb + slot*TO_STAGE;
        uint32_t sB = sA + 16384;
#pragma unroll
        for (int ks = 0; ks < 4; ks++) {
            uint32_t b[8][2];
#pragma unroll
            for (int np = 0; np < 4; np++) {
                uint32_t n = wn*64 + np*16 + (lane & 7) + ((lane >> 4) & 1)*8;
                uint32_t q = ks*2 + ((lane >> 3) & 1);
                uint32_t r[4];
                ldm_x4(r, sB + n*128 + (q ^ (n & 7))*16);
                b[np*2][0] = r[0];   b[np*2][1] = r[1];
                b[np*2+1][0] = r[2]; b[np*2+1][1] = r[3];
            }
            uint32_t a[4][4];
#pragma unroll
            for (int mi = 0; mi < 4; mi++) {
                uint32_t m = wm*64 + mi*16 + (lane & 15);
                uint32_t q = ks*2 + (lane >> 4);
                ldm_x4(a[mi], sA + m*128 + (q ^ (m & 7))*16);
            }
#pragma unroll
            for (int mi = 0; mi < 4; mi++)
#pragma unroll
                for (int ni = 0; ni < 8; ni++)
                    mma16816(acc[mi][ni], a[mi], b[ni]);
        }
    }

#pragma unroll
    for (int mi = 0; mi < 4; mi++) {
#pragma unroll
        for (int ni = 0; ni < 8; ni++) {
            int n = ntile*256 + wn*64 + ni*8 + (lane & 3)*2;
            if (n < Vdim) {
                float2 bv = *(const float2*)(bout + n);
                int gr0 = mtile*128 + wm*64 + mi*16 + (lane >> 2);
                int gr1 = gr0 + 8;
                long o0 = ((long)(gr0 & 127)*Tdim + (gr0 >> 7))*Vdim + n;
                long o1 = ((long)(gr1 & 127)*Tdim + (gr1 >> 7))*Vdim + n;
                *(float2*)(out + o0) = make_float2(acc[mi][ni][0] + bv.x, acc[mi][ni][1] + bv.y);
                *(float2*)(out + o1) = make_float2(acc[mi][ni][2] + bv.x, acc[mi][ni][3] + bv.y);
            }
        }
    }
}

// ================= prep GEMM: bulk-TMA, fp16-pair A =========================
// A: [8][2][3072][64] swizzled pair (+z*aS); B: [8][512][64] swizzled hi (+z*8*512*64)
// MODE 1: t1C = acc * t2, written as chunk-major pair
// MODE 2: gx  = acc + bias, fp32 [z][3072][512]
#define PT_STAGE 65536
#define PT_SMEM  (3*PT_STAGE + 32)

__device__ __forceinline__ void prep_issue(uint32_t sb, uint32_t mb, int k,
    const __half* Ac, const __half* Bc, int mtile, int ntile)
{
    int slot = k % 3;
    uint32_t dst = sb + slot*PT_STAGE;
    uint32_t bar = mb + slot*8;
    BAR_EXPECT(bar, 65536u);
    BULK_CP(dst,         Ac + ((long)(k*2+0)*TBdim + mtile*128)*64, 16384u, bar);
    BULK_CP(dst + 16384, Ac + ((long)(k*2+1)*TBdim + mtile*128)*64, 16384u, bar);
    BULK_CP(dst + 32768, Bc + ((long)k*512 + ntile*256)*64, 32768u, bar);
}

template<int MODE>
__global__ void __launch_bounds__(256, 1) prep_tma(
    const __half* __restrict__ A, const __half* __restrict__ B,
    float* __restrict__ Cf, __half* __restrict__ Cb,
    const float* __restrict__ X, long aS)
{
    extern __shared__ char smem[];
    const uint32_t sb = smem_u32(smem);
    const uint32_t mb = sb + 3*PT_STAGE;
    const int tid = threadIdx.x, wid = tid >> 5, lane = tid & 31;
    const int wm = wid & 1, wn = wid >> 1;
    const int mtile = blockIdx.x, ntile = blockIdx.y, z = blockIdx.z;

    const __half* Az = A + (long)z*aS;
    const __half* Bz = B + (long)z*8*512*64;

    if (tid == 0) {
        MBARRIER_INIT(mb, 1); MBARRIER_INIT(mb + 8, 1); MBARRIER_INIT(mb + 16, 1);
    }
    __syncthreads();
    if (tid == 0) {
        prep_issue(sb, mb, 0, Az, Bz, mtile, ntile);
        prep_issue(sb, mb, 1, Az, Bz, mtile, ntile);
    }

    float acc[4][8][4];
#pragma unroll
    for (int i = 0; i < 4; i++)
#pragma unroll
        for (int j = 0; j < 8; j++)
#pragma unroll
            for (int q = 0; q < 4; q++) acc[i][j][q] = 0.f;

    for (int k = 0; k < 8; k++) {
        int slot = k % 3;
        MBARRIER_WAIT_PARITY(mb + slot*8, (k/3) & 1);
        __syncthreads();
        if (tid == 0 && k + 2 < 8) prep_issue(sb, mb, k + 2, Az, Bz, mtile, ntile);

        uint32_t base = sb + slot*PT_STAGE;
        uint32_t sB = base + 32768;
#pragma unroll
        for (int ks = 0; ks < 4; ks++) {
            uint32_t b[8][2];
#pragma unroll
            for (int np = 0; np < 4; np++) {
                uint32_t n = wn*64 + np*16 + (lane & 7) + ((lane >> 4) & 1)*8;
                uint32_t q = ks*2 + ((lane >> 3) & 1);
                uint32_t r[4];
                ldm_x4(r, sB + n*128 + (q ^ (n & 7))*16);
                b[np*2][0] = r[0];   b[np*2][1] = r[1];
                b[np*2+1][0] = r[2]; b[np*2+1][1] = r[3];
            }
#pragma unroll
            for (int h = 0; h < 2; h++) {
                uint32_t ab = base + h*16384;
                uint32_t a[4][4];
#pragma unroll
                for (int mi = 0; mi < 4; mi++) {
                    uint32_t m = wm*64 + mi*16 + (lane & 15);
                    uint32_t q = ks*2 + (lane >> 4);
                    ldm_x4(a[mi], ab + m*128 + (q ^ (m & 7))*16);
                }
#pragma unroll
                for (int mi = 0; mi < 4; mi++)
#pragma unroll
                    for (int ni = 0; ni < 8; ni++)
                        mma16816(acc[mi][ni], a[mi], b[ni]);
            }
        }
    }

#pragma unroll
    for (int mi = 0; mi < 4; mi++) {
#pragma unroll
        for (int ni = 0; ni < 8; ni++) {
            int n = ntile*256 + wn*64 + ni*8 + (lane & 3)*2;
            int gr0 = mtile*128 + wm*64 + mi*16 + (lane >> 2);
            int gr1 = gr0 + 8;
            if (MODE == 1) {
                const float* Xg = X + (long)z*Bdim*Rdim;
                __half* Cz = Cb + (long)z*(8L*2*TBdim*64);
                int chunk = n >> 6, q = (n & 63) >> 3;
                float v00 = acc[mi][ni][0]*Xg[(gr0 & 127)*512 + n];
                float v01 = acc[mi][ni][1]*Xg[(gr0 & 127)*512 + n + 1];
                float v10 = acc[mi][ni][2]*Xg[(gr1 & 127)*512 + n];
                float v11 = acc[mi][ni][3]*Xg[(gr1 & 127)*512 + n + 1];
                __half2 h0 = __floats2half2_rn(v00, v01);
                __half2 l0 = __floats2half2_rn(v00 - __half2float(__low2half(h0)),
                                               v01 - __half2float(__high2half(h0)));
                __half2 h1 = __floats2half2_rn(v10, v11);
                __half2 l1 = __floats2half2_rn(v10 - __half2float(__low2half(h1)),
                                               v11 - __half2float(__high2half(h1)));
                long b0 = ((long)(chunk*2)*TBdim + gr0)*64 + (q ^ (gr0 & 7))*8 + (n & 7);
                long b1 = ((long)(chunk*2)*TBdim + gr1)*64 + (q ^ (gr1 & 7))*8 + (n & 7);
                *(__half2*)(Cz + b0) = h0;
                *(__half2*)(Cz + b0 + (long)TBdim*64) = l0;
                *(__half2*)(Cz + b1) = h1;
                *(__half2*)(Cz + b1 + (long)TBdim*64) = l1;
            } else {
                const float* Xg = X + z*512;
                float* Cz = Cf + (long)z*TBdim*512;
                float2 bv = make_float2(Xg[n], Xg[n + 1]);
                *(float2*)(Cz + (long)gr0*512 + n) = make_float2(acc[mi][ni][0] + bv.x, acc[mi][ni][1] + bv.y);
                *(float2*)(Cz + (long)gr1*512 + n) = make_float2(acc[mi][ni][2] + bv.x, acc[mi][ni][3] + bv.y);
            }
        }
    }
}

// ---------------- conversions ------------------------------------------------
__global__ void __launch_bounds__(256) k_convWC(const float* __restrict__ W,
                                                __half* __restrict__ Bp)
{   // W[g][k=512][n=512] -> Bp[g][chunk=k/64][n][64] swizzled hi
    __shared__ float t[64][33];
    const int tid = threadIdx.x;
    const int g = blockIdx.z;
    const int n0 = blockIdx.x*32;
    const int k0 = blockIdx.y*64;
    for (int e = tid; e < 64*32; e += 256) {
        int kk = e >> 5, nn = e & 31;
        t[kk][nn] = W[((long)g*512 + k0 + kk)*512 + n0 + nn];
    }
    __syncthreads();
    int nn = tid >> 3, q = tid & 7;
    int n = n0 + nn;
    __half h[8];
#pragma unroll
    for (int i = 0; i < 8; i++) h[i] = __float2half_rn(t[q*8 + i][nn]);
    int qs = q ^ (n & 7);
    *(uint4*)(Bp + (((long)g*8 + blockIdx.y)*512 + n)*64 + qs*8) = *(uint4*)h;
}

__global__ void __launch_bounds__(256) k_convB(const float* __restrict__ Wout)
{
    __shared__ float t[64][33];
    const int tid = threadIdx.x;
    const int n0 = blockIdx.x*32;
    for (int e = tid; e < 64*32; e += 256) {
        int kk = e >> 5, nn = e & 31;
        int n = n0 + nn;
        t[kk][nn] = (n < Vdim) ? Wout[(long)(blockIdx.y*64 + kk)*Vdim + n] : 0.f;
    }
    __syncthreads();
    int nn = tid >> 3, q = tid & 7;
    int n = n0 + nn;
    __half h[8];
#pragma unroll
    for (int i = 0; i < 8; i++) h[i] = __float2half_rn(t[q*8 + i][nn]);
    int qs = q ^ (n & 7);
    *(uint4*)(g_WoC + ((long)blockIdx.y*NPAD + n)*64 + qs*8) = *(uint4*)h;
}

// ---------------- embedding gather -> x2C chunk-major pair -------------------
__global__ void k_gather(const int* __restrict__ caps, const float* __restrict__ emb)
{
    const int b = blockIdx.x, t = blockIdx.y;
    float4 v = make_float4(0.f, 0.f, 0.f, 0.f);
    if (t > 0) {
        int tok = caps[b*Tdim + (t-1)];
        v = ((const float4*)(emb + (long)tok*Edim))[threadIdx.x];
    }
    __half hv[4], lv[4];
    float f[4] = {v.x, v.y, v.z, v.w};
#pragma unroll
    for (int i = 0; i < 4; i++) {
        hv[i] = __float2half_rn(f[i]);
        lv[i] = __float2half_rn(f[i] - __half2float(hv[i]));
    }
    int col = threadIdx.x*4;
    int row = t*Bdim + b;
    int chunk = col >> 6, q = (col & 63) >> 3;
    long bh = ((long)(chunk*2)*TBdim + row)*64 + (q ^ (b & 7))*8 + (col & 7);
    *(uint2*)(g_x2C + bh) = *(uint2*)hv;
    *(uint2*)(g_x2C + bh + (long)TBdim*64) = *(uint2*)lv;
}

__global__ void k_init(const float* __restrict__ h0, const float* __restrict__ c0)
{
    int i = blockIdx.x*blockDim.x + threadIdx.x;    // 65536
    float v = h0[i];
    __half hi = __float2half_rn(v);
    __half lo = __float2half_rn(v - __half2float(hi));
    int b = i >> 9, col = i & 511;
    int chunk = col >> 6, q = (col & 63) >> 3;
    long bh = ((long)(chunk*2)*Bdim + b)*64 + (q ^ (b & 7))*8 + (col & 7);
    g_hC[bh] = hi;
    g_hC[bh + Bdim*64] = lo;
    g_c[i] = c0[i];
    if (i == 0) g_sync = 0;
}

// ---------------- fp32 tiled SGEMM (t2 and t5 in one launch) -----------------
template<int BM,int BN,int BK,int TM,int TN>
__global__ void gemm_k(const float* __restrict__ A,
                       const float* __restrict__ Bm, const float* __restrict__ Bm2,
                       float* __restrict__ C, float* __restrict__ C2,
                       int M, int N, int K, long sB, long sC)
{
    constexpr int THREADS = (BM/TM)*(BN/TN);
    __shared__ float As[BK][BM];
    __shared__ float Bs[BK][BN];
    const int z = blockIdx.z;
    const int g = z & 3;
    const float* Bg = (z < 4 ? Bm : Bm2) + (long)g*sB;
    float* Cg = (z < 4 ? C : C2) + (long)g*sC;
    const int m0 = blockIdx.y*BM;
    const int n0 = blockIdx.x*BN;
    const int tid = threadIdx.x;
    constexpr int AK4 = BK/4;
    const int aRow = tid / AK4, aCol = (tid % AK4)*4;
    constexpr int AROWS = THREADS/AK4;
    constexpr int BN4 = BN/4;
    const int bRow = tid / BN4, bCol = (tid % BN4)*4;
    constexpr int BROWS = THREADS/BN4;
    const int tr = (tid/(BN/TN))*TM, tc = (tid%(BN/TN))*TN;

    float acc[TM][TN];
#pragma unroll
    for (int i = 0; i < TM; i++)
#pragma unroll
        for (int j = 0; j < TN; j++) acc[i][j] = 0.f;

    for (int k0 = 0; k0 < K; k0 += BK) {
#pragma unroll
        for (int i = 0; i < BM; i += AROWS) {
            float4 v = *(const float4*)(A + (long)(m0 + aRow + i)*K + (k0 + aCol));
            As[aCol+0][aRow+i] = v.x; As[aCol+1][aRow+i] = v.y;
            As[aCol+2][aRow+i] = v.z; As[aCol+3][aRow+i] = v.w;
        }
#pragma unroll
        for (int i = 0; i < BK; i += BROWS) {
            float4 v = *(const float4*)(Bg + (long)(k0 + bRow + i)*N + (n0 + bCol));
            *(float4*)&Bs[bRow+i][bCol] = v;
        }
        __syncthreads();
#pragma unroll
        for (int kk = 0; kk < BK; kk++) {
            float rm[TM], rn[TN];
#pragma unroll
            for (int i = 0; i < TM; i++) rm[i] = As[kk][tr+i];
#pragma unroll
            for (int j = 0; j < TN; j++) rn[j] = Bs[kk][tc+j];
#pragma unroll
            for (int i = 0; i < TM; i++)
#pragma unroll
                for (int j = 0; j < TN; j++)
                    acc[i][j] = fmaf(rm[i], rn[j], acc[i][j]);
        }
        __syncthreads();
    }
#pragma unroll
    for (int i = 0; i < TM; i++)
#pragma unroll
        for (int j = 0; j < TN; j++)
            Cg[(long)(m0 + tr + i)*N + n0 + tc + j] = acc[i][j];
}

// ---------------- persistent tensor-core recurrence (bulk-TMA A) -------------
#define RW_STRIDE 1040
#define RW_SLAB   (16*RW_STRIDE)          // 16640
#define RA_BASE   (4*RW_SLAB)             // 66560
#define RA_ST     32768
#define REC_SMEM  (RA_BASE + 3*RA_ST + 32)  // 164,928

__device__ __forceinline__ void gbar(unsigned goal)
{
    __syncthreads();
    __threadfence();
    if (threadIdx.x == 0) {
        atomicAdd(&g_sync, 1u);
        unsigned v;
        do {
            asm volatile("ld.global.acquire.gpu.u32 %0, [%1];" : "=r"(v) : "l"(&g_sync));
        } while (v < goal);
    }
    __syncthreads();
}

__device__ __forceinline__ float sig_f(float x)  { return 1.f/(1.f + __expf(-x)); }
__device__ __forceinline__ float tanh_f(float x) { return 2.f/(1.f + __expf(-2.f*x)) - 1.f; }

__device__ __forceinline__ void rec_issue(uint32_t sbase, uint32_t mb, int k,
                                          const __half* Ac)
{
    int slot = k % 3;
    uint32_t dst = sbase + RA_BASE + slot*RA_ST;
    uint32_t bar = mb + slot*8;
    BAR_EXPECT(bar, 32768u);
    BULK_CP(dst,         Ac + (long)(k*2+0)*Bdim*64, 16384u, bar);
    BULK_CP(dst + 16384, Ac + (long)(k*2+1)*Bdim*64, 16384u, bar);
}

__device__ __forceinline__ void rec_phase(uint32_t sbase, uint32_t wbase, uint32_t mb,
                                          const __half* __restrict__ Asrc,
                                          int tid, int wid, int lane,
                                          float acc[2][4], unsigned* ub)
{
#pragma unroll
    for (int i = 0; i < 2; i++)
#pragma unroll
        for (int q = 0; q < 4; q++) acc[i][q] = 0.f;

    if (tid == 0) { rec_issue(sbase, mb, 0, Asrc); rec_issue(sbase, mb, 1, Asrc); }

    for (int k = 0; k < 8; k++) {
        int slot = k % 3;
        MBARRIER_WAIT_PARITY(mb + slot*8, ub[slot] & 1);
        ub[slot]++;
        __syncthreads();
        if (tid == 0 && k + 2 < 8) rec_issue(sbase, mb, k + 2, Asrc);

        uint32_t st = sbase + RA_BASE + slot*RA_ST;
#pragma unroll
        for (int ks = 0; ks < 4; ks++) {
            int krow = k*64 + ks*16 + ((lane >> 3) & 1)*8;
            uint32_t baddr = wbase + ((lane & 7) + ((lane >> 4) & 1)*8)*RW_STRIDE + krow*2;
            uint32_t rhi[4], rlo[4];
            ldm_x4(rhi, baddr);
            ldm_x4(rlo, baddr + RW_SLAB);
            uint32_t bhi[2][2] = {{rhi[0], rhi[1]}, {rhi[2], rhi[3]}};
            uint32_t blo[2][2] = {{rlo[0], rlo[1]}, {rlo[2], rlo[3]}};
            uint32_t m = wid*16 + (lane & 15);
            uint32_t q = ks*2 + (lane >> 4);
            uint32_t ahi[4], alo[4];
            ldm_x4(ahi, st + m*128 + (q ^ (m & 7))*16);
            ldm_x4(alo, st + 16384 + m*128 + (q ^ (m & 7))*16);
#pragma unroll
            for (int ni = 0; ni < 2; ni++) {
                mma16816(acc[ni], ahi, bhi[ni]);
                mma16816(acc[ni], ahi, blo[ni]);
                mma16816(acc[ni], alo, bhi[ni]);
            }
        }
    }
}

__global__ void __launch_bounds__(256, 1) rec_k(const float* __restrict__ Ua,
                                                const float* __restrict__ Uc)
{
    extern __shared__ char smem[];
    const uint32_t sbase = smem_u32(smem);
    const uint32_t mb = sbase + RA_BASE + 3*RA_ST;
    const int tid = threadIdx.x, wid = tid >> 5, lane = tid & 31;
    const int bx = blockIdx.x;
    const int gg = bx >> 5;
    const int c0 = (bx & 31)*16;

    // one-time weight slice conversion to smem (hi/lo, padded rows)
    {
        const float* UaG = Ua + (long)gg*512*512;
        const float* UcG = Uc + (long)gg*512*512;
        for (int e = tid; e < 512*16; e += 256) {
            int k = e >> 4, j = e & 15;
            float va = UaG[(long)k*512 + c0 + j];
            __half ha = __float2half_rn(va);
            __half la = __float2half_rn(va - __half2float(ha));
            *(__half*)(smem + j*RW_STRIDE + k*2) = ha;
            *(__half*)(smem + RW_SLAB + j*RW_STRIDE + k*2) = la;
            float vc = UcG[(long)k*512 + c0 + j];
            __half hc = __float2half_rn(vc);
            __half lc = __float2half_rn(vc - __half2float(hc));
            *(__half*)(smem + 2*RW_SLAB + j*RW_STRIDE + k*2) = hc;
            *(__half*)(smem + 3*RW_SLAB + j*RW_STRIDE + k*2) = lc;
        }
    }
    if (tid == 0) {
        MBARRIER_INIT(mb, 1); MBARRIER_INIT(mb + 8, 1); MBARRIER_INIT(mb + 16, 1);
    }
    __syncthreads();

    unsigned goal = RC;
    unsigned ub[3] = {0u, 0u, 0u};
    const long GS = (long)TBdim*Hdim;
    const long GH = (long)Bdim*Hdim;
    const __half* t6src = g_t6C + (long)gg*8*2*Bdim*64;

    for (int t = 0; t < Tdim; t++) {
        float acc[2][4];

        // phase A: t6[gg][:, c0..] = (h @ Ua[gg]) * t5 -> t6C pair
        rec_phase(sbase, sbase, mb, g_hC, tid, wid, lane, acc, ub);
        {
            __half* Cz = g_t6C + (long)gg*8*2*Bdim*64;
            const float* t5g = g_t5 + (long)gg*GH;
#pragma unroll
            for (int ni = 0; ni < 2; ni++) {
                int col = c0 + ni*8 + (lane & 3)*2;
                int r0 = wid*16 + (lane >> 2), r1 = r0 + 8;
                int chunk = col >> 6, q = (col & 63) >> 3;
                float2 m0 = *(const float2*)(t5g + (long)r0*512 + col);
                float2 m1 = *(const float2*)(t5g + (long)r1*512 + col);
                float v00 = acc[ni][0]*m0.x, v01 = acc[ni][1]*m0.y;
                float v10 = acc[ni][2]*m1.x, v11 = acc[ni][3]*m1.y;
                __half2 h0 = __floats2half2_rn(v00, v01);
                __half2 l0 = __floats2half2_rn(v00 - __half2float(__low2half(h0)),
                                               v01 - __half2float(__high2half(h0)));
                __half2 h1 = __floats2half2_rn(v10, v11);
                __half2 l1 = __floats2half2_rn(v10 - __half2float(__low2half(h1)),
                                               v11 - __half2float(__high2half(h1)));
                long b0 = ((long)(chunk*2)*Bdim + r0)*64 + (q ^ (r0 & 7))*8 + (col & 7);
                long b1 = ((long)(chunk*2)*Bdim + r1)*64 + (q ^ (r1 & 7))*8 + (col & 7);
                *(__half2*)(Cz + b0) = h0;
                *(__half2*)(Cz + b0 + Bdim*64) = l0;
                *(__half2*)(Cz + b1) = h1;
                *(__half2*)(Cz + b1 + Bdim*64) = l1;
            }
        }
        gbar(goal); goal += RC;

        // phase B: gh[gg][:, c0..] = t6[gg] @ Uc[gg]  (gh kept in regs->global fp32)
        rec_phase(sbase, sbase + 2*RW_SLAB, mb, t6src, tid, wid, lane, acc, ub);
        // store gh to scratch (reuse g_gx? no — separate small buffer): use registers
        // via global g_ghbuf below
        {
#pragma unroll
            for (int ni = 0; ni < 2; ni++) {
                int col = c0 + ni*8 + (lane & 3)*2;
                int r0 = wid*16 + (lane >> 2), r1 = r0 + 8;
                extern __device__ float g_gh[];
                float* Cz = g_gh + (long)gg*GH;
                *(float2*)(Cz + (long)r0*512 + col) = make_float2(acc[ni][0], acc[ni][1]);
                *(float2*)(Cz + (long)r1*512 + col) = make_float2(acc[ni][2], acc[ni][3]);
            }
        }
        gbar(goal); goal += RC;

        // phase C: LSTM pointwise on batch row bx
        {
            extern __device__ float g_gh[];
            const long so = (long)t*Bdim*Hdim;
            int i0 = bx*512 + tid*2;
            float hv[2];
#pragma unroll
            for (int u = 0; u < 2; u++) {
                int i = i0 + u;
                float pi = g_gx[0*GS + so + i] + g_gh[0*GH + i];
                float pf = g_gx[1*GS + so + i] + g_gh[1*GH + i];
                float po = g_gx[2*GS + so + i] + g_gh[2*GH + i];
                float pc = g_gx[3*GS + so + i] + g_gh[3*GH + i];
                float ig = sig_f(pi), fg = sig_f(pf), og = sig_f(po);
                float ct = tanh_f(pc);
                float cn = fg*g_c[i] + ig*ct;
                float hn = og*tanh_f(cn);
                g_c[i] = cn;
                hv[u] = hn;
            }
            __half2 hh = __floats2half2_rn(hv[0], hv[1]);
            __half2 ll = __floats2half2_rn(hv[0] - __half2float(__low2half(hh)),
                                           hv[1] - __half2float(__high2half(hh)));
            int kcol = tid*2;
            int chunk = kcol >> 6, q = (kcol & 63) >> 3;
            // h pair (chunk-major) for next step's phase A
            long bh = ((long)(chunk*2)*Bdim + bx)*64 + (q ^ (bx & 7))*8 + (kcol & 7);
            *(__half2*)(g_hC + bh) = hh;
            *(__half2*)(g_hC + bh + Bdim*64) = ll;
            // hs hi for the out GEMM
            int row = t*Bdim + bx;
            *(__half2*)(g_hsC + ((long)chunk*TBdim + row)*64
                        + (q ^ (row & 7))*8 + (kcol & 7)) = hh;
        }
        gbar(goal); goal += RC;
    }
}

__device__ float g_gh[4*Bdim*Hdim];

// ---------------- launch ------------------------------------------------------
extern "C" void kernel_launch(void* const* d_in, const int* in_sizes, int n_in,
                              void* d_out, int out_size)
{
    const int*   caps = (const int*)  d_in[0];
    const float* tags = (const float*)d_in[1];
    const float* h0   = (const float*)d_in[2];
    const float* c0   = (const float*)d_in[3];
    const float* Wa   = (const float*)d_in[4];
    const float* Wb   = (const float*)d_in[5];
    const float* Wc   = (const float*)d_in[6];
    const float* Ua   = (const float*)d_in[7];
    const float* Ub   = (const float*)d_in[8];
    const float* Uc   = (const float*)d_in[9];
    const float* bi   = (const float*)d_in[10];
    const float* emb  = (const float*)d_in[11];
    const float* Wout = (const float*)d_in[12];
    const float* bout = (const float*)d_in[13];
    float* out = (float*)d_out;

    float *p_t2, *p_t5, *p_gx;
    __half *p_x2C, *p_t1C, *p_WaC, *p_WcC, *p_hsC, *p_WoC;
    cudaGetSymbolAddress((void**)&p_t2,  g_t2);
    cudaGetSymbolAddress((void**)&p_t5,  g_t5);
    cudaGetSymbolAddress((void**)&p_gx,  g_gx);
    cudaGetSymbolAddress((void**)&p_x2C, g_x2C);
    cudaGetSymbolAddress((void**)&p_t1C, g_t1C);
    cudaGetSymbolAddress((void**)&p_WaC, g_WaC);
    cudaGetSymbolAddress((void**)&p_WcC, g_WcC);
    cudaGetSymbolAddress((void**)&p_hsC, g_hsC);
    cudaGetSymbolAddress((void**)&p_WoC, g_WoC);

    cudaFuncSetAttribute((const void*)prep_tma<1>, cudaFuncAttributeMaxDynamicSharedMemorySize, PT_SMEM);
    cudaFuncSetAttribute((const void*)prep_tma<2>, cudaFuncAttributeMaxDynamicSharedMemorySize, PT_SMEM);
    cudaFuncSetAttribute((const void*)rec_k, cudaFuncAttributeMaxDynamicSharedMemorySize, REC_SMEM);
    cudaFuncSetAttribute((const void*)out_gemm_tma, cudaFuncAttributeMaxDynamicSharedMemorySize, TO_SMEM);

    k_gather<<<dim3(Bdim, Tdim), 128>>>(caps, emb);                          // 1
    k_convWC<<<dim3(16, 8, 4), 256>>>(Wa, p_WaC);                             // 2
    gemm_k<32,64,16,4,4><<<dim3(8,4,8), 128>>>(tags, Wb, Ub, p_t2, p_t5,      // 3
        Bdim, Rdim, NTG, (long)NTG*Rdim, (long)Bdim*Rdim);
    prep_tma<1><<<dim3(24,2,4), 256, PT_SMEM>>>(p_x2C, p_WaC, nullptr,        // 4
        p_t1C, p_t2, 0L);
    k_convWC<<<dim3(16, 8, 4), 256>>>(Wc, p_WcC);                             // 5
    k_init<<<256, 256>>>(h0, c0);                                             // 6
    prep_tma<2><<<dim3(24,2,4), 256, PT_SMEM>>>(p_t1C, p_WcC, p_gx,           // 7
        nullptr, bi, 8L*2*TBdim*64);
    k_convB<<<dim3(NPAD/32, 8), 256>>>(Wout);                                 // 8
    rec_k<<<RC, 256, REC_SMEM>>>(Ua, Uc);                                     // 9
    out_gemm_tma<<<dim3(TBdim/128, NPAD/256), 256, TO_SMEM>>>(                // 10
        p_hsC, p_WoC, bout, out);
}

// round 10
// speedup vs baseline: 4.7179x; 1.0069x over previous
#include <cuda_runtime.h>
#include <cuda_fp16.h>
#include <math.h>
#include <cstdint>

#define Bdim 128
#define Tdim 24
#define Edim 512
#define Hdim 512
#define Rdim 512
#define NTG 400
#define Vdim 20000
#define NPAD 20224          // 79*256
#define TBdim (Tdim*Bdim)   // 3072
#define RC 128              // persistent recurrence CTAs

// ---------------- scratch (device globals; no allocation allowed) ----------
__device__ float g_t2[4*Bdim*Rdim];
__device__ float g_t5[4*Bdim*Rdim];
__device__ float g_gx[4L*TBdim*Hdim];
__device__ float g_gh[4*Bdim*Hdim];
__device__ float g_c[Bdim*Hdim];
__device__ unsigned g_sync;
// chunk-major swizzled fp16 layouts
__device__ __half g_x2C[8L*2*TBdim*64];         // xs pair
__device__ __half g_t1C[4L*8*2*TBdim*64];       // t1 pair per gate
__device__ __half g_hC[8L*2*Bdim*64];           // h pair
__device__ __half g_t6C[4L*8*2*Bdim*64];        // t6 pair per gate
__device__ __half g_WaC[4L*8*Rdim*64];          // Wa^T hi per gate
__device__ __half g_WcC[4L*8*Rdim*64];          // Wc^T hi per gate
__device__ __half g_hsC[8L*TBdim*64];           // hs hi (out GEMM A)
__device__ __half g_WoC[8L*NPAD*64];            // Wout^T hi (out GEMM B)

__device__ __forceinline__ uint32_t smem_u32(const void* p) {
    uint32_t a;
    asm("{ .reg .u64 t; cvta.to.shared.u64 t, %1; cvt.u32.u64 %0, t; }" : "=r"(a) : "l"(p));
    return a;
}

__device__ __forceinline__ void ldm_x4(uint32_t* r, uint32_t addr)
{
    asm volatile("ldmatrix.sync.aligned.m8n8.x4.shared.b16 {%0,%1,%2,%3}, [%4];"
        : "=r"(r[0]), "=r"(r[1]), "=r"(r[2]), "=r"(r[3]) : "r"(addr));
}

__device__ __forceinline__ void mma16816(float* c, const uint32_t* a, const uint32_t* b)
{
    asm volatile("mma.sync.aligned.m16n8k16.row.col.f32.f16.f16.f32 "
        "{%0,%1,%2,%3}, {%4,%5,%6,%7}, {%8,%9}, {%0,%1,%2,%3};"
        : "+f"(c[0]), "+f"(c[1]), "+f"(c[2]), "+f"(c[3])
        : "r"(a[0]), "r"(a[1]), "r"(a[2]), "r"(a[3]), "r"(b[0]), "r"(b[1]));
}

#define MBARRIER_INIT(mbar, cnt) \
    asm volatile("mbarrier.init.shared.b64 [%0], %1;" :: "r"((uint32_t)(mbar)), "r"((uint32_t)(cnt)) : "memory")
#define MBARRIER_WAIT_PARITY(mbar, par) do { \
    uint32_t _m = (uint32_t)(mbar), _p = (uint32_t)(par), _d; \
    asm volatile("{\n\t.reg .pred p;\n\t" \
        "mbarrier.try_wait.parity.acquire.cta.shared::cta.b64 p, [%1], %2;\n\t" \
        "selp.b32 %0, 1, 0, p;\n\t}" : "=r"(_d) : "r"(_m), "r"(_p) : "memory"); \
    if (!_d) { \
        asm volatile("{\n\t.reg .pred P1;\n\t" \
            "WL_%=:\n\t" \
            "mbarrier.try_wait.parity.acquire.cta.shared::cta.b64 P1, [%0], %1, 0x989680;\n\t" \
            "@P1 bra.uni WD_%=;\n\t" \
            "bra.uni WL_%=;\n\t" \
            "WD_%=:\n\t}" :: "r"(_m), "r"(_p) : "memory"); \
    } \
} while (0)
#define BULK_CP(dst, src, bytes, bar) \
    asm volatile("cp.async.bulk.shared::cluster.global.mbarrier::complete_tx::bytes " \
        "[%0], [%1], %2, [%3];" :: "r"(dst), "l"(src), "r"((uint32_t)(bytes)), "r"(bar) : "memory")
#define BAR_EXPECT(bar, bytes) \
    asm volatile("mbarrier.arrive.expect_tx.shared.b64 _, [%0], %1;" \
        :: "r"(bar), "r"((uint32_t)(bytes)) : "memory")

// ================= out GEMM: bulk-TMA + mma.sync, 512 threads ===============
#define TO_STAGE 49152
#define TO_SMEM  (3*TO_STAGE + 32)

__device__ __forceinline__ void out_issue(uint32_t sb, uint32_t mb, int k,
                                          const __half* Ac, const __half* Bc,
                                          int mtile, int ntile)
{
    int slot = k % 3;
    uint32_t dst = sb + slot*TO_STAGE;
    uint32_t bar = mb + slot*8;
    BAR_EXPECT(bar, 49152u);
    BULK_CP(dst, Ac + ((long)k*TBdim + mtile*128)*64, 16384u, bar);
    BULK_CP(dst + 16384, Bc + ((long)k*NPAD + ntile*256)*64, 32768u, bar);
}

__global__ void __launch_bounds__(512, 1) out_gemm_tma(
    const __half* __restrict__ Ac, const __half* __restrict__ Bc,
    const float* __restrict__ bout, float* __restrict__ out)
{
    extern __shared__ char smem[];
    const uint32_t sb = smem_u32(smem);
    const uint32_t mb = sb + 3*TO_STAGE;
    const int tid = threadIdx.x, wid = tid >> 5, lane = tid & 31;
    const int wm = wid & 1, wn = wid >> 1;     // 2 x 8 warps, tile 64x32
    const int mtile = blockIdx.x, ntile = blockIdx.y;

    if (tid == 0) {
        MBARRIER_INIT(mb, 1); MBARRIER_INIT(mb + 8, 1); MBARRIER_INIT(mb + 16, 1);
    }
    __syncthreads();
    if (tid == 0) {
        out_issue(sb, mb, 0, Ac, Bc, mtile, ntile);
        out_issue(sb, mb, 1, Ac, Bc, mtile, ntile);
    }

    float acc[4][4][4];
#pragma unroll
    for (int i = 0; i < 4; i++)
#pragma unroll
        for (int j = 0; j < 4; j++)
#pragma unroll
            for (int q = 0; q < 4; q++) acc[i][j][q] = 0.f;

    for (int k = 0; k < 8; k++) {
        int slot = k % 3;
        MBARRIER_WAIT_PARITY(mb + slot*8, (k/3) & 1);
        __syncthreads();
        if (tid == 0 && k + 2 < 8) out_issue(sb, mb, k + 2, Ac, Bc, mtile, ntile);

        uint32_t sA = sb + slot*TO_STAGE;
        uint32_t sB = sA + 16384;
#pragma unroll
        for (int ks = 0; ks < 4; ks++) {
            uint32_t b[4][2];
#pragma unroll
            for (int np = 0; np < 2; np++) {
                uint32_t n = wn*32 + np*16 + (lane & 7) + ((lane >> 4) & 1)*8;
                uint32_t q = ks*2 + ((lane >> 3) & 1);
                uint32_t r[4];
                ldm_x4(r, sB + n*128 + (q ^ (n & 7))*16);
                b[np*2][0] = r[0];   b[np*2][1] = r[1];
                b[np*2+1][0] = r[2]; b[np*2+1][1] = r[3];
            }
            uint32_t a[4][4];
#pragma unroll
            for (int mi = 0; mi < 4; mi++) {
                uint32_t m = wm*64 + mi*16 + (lane & 15);
                uint32_t q = ks*2 + (lane >> 4);
                ldm_x4(a[mi], sA + m*128 + (q ^ (m & 7))*16);
            }
#pragma unroll
            for (int mi = 0; mi < 4; mi++)
#pragma unroll
                for (int ni = 0; ni < 4; ni++)
                    mma16816(acc[mi][ni], a[mi], b[ni]);
        }
    }

#pragma unroll
    for (int mi = 0; mi < 4; mi++) {
#pragma unroll
        for (int ni = 0; ni < 4; ni++) {
            int n = ntile*256 + wn*32 + ni*8 + (lane & 3)*2;
            if (n < Vdim) {
                float2 bv = *(const float2*)(bout + n);
                int gr0 = mtile*128 + wm*64 + mi*16 + (lane >> 2);
                int gr1 = gr0 + 8;
                long o0 = ((long)(gr0 & 127)*Tdim + (gr0 >> 7))*Vdim + n;
                long o1 = ((long)(gr1 & 127)*Tdim + (gr1 >> 7))*Vdim + n;
                *(float2*)(out + o0) = make_float2(acc[mi][ni][0] + bv.x, acc[mi][ni][1] + bv.y);
                *(float2*)(out + o1) = make_float2(acc[mi][ni][2] + bv.x, acc[mi][ni][3] + bv.y);
            }
        }
    }
}

// ================= prep GEMM: bulk-TMA, fp16-pair A, 512 threads ============
#define PT_STAGE 65536
#define PT_SMEM  (3*PT_STAGE + 32)

__device__ __forceinline__ void prep_issue(uint32_t sb, uint32_t mb, int k,
    const __half* Ac, const __half* Bc, int mtile, int ntile)
{
    int slot = k % 3;
    uint32_t dst = sb + slot*PT_STAGE;
    uint32_t bar = mb + slot*8;
    BAR_EXPECT(bar, 65536u);
    BULK_CP(dst,         Ac + ((long)(k*2+0)*TBdim + mtile*128)*64, 16384u, bar);
    BULK_CP(dst + 16384, Ac + ((long)(k*2+1)*TBdim + mtile*128)*64, 16384u, bar);
    BULK_CP(dst + 32768, Bc + ((long)k*512 + ntile*256)*64, 32768u, bar);
}

template<int MODE>
__global__ void __launch_bounds__(512, 1) prep_tma(
    const __half* __restrict__ A, const __half* __restrict__ B,
    float* __restrict__ Cf, __half* __restrict__ Cb,
    const float* __restrict__ X, long aS)
{
    extern __shared__ char smem[];
    const uint32_t sb = smem_u32(smem);
    const uint32_t mb = sb + 3*PT_STAGE;
    const int tid = threadIdx.x, wid = tid >> 5, lane = tid & 31;
    const int wm = wid & 1, wn = wid >> 1;
    const int mtile = blockIdx.x, ntile = blockIdx.y, z = blockIdx.z;

    const __half* Az = A + (long)z*aS;
    const __half* Bz = B + (long)z*8*512*64;

    if (tid == 0) {
        MBARRIER_INIT(mb, 1); MBARRIER_INIT(mb + 8, 1); MBARRIER_INIT(mb + 16, 1);
    }
    __syncthreads();
    if (tid == 0) {
        prep_issue(sb, mb, 0, Az, Bz, mtile, ntile);
        prep_issue(sb, mb, 1, Az, Bz, mtile, ntile);
    }

    float acc[4][4][4];
#pragma unroll
    for (int i = 0; i < 4; i++)
#pragma unroll
        for (int j = 0; j < 4; j++)
#pragma unroll
            for (int q = 0; q < 4; q++) acc[i][j][q] = 0.f;

    for (int k = 0; k < 8; k++) {
        int slot = k % 3;
        MBARRIER_WAIT_PARITY(mb + slot*8, (k/3) & 1);
        __syncthreads();
        if (tid == 0 && k + 2 < 8) prep_issue(sb, mb, k + 2, Az, Bz, mtile, ntile);

        uint32_t base = sb + slot*PT_STAGE;
        uint32_t sB = base + 32768;
#pragma unroll
        for (int ks = 0; ks < 4; ks++) {
            uint32_t b[4][2];
#pragma unroll
            for (int np = 0; np < 2; np++) {
                uint32_t n = wn*32 + np*16 + (lane & 7) + ((lane >> 4) & 1)*8;
                uint32_t q = ks*2 + ((lane >> 3) & 1);
                uint32_t r[4];
                ldm_x4(r, sB + n*128 + (q ^ (n & 7))*16);
                b[np*2][0] = r[0];   b[np*2][1] = r[1];
                b[np*2+1][0] = r[2]; b[np*2+1][1] = r[3];
            }
#pragma unroll
            for (int h = 0; h < 2; h++) {
                uint32_t ab = base + h*16384;
                uint32_t a[4][4];
#pragma unroll
                for (int mi = 0; mi < 4; mi++) {
                    uint32_t m = wm*64 + mi*16 + (lane & 15);
                    uint32_t q = ks*2 + (lane >> 4);
                    ldm_x4(a[mi], ab + m*128 + (q ^ (m & 7))*16);
                }
#pragma unroll
                for (int mi = 0; mi < 4; mi++)
#pragma unroll
                    for (int ni = 0; ni < 4; ni++)
                        mma16816(acc[mi][ni], a[mi], b[ni]);
            }
        }
    }

#pragma unroll
    for (int mi = 0; mi < 4; mi++) {
#pragma unroll
        for (int ni = 0; ni < 4; ni++) {
            int n = ntile*256 + wn*32 + ni*8 + (lane & 3)*2;
            int gr0 = mtile*128 + wm*64 + mi*16 + (lane >> 2);
            int gr1 = gr0 + 8;
            if (MODE == 1) {
                const float* Xg = X + (long)z*Bdim*Rdim;
                __half* Cz = Cb + (long)z*(8L*2*TBdim*64);
                int chunk = n >> 6, q = (n & 63) >> 3;
                float v00 = acc[mi][ni][0]*Xg[(gr0 & 127)*512 + n];
                float v01 = acc[mi][ni][1]*Xg[(gr0 & 127)*512 + n + 1];
                float v10 = acc[mi][ni][2]*Xg[(gr1 & 127)*512 + n];
                float v11 = acc[mi][ni][3]*Xg[(gr1 & 127)*512 + n + 1];
                __half2 h0 = __floats2half2_rn(v00, v01);
                __half2 l0 = __floats2half2_rn(v00 - __half2float(__low2half(h0)),
                                               v01 - __half2float(__high2half(h0)));
                __half2 h1 = __floats2half2_rn(v10, v11);
                __half2 l1 = __floats2half2_rn(v10 - __half2float(__low2half(h1)),
                                               v11 - __half2float(__high2half(h1)));
                long b0 = ((long)(chunk*2)*TBdim + gr0)*64 + (q ^ (gr0 & 7))*8 + (n & 7);
                long b1 = ((long)(chunk*2)*TBdim + gr1)*64 + (q ^ (gr1 & 7))*8 + (n & 7);
                *(__half2*)(Cz + b0) = h0;
                *(__half2*)(Cz + b0 + (long)TBdim*64) = l0;
                *(__half2*)(Cz + b1) = h1;
                *(__half2*)(Cz + b1 + (long)TBdim*64) = l1;
            } else {
                const float* Xg = X + z*512;
                float* Cz = Cf + (long)z*TBdim*512;
                float2 bv = make_float2(Xg[n], Xg[n + 1]);
                *(float2*)(Cz + (long)gr0*512 + n) = make_float2(acc[mi][ni][0] + bv.x, acc[mi][ni][1] + bv.y);
                *(float2*)(Cz + (long)gr1*512 + n) = make_float2(acc[mi][ni][2] + bv.x, acc[mi][ni][3] + bv.y);
            }
        }
    }
}

// ---------------- conversions ------------------------------------------------
__global__ void __launch_bounds__(256) k_convWC(const float* __restrict__ W,
                                                __half* __restrict__ Bp)
{
    __shared__ float t[64][33];
    const int tid = threadIdx.x;
    const int g = blockIdx.z;
    const int n0 = blockIdx.x*32;
    const int k0 = blockIdx.y*64;
    for (int e = tid; e < 64*32; e += 256) {
        int kk = e >> 5, nn = e & 31;
        t[kk][nn] = W[((long)g*512 + k0 + kk)*512 + n0 + nn];
    }
    __syncthreads();
    int nn = tid >> 3, q = tid & 7;
    int n = n0 + nn;
    __half h[8];
#pragma unroll
    for (int i = 0; i < 8; i++) h[i] = __float2half_rn(t[q*8 + i][nn]);
    int qs = q ^ (n & 7);
    *(uint4*)(Bp + (((long)g*8 + blockIdx.y)*512 + n)*64 + qs*8) = *(uint4*)h;
}

__global__ void __launch_bounds__(256) k_convB(const float* __restrict__ Wout)
{
    __shared__ float t[64][33];
    const int tid = threadIdx.x;
    const int n0 = blockIdx.x*32;
    for (int e = tid; e < 64*32; e += 256) {
        int kk = e >> 5, nn = e & 31;
        int n = n0 + nn;
        t[kk][nn] = (n < Vdim) ? Wout[(long)(blockIdx.y*64 + kk)*Vdim + n] : 0.f;
    }
    __syncthreads();
    int nn = tid >> 3, q = tid & 7;
    int n = n0 + nn;
    __half h[8];
#pragma unroll
    for (int i = 0; i < 8; i++) h[i] = __float2half_rn(t[q*8 + i][nn]);
    int qs = q ^ (n & 7);
    *(uint4*)(g_WoC + ((long)blockIdx.y*NPAD + n)*64 + qs*8) = *(uint4*)h;
}

// ---------------- embedding gather -> x2C chunk-major pair -------------------
__global__ void k_gather(const int* __restrict__ caps, const float* __restrict__ emb)
{
    const int b = blockIdx.x, t = blockIdx.y;
    float4 v = make_float4(0.f, 0.f, 0.f, 0.f);
    if (t > 0) {
        int tok = caps[b*Tdim + (t-1)];
        v = ((const float4*)(emb + (long)tok*Edim))[threadIdx.x];
    }
    __half hv[4], lv[4];
    float f[4] = {v.x, v.y, v.z, v.w};
#pragma unroll
    for (int i = 0; i < 4; i++) {
        hv[i] = __float2half_rn(f[i]);
        lv[i] = __float2half_rn(f[i] - __half2float(hv[i]));
    }
    int col = threadIdx.x*4;
    int row = t*Bdim + b;
    int chunk = col >> 6, q = (col & 63) >> 3;
    long bh = ((long)(chunk*2)*TBdim + row)*64 + (q ^ (b & 7))*8 + (col & 7);
    *(uint2*)(g_x2C + bh) = *(uint2*)hv;
    *(uint2*)(g_x2C + bh + (long)TBdim*64) = *(uint2*)lv;
}

__global__ void k_init(const float* __restrict__ h0, const float* __restrict__ c0)
{
    int i = blockIdx.x*blockDim.x + threadIdx.x;
    float v = h0[i];
    __half hi = __float2half_rn(v);
    __half lo = __float2half_rn(v - __half2float(hi));
    int b = i >> 9, col = i & 511;
    int chunk = col >> 6, q = (col & 63) >> 3;
    long bh = ((long)(chunk*2)*Bdim + b)*64 + (q ^ (b & 7))*8 + (col & 7);
    g_hC[bh] = hi;
    g_hC[bh + Bdim*64] = lo;
    g_c[i] = c0[i];
    if (i == 0) g_sync = 0;
}

// ---------------- fp32 tiled SGEMM (t2 and t5 in one launch) -----------------
template<int BM,int BN,int BK,int TM,int TN>
__global__ void gemm_k(const float* __restrict__ A,
                       const float* __restrict__ Bm, const float* __restrict__ Bm2,
                       float* __restrict__ C, float* __restrict__ C2,
                       int M, int N, int K, long sB, long sC)
{
    constexpr int THREADS = (BM/TM)*(BN/TN);
    __shared__ float As[BK][BM];
    __shared__ float Bs[BK][BN];
    const int z = blockIdx.z;
    const int g = z & 3;
    const float* Bg = (z < 4 ? Bm : Bm2) + (long)g*sB;
    float* Cg = (z < 4 ? C : C2) + (long)g*sC;
    const int m0 = blockIdx.y*BM;
    const int n0 = blockIdx.x*BN;
    const int tid = threadIdx.x;
    constexpr int AK4 = BK/4;
    const int aRow = tid / AK4, aCol = (tid % AK4)*4;
    constexpr int AROWS = THREADS/AK4;
    constexpr int BN4 = BN/4;
    const int bRow = tid / BN4, bCol = (tid % BN4)*4;
    constexpr int BROWS = THREADS/BN4;
    const int tr = (tid/(BN/TN))*TM, tc = (tid%(BN/TN))*TN;

    float acc[TM][TN];
#pragma unroll
    for (int i = 0; i < TM; i++)
#pragma unroll
        for (int j = 0; j < TN; j++) acc[i][j] = 0.f;

    for (int k0 = 0; k0 < K; k0 += BK) {
#pragma unroll
        for (int i = 0; i < BM; i += AROWS) {
            float4 v = *(const float4*)(A + (long)(m0 + aRow + i)*K + (k0 + aCol));
            As[aCol+0][aRow+i] = v.x; As[aCol+1][aRow+i] = v.y;
            As[aCol+2][aRow+i] = v.z; As[aCol+3][aRow+i] = v.w;
        }
#pragma unroll
        for (int i = 0; i < BK; i += BROWS) {
            float4 v = *(const float4*)(Bg + (long)(k0 + bRow + i)*N + (n0 + bCol));
            *(float4*)&Bs[bRow+i][bCol] = v;
        }
        __syncthreads();
#pragma unroll
        for (int kk = 0; kk < BK; kk++) {
            float rm[TM], rn[TN];
#pragma unroll
            for (int i = 0; i < TM; i++) rm[i] = As[kk][tr+i];
#pragma unroll
            for (int j = 0; j < TN; j++) rn[j] = Bs[kk][tc+j];
#pragma unroll
            for (int i = 0; i < TM; i++)
#pragma unroll
                for (int j = 0; j < TN; j++)
                    acc[i][j] = fmaf(rm[i], rn[j], acc[i][j]);
        }
        __syncthreads();
    }
#pragma unroll
    for (int i = 0; i < TM; i++)
#pragma unroll
        for (int j = 0; j < TN; j++)
            Cg[(long)(m0 + tr + i)*N + n0 + tc + j] = acc[i][j];
}

// ---------------- persistent tensor-core recurrence (bulk-TMA A) -------------
#define RW_STRIDE 1040
#define RW_SLAB   (16*RW_STRIDE)
#define RA_BASE   (4*RW_SLAB)
#define RA_ST     32768
#define REC_SMEM  (RA_BASE + 3*RA_ST + 32)

__device__ __forceinline__ void gbar(unsigned goal)
{
    __syncthreads();
    __threadfence();
    if (threadIdx.x == 0) {
        atomicAdd(&g_sync, 1u);
        unsigned v;
        do {
            asm volatile("ld.global.acquire.gpu.u32 %0, [%1];" : "=r"(v) : "l"(&g_sync));
        } while (v < goal);
    }
    __syncthreads();
}

__device__ __forceinline__ float sig_f(float x)  { return 1.f/(1.f + __expf(-x)); }
__device__ __forceinline__ float tanh_f(float x) { return 2.f/(1.f + __expf(-2.f*x)) - 1.f; }

__device__ __forceinline__ void rec_issue(uint32_t sbase, uint32_t mb, int k,
                                          const __half* Ac)
{
    int slot = k % 3;
    uint32_t dst = sbase + RA_BASE + slot*RA_ST;
    uint32_t bar = mb + slot*8;
    BAR_EXPECT(bar, 32768u);
    BULK_CP(dst,         Ac + (long)(k*2+0)*Bdim*64, 16384u, bar);
    BULK_CP(dst + 16384, Ac + (long)(k*2+1)*Bdim*64, 16384u, bar);
}

__device__ __forceinline__ void rec_phase(uint32_t sbase, uint32_t wbase, uint32_t mb,
                                          const __half* __restrict__ Asrc,
                                          int tid, int wid, int lane,
                                          float acc[2][4], unsigned* ub)
{
#pragma unroll
    for (int i = 0; i < 2; i++)
#pragma unroll
        for (int q = 0; q < 4; q++) acc[i][q] = 0.f;

    if (tid == 0) { rec_issue(sbase, mb, 0, Asrc); rec_issue(sbase, mb, 1, Asrc); }

    for (int k = 0; k < 8; k++) {
        int slot = k % 3;
        MBARRIER_WAIT_PARITY(mb + slot*8, ub[slot] & 1);
        ub[slot]++;
        __syncthreads();
        if (tid == 0 && k + 2 < 8) rec_issue(sbase, mb, k + 2, Asrc);

        uint32_t st = sbase + RA_BASE + slot*RA_ST;
#pragma unroll
        for (int ks = 0; ks < 4; ks++) {
            int krow = k*64 + ks*16 + ((lane >> 3) & 1)*8;
            uint32_t baddr = wbase + ((lane & 7) + ((lane >> 4) & 1)*8)*RW_STRIDE + krow*2;
            uint32_t rhi[4], rlo[4];
            ldm_x4(rhi, baddr);
            ldm_x4(rlo, baddr + RW_SLAB);
            uint32_t bhi[2][2] = {{rhi[0], rhi[1]}, {rhi[2], rhi[3]}};
            uint32_t blo[2][2] = {{rlo[0], rlo[1]}, {rlo[2], rlo[3]}};
            uint32_t m = wid*16 + (lane & 15);
            uint32_t q = ks*2 + (lane >> 4);
            uint32_t ahi[4], alo[4];
            ldm_x4(ahi, st + m*128 + (q ^ (m & 7))*16);
            ldm_x4(alo, st + 16384 + m*128 + (q ^ (m & 7))*16);
#pragma unroll
            for (int ni = 0; ni < 2; ni++) {
                mma16816(acc[ni], ahi, bhi[ni]);
                mma16816(acc[ni], ahi, blo[ni]);
                mma16816(acc[ni], alo, bhi[ni]);
            }
        }
    }
}

__global__ void __launch_bounds__(256, 1) rec_k(const float* __restrict__ Ua,
                                                const float* __restrict__ Uc)
{
    extern __shared__ char smem[];
    const uint32_t sbase = smem_u32(smem);
    const uint32_t mb = sbase + RA_BASE + 3*RA_ST;
    const int tid = threadIdx.x, wid = tid >> 5, lane = tid & 31;
    const int bx = blockIdx.x;
    const int gg = bx >> 5;
    const int c0 = (bx & 31)*16;

    {
        const float* UaG = Ua + (long)gg*512*512;
        const float* UcG = Uc + (long)gg*512*512;
        for (int e = tid; e < 512*16; e += 256) {
            int k = e >> 4, j = e & 15;
            float va = UaG[(long)k*512 + c0 + j];
            __half ha = __float2half_rn(va);
            __half la = __float2half_rn(va - __half2float(ha));
            *(__half*)(smem + j*RW_STRIDE + k*2) = ha;
            *(__half*)(smem + RW_SLAB + j*RW_STRIDE + k*2) = la;
            float vc = UcG[(long)k*512 + c0 + j];
            __half hc = __float2half_rn(vc);
            __half lc = __float2half_rn(vc - __half2float(hc));
            *(__half*)(smem + 2*RW_SLAB + j*RW_STRIDE + k*2) = hc;
            *(__half*)(smem + 3*RW_SLAB + j*RW_STRIDE + k*2) = lc;
        }
    }
    if (tid == 0) {
        MBARRIER_INIT(mb, 1); MBARRIER_INIT(mb + 8, 1); MBARRIER_INIT(mb + 16, 1);
    }
    __syncthreads();

    unsigned goal = RC;
    unsigned ub[3] = {0u, 0u, 0u};
    const long GS = (long)TBdim*Hdim;
    const long GH = (long)Bdim*Hdim;
    const __half* t6src = g_t6C + (long)gg*8*2*Bdim*64;

    // register-resident cell state (CTA bx owns batch row bx)
    const int ci = bx*512 + tid*2;
    float creg0 = g_c[ci], creg1 = g_c[ci + 1];

    for (int t = 0; t < Tdim; t++) {
        float acc[2][4];

        // phase A: t6[gg][:, c0..] = (h @ Ua[gg]) * t5 -> t6C pair
        rec_phase(sbase, sbase, mb, g_hC, tid, wid, lane, acc, ub);
        {
            __half* Cz = g_t6C + (long)gg*8*2*Bdim*64;
            const float* t5g = g_t5 + (long)gg*GH;
#pragma unroll
            for (int ni = 0; ni < 2; ni++) {
                int col = c0 + ni*8 + (lane & 3)*2;
                int r0 = wid*16 + (lane >> 2), r1 = r0 + 8;
                int chunk = col >> 6, q = (col & 63) >> 3;
                float2 m0 = *(const float2*)(t5g + (long)r0*512 + col);
                float2 m1 = *(const float2*)(t5g + (long)r1*512 + col);
                float v00 = acc[ni][0]*m0.x, v01 = acc[ni][1]*m0.y;
                float v10 = acc[ni][2]*m1.x, v11 = acc[ni][3]*m1.y;
                __half2 h0 = __floats2half2_rn(v00, v01);
                __half2 l0 = __floats2half2_rn(v00 - __half2float(__low2half(h0)),
                                               v01 - __half2float(__high2half(h0)));
                __half2 h1 = __floats2half2_rn(v10, v11);
                __half2 l1 = __floats2half2_rn(v10 - __half2float(__low2half(h1)),
                                               v11 - __half2float(__high2half(h1)));
                long b0 = ((long)(chunk*2)*Bdim + r0)*64 + (q ^ (r0 & 7))*8 + (col & 7);
                long b1 = ((long)(chunk*2)*Bdim + r1)*64 + (q ^ (r1 & 7))*8 + (col & 7);
                *(__half2*)(Cz + b0) = h0;
                *(__half2*)(Cz + b0 + Bdim*64) = l0;
                *(__half2*)(Cz + b1) = h1;
                *(__half2*)(Cz + b1 + Bdim*64) = l1;
            }
        }
        gbar(goal); goal += RC;

        // phase B: gh[gg][:, c0..] = t6[gg] @ Uc[gg]
        rec_phase(sbase, sbase + 2*RW_SLAB, mb, t6src, tid, wid, lane, acc, ub);
        {
            float* Cz = g_gh + (long)gg*GH;
#pragma unroll
            for (int ni = 0; ni < 2; ni++) {
                int col = c0 + ni*8 + (lane & 3)*2;
                int r0 = wid*16 + (lane >> 2), r1 = r0 + 8;
                *(float2*)(Cz + (long)r0*512 + col) = make_float2(acc[ni][0], acc[ni][1]);
                *(float2*)(Cz + (long)r1*512 + col) = make_float2(acc[ni][2], acc[ni][3]);
            }
        }
        gbar(goal); goal += RC;

        // phase C: LSTM pointwise on batch row bx (c in registers)
        {
            const long so = (long)t*Bdim*Hdim;
            int i0 = bx*512 + tid*2;
            float hv[2];
#pragma unroll
            for (int u = 0; u < 2; u++) {
                int i = i0 + u;
                float pi = g_gx[0*GS + so + i] + g_gh[0*GH + i];
                float pf = g_gx[1*GS + so + i] + g_gh[1*GH + i];
                float po = g_gx[2*GS + so + i] + g_gh[2*GH + i];
                float pc = g_gx[3*GS + so + i] + g_gh[3*GH + i];
                float ig = sig_f(pi), fg = sig_f(pf), og = sig_f(po);
                float ct = tanh_f(pc);
                float cprev = u == 0 ? creg0 : creg1;
                float cn = fg*cprev + ig*ct;
                float hn = og*tanh_f(cn);
                if (u == 0) creg0 = cn; else creg1 = cn;
                hv[u] = hn;
            }
            __half2 hh = __floats2half2_rn(hv[0], hv[1]);
            __half2 ll = __floats2half2_rn(hv[0] - __half2float(__low2half(hh)),
                                           hv[1] - __half2float(__high2half(hh)));
            int kcol = tid*2;
            int chunk = kcol >> 6, q = (kcol & 63) >> 3;
            long bh = ((long)(chunk*2)*Bdim + bx)*64 + (q ^ (bx & 7))*8 + (kcol & 7);
            *(__half2*)(g_hC + bh) = hh;
            *(__half2*)(g_hC + bh + Bdim*64) = ll;
            int row = t*Bdim + bx;
            *(__half2*)(g_hsC + ((long)chunk*TBdim + row)*64
                        + (q ^ (row & 7))*8 + (kcol & 7)) = hh;
        }
        gbar(goal); goal += RC;
    }
}

// ---------------- launch ------------------------------------------------------
extern "C" void kernel_launch(void* const* d_in, const int* in_sizes, int n_in,
                              void* d_out, int out_size)
{
    const int*   caps = (const int*)  d_in[0];
    const float* tags = (const float*)d_in[1];
    const float* h0   = (const float*)d_in[2];
    const float* c0   = (const float*)d_in[3];
    const float* Wa   = (const float*)d_in[4];
    const float* Wb   = (const float*)d_in[5];
    const float* Wc   = (const float*)d_in[6];
    const float* Ua   = (const float*)d_in[7];
    const float* Ub   = (const float*)d_in[8];
    const float* Uc   = (const float*)d_in[9];
    const float* bi   = (const float*)d_in[10];
    const float* emb  = (const float*)d_in[11];
    const float* Wout = (const float*)d_in[12];
    const float* bout = (const float*)d_in[13];
    float* out = (float*)d_out;

    float *p_t2, *p_t5, *p_gx;
    __half *p_x2C, *p_t1C, *p_WaC, *p_WcC, *p_hsC, *p_WoC;
    cudaGetSymbolAddress((void**)&p_t2,  g_t2);
    cudaGetSymbolAddress((void**)&p_t5,  g_t5);
    cudaGetSymbolAddress((void**)&p_gx,  g_gx);
    cudaGetSymbolAddress((void**)&p_x2C, g_x2C);
    cudaGetSymbolAddress((void**)&p_t1C, g_t1C);
    cudaGetSymbolAddress((void**)&p_WaC, g_WaC);
    cudaGetSymbolAddress((void**)&p_WcC, g_WcC);
    cudaGetSymbolAddress((void**)&p_hsC, g_hsC);
    cudaGetSymbolAddress((void**)&p_WoC, g_WoC);

    cudaFuncSetAttribute((const void*)prep_tma<1>, cudaFuncAttributeMaxDynamicSharedMemorySize, PT_SMEM);
    cudaFuncSetAttribute((const void*)prep_tma<2>, cudaFuncAttributeMaxDynamicSharedMemorySize, PT_SMEM);
    cudaFuncSetAttribute((const void*)rec_k, cudaFuncAttributeMaxDynamicSharedMemorySize, REC_SMEM);
    cudaFuncSetAttribute((const void*)out_gemm_tma, cudaFuncAttributeMaxDynamicSharedMemorySize, TO_SMEM);

    k_gather<<<dim3(Bdim, Tdim), 128>>>(caps, emb);                          // 1
    k_convWC<<<dim3(16, 8, 4), 256>>>(Wa, p_WaC);                             // 2
    gemm_k<32,64,16,4,4><<<dim3(8,4,8), 128>>>(tags, Wb, Ub, p_t2, p_t5,      // 3
        Bdim, Rdim, NTG, (long)NTG*Rdim, (long)Bdim*Rdim);
    prep_tma<1><<<dim3(24,2,4), 512, PT_SMEM>>>(p_x2C, p_WaC, nullptr,        // 4 (profiled)
        p_t1C, p_t2, 0L);
    k_convWC<<<dim3(16, 8, 4), 256>>>(Wc, p_WcC);                             // 5
    k_init<<<256, 256>>>(h0, c0);                                             // 6
    prep_tma<2><<<dim3(24,2,4), 512, PT_SMEM>>>(p_t1C, p_WcC, p_gx,           // 7
        nullptr, bi, 8L*2*TBdim*64);
    k_convB<<<dim3(NPAD/32, 8), 256>>>(Wout);                                 // 8
    rec_k<<<RC, 256, REC_SMEM>>>(Ua, Uc);                                     // 9
    out_gemm_tma<<<dim3(TBdim/128, NPAD/256), 512, TO_SMEM>>>(                // 10
        p_hsC, p_WoC, bout, out);
}

// round 11
// speedup vs baseline: 4.8920x; 1.0369x over previous
#include <cuda_runtime.h>
#include <cuda_fp16.h>
#include <math.h>
#include <cstdint>

#define Bdim 128
#define Tdim 24
#define Edim 512
#define Hdim 512
#define Rdim 512
#define NTG 400
#define Vdim 20000
#define NPAD 20224          // 79*256
#define TBdim (Tdim*Bdim)   // 3072
#define RC 128              // persistent recurrence CTAs

// ---------------- scratch (device globals; no allocation allowed) ----------
__device__ float g_t2[4*Bdim*Rdim];
__device__ float g_t5[4*Bdim*Rdim];
__device__ float g_gx[4L*TBdim*Hdim];
__device__ float g_gh[4*Bdim*Hdim];
__device__ float g_c[Bdim*Hdim];
__device__ unsigned g_sync;
// chunk-major swizzled fp16 layouts
__device__ __half g_x2C[8L*2*TBdim*64];         // xs pair
__device__ __half g_t1C[4L*8*2*TBdim*64];       // t1 pair per gate
__device__ __half g_hC[8L*2*Bdim*64];           // h pair
__device__ __half g_t6C[4L*8*2*Bdim*64];        // t6 pair per gate
__device__ __half g_WaC[4L*8*Rdim*64];          // Wa^T hi per gate
__device__ __half g_WcC[4L*8*Rdim*64];          // Wc^T hi per gate
__device__ __half g_hsC[8L*TBdim*64];           // hs hi (out GEMM A)
__device__ __half g_WoC[8L*NPAD*64];            // Wout^T hi (out GEMM B)

__device__ __forceinline__ uint32_t smem_u32(const void* p) {
    uint32_t a;
    asm("{ .reg .u64 t; cvta.to.shared.u64 t, %1; cvt.u32.u64 %0, t; }" : "=r"(a) : "l"(p));
    return a;
}

__device__ __forceinline__ void ldm_x4(uint32_t* r, uint32_t addr)
{
    asm volatile("ldmatrix.sync.aligned.m8n8.x4.shared.b16 {%0,%1,%2,%3}, [%4];"
        : "=r"(r[0]), "=r"(r[1]), "=r"(r[2]), "=r"(r[3]) : "r"(addr));
}

__device__ __forceinline__ void mma16816(float* c, const uint32_t* a, const uint32_t* b)
{
    asm volatile("mma.sync.aligned.m16n8k16.row.col.f32.f16.f16.f32 "
        "{%0,%1,%2,%3}, {%4,%5,%6,%7}, {%8,%9}, {%0,%1,%2,%3};"
        : "+f"(c[0]), "+f"(c[1]), "+f"(c[2]), "+f"(c[3])
        : "r"(a[0]), "r"(a[1]), "r"(a[2]), "r"(a[3]), "r"(b[0]), "r"(b[1]));
}

#define MBARRIER_INIT(mbar, cnt) \
    asm volatile("mbarrier.init.shared.b64 [%0], %1;" :: "r"((uint32_t)(mbar)), "r"((uint32_t)(cnt)) : "memory")
#define MBARRIER_ARRIVE(mbar) \
    asm volatile("mbarrier.arrive.shared.b64 _, [%0];" :: "r"((uint32_t)(mbar)) : "memory")
#define MBARRIER_WAIT_PARITY(mbar, par) do { \
    uint32_t _m = (uint32_t)(mbar), _p = (uint32_t)(par), _d; \
    asm volatile("{\n\t.reg .pred p;\n\t" \
        "mbarrier.try_wait.parity.acquire.cta.shared::cta.b64 p, [%1], %2;\n\t" \
        "selp.b32 %0, 1, 0, p;\n\t}" : "=r"(_d) : "r"(_m), "r"(_p) : "memory"); \
    if (!_d) { \
        asm volatile("{\n\t.reg .pred P1;\n\t" \
            "WL_%=:\n\t" \
            "mbarrier.try_wait.parity.acquire.cta.shared::cta.b64 P1, [%0], %1, 0x989680;\n\t" \
            "@P1 bra.uni WD_%=;\n\t" \
            "bra.uni WL_%=;\n\t" \
            "WD_%=:\n\t}" :: "r"(_m), "r"(_p) : "memory"); \
    } \
} while (0)
#define BULK_CP(dst, src, bytes, bar) \
    asm volatile("cp.async.bulk.shared::cluster.global.mbarrier::complete_tx::bytes " \
        "[%0], [%1], %2, [%3];" :: "r"(dst), "l"(src), "r"((uint32_t)(bytes)), "r"(bar) : "memory")
#define BAR_EXPECT(bar, bytes) \
    asm volatile("mbarrier.arrive.expect_tx.shared.b64 _, [%0], %1;" \
        :: "r"(bar), "r"((uint32_t)(bytes)) : "memory")

// ================= out GEMM: bulk-TMA + free-flow pipeline ==================
// barriers: full[s] = mb + s*8 ; empty[s] = mb + 24 + s*8
#define TO_STAGE 49152
#define TO_SMEM  (3*TO_STAGE + 64)

__device__ __forceinline__ void out_issue(uint32_t sb, uint32_t mb, int k,
                                          const __half* Ac, const __half* Bc,
                                          int mtile, int ntile)
{
    int slot = k % 3;
    uint32_t dst = sb + slot*TO_STAGE;
    uint32_t bar = mb + slot*8;
    BAR_EXPECT(bar, 49152u);
    BULK_CP(dst, Ac + ((long)k*TBdim + mtile*128)*64, 16384u, bar);
    BULK_CP(dst + 16384, Bc + ((long)k*NPAD + ntile*256)*64, 32768u, bar);
}

__global__ void __launch_bounds__(512, 1) out_gemm_tma(
    const __half* __restrict__ Ac, const __half* __restrict__ Bc,
    const float* __restrict__ bout, float* __restrict__ out)
{
    extern __shared__ char smem[];
    const uint32_t sb = smem_u32(smem);
    const uint32_t mb = sb + 3*TO_STAGE;
    const int tid = threadIdx.x, wid = tid >> 5, lane = tid & 31;
    const int wm = wid & 1, wn = wid >> 1;     // 2 x 8 warps, tile 64x32
    const int mtile = blockIdx.x, ntile = blockIdx.y;

    if (tid == 0) {
#pragma unroll
        for (int s = 0; s < 3; s++) {
            MBARRIER_INIT(mb + s*8, 1);
            MBARRIER_INIT(mb + 24 + s*8, 512);
        }
    }
    __syncthreads();
    if (tid == 0) {
        out_issue(sb, mb, 0, Ac, Bc, mtile, ntile);
        out_issue(sb, mb, 1, Ac, Bc, mtile, ntile);
        out_issue(sb, mb, 2, Ac, Bc, mtile, ntile);
    }

    float acc[4][4][4];
#pragma unroll
    for (int i = 0; i < 4; i++)
#pragma unroll
        for (int j = 0; j < 4; j++)
#pragma unroll
            for (int q = 0; q < 4; q++) acc[i][j][q] = 0.f;

    for (int k = 0; k < 8; k++) {
        int slot = k % 3;
        MBARRIER_WAIT_PARITY(mb + slot*8, (k/3) & 1);

        uint32_t sA = sb + slot*TO_STAGE;
        uint32_t sB = sA + 16384;
#pragma unroll
        for (int ks = 0; ks < 4; ks++) {
            uint32_t b[4][2];
#pragma unroll
            for (int np = 0; np < 2; np++) {
                uint32_t n = wn*32 + np*16 + (lane & 7) + ((lane >> 4) & 1)*8;
                uint32_t q = ks*2 + ((lane >> 3) & 1);
                uint32_t r[4];
                ldm_x4(r, sB + n*128 + (q ^ (n & 7))*16);
                b[np*2][0] = r[0];   b[np*2][1] = r[1];
                b[np*2+1][0] = r[2]; b[np*2+1][1] = r[3];
            }
            uint32_t a[4][4];
#pragma unroll
            for (int mi = 0; mi < 4; mi++) {
                uint32_t m = wm*64 + mi*16 + (lane & 15);
                uint32_t q = ks*2 + (lane >> 4);
                ldm_x4(a[mi], sA + m*128 + (q ^ (m & 7))*16);
            }
#pragma unroll
            for (int mi = 0; mi < 4; mi++)
#pragma unroll
                for (int ni = 0; ni < 4; ni++)
                    mma16816(acc[mi][ni], a[mi], b[ni]);
        }
        MBARRIER_ARRIVE(mb + 24 + slot*8);
        if (tid == 0 && k < 5) {
            MBARRIER_WAIT_PARITY(mb + 24 + slot*8, (k/3) & 1);
            out_issue(sb, mb, k + 3, Ac, Bc, mtile, ntile);
        }
    }

#pragma unroll
    for (int mi = 0; mi < 4; mi++) {
#pragma unroll
        for (int ni = 0; ni < 4; ni++) {
            int n = ntile*256 + wn*32 + ni*8 + (lane & 3)*2;
            if (n < Vdim) {
                float2 bv = *(const float2*)(bout + n);
                int gr0 = mtile*128 + wm*64 + mi*16 + (lane >> 2);
                int gr1 = gr0 + 8;
                long o0 = ((long)(gr0 & 127)*Tdim + (gr0 >> 7))*Vdim + n;
                long o1 = ((long)(gr1 & 127)*Tdim + (gr1 >> 7))*Vdim + n;
                *(float2*)(out + o0) = make_float2(acc[mi][ni][0] + bv.x, acc[mi][ni][1] + bv.y);
                *(float2*)(out + o1) = make_float2(acc[mi][ni][2] + bv.x, acc[mi][ni][3] + bv.y);
            }
        }
    }
}

// ================= prep GEMM: bulk-TMA free-flow, fp16-pair A ===============
#define PT_STAGE 65536
#define PT_SMEM  (3*PT_STAGE + 64)

__device__ __forceinline__ void prep_issue(uint32_t sb, uint32_t mb, int k,
    const __half* Ac, const __half* Bc, int mtile, int ntile)
{
    int slot = k % 3;
    uint32_t dst = sb + slot*PT_STAGE;
    uint32_t bar = mb + slot*8;
    BAR_EXPECT(bar, 65536u);
    BULK_CP(dst,         Ac + ((long)(k*2+0)*TBdim + mtile*128)*64, 16384u, bar);
    BULK_CP(dst + 16384, Ac + ((long)(k*2+1)*TBdim + mtile*128)*64, 16384u, bar);
    BULK_CP(dst + 32768, Bc + ((long)k*512 + ntile*256)*64, 32768u, bar);
}

template<int MODE>
__global__ void __launch_bounds__(512, 1) prep_tma(
    const __half* __restrict__ A, const __half* __restrict__ B,
    float* __restrict__ Cf, __half* __restrict__ Cb,
    const float* __restrict__ X, long aS)
{
    extern __shared__ char smem[];
    const uint32_t sb = smem_u32(smem);
    const uint32_t mb = sb + 3*PT_STAGE;
    const int tid = threadIdx.x, wid = tid >> 5, lane = tid & 31;
    const int wm = wid & 1, wn = wid >> 1;
    const int mtile = blockIdx.x, ntile = blockIdx.y, z = blockIdx.z;

    const __half* Az = A + (long)z*aS;
    const __half* Bz = B + (long)z*8*512*64;

    if (tid == 0) {
#pragma unroll
        for (int s = 0; s < 3; s++) {
            MBARRIER_INIT(mb + s*8, 1);
            MBARRIER_INIT(mb + 24 + s*8, 512);
        }
    }
    __syncthreads();
    if (tid == 0) {
        prep_issue(sb, mb, 0, Az, Bz, mtile, ntile);
        prep_issue(sb, mb, 1, Az, Bz, mtile, ntile);
        prep_issue(sb, mb, 2, Az, Bz, mtile, ntile);
    }

    float acc[4][4][4];
#pragma unroll
    for (int i = 0; i < 4; i++)
#pragma unroll
        for (int j = 0; j < 4; j++)
#pragma unroll
            for (int q = 0; q < 4; q++) acc[i][j][q] = 0.f;

    for (int k = 0; k < 8; k++) {
        int slot = k % 3;
        MBARRIER_WAIT_PARITY(mb + slot*8, (k/3) & 1);

        uint32_t base = sb + slot*PT_STAGE;
        uint32_t sB = base + 32768;
#pragma unroll
        for (int ks = 0; ks < 4; ks++) {
            uint32_t b[4][2];
#pragma unroll
            for (int np = 0; np < 2; np++) {
                uint32_t n = wn*32 + np*16 + (lane & 7) + ((lane >> 4) & 1)*8;
                uint32_t q = ks*2 + ((lane >> 3) & 1);
                uint32_t r[4];
                ldm_x4(r, sB + n*128 + (q ^ (n & 7))*16);
                b[np*2][0] = r[0];   b[np*2][1] = r[1];
                b[np*2+1][0] = r[2]; b[np*2+1][1] = r[3];
            }
#pragma unroll
            for (int h = 0; h < 2; h++) {
                uint32_t ab = base + h*16384;
                uint32_t a[4][4];
#pragma unroll
                for (int mi = 0; mi < 4; mi++) {
                    uint32_t m = wm*64 + mi*16 + (lane & 15);
                    uint32_t q = ks*2 + (lane >> 4);
                    ldm_x4(a[mi], ab + m*128 + (q ^ (m & 7))*16);
                }
#pragma unroll
                for (int mi = 0; mi < 4; mi++)
#pragma unroll
                    for (int ni = 0; ni < 4; ni++)
                        mma16816(acc[mi][ni], a[mi], b[ni]);
            }
        }
        MBARRIER_ARRIVE(mb + 24 + slot*8);
        if (tid == 0 && k < 5) {
            MBARRIER_WAIT_PARITY(mb + 24 + slot*8, (k/3) & 1);
            prep_issue(sb, mb, k + 3, Az, Bz, mtile, ntile);
        }
    }

#pragma unroll
    for (int mi = 0; mi < 4; mi++) {
#pragma unroll
        for (int ni = 0; ni < 4; ni++) {
            int n = ntile*256 + wn*32 + ni*8 + (lane & 3)*2;
            int gr0 = mtile*128 + wm*64 + mi*16 + (lane >> 2);
            int gr1 = gr0 + 8;
            if (MODE == 1) {
                const float* Xg = X + (long)z*Bdim*Rdim;
                __half* Cz = Cb + (long)z*(8L*2*TBdim*64);
                int chunk = n >> 6, q = (n & 63) >> 3;
                float v00 = acc[mi][ni][0]*Xg[(gr0 & 127)*512 + n];
                float v01 = acc[mi][ni][1]*Xg[(gr0 & 127)*512 + n + 1];
                float v10 = acc[mi][ni][2]*Xg[(gr1 & 127)*512 + n];
                float v11 = acc[mi][ni][3]*Xg[(gr1 & 127)*512 + n + 1];
                __half2 h0 = __floats2half2_rn(v00, v01);
                __half2 l0 = __floats2half2_rn(v00 - __half2float(__low2half(h0)),
                                               v01 - __half2float(__high2half(h0)));
                __half2 h1 = __floats2half2_rn(v10, v11);
                __half2 l1 = __floats2half2_rn(v10 - __half2float(__low2half(h1)),
                                               v11 - __half2float(__high2half(h1)));
                long b0 = ((long)(chunk*2)*TBdim + gr0)*64 + (q ^ (gr0 & 7))*8 + (n & 7);
                long b1 = ((long)(chunk*2)*TBdim + gr1)*64 + (q ^ (gr1 & 7))*8 + (n & 7);
                *(__half2*)(Cz + b0) = h0;
                *(__half2*)(Cz + b0 + (long)TBdim*64) = l0;
                *(__half2*)(Cz + b1) = h1;
                *(__half2*)(Cz + b1 + (long)TBdim*64) = l1;
            } else {
                const float* Xg = X + z*512;
                float* Cz = Cf + (long)z*TBdim*512;
                float2 bv = make_float2(Xg[n], Xg[n + 1]);
                *(float2*)(Cz + (long)gr0*512 + n) = make_float2(acc[mi][ni][0] + bv.x, acc[mi][ni][1] + bv.y);
                *(float2*)(Cz + (long)gr1*512 + n) = make_float2(acc[mi][ni][2] + bv.x, acc[mi][ni][3] + bv.y);
            }
        }
    }
}

// ---------------- conversions ------------------------------------------------
__global__ void __launch_bounds__(256) k_convWC(const float* __restrict__ W,
                                                __half* __restrict__ Bp)
{
    __shared__ float t[64][33];
    const int tid = threadIdx.x;
    const int g = blockIdx.z;
    const int n0 = blockIdx.x*32;
    const int k0 = blockIdx.y*64;
    for (int e = tid; e < 64*32; e += 256) {
        int kk = e >> 5, nn = e & 31;
        t[kk][nn] = W[((long)g*512 + k0 + kk)*512 + n0 + nn];
    }
    __syncthreads();
    int nn = tid >> 3, q = tid & 7;
    int n = n0 + nn;
    __half h[8];
#pragma unroll
    for (int i = 0; i < 8; i++) h[i] = __float2half_rn(t[q*8 + i][nn]);
    int qs = q ^ (n & 7);
    *(uint4*)(Bp + (((long)g*8 + blockIdx.y)*512 + n)*64 + qs*8) = *(uint4*)h;
}

__global__ void __launch_bounds__(256) k_convB(const float* __restrict__ Wout)
{
    __shared__ float t[64][33];
    const int tid = threadIdx.x;
    const int n0 = blockIdx.x*32;
    for (int e = tid; e < 64*32; e += 256) {
        int kk = e >> 5, nn = e & 31;
        int n = n0 + nn;
        t[kk][nn] = (n < Vdim) ? Wout[(long)(blockIdx.y*64 + kk)*Vdim + n] : 0.f;
    }
    __syncthreads();
    int nn = tid >> 3, q = tid & 7;
    int n = n0 + nn;
    __half h[8];
#pragma unroll
    for (int i = 0; i < 8; i++) h[i] = __float2half_rn(t[q*8 + i][nn]);
    int qs = q ^ (n & 7);
    *(uint4*)(g_WoC + ((long)blockIdx.y*NPAD + n)*64 + qs*8) = *(uint4*)h;
}

// ---------------- embedding gather -> x2C chunk-major pair -------------------
__global__ void k_gather(const int* __restrict__ caps, const float* __restrict__ emb)
{
    const int b = blockIdx.x, t = blockIdx.y;
    float4 v = make_float4(0.f, 0.f, 0.f, 0.f);
    if (t > 0) {
        int tok = caps[b*Tdim + (t-1)];
        v = ((const float4*)(emb + (long)tok*Edim))[threadIdx.x];
    }
    __half hv[4], lv[4];
    float f[4] = {v.x, v.y, v.z, v.w};
#pragma unroll
    for (int i = 0; i < 4; i++) {
        hv[i] = __float2half_rn(f[i]);
        lv[i] = __float2half_rn(f[i] - __half2float(hv[i]));
    }
    int col = threadIdx.x*4;
    int row = t*Bdim + b;
    int chunk = col >> 6, q = (col & 63) >> 3;
    long bh = ((long)(chunk*2)*TBdim + row)*64 + (q ^ (b & 7))*8 + (col & 7);
    *(uint2*)(g_x2C + bh) = *(uint2*)hv;
    *(uint2*)(g_x2C + bh + (long)TBdim*64) = *(uint2*)lv;
}

__global__ void k_init(const float* __restrict__ h0, const float* __restrict__ c0)
{
    int i = blockIdx.x*blockDim.x + threadIdx.x;
    float v = h0[i];
    __half hi = __float2half_rn(v);
    __half lo = __float2half_rn(v - __half2float(hi));
    int b = i >> 9, col = i & 511;
    int chunk = col >> 6, q = (col & 63) >> 3;
    long bh = ((long)(chunk*2)*Bdim + b)*64 + (q ^ (b & 7))*8 + (col & 7);
    g_hC[bh] = hi;
    g_hC[bh + Bdim*64] = lo;
    g_c[i] = c0[i];
    if (i == 0) g_sync = 0;
}

// ---------------- fp32 tiled SGEMM (t2 and t5 in one launch) -----------------
template<int BM,int BN,int BK,int TM,int TN>
__global__ void gemm_k(const float* __restrict__ A,
                       const float* __restrict__ Bm, const float* __restrict__ Bm2,
                       float* __restrict__ C, float* __restrict__ C2,
                       int M, int N, int K, long sB, long sC)
{
    constexpr int THREADS = (BM/TM)*(BN/TN);
    __shared__ float As[BK][BM];
    __shared__ float Bs[BK][BN];
    const int z = blockIdx.z;
    const int g = z & 3;
    const float* Bg = (z < 4 ? Bm : Bm2) + (long)g*sB;
    float* Cg = (z < 4 ? C : C2) + (long)g*sC;
    const int m0 = blockIdx.y*BM;
    const int n0 = blockIdx.x*BN;
    const int tid = threadIdx.x;
    constexpr int AK4 = BK/4;
    const int aRow = tid / AK4, aCol = (tid % AK4)*4;
    constexpr int AROWS = THREADS/AK4;
    constexpr int BN4 = BN/4;
    const int bRow = tid / BN4, bCol = (tid % BN4)*4;
    constexpr int BROWS = THREADS/BN4;
    const int tr = (tid/(BN/TN))*TM, tc = (tid%(BN/TN))*TN;

    float acc[TM][TN];
#pragma unroll
    for (int i = 0; i < TM; i++)
#pragma unroll
        for (int j = 0; j < TN; j++) acc[i][j] = 0.f;

    for (int k0 = 0; k0 < K; k0 += BK) {
#pragma unroll
        for (int i = 0; i < BM; i += AROWS) {
            float4 v = *(const float4*)(A + (long)(m0 + aRow + i)*K + (k0 + aCol));
            As[aCol+0][aRow+i] = v.x; As[aCol+1][aRow+i] = v.y;
            As[aCol+2][aRow+i] = v.z; As[aCol+3][aRow+i] = v.w;
        }
#pragma unroll
        for (int i = 0; i < BK; i += BROWS) {
            float4 v = *(const float4*)(Bg + (long)(k0 + bRow + i)*N + (n0 + bCol));
            *(float4*)&Bs[bRow+i][bCol] = v;
        }
        __syncthreads();
#pragma unroll
        for (int kk = 0; kk < BK; kk++) {
            float rm[TM], rn[TN];
#pragma unroll
            for (int i = 0; i < TM; i++) rm[i] = As[kk][tr+i];
#pragma unroll
            for (int j = 0; j < TN; j++) rn[j] = Bs[kk][tc+j];
#pragma unroll
            for (int i = 0; i < TM; i++)
#pragma unroll
                for (int j = 0; j < TN; j++)
                    acc[i][j] = fmaf(rm[i], rn[j], acc[i][j]);
        }
        __syncthreads();
    }
#pragma unroll
    for (int i = 0; i < TM; i++)
#pragma unroll
        for (int j = 0; j < TN; j++)
            Cg[(long)(m0 + tr + i)*N + n0 + tc + j] = acc[i][j];
}

// ---------------- persistent tensor-core recurrence (free-flow TMA) ----------
#define RW_STRIDE 1040
#define RW_SLAB   (16*RW_STRIDE)
#define RA_BASE   (4*RW_SLAB)
#define RA_ST     32768
#define REC_SMEM  (RA_BASE + 3*RA_ST + 64)

__device__ __forceinline__ void gbar(unsigned goal)
{
    __syncthreads();
    __threadfence();
    if (threadIdx.x == 0) {
        atomicAdd(&g_sync, 1u);
        unsigned v;
        do {
            asm volatile("ld.global.acquire.gpu.u32 %0, [%1];" : "=r"(v) : "l"(&g_sync));
        } while (v < goal);
    }
    __syncthreads();
}

__device__ __forceinline__ float sig_f(float x)  { return 1.f/(1.f + __expf(-x)); }
__device__ __forceinline__ float tanh_f(float x) { return 2.f/(1.f + __expf(-2.f*x)) - 1.f; }

__device__ __forceinline__ void rec_issue(uint32_t sbase, uint32_t mb, int k,
                                          const __half* Ac)
{
    int slot = k % 3;
    uint32_t dst = sbase + RA_BASE + slot*RA_ST;
    uint32_t bar = mb + slot*8;
    BAR_EXPECT(bar, 32768u);
    BULK_CP(dst,         Ac + (long)(k*2+0)*Bdim*64, 16384u, bar);
    BULK_CP(dst + 16384, Ac + (long)(k*2+1)*Bdim*64, 16384u, bar);
}

// full[s] = mb + s*8 ; empty[s] = mb + 24 + s*8 (count 256)
__device__ __forceinline__ void rec_phase(uint32_t sbase, uint32_t wbase, uint32_t mb,
                                          const __half* __restrict__ Asrc,
                                          int tid, int wid, int lane,
                                          float acc[2][4],
                                          unsigned* ub, unsigned* ue, bool prime)
{
#pragma unroll
    for (int i = 0; i < 2; i++)
#pragma unroll
        for (int q = 0; q < 4; q++) acc[i][q] = 0.f;

    if (tid == 0) {
#pragma unroll
        for (int j = 0; j < 3; j++) {
            if (!prime) {
                MBARRIER_WAIT_PARITY(mb + 24 + j*8, ue[j] & 1);
                ue[j]++;
            }
            rec_issue(sbase, mb, j, Asrc);
        }
    }

    for (int k = 0; k < 8; k++) {
        int slot = k % 3;
        MBARRIER_WAIT_PARITY(mb + slot*8, ub[slot] & 1);
        ub[slot]++;

        uint32_t st = sbase + RA_BASE + slot*RA_ST;
#pragma unroll
        for (int ks = 0; ks < 4; ks++) {
            int krow = k*64 + ks*16 + ((lane >> 3) & 1)*8;
            uint32_t baddr = wbase + ((lane & 7) + ((lane >> 4) & 1)*8)*RW_STRIDE + krow*2;
            uint32_t rhi[4], rlo[4];
            ldm_x4(rhi, baddr);
            ldm_x4(rlo, baddr + RW_SLAB);
            uint32_t bhi[2][2] = {{rhi[0], rhi[1]}, {rhi[2], rhi[3]}};
            uint32_t blo[2][2] = {{rlo[0], rlo[1]}, {rlo[2], rlo[3]}};
            uint32_t m = wid*16 + (lane & 15);
            uint32_t q = ks*2 + (lane >> 4);
            uint32_t ahi[4], alo[4];
            ldm_x4(ahi, st + m*128 + (q ^ (m & 7))*16);
            ldm_x4(alo, st + 16384 + m*128 + (q ^ (m & 7))*16);
#pragma unroll
            for (int ni = 0; ni < 2; ni++) {
                mma16816(acc[ni], ahi, bhi[ni]);
                mma16816(acc[ni], ahi, blo[ni]);
                mma16816(acc[ni], alo, bhi[ni]);
            }
        }
        MBARRIER_ARRIVE(mb + 24 + slot*8);
        if (tid == 0 && k < 5) {
            MBARRIER_WAIT_PARITY(mb + 24 + slot*8, ue[slot] & 1);
            ue[slot]++;
            rec_issue(sbase, mb, k + 3, Asrc);
        }
    }
}

__global__ void __launch_bounds__(256, 1) rec_k(const float* __restrict__ Ua,
                                                const float* __restrict__ Uc)
{
    extern __shared__ char smem[];
    const uint32_t sbase = smem_u32(smem);
    const uint32_t mb = sbase + RA_BASE + 3*RA_ST;
    const int tid = threadIdx.x, wid = tid >> 5, lane = tid & 31;
    const int bx = blockIdx.x;
    const int gg = bx >> 5;
    const int c0 = (bx & 31)*16;

    {
        const float* UaG = Ua + (long)gg*512*512;
        const float* UcG = Uc + (long)gg*512*512;
        for (int e = tid; e < 512*16; e += 256) {
            int k = e >> 4, j = e & 15;
            float va = UaG[(long)k*512 + c0 + j];
            __half ha = __float2half_rn(va);
            __half la = __float2half_rn(va - __half2float(ha));
            *(__half*)(smem + j*RW_STRIDE + k*2) = ha;
            *(__half*)(smem + RW_SLAB + j*RW_STRIDE + k*2) = la;
            float vc = UcG[(long)k*512 + c0 + j];
            __half hc = __float2half_rn(vc);
            __half lc = __float2half_rn(vc - __half2float(hc));
            *(__half*)(smem + 2*RW_SLAB + j*RW_STRIDE + k*2) = hc;
            *(__half*)(smem + 3*RW_SLAB + j*RW_STRIDE + k*2) = lc;
        }
    }
    if (tid == 0) {
#pragma unroll
        for (int s = 0; s < 3; s++) {
            MBARRIER_INIT(mb + s*8, 1);
            MBARRIER_INIT(mb + 24 + s*8, 256);
        }
    }
    __syncthreads();

    unsigned goal = RC;
    unsigned ub[3] = {0u, 0u, 0u};
    unsigned ue[3] = {0u, 0u, 0u};
    bool prime = true;
    const long GS = (long)TBdim*Hdim;
    const long GH = (long)Bdim*Hdim;
    const __half* t6src = g_t6C + (long)gg*8*2*Bdim*64;

    const int ci = bx*512 + tid*2;
    float creg0 = g_c[ci], creg1 = g_c[ci + 1];

    for (int t = 0; t < Tdim; t++) {
        float acc[2][4];

        // phase A: t6[gg][:, c0..] = (h @ Ua[gg]) * t5 -> t6C pair
        rec_phase(sbase, sbase, mb, g_hC, tid, wid, lane, acc, ub, ue, prime);
        prime = false;
        {
            __half* Cz = g_t6C + (long)gg*8*2*Bdim*64;
            const float* t5g = g_t5 + (long)gg*GH;
#pragma unroll
            for (int ni = 0; ni < 2; ni++) {
                int col = c0 + ni*8 + (lane & 3)*2;
                int r0 = wid*16 + (lane >> 2), r1 = r0 + 8;
                int chunk = col >> 6, q = (col & 63) >> 3;
                float2 m0 = *(const float2*)(t5g + (long)r0*512 + col);
                float2 m1 = *(const float2*)(t5g + (long)r1*512 + col);
                float v00 = acc[ni][0]*m0.x, v01 = acc[ni][1]*m0.y;
                float v10 = acc[ni][2]*m1.x, v11 = acc[ni][3]*m1.y;
                __half2 h0 = __floats2half2_rn(v00, v01);
                __half2 l0 = __floats2half2_rn(v00 - __half2float(__low2half(h0)),
                                               v01 - __half2float(__high2half(h0)));
                __half2 h1 = __floats2half2_rn(v10, v11);
                __half2 l1 = __floats2half2_rn(v10 - __half2float(__low2half(h1)),
                                               v11 - __half2float(__high2half(h1)));
                long b0 = ((long)(chunk*2)*Bdim + r0)*64 + (q ^ (r0 & 7))*8 + (col & 7);
                long b1 = ((long)(chunk*2)*Bdim + r1)*64 + (q ^ (r1 & 7))*8 + (col & 7);
                *(__half2*)(Cz + b0) = h0;
                *(__half2*)(Cz + b0 + Bdim*64) = l0;
                *(__half2*)(Cz + b1) = h1;
                *(__half2*)(Cz + b1 + Bdim*64) = l1;
            }
        }
        gbar(goal); goal += RC;

        // phase B: gh[gg][:, c0..] = t6[gg] @ Uc[gg]
        rec_phase(sbase, sbase + 2*RW_SLAB, mb, t6src, tid, wid, lane, acc, ub, ue, false);
        {
            float* Cz = g_gh + (long)gg*GH;
#pragma unroll
            for (int ni = 0; ni < 2; ni++) {
                int col = c0 + ni*8 + (lane & 3)*2;
                int r0 = wid*16 + (lane >> 2), r1 = r0 + 8;
                *(float2*)(Cz + (long)r0*512 + col) = make_float2(acc[ni][0], acc[ni][1]);
                *(float2*)(Cz + (long)r1*512 + col) = make_float2(acc[ni][2], acc[ni][3]);
            }
        }
        gbar(goal); goal += RC;

        // phase C: LSTM pointwise on batch row bx (c in registers)
        {
            const long so = (long)t*Bdim*Hdim;
            int i0 = bx*512 + tid*2;
            float hv[2];
#pragma unroll
            for (int u = 0; u < 2; u++) {
                int i = i0 + u;
                float pi = g_gx[0*GS + so + i] + g_gh[0*GH + i];
                float pf = g_gx[1*GS + so + i] + g_gh[1*GH + i];
                float po = g_gx[2*GS + so + i] + g_gh[2*GH + i];
                float pc = g_gx[3*GS + so + i] + g_gh[3*GH + i];
                float ig = sig_f(pi), fg = sig_f(pf), og = sig_f(po);
                float ct = tanh_f(pc);
                float cprev = u == 0 ? creg0 : creg1;
                float cn = fg*cprev + ig*ct;
                float hn = og*tanh_f(cn);
                if (u == 0) creg0 = cn; else creg1 = cn;
                hv[u] = hn;
            }
            __half2 hh = __floats2half2_rn(hv[0], hv[1]);
            __half2 ll = __floats2half2_rn(hv[0] - __half2float(__low2half(hh)),
                                           hv[1] - __half2float(__high2half(hh)));
            int kcol = tid*2;
            int chunk = kcol >> 6, q = (kcol & 63) >> 3;
            long bh = ((long)(chunk*2)*Bdim + bx)*64 + (q ^ (bx & 7))*8 + (kcol & 7);
            *(__half2*)(g_hC + bh) = hh;
            *(__half2*)(g_hC + bh + Bdim*64) = ll;
            int row = t*Bdim + bx;
            *(__half2*)(g_hsC + ((long)chunk*TBdim + row)*64
                        + (q ^ (row & 7))*8 + (kcol & 7)) = hh;
        }
        gbar(goal); goal += RC;
    }
}

// ---------------- launch ------------------------------------------------------
extern "C" void kernel_launch(void* const* d_in, const int* in_sizes, int n_in,
                              void* d_out, int out_size)
{
    const int*   caps = (const int*)  d_in[0];
    const float* tags = (const float*)d_in[1];
    const float* h0   = (const float*)d_in[2];
    const float* c0   = (const float*)d_in[3];
    const float* Wa   = (const float*)d_in[4];
    const float* Wb   = (const float*)d_in[5];
    const float* Wc   = (const float*)d_in[6];
    const float* Ua   = (const float*)d_in[7];
    const float* Ub   = (const float*)d_in[8];
    const float* Uc   = (const float*)d_in[9];
    const float* bi   = (const float*)d_in[10];
    const float* emb  = (const float*)d_in[11];
    const float* Wout = (const float*)d_in[12];
    const float* bout = (const float*)d_in[13];
    float* out = (float*)d_out;

    float *p_t2, *p_t5, *p_gx;
    __half *p_x2C, *p_t1C, *p_WaC, *p_WcC, *p_hsC, *p_WoC;
    cudaGetSymbolAddress((void**)&p_t2,  g_t2);
    cudaGetSymbolAddress((void**)&p_t5,  g_t5);
    cudaGetSymbolAddress((void**)&p_gx,  g_gx);
    cudaGetSymbolAddress((void**)&p_x2C, g_x2C);
    cudaGetSymbolAddress((void**)&p_t1C, g_t1C);
    cudaGetSymbolAddress((void**)&p_WaC, g_WaC);
    cudaGetSymbolAddress((void**)&p_WcC, g_WcC);
    cudaGetSymbolAddress((void**)&p_hsC, g_hsC);
    cudaGetSymbolAddress((void**)&p_WoC, g_WoC);

    cudaFuncSetAttribute((const void*)prep_tma<1>, cudaFuncAttributeMaxDynamicSharedMemorySize, PT_SMEM);
    cudaFuncSetAttribute((const void*)prep_tma<2>, cudaFuncAttributeMaxDynamicSharedMemorySize, PT_SMEM);
    cudaFuncSetAttribute((const void*)rec_k, cudaFuncAttributeMaxDynamicSharedMemorySize, REC_SMEM);
    cudaFuncSetAttribute((const void*)out_gemm_tma, cudaFuncAttributeMaxDynamicSharedMemorySize, TO_SMEM);

    k_gather<<<dim3(Bdim, Tdim), 128>>>(caps, emb);                          // 1
    k_convWC<<<dim3(16, 8, 4), 256>>>(Wa, p_WaC);                             // 2
    gemm_k<32,64,16,4,4><<<dim3(8,4,8), 128>>>(tags, Wb, Ub, p_t2, p_t5,      // 3
        Bdim, Rdim, NTG, (long)NTG*Rdim, (long)Bdim*Rdim);
    prep_tma<1><<<dim3(24,2,4), 512, PT_SMEM>>>(p_x2C, p_WaC, nullptr,        // 4 (profiled)
        p_t1C, p_t2, 0L);
    k_convWC<<<dim3(16, 8, 4), 256>>>(Wc, p_WcC);                             // 5
    k_init<<<256, 256>>>(h0, c0);                                             // 6
    prep_tma<2><<<dim3(24,2,4), 512, PT_SMEM>>>(p_t1C, p_WcC, p_gx,           // 7
        nullptr, bi, 8L*2*TBdim*64);
    k_convB<<<dim3(NPAD/32, 8), 256>>>(Wout);                                 // 8
    rec_k<<<RC, 256, REC_SMEM>>>(Ua, Uc);                                     // 9
    out_gemm_tma<<<dim3(TBdim/128, NPAD/256), 512, TO_SMEM>>>(                // 10
        p_hsC, p_WoC, bout, out);
}

// round 12
// speedup vs baseline: 5.5176x; 1.1279x over previous
#include <cuda_runtime.h>
#include <cuda_fp16.h>
#include <math.h>
#include <cstdint>

#define Bdim 128
#define Tdim 24
#define Edim 512
#define Hdim 512
#define Rdim 512
#define NTG 400
#define Vdim 20000
#define NPAD 20224          // 79*256
#define TBdim (Tdim*Bdim)   // 3072
#define RC 128              // persistent recurrence CTAs

// ---------------- scratch (device globals; no allocation allowed) ----------
__device__ float g_t2[4*Bdim*Rdim];
__device__ float g_t5[4*Bdim*Rdim];
__device__ float g_gx[4L*TBdim*Hdim];
__device__ float g_gh[4*Bdim*Hdim];
__device__ float g_c[Bdim*Hdim];
__device__ unsigned g_sync;
// chunk-major swizzled fp16 layouts (hi-only): [.. chunk ..][rows][64]
__device__ __half g_x2C[8L*TBdim*64];           // xs hi
__device__ __half g_t1C[4L*8*TBdim*64];         // t1 hi per gate
__device__ __half g_hC[8L*Bdim*64];             // h hi
__device__ __half g_t6C[4L*8*Bdim*64];          // t6 hi per gate
__device__ __half g_WaC[4L*8*Rdim*64];          // Wa^T hi per gate
__device__ __half g_WcC[4L*8*Rdim*64];          // Wc^T hi per gate
__device__ __half g_hsC[8L*TBdim*64];           // hs hi (out GEMM A)
__device__ __half g_WoC[8L*NPAD*64];            // Wout^T hi (out GEMM B)

__device__ __forceinline__ uint32_t smem_u32(const void* p) {
    uint32_t a;
    asm("{ .reg .u64 t; cvta.to.shared.u64 t, %1; cvt.u32.u64 %0, t; }" : "=r"(a) : "l"(p));
    return a;
}

__device__ __forceinline__ void ldm_x4(uint32_t* r, uint32_t addr)
{
    asm volatile("ldmatrix.sync.aligned.m8n8.x4.shared.b16 {%0,%1,%2,%3}, [%4];"
        : "=r"(r[0]), "=r"(r[1]), "=r"(r[2]), "=r"(r[3]) : "r"(addr));
}

__device__ __forceinline__ void mma16816(float* c, const uint32_t* a, const uint32_t* b)
{
    asm volatile("mma.sync.aligned.m16n8k16.row.col.f32.f16.f16.f32 "
        "{%0,%1,%2,%3}, {%4,%5,%6,%7}, {%8,%9}, {%0,%1,%2,%3};"
        : "+f"(c[0]), "+f"(c[1]), "+f"(c[2]), "+f"(c[3])
        : "r"(a[0]), "r"(a[1]), "r"(a[2]), "r"(a[3]), "r"(b[0]), "r"(b[1]));
}

#define MBARRIER_INIT(mbar, cnt) \
    asm volatile("mbarrier.init.shared.b64 [%0], %1;" :: "r"((uint32_t)(mbar)), "r"((uint32_t)(cnt)) : "memory")
#define MBARRIER_ARRIVE(mbar) \
    asm volatile("mbarrier.arrive.shared.b64 _, [%0];" :: "r"((uint32_t)(mbar)) : "memory")
#define MBARRIER_WAIT_PARITY(mbar, par) do { \
    uint32_t _m = (uint32_t)(mbar), _p = (uint32_t)(par), _d; \
    asm volatile("{\n\t.reg .pred p;\n\t" \
        "mbarrier.try_wait.parity.acquire.cta.shared::cta.b64 p, [%1], %2;\n\t" \
        "selp.b32 %0, 1, 0, p;\n\t}" : "=r"(_d) : "r"(_m), "r"(_p) : "memory"); \
    if (!_d) { \
        asm volatile("{\n\t.reg .pred P1;\n\t" \
            "WL_%=:\n\t" \
            "mbarrier.try_wait.parity.acquire.cta.shared::cta.b64 P1, [%0], %1, 0x989680;\n\t" \
            "@P1 bra.uni WD_%=;\n\t" \
            "bra.uni WL_%=;\n\t" \
            "WD_%=:\n\t}" :: "r"(_m), "r"(_p) : "memory"); \
    } \
} while (0)
#define BULK_CP(dst, src, bytes, bar) \
    asm volatile("cp.async.bulk.shared::cluster.global.mbarrier::complete_tx::bytes " \
        "[%0], [%1], %2, [%3];" :: "r"(dst), "l"(src), "r"((uint32_t)(bytes)), "r"(bar) : "memory")
#define BAR_EXPECT(bar, bytes) \
    asm volatile("mbarrier.arrive.expect_tx.shared.b64 _, [%0], %1;" \
        :: "r"(bar), "r"((uint32_t)(bytes)) : "memory")

// ================= unified hi-only MMA GEMM (out / t1 / gx) =================
// A: [chunk][TBdim][64] hi (+z*aS) ; B: [chunk][bRows][64] hi (+z*bS)
// MODE 0: out logits (bias + row remap, n<Vdim guard), bRows=NPAD
// MODE 1: t1C hi = acc * t2[z]
// MODE 2: gx fp32 = acc + bias[z]
#define MM_STAGE 49152
#define MM_SMEM  (3*MM_STAGE + 64)

__device__ __forceinline__ void mm_issue(uint32_t sb, uint32_t mb, int k,
                                         const __half* Ac, const __half* Bc,
                                         int mtile, int ntile, int bRows)
{
    int slot = k % 3;
    uint32_t dst = sb + slot*MM_STAGE;
    uint32_t bar = mb + slot*8;
    BAR_EXPECT(bar, 49152u);
    BULK_CP(dst, Ac + ((long)k*TBdim + mtile*128)*64, 16384u, bar);
    BULK_CP(dst + 16384, Bc + ((long)k*bRows + ntile*256)*64, 32768u, bar);
}

template<int MODE>
__global__ void __launch_bounds__(512, 1) mm_k(
    const __half* __restrict__ A, const __half* __restrict__ B,
    float* __restrict__ Cf, __half* __restrict__ Cb,
    const float* __restrict__ X, long aS, long bS, int bRows)
{
    extern __shared__ char smem[];
    const uint32_t sb = smem_u32(smem);
    const uint32_t mb = sb + 3*MM_STAGE;
    const int tid = threadIdx.x, wid = tid >> 5, lane = tid & 31;
    const int wm = wid & 1, wn = wid >> 1;     // 2 x 8 warps, tile 64x32
    const int mtile = blockIdx.x, ntile = blockIdx.y, z = blockIdx.z;

    const __half* Az = A + (long)z*aS;
    const __half* Bz = B + (long)z*bS;

    if (tid == 0) {
#pragma unroll
        for (int s = 0; s < 3; s++) {
            MBARRIER_INIT(mb + s*8, 1);
            MBARRIER_INIT(mb + 24 + s*8, 512);
        }
    }
    __syncthreads();
    if (tid == 0) {
        mm_issue(sb, mb, 0, Az, Bz, mtile, ntile, bRows);
        mm_issue(sb, mb, 1, Az, Bz, mtile, ntile, bRows);
        mm_issue(sb, mb, 2, Az, Bz, mtile, ntile, bRows);
    }

    float acc[4][4][4];
#pragma unroll
    for (int i = 0; i < 4; i++)
#pragma unroll
        for (int j = 0; j < 4; j++)
#pragma unroll
            for (int q = 0; q < 4; q++) acc[i][j][q] = 0.f;

    for (int k = 0; k < 8; k++) {
        int slot = k % 3;
        MBARRIER_WAIT_PARITY(mb + slot*8, (k/3) & 1);

        uint32_t sA = sb + slot*MM_STAGE;
        uint32_t sB = sA + 16384;
#pragma unroll
        for (int ks = 0; ks < 4; ks++) {
            uint32_t b[4][2];
#pragma unroll
            for (int np = 0; np < 2; np++) {
                uint32_t n = wn*32 + np*16 + (lane & 7) + ((lane >> 4) & 1)*8;
                uint32_t q = ks*2 + ((lane >> 3) & 1);
                uint32_t r[4];
                ldm_x4(r, sB + n*128 + (q ^ (n & 7))*16);
                b[np*2][0] = r[0];   b[np*2][1] = r[1];
                b[np*2+1][0] = r[2]; b[np*2+1][1] = r[3];
            }
            uint32_t a[4][4];
#pragma unroll
            for (int mi = 0; mi < 4; mi++) {
                uint32_t m = wm*64 + mi*16 + (lane & 15);
                uint32_t q = ks*2 + (lane >> 4);
                ldm_x4(a[mi], sA + m*128 + (q ^ (m & 7))*16);
            }
#pragma unroll
            for (int mi = 0; mi < 4; mi++)
#pragma unroll
                for (int ni = 0; ni < 4; ni++)
                    mma16816(acc[mi][ni], a[mi], b[ni]);
        }
        MBARRIER_ARRIVE(mb + 24 + slot*8);
        if (tid == 0 && k < 5) {
            MBARRIER_WAIT_PARITY(mb + 24 + slot*8, (k/3) & 1);
            mm_issue(sb, mb, k + 3, Az, Bz, mtile, ntile, bRows);
        }
    }

#pragma unroll
    for (int mi = 0; mi < 4; mi++) {
#pragma unroll
        for (int ni = 0; ni < 4; ni++) {
            int n = ntile*256 + wn*32 + ni*8 + (lane & 3)*2;
            int gr0 = mtile*128 + wm*64 + mi*16 + (lane >> 2);
            int gr1 = gr0 + 8;
            if (MODE == 0) {
                if (n < Vdim) {
                    float2 bv = *(const float2*)(X + n);
                    long o0 = ((long)(gr0 & 127)*Tdim + (gr0 >> 7))*Vdim + n;
                    long o1 = ((long)(gr1 & 127)*Tdim + (gr1 >> 7))*Vdim + n;
                    *(float2*)(Cf + o0) = make_float2(acc[mi][ni][0] + bv.x, acc[mi][ni][1] + bv.y);
                    *(float2*)(Cf + o1) = make_float2(acc[mi][ni][2] + bv.x, acc[mi][ni][3] + bv.y);
                }
            } else if (MODE == 1) {
                const float* Xg = X + (long)z*Bdim*Rdim;
                __half* Cz = Cb + (long)z*(8L*TBdim*64);
                int chunk = n >> 6, q = (n & 63) >> 3;
                __half2 h0 = __floats2half2_rn(acc[mi][ni][0]*Xg[(gr0 & 127)*512 + n],
                                               acc[mi][ni][1]*Xg[(gr0 & 127)*512 + n + 1]);
                __half2 h1 = __floats2half2_rn(acc[mi][ni][2]*Xg[(gr1 & 127)*512 + n],
                                               acc[mi][ni][3]*Xg[(gr1 & 127)*512 + n + 1]);
                *(__half2*)(Cz + ((long)chunk*TBdim + gr0)*64 + (q ^ (gr0 & 7))*8 + (n & 7)) = h0;
                *(__half2*)(Cz + ((long)chunk*TBdim + gr1)*64 + (q ^ (gr1 & 7))*8 + (n & 7)) = h1;
            } else {
                const float* Xg = X + z*512;
                float* Cz = Cf + (long)z*TBdim*512;
                float2 bv = make_float2(Xg[n], Xg[n + 1]);
                *(float2*)(Cz + (long)gr0*512 + n) = make_float2(acc[mi][ni][0] + bv.x, acc[mi][ni][1] + bv.y);
                *(float2*)(Cz + (long)gr1*512 + n) = make_float2(acc[mi][ni][2] + bv.x, acc[mi][ni][3] + bv.y);
            }
        }
    }
}

// ---------------- conversions ------------------------------------------------
__global__ void __launch_bounds__(256) k_convWC(const float* __restrict__ W,
                                                __half* __restrict__ Bp)
{
    __shared__ float t[64][33];
    const int tid = threadIdx.x;
    const int g = blockIdx.z;
    const int n0 = blockIdx.x*32;
    const int k0 = blockIdx.y*64;
    for (int e = tid; e < 64*32; e += 256) {
        int kk = e >> 5, nn = e & 31;
        t[kk][nn] = W[((long)g*512 + k0 + kk)*512 + n0 + nn];
    }
    __syncthreads();
    int nn = tid >> 3, q = tid & 7;
    int n = n0 + nn;
    __half h[8];
#pragma unroll
    for (int i = 0; i < 8; i++) h[i] = __float2half_rn(t[q*8 + i][nn]);
    int qs = q ^ (n & 7);
    *(uint4*)(Bp + (((long)g*8 + blockIdx.y)*512 + n)*64 + qs*8) = *(uint4*)h;
}

__global__ void __launch_bounds__(256) k_convB(const float* __restrict__ Wout)
{
    __shared__ float t[64][33];
    const int tid = threadIdx.x;
    const int n0 = blockIdx.x*32;
    for (int e = tid; e < 64*32; e += 256) {
        int kk = e >> 5, nn = e & 31;
        int n = n0 + nn;
        t[kk][nn] = (n < Vdim) ? Wout[(long)(blockIdx.y*64 + kk)*Vdim + n] : 0.f;
    }
    __syncthreads();
    int nn = tid >> 3, q = tid & 7;
    int n = n0 + nn;
    __half h[8];
#pragma unroll
    for (int i = 0; i < 8; i++) h[i] = __float2half_rn(t[q*8 + i][nn]);
    int qs = q ^ (n & 7);
    *(uint4*)(g_WoC + ((long)blockIdx.y*NPAD + n)*64 + qs*8) = *(uint4*)h;
}

// ---------------- embedding gather -> x2C hi-only ----------------------------
__global__ void k_gather(const int* __restrict__ caps, const float* __restrict__ emb)
{
    const int b = blockIdx.x, t = blockIdx.y;
    float4 v = make_float4(0.f, 0.f, 0.f, 0.f);
    if (t > 0) {
        int tok = caps[b*Tdim + (t-1)];
        v = ((const float4*)(emb + (long)tok*Edim))[threadIdx.x];
    }
    __half hv[4];
    hv[0] = __float2half_rn(v.x); hv[1] = __float2half_rn(v.y);
    hv[2] = __float2half_rn(v.z); hv[3] = __float2half_rn(v.w);
    int col = threadIdx.x*4;
    int row = t*Bdim + b;
    int chunk = col >> 6, q = (col & 63) >> 3;
    *(uint2*)(g_x2C + ((long)chunk*TBdim + row)*64 + (q ^ (row & 7))*8 + (col & 7)) = *(uint2*)hv;
}

__global__ void k_init(const float* __restrict__ h0, const float* __restrict__ c0)
{
    int i = blockIdx.x*blockDim.x + threadIdx.x;
    int b = i >> 9, col = i & 511;
    int chunk = col >> 6, q = (col & 63) >> 3;
    g_hC[((long)chunk*Bdim + b)*64 + (q ^ (b & 7))*8 + (col & 7)] = __float2half_rn(h0[i]);
    g_c[i] = c0[i];
    if (i == 0) g_sync = 0;
}

// ---------------- fp32 tiled SGEMM (t2 and t5 in one launch) -----------------
template<int BM,int BN,int BK,int TM,int TN>
__global__ void gemm_k(const float* __restrict__ A,
                       const float* __restrict__ Bm, const float* __restrict__ Bm2,
                       float* __restrict__ C, float* __restrict__ C2,
                       int M, int N, int K, long sB, long sC)
{
    constexpr int THREADS = (BM/TM)*(BN/TN);
    __shared__ float As[BK][BM];
    __shared__ float Bs[BK][BN];
    const int z = blockIdx.z;
    const int g = z & 3;
    const float* Bg = (z < 4 ? Bm : Bm2) + (long)g*sB;
    float* Cg = (z < 4 ? C : C2) + (long)g*sC;
    const int m0 = blockIdx.y*BM;
    const int n0 = blockIdx.x*BN;
    const int tid = threadIdx.x;
    constexpr int AK4 = BK/4;
    const int aRow = tid / AK4, aCol = (tid % AK4)*4;
    constexpr int AROWS = THREADS/AK4;
    constexpr int BN4 = BN/4;
    const int bRow = tid / BN4, bCol = (tid % BN4)*4;
    constexpr int BROWS = THREADS/BN4;
    const int tr = (tid/(BN/TN))*TM, tc = (tid%(BN/TN))*TN;

    float acc[TM][TN];
#pragma unroll
    for (int i = 0; i < TM; i++)
#pragma unroll
        for (int j = 0; j < TN; j++) acc[i][j] = 0.f;

    for (int k0 = 0; k0 < K; k0 += BK) {
#pragma unroll
        for (int i = 0; i < BM; i += AROWS) {
            float4 v = *(const float4*)(A + (long)(m0 + aRow + i)*K + (k0 + aCol));
            As[aCol+0][aRow+i] = v.x; As[aCol+1][aRow+i] = v.y;
            As[aCol+2][aRow+i] = v.z; As[aCol+3][aRow+i] = v.w;
        }
#pragma unroll
        for (int i = 0; i < BK; i += BROWS) {
            float4 v = *(const float4*)(Bg + (long)(k0 + bRow + i)*N + (n0 + bCol));
            *(float4*)&Bs[bRow+i][bCol] = v;
        }
        __syncthreads();
#pragma unroll
        for (int kk = 0; kk < BK; kk++) {
            float rm[TM], rn[TN];
#pragma unroll
            for (int i = 0; i < TM; i++) rm[i] = As[kk][tr+i];
#pragma unroll
            for (int j = 0; j < TN; j++) rn[j] = Bs[kk][tc+j];
#pragma unroll
            for (int i = 0; i < TM; i++)
#pragma unroll
                for (int j = 0; j < TN; j++)
                    acc[i][j] = fmaf(rm[i], rn[j], acc[i][j]);
        }
        __syncthreads();
    }
#pragma unroll
    for (int i = 0; i < TM; i++)
#pragma unroll
        for (int j = 0; j < TN; j++)
            Cg[(long)(m0 + tr + i)*N + n0 + tc + j] = acc[i][j];
}

// ---------------- persistent tensor-core recurrence (hi-A, hi+lo W) ----------
#define RW_STRIDE 1040
#define RW_SLAB   (16*RW_STRIDE)
#define RA_BASE   (4*RW_SLAB)
#define RA_ST     16384
#define REC_SMEM  (RA_BASE + 3*RA_ST + 64)

__device__ __forceinline__ void gbar(unsigned goal)
{
    __syncthreads();
    __threadfence();
    if (threadIdx.x == 0) {
        atomicAdd(&g_sync, 1u);
        unsigned v;
        do {
            asm volatile("ld.global.acquire.gpu.u32 %0, [%1];" : "=r"(v) : "l"(&g_sync));
        } while (v < goal);
    }
    __syncthreads();
}

__device__ __forceinline__ float sig_f(float x)  { return 1.f/(1.f + __expf(-x)); }
__device__ __forceinline__ float tanh_f(float x) { return 2.f/(1.f + __expf(-2.f*x)) - 1.f; }

__device__ __forceinline__ void rec_issue(uint32_t sbase, uint32_t mb, int k,
                                          const __half* Ac)
{
    int slot = k % 3;
    uint32_t bar = mb + slot*8;
    BAR_EXPECT(bar, 16384u);
    BULK_CP(sbase + RA_BASE + slot*RA_ST, Ac + (long)k*Bdim*64, 16384u, bar);
}

// full[s] = mb + s*8 ; empty[s] = mb + 24 + s*8 (count 256)
__device__ __forceinline__ void rec_phase(uint32_t sbase, uint32_t wbase, uint32_t mb,
                                          const __half* __restrict__ Asrc,
                                          int tid, int wid, int lane,
                                          float acc[2][4],
                                          unsigned* ub, unsigned* ue, bool prime)
{
#pragma unroll
    for (int i = 0; i < 2; i++)
#pragma unroll
        for (int q = 0; q < 4; q++) acc[i][q] = 0.f;

    if (tid == 0) {
#pragma unroll
        for (int j = 0; j < 3; j++) {
            if (!prime) {
                MBARRIER_WAIT_PARITY(mb + 24 + j*8, ue[j] & 1);
                ue[j]++;
            }
            rec_issue(sbase, mb, j, Asrc);
        }
    }

    for (int k = 0; k < 8; k++) {
        int slot = k % 3;
        MBARRIER_WAIT_PARITY(mb + slot*8, ub[slot] & 1);
        ub[slot]++;

        uint32_t st = sbase + RA_BASE + slot*RA_ST;
#pragma unroll
        for (int ks = 0; ks < 4; ks++) {
            int krow = k*64 + ks*16 + ((lane >> 3) & 1)*8;
            uint32_t baddr = wbase + ((lane & 7) + ((lane >> 4) & 1)*8)*RW_STRIDE + krow*2;
            uint32_t rhi[4], rlo[4];
            ldm_x4(rhi, baddr);
            ldm_x4(rlo, baddr + RW_SLAB);
            uint32_t bhi[2][2] = {{rhi[0], rhi[1]}, {rhi[2], rhi[3]}};
            uint32_t blo[2][2] = {{rlo[0], rlo[1]}, {rlo[2], rlo[3]}};
            uint32_t m = wid*16 + (lane & 15);
            uint32_t q = ks*2 + (lane >> 4);
            uint32_t ahi[4];
            ldm_x4(ahi, st + m*128 + (q ^ (m & 7))*16);
#pragma unroll
            for (int ni = 0; ni < 2; ni++) {
                mma16816(acc[ni], ahi, bhi[ni]);
                mma16816(acc[ni], ahi, blo[ni]);
            }
        }
        MBARRIER_ARRIVE(mb + 24 + slot*8);
        if (tid == 0 && k < 5) {
            MBARRIER_WAIT_PARITY(mb + 24 + slot*8, ue[slot] & 1);
            ue[slot]++;
            rec_issue(sbase, mb, k + 3, Asrc);
        }
    }
}

__global__ void __launch_bounds__(256, 1) rec_k(const float* __restrict__ Ua,
                                                const float* __restrict__ Uc)
{
    extern __shared__ char smem[];
    const uint32_t sbase = smem_u32(smem);
    const uint32_t mb = sbase + RA_BASE + 3*RA_ST;
    const int tid = threadIdx.x, wid = tid >> 5, lane = tid & 31;
    const int bx = blockIdx.x;
    const int gg = bx >> 5;
    const int c0 = (bx & 31)*16;

    {
        const float* UaG = Ua + (long)gg*512*512;
        const float* UcG = Uc + (long)gg*512*512;
        for (int e = tid; e < 512*16; e += 256) {
            int k = e >> 4, j = e & 15;
            float va = UaG[(long)k*512 + c0 + j];
            __half ha = __float2half_rn(va);
            __half la = __float2half_rn(va - __half2float(ha));
            *(__half*)(smem + j*RW_STRIDE + k*2) = ha;
            *(__half*)(smem + RW_SLAB + j*RW_STRIDE + k*2) = la;
            float vc = UcG[(long)k*512 + c0 + j];
            __half hc = __float2half_rn(vc);
            __half lc = __float2half_rn(vc - __half2float(hc));
            *(__half*)(smem + 2*RW_SLAB + j*RW_STRIDE + k*2) = hc;
            *(__half*)(smem + 3*RW_SLAB + j*RW_STRIDE + k*2) = lc;
        }
    }
    if (tid == 0) {
#pragma unroll
        for (int s = 0; s < 3; s++) {
            MBARRIER_INIT(mb + s*8, 1);
            MBARRIER_INIT(mb + 24 + s*8, 256);
        }
    }
    __syncthreads();

    unsigned goal = RC;
    unsigned ub[3] = {0u, 0u, 0u};
    unsigned ue[3] = {0u, 0u, 0u};
    bool prime = true;
    const long GS = (long)TBdim*Hdim;
    const long GH = (long)Bdim*Hdim;
    const __half* t6src = g_t6C + (long)gg*8*Bdim*64;

    const int ci = bx*512 + tid*2;
    float creg0 = g_c[ci], creg1 = g_c[ci + 1];

    for (int t = 0; t < Tdim; t++) {
        float acc[2][4];

        // phase A: t6[gg][:, c0..] = (h @ Ua[gg]) * t5 -> t6C hi
        rec_phase(sbase, sbase, mb, g_hC, tid, wid, lane, acc, ub, ue, prime);
        prime = false;
        {
            __half* Cz = g_t6C + (long)gg*8*Bdim*64;
            const float* t5g = g_t5 + (long)gg*GH;
#pragma unroll
            for (int ni = 0; ni < 2; ni++) {
                int col = c0 + ni*8 + (lane & 3)*2;
                int r0 = wid*16 + (lane >> 2), r1 = r0 + 8;
                int chunk = col >> 6, q = (col & 63) >> 3;
                float2 m0 = *(const float2*)(t5g + (long)r0*512 + col);
                float2 m1 = *(const float2*)(t5g + (long)r1*512 + col);
                __half2 h0 = __floats2half2_rn(acc[ni][0]*m0.x, acc[ni][1]*m0.y);
                __half2 h1 = __floats2half2_rn(acc[ni][2]*m1.x, acc[ni][3]*m1.y);
                *(__half2*)(Cz + ((long)chunk*Bdim + r0)*64 + (q ^ (r0 & 7))*8 + (col & 7)) = h0;
                *(__half2*)(Cz + ((long)chunk*Bdim + r1)*64 + (q ^ (r1 & 7))*8 + (col & 7)) = h1;
            }
        }
        gbar(goal); goal += RC;

        // phase B: gh[gg][:, c0..] = t6[gg] @ Uc[gg]
        rec_phase(sbase, sbase + 2*RW_SLAB, mb, t6src, tid, wid, lane, acc, ub, ue, false);
        {
            float* Cz = g_gh + (long)gg*GH;
#pragma unroll
            for (int ni = 0; ni < 2; ni++) {
                int col = c0 + ni*8 + (lane & 3)*2;
                int r0 = wid*16 + (lane >> 2), r1 = r0 + 8;
                *(float2*)(Cz + (long)r0*512 + col) = make_float2(acc[ni][0], acc[ni][1]);
                *(float2*)(Cz + (long)r1*512 + col) = make_float2(acc[ni][2], acc[ni][3]);
            }
        }
        gbar(goal); goal += RC;

        // phase C: LSTM pointwise on batch row bx (c in registers)
        {
            const long so = (long)t*Bdim*Hdim;
            int i0 = bx*512 + tid*2;
            float hv[2];
#pragma unroll
            for (int u = 0; u < 2; u++) {
                int i = i0 + u;
                float pi = g_gx[0*GS + so + i] + g_gh[0*GH + i];
                float pf = g_gx[1*GS + so + i] + g_gh[1*GH + i];
                float po = g_gx[2*GS + so + i] + g_gh[2*GH + i];
                float pc = g_gx[3*GS + so + i] + g_gh[3*GH + i];
                float ig = sig_f(pi), fg = sig_f(pf), og = sig_f(po);
                float ct = tanh_f(pc);
                float cprev = u == 0 ? creg0 : creg1;
                float cn = fg*cprev + ig*ct;
                float hn = og*tanh_f(cn);
                if (u == 0) creg0 = cn; else creg1 = cn;
                hv[u] = hn;
            }
            __half2 hh = __floats2half2_rn(hv[0], hv[1]);
            int kcol = tid*2;
            int chunk = kcol >> 6, q = (kcol & 63) >> 3;
            *(__half2*)(g_hC + ((long)chunk*Bdim + bx)*64
                        + (q ^ (bx & 7))*8 + (kcol & 7)) = hh;
            int row = t*Bdim + bx;
            *(__half2*)(g_hsC + ((long)chunk*TBdim + row)*64
                        + (q ^ (row & 7))*8 + (kcol & 7)) = hh;
        }
        gbar(goal); goal += RC;
    }
}

// ---------------- launch ------------------------------------------------------
extern "C" void kernel_launch(void* const* d_in, const int* in_sizes, int n_in,
                              void* d_out, int out_size)
{
    const int*   caps = (const int*)  d_in[0];
    const float* tags = (const float*)d_in[1];
    const float* h0   = (const float*)d_in[2];
    const float* c0   = (const float*)d_in[3];
    const float* Wa   = (const float*)d_in[4];
    const float* Wb   = (const float*)d_in[5];
    const float* Wc   = (const float*)d_in[6];
    const float* Ua   = (const float*)d_in[7];
    const float* Ub   = (const float*)d_in[8];
    const float* Uc   = (const float*)d_in[9];
    const float* bi   = (const float*)d_in[10];
    const float* emb  = (const float*)d_in[11];
    const float* Wout = (const float*)d_in[12];
    const float* bout = (const float*)d_in[13];
    float* out = (float*)d_out;

    float *p_t2, *p_t5, *p_gx;
    __half *p_x2C, *p_t1C, *p_WaC, *p_WcC, *p_hsC, *p_WoC;
    cudaGetSymbolAddress((void**)&p_t2,  g_t2);
    cudaGetSymbolAddress((void**)&p_t5,  g_t5);
    cudaGetSymbolAddress((void**)&p_gx,  g_gx);
    cudaGetSymbolAddress((void**)&p_x2C, g_x2C);
    cudaGetSymbolAddress((void**)&p_t1C, g_t1C);
    cudaGetSymbolAddress((void**)&p_WaC, g_WaC);
    cudaGetSymbolAddress((void**)&p_WcC, g_WcC);
    cudaGetSymbolAddress((void**)&p_hsC, g_hsC);
    cudaGetSymbolAddress((void**)&p_WoC, g_WoC);

    cudaFuncSetAttribute((const void*)mm_k<0>, cudaFuncAttributeMaxDynamicSharedMemorySize, MM_SMEM);
    cudaFuncSetAttribute((const void*)mm_k<1>, cudaFuncAttributeMaxDynamicSharedMemorySize, MM_SMEM);
    cudaFuncSetAttribute((const void*)mm_k<2>, cudaFuncAttributeMaxDynamicSharedMemorySize, MM_SMEM);
    cudaFuncSetAttribute((const void*)rec_k, cudaFuncAttributeMaxDynamicSharedMemorySize, REC_SMEM);

    k_gather<<<dim3(Bdim, Tdim), 128>>>(caps, emb);                          // 1
    k_convWC<<<dim3(16, 8, 4), 256>>>(Wa, p_WaC);                             // 2
    gemm_k<32,64,16,4,4><<<dim3(8,4,8), 128>>>(tags, Wb, Ub, p_t2, p_t5,      // 3
        Bdim, Rdim, NTG, (long)NTG*Rdim, (long)Bdim*Rdim);
    mm_k<1><<<dim3(24,2,4), 512, MM_SMEM>>>(p_x2C, p_WaC, nullptr,            // 4 (profiled)
        p_t1C, p_t2, 0L, 8L*512*64, 512);
    k_convWC<<<dim3(16, 8, 4), 256>>>(Wc, p_WcC);                             // 5
    k_init<<<256, 256>>>(h0, c0);                                             // 6
    mm_k<2><<<dim3(24,2,4), 512, MM_SMEM>>>(p_t1C, p_WcC, p_gx,               // 7
        nullptr, bi, 8L*TBdim*64, 8L*512*64, 512);
    k_convB<<<dim3(NPAD/32, 8), 256>>>(Wout);                                 // 8
    rec_k<<<RC, 256, REC_SMEM>>>(Ua, Uc);                                     // 9
    mm_k<0><<<dim3(TBdim/128, NPAD/256), 512, MM_SMEM>>>(                     // 10
        p_hsC, p_WoC, out, nullptr, bout, 0L, 0L, NPAD);
}

// round 13
// speedup vs baseline: 5.7246x; 1.0375x over previous
#include <cuda_runtime.h>
#include <cuda_fp16.h>
#include <math.h>
#include <cstdint>

#define Bdim 128
#define Tdim 24
#define Edim 512
#define Hdim 512
#define Rdim 512
#define NTG 400
#define Vdim 20000
#define NPAD 20224          // 79*256
#define TBdim (Tdim*Bdim)   // 3072
#define RC 128              // persistent recurrence CTAs

// ---------------- scratch (device globals; no allocation allowed) ----------
__device__ float g_t2[4*Bdim*Rdim];
__device__ float g_t5[4*Bdim*Rdim];
__device__ float g_gx[4L*TBdim*Hdim];
__device__ float g_gh[4*Bdim*Hdim];
__device__ float g_c[Bdim*Hdim];
__device__ unsigned g_sync;
// chunk-major swizzled fp16 layouts (hi-only): [.. chunk ..][rows][64]
__device__ __half g_x2C[8L*TBdim*64];           // xs hi
__device__ __half g_t1C[4L*8*TBdim*64];         // t1 hi per gate
__device__ __half g_hC[8L*Bdim*64];             // h hi
__device__ __half g_t6C[4L*8*Bdim*64];          // t6 hi per gate
__device__ __half g_WaC[4L*8*Rdim*64];          // Wa^T hi per gate
__device__ __half g_WcC[4L*8*Rdim*64];          // Wc^T hi per gate
__device__ __half g_hsC[8L*TBdim*64];           // hs hi (out GEMM A)
__device__ __half g_WoC[8L*NPAD*64];            // Wout^T hi (out GEMM B)

__device__ __forceinline__ uint32_t smem_u32(const void* p) {
    uint32_t a;
    asm("{ .reg .u64 t; cvta.to.shared.u64 t, %1; cvt.u32.u64 %0, t; }" : "=r"(a) : "l"(p));
    return a;
}

__device__ __forceinline__ void ldm_x4(uint32_t* r, uint32_t addr)
{
    asm volatile("ldmatrix.sync.aligned.m8n8.x4.shared.b16 {%0,%1,%2,%3}, [%4];"
        : "=r"(r[0]), "=r"(r[1]), "=r"(r[2]), "=r"(r[3]) : "r"(addr));
}

__device__ __forceinline__ void mma16816(float* c, const uint32_t* a, const uint32_t* b)
{
    asm volatile("mma.sync.aligned.m16n8k16.row.col.f32.f16.f16.f32 "
        "{%0,%1,%2,%3}, {%4,%5,%6,%7}, {%8,%9}, {%0,%1,%2,%3};"
        : "+f"(c[0]), "+f"(c[1]), "+f"(c[2]), "+f"(c[3])
        : "r"(a[0]), "r"(a[1]), "r"(a[2]), "r"(a[3]), "r"(b[0]), "r"(b[1]));
}

#define MBARRIER_INIT(mbar, cnt) \
    asm volatile("mbarrier.init.shared.b64 [%0], %1;" :: "r"((uint32_t)(mbar)), "r"((uint32_t)(cnt)) : "memory")
#define MBARRIER_ARRIVE(mbar) \
    asm volatile("mbarrier.arrive.shared.b64 _, [%0];" :: "r"((uint32_t)(mbar)) : "memory")
#define MBARRIER_WAIT_PARITY(mbar, par) do { \
    uint32_t _m = (uint32_t)(mbar), _p = (uint32_t)(par), _d; \
    asm volatile("{\n\t.reg .pred p;\n\t" \
        "mbarrier.try_wait.parity.acquire.cta.shared::cta.b64 p, [%1], %2;\n\t" \
        "selp.b32 %0, 1, 0, p;\n\t}" : "=r"(_d) : "r"(_m), "r"(_p) : "memory"); \
    if (!_d) { \
        asm volatile("{\n\t.reg .pred P1;\n\t" \
            "WL_%=:\n\t" \
            "mbarrier.try_wait.parity.acquire.cta.shared::cta.b64 P1, [%0], %1, 0x989680;\n\t" \
            "@P1 bra.uni WD_%=;\n\t" \
            "bra.uni WL_%=;\n\t" \
            "WD_%=:\n\t}" :: "r"(_m), "r"(_p) : "memory"); \
    } \
} while (0)
#define BULK_CP(dst, src, bytes, bar) \
    asm volatile("cp.async.bulk.shared::cluster.global.mbarrier::complete_tx::bytes " \
        "[%0], [%1], %2, [%3];" :: "r"(dst), "l"(src), "r"((uint32_t)(bytes)), "r"(bar) : "memory")
#define BAR_EXPECT(bar, bytes) \
    asm volatile("mbarrier.arrive.expect_tx.shared.b64 _, [%0], %1;" \
        :: "r"(bar), "r"((uint32_t)(bytes)) : "memory")

// ================= unified hi-only MMA GEMM (out / t1 / gx) =================
// 256 threads, 8 warps (2 x 4), warp tile 64x64.
// A: [chunk][TBdim][64] hi (+z*aS) ; B: [chunk][bRows][64] hi (+z*bS)
// MODE 0: out logits; MODE 1: t1C hi = acc*t2[z]; MODE 2: gx fp32 = acc+bias[z]
#define MM_STAGE 49152
#define MM_SMEM  (3*MM_STAGE + 64)

__device__ __forceinline__ void mm_issue(uint32_t sb, uint32_t mb, int k,
                                         const __half* Ac, const __half* Bc,
                                         int mtile, int ntile, int bRows)
{
    int slot = k % 3;
    uint32_t dst = sb + slot*MM_STAGE;
    uint32_t bar = mb + slot*8;
    BAR_EXPECT(bar, 49152u);
    BULK_CP(dst, Ac + ((long)k*TBdim + mtile*128)*64, 16384u, bar);
    BULK_CP(dst + 16384, Bc + ((long)k*bRows + ntile*256)*64, 32768u, bar);
}

template<int MODE>
__global__ void __launch_bounds__(256, 1) mm_k(
    const __half* __restrict__ A, const __half* __restrict__ B,
    float* __restrict__ Cf, __half* __restrict__ Cb,
    const float* __restrict__ X, long aS, long bS, int bRows)
{
    extern __shared__ char smem[];
    const uint32_t sb = smem_u32(smem);
    const uint32_t mb = sb + 3*MM_STAGE;
    const int tid = threadIdx.x, wid = tid >> 5, lane = tid & 31;
    const int wm = wid & 1, wn = wid >> 1;     // 2 x 4 warps, tile 64x64
    const int mtile = blockIdx.x, ntile = blockIdx.y, z = blockIdx.z;

    const __half* Az = A + (long)z*aS;
    const __half* Bz = B + (long)z*bS;

    if (tid == 0) {
#pragma unroll
        for (int s = 0; s < 3; s++) {
            MBARRIER_INIT(mb + s*8, 1);
            MBARRIER_INIT(mb + 24 + s*8, 256);
        }
    }
    __syncthreads();
    if (tid == 0) {
        mm_issue(sb, mb, 0, Az, Bz, mtile, ntile, bRows);
        mm_issue(sb, mb, 1, Az, Bz, mtile, ntile, bRows);
        mm_issue(sb, mb, 2, Az, Bz, mtile, ntile, bRows);
    }

    float acc[4][8][4];
#pragma unroll
    for (int i = 0; i < 4; i++)
#pragma unroll
        for (int j = 0; j < 8; j++)
#pragma unroll
            for (int q = 0; q < 4; q++) acc[i][j][q] = 0.f;

    for (int k = 0; k < 8; k++) {
        int slot = k % 3;
        MBARRIER_WAIT_PARITY(mb + slot*8, (k/3) & 1);

        uint32_t sA = sb + slot*MM_STAGE;
        uint32_t sB = sA + 16384;
#pragma unroll
        for (int ks = 0; ks < 4; ks++) {
            uint32_t b[8][2];
#pragma unroll
            for (int np = 0; np < 4; np++) {
                uint32_t n = wn*64 + np*16 + (lane & 7) + ((lane >> 4) & 1)*8;
                uint32_t q = ks*2 + ((lane >> 3) & 1);
                uint32_t r[4];
                ldm_x4(r, sB + n*128 + (q ^ (n & 7))*16);
                b[np*2][0] = r[0];   b[np*2][1] = r[1];
                b[np*2+1][0] = r[2]; b[np*2+1][1] = r[3];
            }
            uint32_t a[4][4];
#pragma unroll
            for (int mi = 0; mi < 4; mi++) {
                uint32_t m = wm*64 + mi*16 + (lane & 15);
                uint32_t q = ks*2 + (lane >> 4);
                ldm_x4(a[mi], sA + m*128 + (q ^ (m & 7))*16);
            }
#pragma unroll
            for (int mi = 0; mi < 4; mi++)
#pragma unroll
                for (int ni = 0; ni < 8; ni++)
                    mma16816(acc[mi][ni], a[mi], b[ni]);
        }
        MBARRIER_ARRIVE(mb + 24 + slot*8);
        if (tid == 0 && k < 5) {
            MBARRIER_WAIT_PARITY(mb + 24 + slot*8, (k/3) & 1);
            mm_issue(sb, mb, k + 3, Az, Bz, mtile, ntile, bRows);
        }
    }

#pragma unroll
    for (int mi = 0; mi < 4; mi++) {
#pragma unroll
        for (int ni = 0; ni < 8; ni++) {
            int n = ntile*256 + wn*64 + ni*8 + (lane & 3)*2;
            int gr0 = mtile*128 + wm*64 + mi*16 + (lane >> 2);
            int gr1 = gr0 + 8;
            if (MODE == 0) {
                if (n < Vdim) {
                    float2 bv = *(const float2*)(X + n);
                    long o0 = ((long)(gr0 & 127)*Tdim + (gr0 >> 7))*Vdim + n;
                    long o1 = ((long)(gr1 & 127)*Tdim + (gr1 >> 7))*Vdim + n;
                    *(float2*)(Cf + o0) = make_float2(acc[mi][ni][0] + bv.x, acc[mi][ni][1] + bv.y);
                    *(float2*)(Cf + o1) = make_float2(acc[mi][ni][2] + bv.x, acc[mi][ni][3] + bv.y);
                }
            } else if (MODE == 1) {
                const float* Xg = X + (long)z*Bdim*Rdim;
                __half* Cz = Cb + (long)z*(8L*TBdim*64);
                int chunk = n >> 6, q = (n & 63) >> 3;
                __half2 h0 = __floats2half2_rn(acc[mi][ni][0]*Xg[(gr0 & 127)*512 + n],
                                               acc[mi][ni][1]*Xg[(gr0 & 127)*512 + n + 1]);
                __half2 h1 = __floats2half2_rn(acc[mi][ni][2]*Xg[(gr1 & 127)*512 + n],
                                               acc[mi][ni][3]*Xg[(gr1 & 127)*512 + n + 1]);
                *(__half2*)(Cz + ((long)chunk*TBdim + gr0)*64 + (q ^ (gr0 & 7))*8 + (n & 7)) = h0;
                *(__half2*)(Cz + ((long)chunk*TBdim + gr1)*64 + (q ^ (gr1 & 7))*8 + (n & 7)) = h1;
            } else {
                const float* Xg = X + z*512;
                float* Cz = Cf + (long)z*TBdim*512;
                float2 bv = make_float2(Xg[n], Xg[n + 1]);
                *(float2*)(Cz + (long)gr0*512 + n) = make_float2(acc[mi][ni][0] + bv.x, acc[mi][ni][1] + bv.y);
                *(float2*)(Cz + (long)gr1*512 + n) = make_float2(acc[mi][ni][2] + bv.x, acc[mi][ni][3] + bv.y);
            }
        }
    }
}

// ---------------- conversions ------------------------------------------------
__global__ void __launch_bounds__(256) k_convWC(const float* __restrict__ W,
                                                __half* __restrict__ Bp)
{
    __shared__ float t[64][33];
    const int tid = threadIdx.x;
    const int g = blockIdx.z;
    const int n0 = blockIdx.x*32;
    const int k0 = blockIdx.y*64;
    for (int e = tid; e < 64*32; e += 256) {
        int kk = e >> 5, nn = e & 31;
        t[kk][nn] = W[((long)g*512 + k0 + kk)*512 + n0 + nn];
    }
    __syncthreads();
    int nn = tid >> 3, q = tid & 7;
    int n = n0 + nn;
    __half h[8];
#pragma unroll
    for (int i = 0; i < 8; i++) h[i] = __float2half_rn(t[q*8 + i][nn]);
    int qs = q ^ (n & 7);
    *(uint4*)(Bp + (((long)g*8 + blockIdx.y)*512 + n)*64 + qs*8) = *(uint4*)h;
}

__global__ void __launch_bounds__(256) k_convB(const float* __restrict__ Wout)
{
    __shared__ float t[64][33];
    const int tid = threadIdx.x;
    const int n0 = blockIdx.x*32;
    for (int e = tid; e < 64*32; e += 256) {
        int kk = e >> 5, nn = e & 31;
        int n = n0 + nn;
        t[kk][nn] = (n < Vdim) ? Wout[(long)(blockIdx.y*64 + kk)*Vdim + n] : 0.f;
    }
    __syncthreads();
    int nn = tid >> 3, q = tid & 7;
    int n = n0 + nn;
    __half h[8];
#pragma unroll
    for (int i = 0; i < 8; i++) h[i] = __float2half_rn(t[q*8 + i][nn]);
    int qs = q ^ (n & 7);
    *(uint4*)(g_WoC + ((long)blockIdx.y*NPAD + n)*64 + qs*8) = *(uint4*)h;
}

// ---------------- embedding gather -> x2C hi-only ----------------------------
__global__ void k_gather(const int* __restrict__ caps, const float* __restrict__ emb)
{
    const int b = blockIdx.x, t = blockIdx.y;
    float4 v = make_float4(0.f, 0.f, 0.f, 0.f);
    if (t > 0) {
        int tok = caps[b*Tdim + (t-1)];
        v = ((const float4*)(emb + (long)tok*Edim))[threadIdx.x];
    }
    __half hv[4];
    hv[0] = __float2half_rn(v.x); hv[1] = __float2half_rn(v.y);
    hv[2] = __float2half_rn(v.z); hv[3] = __float2half_rn(v.w);
    int col = threadIdx.x*4;
    int row = t*Bdim + b;
    int chunk = col >> 6, q = (col & 63) >> 3;
    *(uint2*)(g_x2C + ((long)chunk*TBdim + row)*64 + (q ^ (row & 7))*8 + (col & 7)) = *(uint2*)hv;
}

__global__ void k_init(const float* __restrict__ h0, const float* __restrict__ c0)
{
    int i = blockIdx.x*blockDim.x + threadIdx.x;
    int b = i >> 9, col = i & 511;
    int chunk = col >> 6, q = (col & 63) >> 3;
    g_hC[((long)chunk*Bdim + b)*64 + (q ^ (b & 7))*8 + (col & 7)] = __float2half_rn(h0[i]);
    g_c[i] = c0[i];
    if (i == 0) g_sync = 0;
}

// ---------------- fp32 tiled SGEMM (t2 and t5 in one launch) -----------------
template<int BM,int BN,int BK,int TM,int TN>
__global__ void gemm_k(const float* __restrict__ A,
                       const float* __restrict__ Bm, const float* __restrict__ Bm2,
                       float* __restrict__ C, float* __restrict__ C2,
                       int M, int N, int K, long sB, long sC)
{
    constexpr int THREADS = (BM/TM)*(BN/TN);
    __shared__ float As[BK][BM];
    __shared__ float Bs[BK][BN];
    const int z = blockIdx.z;
    const int g = z & 3;
    const float* Bg = (z < 4 ? Bm : Bm2) + (long)g*sB;
    float* Cg = (z < 4 ? C : C2) + (long)g*sC;
    const int m0 = blockIdx.y*BM;
    const int n0 = blockIdx.x*BN;
    const int tid = threadIdx.x;
    constexpr int AK4 = BK/4;
    const int aRow = tid / AK4, aCol = (tid % AK4)*4;
    constexpr int AROWS = THREADS/AK4;
    constexpr int BN4 = BN/4;
    const int bRow = tid / BN4, bCol = (tid % BN4)*4;
    constexpr int BROWS = THREADS/BN4;
    const int tr = (tid/(BN/TN))*TM, tc = (tid%(BN/TN))*TN;

    float acc[TM][TN];
#pragma unroll
    for (int i = 0; i < TM; i++)
#pragma unroll
        for (int j = 0; j < TN; j++) acc[i][j] = 0.f;

    for (int k0 = 0; k0 < K; k0 += BK) {
#pragma unroll
        for (int i = 0; i < BM; i += AROWS) {
            float4 v = *(const float4*)(A + (long)(m0 + aRow + i)*K + (k0 + aCol));
            As[aCol+0][aRow+i] = v.x; As[aCol+1][aRow+i] = v.y;
            As[aCol+2][aRow+i] = v.z; As[aCol+3][aRow+i] = v.w;
        }
#pragma unroll
        for (int i = 0; i < BK; i += BROWS) {
            float4 v = *(const float4*)(Bg + (long)(k0 + bRow + i)*N + (n0 + bCol));
            *(float4*)&Bs[bRow+i][bCol] = v;
        }
        __syncthreads();
#pragma unroll
        for (int kk = 0; kk < BK; kk++) {
            float rm[TM], rn[TN];
#pragma unroll
            for (int i = 0; i < TM; i++) rm[i] = As[kk][tr+i];
#pragma unroll
            for (int j = 0; j < TN; j++) rn[j] = Bs[kk][tc+j];
#pragma unroll
            for (int i = 0; i < TM; i++)
#pragma unroll
                for (int j = 0; j < TN; j++)
                    acc[i][j] = fmaf(rm[i], rn[j], acc[i][j]);
        }
        __syncthreads();
    }
#pragma unroll
    for (int i = 0; i < TM; i++)
#pragma unroll
        for (int j = 0; j < TN; j++)
            Cg[(long)(m0 + tr + i)*N + n0 + tc + j] = acc[i][j];
}

// ---------------- persistent tensor-core recurrence (hi A, hi W) -------------
#define RW_STRIDE 1040
#define RW_SLAB   (16*RW_STRIDE)
#define RA_BASE   (2*RW_SLAB)
#define RA_ST     16384
#define REC_SMEM  (RA_BASE + 3*RA_ST + 64)

__device__ __forceinline__ void gbar(unsigned goal)
{
    __syncthreads();
    __threadfence();
    if (threadIdx.x == 0) {
        atomicAdd(&g_sync, 1u);
        unsigned v;
        do {
            asm volatile("ld.global.acquire.gpu.u32 %0, [%1];" : "=r"(v) : "l"(&g_sync));
        } while (v < goal);
    }
    __syncthreads();
}

__device__ __forceinline__ float sig_f(float x)  { return 1.f/(1.f + __expf(-x)); }
__device__ __forceinline__ float tanh_f(float x) { return 2.f/(1.f + __expf(-2.f*x)) - 1.f; }

__device__ __forceinline__ void rec_issue(uint32_t sbase, uint32_t mb, int k,
                                          const __half* Ac)
{
    int slot = k % 3;
    uint32_t bar = mb + slot*8;
    BAR_EXPECT(bar, 16384u);
    BULK_CP(sbase + RA_BASE + slot*RA_ST, Ac + (long)k*Bdim*64, 16384u, bar);
}

// full[s] = mb + s*8 ; empty[s] = mb + 24 + s*8 (count 256)
__device__ __forceinline__ void rec_phase(uint32_t sbase, uint32_t wbase, uint32_t mb,
                                          const __half* __restrict__ Asrc,
                                          int tid, int wid, int lane,
                                          float acc[2][4],
                                          unsigned* ub, unsigned* ue, bool prime)
{
#pragma unroll
    for (int i = 0; i < 2; i++)
#pragma unroll
        for (int q = 0; q < 4; q++) acc[i][q] = 0.f;

    if (tid == 0) {
#pragma unroll
        for (int j = 0; j < 3; j++) {
            if (!prime) {
                MBARRIER_WAIT_PARITY(mb + 24 + j*8, ue[j] & 1);
                ue[j]++;
            }
            rec_issue(sbase, mb, j, Asrc);
        }
    }

    for (int k = 0; k < 8; k++) {
        int slot = k % 3;
        MBARRIER_WAIT_PARITY(mb + slot*8, ub[slot] & 1);
        ub[slot]++;

        uint32_t st = sbase + RA_BASE + slot*RA_ST;
#pragma unroll
        for (int ks = 0; ks < 4; ks++) {
            int krow = k*64 + ks*16 + ((lane >> 3) & 1)*8;
            uint32_t baddr = wbase + ((lane & 7) + ((lane >> 4) & 1)*8)*RW_STRIDE + krow*2;
            uint32_t rhi[4];
            ldm_x4(rhi, baddr);
            uint32_t bhi[2][2] = {{rhi[0], rhi[1]}, {rhi[2], rhi[3]}};
            uint32_t m = wid*16 + (lane & 15);
            uint32_t q = ks*2 + (lane >> 4);
            uint32_t ahi[4];
            ldm_x4(ahi, st + m*128 + (q ^ (m & 7))*16);
#pragma unroll
            for (int ni = 0; ni < 2; ni++)
                mma16816(acc[ni], ahi, bhi[ni]);
        }
        MBARRIER_ARRIVE(mb + 24 + slot*8);
        if (tid == 0 && k < 5) {
            MBARRIER_WAIT_PARITY(mb + 24 + slot*8, ue[slot] & 1);
            ue[slot]++;
            rec_issue(sbase, mb, k + 3, Asrc);
        }
    }
}

__global__ void __launch_bounds__(256, 1) rec_k(const float* __restrict__ Ua,
                                                const float* __restrict__ Uc)
{
    extern __shared__ char smem[];
    const uint32_t sbase = smem_u32(smem);
    const uint32_t mb = sbase + RA_BASE + 3*RA_ST;
    const int tid = threadIdx.x, wid = tid >> 5, lane = tid & 31;
    const int bx = blockIdx.x;
    const int gg = bx >> 5;
    const int c0 = (bx & 31)*16;

    {   // one-time weight slice conversion to smem (hi only)
        const float* UaG = Ua + (long)gg*512*512;
        const float* UcG = Uc + (long)gg*512*512;
        for (int e = tid; e < 512*16; e += 256) {
            int k = e >> 4, j = e & 15;
            *(__half*)(smem + j*RW_STRIDE + k*2) =
                __float2half_rn(UaG[(long)k*512 + c0 + j]);
            *(__half*)(smem + RW_SLAB + j*RW_STRIDE + k*2) =
                __float2half_rn(UcG[(long)k*512 + c0 + j]);
        }
    }
    if (tid == 0) {
#pragma unroll
        for (int s = 0; s < 3; s++) {
            MBARRIER_INIT(mb + s*8, 1);
            MBARRIER_INIT(mb + 24 + s*8, 256);
        }
    }
    __syncthreads();

    unsigned goal = RC;
    unsigned ub[3] = {0u, 0u, 0u};
    unsigned ue[3] = {0u, 0u, 0u};
    bool prime = true;
    const long GS = (long)TBdim*Hdim;
    const long GH = (long)Bdim*Hdim;
    const __half* t6src = g_t6C + (long)gg*8*Bdim*64;

    const int ci = bx*512 + tid*2;
    float creg0 = g_c[ci], creg1 = g_c[ci + 1];

    for (int t = 0; t < Tdim; t++) {
        float acc[2][4];

        // phase A: t6[gg][:, c0..] = (h @ Ua[gg]) * t5 -> t6C hi
        rec_phase(sbase, sbase, mb, g_hC, tid, wid, lane, acc, ub, ue, prime);
        prime = false;
        {
            __half* Cz = g_t6C + (long)gg*8*Bdim*64;
            const float* t5g = g_t5 + (long)gg*GH;
#pragma unroll
            for (int ni = 0; ni < 2; ni++) {
                int col = c0 + ni*8 + (lane & 3)*2;
                int r0 = wid*16 + (lane >> 2), r1 = r0 + 8;
                int chunk = col >> 6, q = (col & 63) >> 3;
                float2 m0 = *(const float2*)(t5g + (long)r0*512 + col);
                float2 m1 = *(const float2*)(t5g + (long)r1*512 + col);
                __half2 h0 = __floats2half2_rn(acc[ni][0]*m0.x, acc[ni][1]*m0.y);
                __half2 h1 = __floats2half2_rn(acc[ni][2]*m1.x, acc[ni][3]*m1.y);
                *(__half2*)(Cz + ((long)chunk*Bdim + r0)*64 + (q ^ (r0 & 7))*8 + (col & 7)) = h0;
                *(__half2*)(Cz + ((long)chunk*Bdim + r1)*64 + (q ^ (r1 & 7))*8 + (col & 7)) = h1;
            }
        }
        gbar(goal); goal += RC;

        // phase B: gh[gg][:, c0..] = t6[gg] @ Uc[gg]
        rec_phase(sbase, sbase + RW_SLAB, mb, t6src, tid, wid, lane, acc, ub, ue, false);
        {
            float* Cz = g_gh + (long)gg*GH;
#pragma unroll
            for (int ni = 0; ni < 2; ni++) {
                int col = c0 + ni*8 + (lane & 3)*2;
                int r0 = wid*16 + (lane >> 2), r1 = r0 + 8;
                *(float2*)(Cz + (long)r0*512 + col) = make_float2(acc[ni][0], acc[ni][1]);
                *(float2*)(Cz + (long)r1*512 + col) = make_float2(acc[ni][2], acc[ni][3]);
            }
        }
        gbar(goal); goal += RC;

        // phase C: LSTM pointwise on batch row bx (c in registers)
        {
            const long so = (long)t*Bdim*Hdim;
            int i0 = bx*512 + tid*2;
            float hv[2];
#pragma unroll
            for (int u = 0; u < 2; u++) {
                int i = i0 + u;
                float pi = g_gx[0*GS + so + i] + g_gh[0*GH + i];
                float pf = g_gx[1*GS + so + i] + g_gh[1*GH + i];
                float po = g_gx[2*GS + so + i] + g_gh[2*GH + i];
                float pc = g_gx[3*GS + so + i] + g_gh[3*GH + i];
                float ig = sig_f(pi), fg = sig_f(pf), og = sig_f(po);
                float ct = tanh_f(pc);
                float cprev = u == 0 ? creg0 : creg1;
                float cn = fg*cprev + ig*ct;
                float hn = og*tanh_f(cn);
                if (u == 0) creg0 = cn; else creg1 = cn;
                hv[u] = hn;
            }
            __half2 hh = __floats2half2_rn(hv[0], hv[1]);
            int kcol = tid*2;
            int chunk = kcol >> 6, q = (kcol & 63) >> 3;
            *(__half2*)(g_hC + ((long)chunk*Bdim + bx)*64
                        + (q ^ (bx & 7))*8 + (kcol & 7)) = hh;
            int row = t*Bdim + bx;
            *(__half2*)(g_hsC + ((long)chunk*TBdim + row)*64
                        + (q ^ (row & 7))*8 + (kcol & 7)) = hh;
        }
        gbar(goal); goal += RC;
    }
}

// ---------------- launch ------------------------------------------------------
extern "C" void kernel_launch(void* const* d_in, const int* in_sizes, int n_in,
                              void* d_out, int out_size)
{
    const int*   caps = (const int*)  d_in[0];
    const float* tags = (const float*)d_in[1];
    const float* h0   = (const float*)d_in[2];
    const float* c0   = (const float*)d_in[3];
    const float* Wa   = (const float*)d_in[4];
    const float* Wb   = (const float*)d_in[5];
    const float* Wc   = (const float*)d_in[6];
    const float* Ua   = (const float*)d_in[7];
    const float* Ub   = (const float*)d_in[8];
    const float* Uc   = (const float*)d_in[9];
    const float* bi   = (const float*)d_in[10];
    const float* emb  = (const float*)d_in[11];
    const float* Wout = (const float*)d_in[12];
    const float* bout = (const float*)d_in[13];
    float* out = (float*)d_out;

    float *p_t2, *p_t5, *p_gx;
    __half *p_x2C, *p_t1C, *p_WaC, *p_WcC, *p_hsC, *p_WoC;
    cudaGetSymbolAddress((void**)&p_t2,  g_t2);
    cudaGetSymbolAddress((void**)&p_t5,  g_t5);
    cudaGetSymbolAddress((void**)&p_gx,  g_gx);
    cudaGetSymbolAddress((void**)&p_x2C, g_x2C);
    cudaGetSymbolAddress((void**)&p_t1C, g_t1C);
    cudaGetSymbolAddress((void**)&p_WaC, g_WaC);
    cudaGetSymbolAddress((void**)&p_WcC, g_WcC);
    cudaGetSymbolAddress((void**)&p_hsC, g_hsC);
    cudaGetSymbolAddress((void**)&p_WoC, g_WoC);

    cudaFuncSetAttribute((const void*)mm_k<0>, cudaFuncAttributeMaxDynamicSharedMemorySize, MM_SMEM);
    cudaFuncSetAttribute((const void*)mm_k<1>, cudaFuncAttributeMaxDynamicSharedMemorySize, MM_SMEM);
    cudaFuncSetAttribute((const void*)mm_k<2>, cudaFuncAttributeMaxDynamicSharedMemorySize, MM_SMEM);
    cudaFuncSetAttribute((const void*)rec_k, cudaFuncAttributeMaxDynamicSharedMemorySize, REC_SMEM);

    k_gather<<<dim3(Bdim, Tdim), 128>>>(caps, emb);                          // 1
    k_convWC<<<dim3(16, 8, 4), 256>>>(Wa, p_WaC);                             // 2
    gemm_k<32,64,16,4,4><<<dim3(8,4,8), 128>>>(tags, Wb, Ub, p_t2, p_t5,      // 3
        Bdim, Rdim, NTG, (long)NTG*Rdim, (long)Bdim*Rdim);
    mm_k<1><<<dim3(24,2,4), 256, MM_SMEM>>>(p_x2C, p_WaC, nullptr,            // 4 (profiled)
        p_t1C, p_t2, 0L, 8L*512*64, 512);
    k_convWC<<<dim3(16, 8, 4), 256>>>(Wc, p_WcC);                             // 5
    k_init<<<256, 256>>>(h0, c0);                                             // 6
    mm_k<2><<<dim3(24,2,4), 256, MM_SMEM>>>(p_t1C, p_WcC, p_gx,               // 7
        nullptr, bi, 8L*TBdim*64, 8L*512*64, 512);
    k_convB<<<dim3(NPAD/32, 8), 256>>>(Wout);                                 // 8
    rec_k<<<RC, 256, REC_SMEM>>>(Ua, Uc);                                     // 9
    mm_k<0><<<dim3(TBdim/128, NPAD/256), 256, MM_SMEM>>>(                     // 10
        p_hsC, p_WoC, out, nullptr, bout, 0L, 0L, NPAD);
}

// round 14
// speedup vs baseline: 6.1861x; 1.0806x over previous
#include <cuda_runtime.h>
#include <cuda_fp16.h>
#include <math.h>
#include <cstdint>

#define Bdim 128
#define Tdim 24
#define Edim 512
#define Hdim 512
#define Rdim 512
#define NTG 400
#define Vdim 20000
#define NPAD 20224          // 158*128
#define TBdim (Tdim*Bdim)   // 3072
#define RC 128              // persistent recurrence CTAs

// ---------------- scratch (device globals; no allocation allowed) ----------
__device__ float g_t2[4*Bdim*Rdim];
__device__ float g_t5[4*Bdim*Rdim];
__device__ float g_gx[4L*TBdim*Hdim];
__device__ float g_gh[4*Bdim*Hdim];
__device__ float g_c[Bdim*Hdim];
__device__ unsigned g_sync;
// chunk-major swizzled fp16 layouts (hi-only): [.. chunk ..][rows][64]
__device__ __half g_x2C[8L*TBdim*64];           // xs hi
__device__ __half g_t1C[4L*8*TBdim*64];         // t1 hi per gate
__device__ __half g_hC[8L*Bdim*64];             // h hi
__device__ __half g_t6C[4L*8*Bdim*64];          // t6 hi per gate
__device__ __half g_WaC[4L*8*Rdim*64];          // Wa^T hi per gate
__device__ __half g_WcC[4L*8*Rdim*64];          // Wc^T hi per gate
__device__ __half g_hsC[8L*TBdim*64];           // hs hi (out GEMM A)
__device__ __half g_WoC[8L*NPAD*64];            // Wout^T hi (out GEMM B)

__device__ __forceinline__ uint32_t smem_u32(const void* p) {
    uint32_t a;
    asm("{ .reg .u64 t; cvta.to.shared.u64 t, %1; cvt.u32.u64 %0, t; }" : "=r"(a) : "l"(p));
    return a;
}

__device__ __forceinline__ void ldm_x4(uint32_t* r, uint32_t addr)
{
    asm volatile("ldmatrix.sync.aligned.m8n8.x4.shared.b16 {%0,%1,%2,%3}, [%4];"
        : "=r"(r[0]), "=r"(r[1]), "=r"(r[2]), "=r"(r[3]) : "r"(addr));
}

__device__ __forceinline__ void mma16816(float* c, const uint32_t* a, const uint32_t* b)
{
    asm volatile("mma.sync.aligned.m16n8k16.row.col.f32.f16.f16.f32 "
        "{%0,%1,%2,%3}, {%4,%5,%6,%7}, {%8,%9}, {%0,%1,%2,%3};"
        : "+f"(c[0]), "+f"(c[1]), "+f"(c[2]), "+f"(c[3])
        : "r"(a[0]), "r"(a[1]), "r"(a[2]), "r"(a[3]), "r"(b[0]), "r"(b[1]));
}

#define MBARRIER_INIT(mbar, cnt) \
    asm volatile("mbarrier.init.shared.b64 [%0], %1;" :: "r"((uint32_t)(mbar)), "r"((uint32_t)(cnt)) : "memory")
#define MBARRIER_ARRIVE(mbar) \
    asm volatile("mbarrier.arrive.shared.b64 _, [%0];" :: "r"((uint32_t)(mbar)) : "memory")
#define MBARRIER_WAIT_PARITY(mbar, par) do { \
    uint32_t _m = (uint32_t)(mbar), _p = (uint32_t)(par), _d; \
    asm volatile("{\n\t.reg .pred p;\n\t" \
        "mbarrier.try_wait.parity.acquire.cta.shared::cta.b64 p, [%1], %2;\n\t" \
        "selp.b32 %0, 1, 0, p;\n\t}" : "=r"(_d) : "r"(_m), "r"(_p) : "memory"); \
    if (!_d) { \
        asm volatile("{\n\t.reg .pred P1;\n\t" \
            "WL_%=:\n\t" \
            "mbarrier.try_wait.parity.acquire.cta.shared::cta.b64 P1, [%0], %1, 0x989680;\n\t" \
            "@P1 bra.uni WD_%=;\n\t" \
            "bra.uni WL_%=;\n\t" \
            "WD_%=:\n\t}" :: "r"(_m), "r"(_p) : "memory"); \
    } \
} while (0)
#define BULK_CP(dst, src, bytes, bar) \
    asm volatile("cp.async.bulk.shared::cluster.global.mbarrier::complete_tx::bytes " \
        "[%0], [%1], %2, [%3];" :: "r"(dst), "l"(src), "r"((uint32_t)(bytes)), "r"(bar) : "memory")
#define BAR_EXPECT(bar, bytes) \
    asm volatile("mbarrier.arrive.expect_tx.shared.b64 _, [%0], %1;" \
        :: "r"(bar), "r"((uint32_t)(bytes)) : "memory")

// ================= unified hi-only MMA GEMM (out / t1 / gx) =================
// 256 threads, 8 warps (2 x 4), CTA tile 128x128, warp tile 64x32.
// 3 stages x 32KB = 96KB smem -> 2 CTAs/SM.
// A: [chunk][TBdim][64] hi (+z*aS) ; B: [chunk][bRows][64] hi (+z*bS)
// MODE 0: out logits; MODE 1: t1C hi = acc*t2[z]; MODE 2: gx fp32 = acc+bias[z]
#define MM_STAGE 32768
#define MM_SMEM  (3*MM_STAGE + 64)

__device__ __forceinline__ void mm_issue(uint32_t sb, uint32_t mb, int k,
                                         const __half* Ac, const __half* Bc,
                                         int mtile, int ntile, int bRows)
{
    int slot = k % 3;
    uint32_t dst = sb + slot*MM_STAGE;
    uint32_t bar = mb + slot*8;
    BAR_EXPECT(bar, 32768u);
    BULK_CP(dst, Ac + ((long)k*TBdim + mtile*128)*64, 16384u, bar);
    BULK_CP(dst + 16384, Bc + ((long)k*bRows + ntile*128)*64, 16384u, bar);
}

template<int MODE>
__global__ void __launch_bounds__(256, 2) mm_k(
    const __half* __restrict__ A, const __half* __restrict__ B,
    float* __restrict__ Cf, __half* __restrict__ Cb,
    const float* __restrict__ X, long aS, long bS, int bRows)
{
    extern __shared__ char smem[];
    const uint32_t sb = smem_u32(smem);
    const uint32_t mb = sb + 3*MM_STAGE;
    const int tid = threadIdx.x, wid = tid >> 5, lane = tid & 31;
    const int wm = wid & 1, wn = wid >> 1;     // 2 x 4 warps, tile 64x32
    const int mtile = blockIdx.x, ntile = blockIdx.y, z = blockIdx.z;

    const __half* Az = A + (long)z*aS;
    const __half* Bz = B + (long)z*bS;

    if (tid == 0) {
#pragma unroll
        for (int s = 0; s < 3; s++) {
            MBARRIER_INIT(mb + s*8, 1);
            MBARRIER_INIT(mb + 24 + s*8, 256);
        }
    }
    __syncthreads();
    if (tid == 0) {
        mm_issue(sb, mb, 0, Az, Bz, mtile, ntile, bRows);
        mm_issue(sb, mb, 1, Az, Bz, mtile, ntile, bRows);
        mm_issue(sb, mb, 2, Az, Bz, mtile, ntile, bRows);
    }

    float acc[4][4][4];
#pragma unroll
    for (int i = 0; i < 4; i++)
#pragma unroll
        for (int j = 0; j < 4; j++)
#pragma unroll
            for (int q = 0; q < 4; q++) acc[i][j][q] = 0.f;

    for (int k = 0; k < 8; k++) {
        int slot = k % 3;
        MBARRIER_WAIT_PARITY(mb + slot*8, (k/3) & 1);

        uint32_t sA = sb + slot*MM_STAGE;
        uint32_t sB = sA + 16384;
#pragma unroll
        for (int ks = 0; ks < 4; ks++) {
            uint32_t b[4][2];
#pragma unroll
            for (int np = 0; np < 2; np++) {
                uint32_t n = wn*32 + np*16 + (lane & 7) + ((lane >> 4) & 1)*8;
                uint32_t q = ks*2 + ((lane >> 3) & 1);
                uint32_t r[4];
                ldm_x4(r, sB + n*128 + (q ^ (n & 7))*16);
                b[np*2][0] = r[0];   b[np*2][1] = r[1];
                b[np*2+1][0] = r[2]; b[np*2+1][1] = r[3];
            }
            uint32_t a[4][4];
#pragma unroll
            for (int mi = 0; mi < 4; mi++) {
                uint32_t m = wm*64 + mi*16 + (lane & 15);
                uint32_t q = ks*2 + (lane >> 4);
                ldm_x4(a[mi], sA + m*128 + (q ^ (m & 7))*16);
            }
#pragma unroll
            for (int mi = 0; mi < 4; mi++)
#pragma unroll
                for (int ni = 0; ni < 4; ni++)
                    mma16816(acc[mi][ni], a[mi], b[ni]);
        }
        MBARRIER_ARRIVE(mb + 24 + slot*8);
        if (tid == 0 && k < 5) {
            MBARRIER_WAIT_PARITY(mb + 24 + slot*8, (k/3) & 1);
            mm_issue(sb, mb, k + 3, Az, Bz, mtile, ntile, bRows);
        }
    }

#pragma unroll
    for (int mi = 0; mi < 4; mi++) {
#pragma unroll
        for (int ni = 0; ni < 4; ni++) {
            int n = ntile*128 + wn*32 + ni*8 + (lane & 3)*2;
            int gr0 = mtile*128 + wm*64 + mi*16 + (lane >> 2);
            int gr1 = gr0 + 8;
            if (MODE == 0) {
                if (n < Vdim) {
                    float2 bv = *(const float2*)(X + n);
                    long o0 = ((long)(gr0 & 127)*Tdim + (gr0 >> 7))*Vdim + n;
                    long o1 = ((long)(gr1 & 127)*Tdim + (gr1 >> 7))*Vdim + n;
                    *(float2*)(Cf + o0) = make_float2(acc[mi][ni][0] + bv.x, acc[mi][ni][1] + bv.y);
                    *(float2*)(Cf + o1) = make_float2(acc[mi][ni][2] + bv.x, acc[mi][ni][3] + bv.y);
                }
            } else if (MODE == 1) {
                const float* Xg = X + (long)z*Bdim*Rdim;
                __half* Cz = Cb + (long)z*(8L*TBdim*64);
                int chunk = n >> 6, q = (n & 63) >> 3;
                __half2 h0 = __floats2half2_rn(acc[mi][ni][0]*Xg[(gr0 & 127)*512 + n],
                                               acc[mi][ni][1]*Xg[(gr0 & 127)*512 + n + 1]);
                __half2 h1 = __floats2half2_rn(acc[mi][ni][2]*Xg[(gr1 & 127)*512 + n],
                                               acc[mi][ni][3]*Xg[(gr1 & 127)*512 + n + 1]);
                *(__half2*)(Cz + ((long)chunk*TBdim + gr0)*64 + (q ^ (gr0 & 7))*8 + (n & 7)) = h0;
                *(__half2*)(Cz + ((long)chunk*TBdim + gr1)*64 + (q ^ (gr1 & 7))*8 + (n & 7)) = h1;
            } else {
                const float* Xg = X + z*512;
                float* Cz = Cf + (long)z*TBdim*512;
                float2 bv = make_float2(Xg[n], Xg[n + 1]);
                *(float2*)(Cz + (long)gr0*512 + n) = make_float2(acc[mi][ni][0] + bv.x, acc[mi][ni][1] + bv.y);
                *(float2*)(Cz + (long)gr1*512 + n) = make_float2(acc[mi][ni][2] + bv.x, acc[mi][ni][3] + bv.y);
            }
        }
    }
}

// ---------------- conversions ------------------------------------------------
__global__ void __launch_bounds__(256) k_convWC(const float* __restrict__ W,
                                                __half* __restrict__ Bp)
{
    __shared__ float t[64][33];
    const int tid = threadIdx.x;
    const int g = blockIdx.z;
    const int n0 = blockIdx.x*32;
    const int k0 = blockIdx.y*64;
    for (int e = tid; e < 64*32; e += 256) {
        int kk = e >> 5, nn = e & 31;
        t[kk][nn] = W[((long)g*512 + k0 + kk)*512 + n0 + nn];
    }
    __syncthreads();
    int nn = tid >> 3, q = tid & 7;
    int n = n0 + nn;
    __half h[8];
#pragma unroll
    for (int i = 0; i < 8; i++) h[i] = __float2half_rn(t[q*8 + i][nn]);
    int qs = q ^ (n & 7);
    *(uint4*)(Bp + (((long)g*8 + blockIdx.y)*512 + n)*64 + qs*8) = *(uint4*)h;
}

__global__ void __launch_bounds__(256) k_convB(const float* __restrict__ Wout)
{
    __shared__ float t[64][33];
    const int tid = threadIdx.x;
    const int n0 = blockIdx.x*32;
    for (int e = tid; e < 64*32; e += 256) {
        int kk = e >> 5, nn = e & 31;
        int n = n0 + nn;
        t[kk][nn] = (n < Vdim) ? Wout[(long)(blockIdx.y*64 + kk)*Vdim + n] : 0.f;
    }
    __syncthreads();
    int nn = tid >> 3, q = tid & 7;
    int n = n0 + nn;
    __half h[8];
#pragma unroll
    for (int i = 0; i < 8; i++) h[i] = __float2half_rn(t[q*8 + i][nn]);
    int qs = q ^ (n & 7);
    *(uint4*)(g_WoC + ((long)blockIdx.y*NPAD + n)*64 + qs*8) = *(uint4*)h;
}

// ---------------- embedding gather -> x2C hi-only ----------------------------
__global__ void k_gather(const int* __restrict__ caps, const float* __restrict__ emb)
{
    const int b = blockIdx.x, t = blockIdx.y;
    float4 v = make_float4(0.f, 0.f, 0.f, 0.f);
    if (t > 0) {
        int tok = caps[b*Tdim + (t-1)];
        v = ((const float4*)(emb + (long)tok*Edim))[threadIdx.x];
    }
    __half hv[4];
    hv[0] = __float2half_rn(v.x); hv[1] = __float2half_rn(v.y);
    hv[2] = __float2half_rn(v.z); hv[3] = __float2half_rn(v.w);
    int col = threadIdx.x*4;
    int row = t*Bdim + b;
    int chunk = col >> 6, q = (col & 63) >> 3;
    *(uint2*)(g_x2C + ((long)chunk*TBdim + row)*64 + (q ^ (row & 7))*8 + (col & 7)) = *(uint2*)hv;
}

__global__ void k_init(const float* __restrict__ h0, const float* __restrict__ c0)
{
    int i = blockIdx.x*blockDim.x + threadIdx.x;
    int b = i >> 9, col = i & 511;
    int chunk = col >> 6, q = (col & 63) >> 3;
    g_hC[((long)chunk*Bdim + b)*64 + (q ^ (b & 7))*8 + (col & 7)] = __float2half_rn(h0[i]);
    g_c[i] = c0[i];
    if (i == 0) g_sync = 0;
}

// ---------------- fp32 tiled SGEMM (t2 and t5 in one launch) -----------------
template<int BM,int BN,int BK,int TM,int TN>
__global__ void gemm_k(const float* __restrict__ A,
                       const float* __restrict__ Bm, const float* __restrict__ Bm2,
                       float* __restrict__ C, float* __restrict__ C2,
                       int M, int N, int K, long sB, long sC)
{
    constexpr int THREADS = (BM/TM)*(BN/TN);
    __shared__ float As[BK][BM];
    __shared__ float Bs[BK][BN];
    const int z = blockIdx.z;
    const int g = z & 3;
    const float* Bg = (z < 4 ? Bm : Bm2) + (long)g*sB;
    float* Cg = (z < 4 ? C : C2) + (long)g*sC;
    const int m0 = blockIdx.y*BM;
    const int n0 = blockIdx.x*BN;
    const int tid = threadIdx.x;
    constexpr int AK4 = BK/4;
    const int aRow = tid / AK4, aCol = (tid % AK4)*4;
    constexpr int AROWS = THREADS/AK4;
    constexpr int BN4 = BN/4;
    const int bRow = tid / BN4, bCol = (tid % BN4)*4;
    constexpr int BROWS = THREADS/BN4;
    const int tr = (tid/(BN/TN))*TM, tc = (tid%(BN/TN))*TN;

    float acc[TM][TN];
#pragma unroll
    for (int i = 0; i < TM; i++)
#pragma unroll
        for (int j = 0; j < TN; j++) acc[i][j] = 0.f;

    for (int k0 = 0; k0 < K; k0 += BK) {
#pragma unroll
        for (int i = 0; i < BM; i += AROWS) {
            float4 v = *(const float4*)(A + (long)(m0 + aRow + i)*K + (k0 + aCol));
            As[aCol+0][aRow+i] = v.x; As[aCol+1][aRow+i] = v.y;
            As[aCol+2][aRow+i] = v.z; As[aCol+3][aRow+i] = v.w;
        }
#pragma unroll
        for (int i = 0; i < BK; i += BROWS) {
            float4 v = *(const float4*)(Bg + (long)(k0 + bRow + i)*N + (n0 + bCol));
            *(float4*)&Bs[bRow+i][bCol] = v;
        }
        __syncthreads();
#pragma unroll
        for (int kk = 0; kk < BK; kk++) {
            float rm[TM], rn[TN];
#pragma unroll
            for (int i = 0; i < TM; i++) rm[i] = As[kk][tr+i];
#pragma unroll
            for (int j = 0; j < TN; j++) rn[j] = Bs[kk][tc+j];
#pragma unroll
            for (int i = 0; i < TM; i++)
#pragma unroll
                for (int j = 0; j < TN; j++)
                    acc[i][j] = fmaf(rm[i], rn[j], acc[i][j]);
        }
        __syncthreads();
    }
#pragma unroll
    for (int i = 0; i < TM; i++)
#pragma unroll
        for (int j = 0; j < TN; j++)
            Cg[(long)(m0 + tr + i)*N + n0 + tc + j] = acc[i][j];
}

// ---------------- persistent tensor-core recurrence (hi A, hi W) -------------
#define RW_STRIDE 1040
#define RW_SLAB   (16*RW_STRIDE)
#define RA_BASE   (2*RW_SLAB)
#define RA_ST     16384
#define REC_SMEM  (RA_BASE + 3*RA_ST + 64)

__device__ __forceinline__ void gbar(unsigned goal)
{
    __syncthreads();
    __threadfence();
    if (threadIdx.x == 0) {
        atomicAdd(&g_sync, 1u);
        unsigned v;
        do {
            asm volatile("ld.global.acquire.gpu.u32 %0, [%1];" : "=r"(v) : "l"(&g_sync));
        } while (v < goal);
    }
    __syncthreads();
}

__device__ __forceinline__ float sig_f(float x)  { return 1.f/(1.f + __expf(-x)); }
__device__ __forceinline__ float tanh_f(float x) { return 2.f/(1.f + __expf(-2.f*x)) - 1.f; }

__device__ __forceinline__ void rec_issue(uint32_t sbase, uint32_t mb, int k,
                                          const __half* Ac)
{
    int slot = k % 3;
    uint32_t bar = mb + slot*8;
    BAR_EXPECT(bar, 16384u);
    BULK_CP(sbase + RA_BASE + slot*RA_ST, Ac + (long)k*Bdim*64, 16384u, bar);
}

// full[s] = mb + s*8 ; empty[s] = mb + 24 + s*8 (count 256)
__device__ __forceinline__ void rec_phase(uint32_t sbase, uint32_t wbase, uint32_t mb,
                                          const __half* __restrict__ Asrc,
                                          int tid, int wid, int lane,
                                          float acc[2][4],
                                          unsigned* ub, unsigned* ue, bool prime)
{
#pragma unroll
    for (int i = 0; i < 2; i++)
#pragma unroll
        for (int q = 0; q < 4; q++) acc[i][q] = 0.f;

    if (tid == 0) {
#pragma unroll
        for (int j = 0; j < 3; j++) {
            if (!prime) {
                MBARRIER_WAIT_PARITY(mb + 24 + j*8, ue[j] & 1);
                ue[j]++;
            }
            rec_issue(sbase, mb, j, Asrc);
        }
    }

    for (int k = 0; k < 8; k++) {
        int slot = k % 3;
        MBARRIER_WAIT_PARITY(mb + slot*8, ub[slot] & 1);
        ub[slot]++;

        uint32_t st = sbase + RA_BASE + slot*RA_ST;
#pragma unroll
        for (int ks = 0; ks < 4; ks++) {
            int krow = k*64 + ks*16 + ((lane >> 3) & 1)*8;
            uint32_t baddr = wbase + ((lane & 7) + ((lane >> 4) & 1)*8)*RW_STRIDE + krow*2;
            uint32_t rhi[4];
            ldm_x4(rhi, baddr);
            uint32_t bhi[2][2] = {{rhi[0], rhi[1]}, {rhi[2], rhi[3]}};
            uint32_t m = wid*16 + (lane & 15);
            uint32_t q = ks*2 + (lane >> 4);
            uint32_t ahi[4];
            ldm_x4(ahi, st + m*128 + (q ^ (m & 7))*16);
#pragma unroll
            for (int ni = 0; ni < 2; ni++)
                mma16816(acc[ni], ahi, bhi[ni]);
        }
        MBARRIER_ARRIVE(mb + 24 + slot*8);
        if (tid == 0 && k < 5) {
            MBARRIER_WAIT_PARITY(mb + 24 + slot*8, ue[slot] & 1);
            ue[slot]++;
            rec_issue(sbase, mb, k + 3, Asrc);
        }
    }
}

__global__ void __launch_bounds__(256, 1) rec_k(const float* __restrict__ Ua,
                                                const float* __restrict__ Uc)
{
    extern __shared__ char smem[];
    const uint32_t sbase = smem_u32(smem);
    const uint32_t mb = sbase + RA_BASE + 3*RA_ST;
    const int tid = threadIdx.x, wid = tid >> 5, lane = tid & 31;
    const int bx = blockIdx.x;
    const int gg = bx >> 5;
    const int c0 = (bx & 31)*16;

    {   // one-time weight slice conversion to smem (hi only)
        const float* UaG = Ua + (long)gg*512*512;
        const float* UcG = Uc + (long)gg*512*512;
        for (int e = tid; e < 512*16; e += 256) {
            int k = e >> 4, j = e & 15;
            *(__half*)(smem + j*RW_STRIDE + k*2) =
                __float2half_rn(UaG[(long)k*512 + c0 + j]);
            *(__half*)(smem + RW_SLAB + j*RW_STRIDE + k*2) =
                __float2half_rn(UcG[(long)k*512 + c0 + j]);
        }
    }
    if (tid == 0) {
#pragma unroll
        for (int s = 0; s < 3; s++) {
            MBARRIER_INIT(mb + s*8, 1);
            MBARRIER_INIT(mb + 24 + s*8, 256);
        }
    }
    __syncthreads();

    unsigned goal = RC;
    unsigned ub[3] = {0u, 0u, 0u};
    unsigned ue[3] = {0u, 0u, 0u};
    bool prime = true;
    const long GS = (long)TBdim*Hdim;
    const long GH = (long)Bdim*Hdim;
    const __half* t6src = g_t6C + (long)gg*8*Bdim*64;

    const int ci = bx*512 + tid*2;
    float creg0 = g_c[ci], creg1 = g_c[ci + 1];

    for (int t = 0; t < Tdim; t++) {
        float acc[2][4];

        // phase A: t6[gg][:, c0..] = (h @ Ua[gg]) * t5 -> t6C hi
        rec_phase(sbase, sbase, mb, g_hC, tid, wid, lane, acc, ub, ue, prime);
        prime = false;
        {
            __half* Cz = g_t6C + (long)gg*8*Bdim*64;
            const float* t5g = g_t5 + (long)gg*GH;
#pragma unroll
            for (int ni = 0; ni < 2; ni++) {
                int col = c0 + ni*8 + (lane & 3)*2;
                int r0 = wid*16 + (lane >> 2), r1 = r0 + 8;
                int chunk = col >> 6, q = (col & 63) >> 3;
                float2 m0 = *(const float2*)(t5g + (long)r0*512 + col);
                float2 m1 = *(const float2*)(t5g + (long)r1*512 + col);
                __half2 h0 = __floats2half2_rn(acc[ni][0]*m0.x, acc[ni][1]*m0.y);
                __half2 h1 = __floats2half2_rn(acc[ni][2]*m1.x, acc[ni][3]*m1.y);
                *(__half2*)(Cz + ((long)chunk*Bdim + r0)*64 + (q ^ (r0 & 7))*8 + (col & 7)) = h0;
                *(__half2*)(Cz + ((long)chunk*Bdim + r1)*64 + (q ^ (r1 & 7))*8 + (col & 7)) = h1;
            }
        }
        gbar(goal); goal += RC;

        // phase B: gh[gg][:, c0..] = t6[gg] @ Uc[gg]
        rec_phase(sbase, sbase + RW_SLAB, mb, t6src, tid, wid, lane, acc, ub, ue, false);
        {
            float* Cz = g_gh + (long)gg*GH;
#pragma unroll
            for (int ni = 0; ni < 2; ni++) {
                int col = c0 + ni*8 + (lane & 3)*2;
                int r0 = wid*16 + (lane >> 2), r1 = r0 + 8;
                *(float2*)(Cz + (long)r0*512 + col) = make_float2(acc[ni][0], acc[ni][1]);
                *(float2*)(Cz + (long)r1*512 + col) = make_float2(acc[ni][2], acc[ni][3]);
            }
        }
        gbar(goal); goal += RC;

        // phase C: LSTM pointwise on batch row bx (c in registers)
        {
            const long so = (long)t*Bdim*Hdim;
            int i0 = bx*512 + tid*2;
            float hv[2];
#pragma unroll
            for (int u = 0; u < 2; u++) {
                int i = i0 + u;
                float pi = g_gx[0*GS + so + i] + g_gh[0*GH + i];
                float pf = g_gx[1*GS + so + i] + g_gh[1*GH + i];
                float po = g_gx[2*GS + so + i] + g_gh[2*GH + i];
                float pc = g_gx[3*GS + so + i] + g_gh[3*GH + i];
                float ig = sig_f(pi), fg = sig_f(pf), og = sig_f(po);
                float ct = tanh_f(pc);
                float cprev = u == 0 ? creg0 : creg1;
                float cn = fg*cprev + ig*ct;
                float hn = og*tanh_f(cn);
                if (u == 0) creg0 = cn; else creg1 = cn;
                hv[u] = hn;
            }
            __half2 hh = __floats2half2_rn(hv[0], hv[1]);
            int kcol = tid*2;
            int chunk = kcol >> 6, q = (kcol & 63) >> 3;
            *(__half2*)(g_hC + ((long)chunk*Bdim + bx)*64
                        + (q ^ (bx & 7))*8 + (kcol & 7)) = hh;
            int row = t*Bdim + bx;
            *(__half2*)(g_hsC + ((long)chunk*TBdim + row)*64
                        + (q ^ (row & 7))*8 + (kcol & 7)) = hh;
        }
        gbar(goal); goal += RC;
    }
}

// ---------------- launch ------------------------------------------------------
extern "C" void kernel_launch(void* const* d_in, const int* in_sizes, int n_in,
                              void* d_out, int out_size)
{
    const int*   caps = (const int*)  d_in[0];
    const float* tags = (const float*)d_in[1];
    const float* h0   = (const float*)d_in[2];
    const float* c0   = (const float*)d_in[3];
    const float* Wa   = (const float*)d_in[4];
    const float* Wb   = (const float*)d_in[5];
    const float* Wc   = (const float*)d_in[6];
    const float* Ua   = (const float*)d_in[7];
    const float* Ub   = (const float*)d_in[8];
    const float* Uc   = (const float*)d_in[9];
    const float* bi   = (const float*)d_in[10];
    const float* emb  = (const float*)d_in[11];
    const float* Wout = (const float*)d_in[12];
    const float* bout = (const float*)d_in[13];
    float* out = (float*)d_out;

    float *p_t2, *p_t5, *p_gx;
    __half *p_x2C, *p_t1C, *p_WaC, *p_WcC, *p_hsC, *p_WoC;
    cudaGetSymbolAddress((void**)&p_t2,  g_t2);
    cudaGetSymbolAddress((void**)&p_t5,  g_t5);
    cudaGetSymbolAddress((void**)&p_gx,  g_gx);
    cudaGetSymbolAddress((void**)&p_x2C, g_x2C);
    cudaGetSymbolAddress((void**)&p_t1C, g_t1C);
    cudaGetSymbolAddress((void**)&p_WaC, g_WaC);
    cudaGetSymbolAddress((void**)&p_WcC, g_WcC);
    cudaGetSymbolAddress((void**)&p_hsC, g_hsC);
    cudaGetSymbolAddress((void**)&p_WoC, g_WoC);

    cudaFuncSetAttribute((const void*)mm_k<0>, cudaFuncAttributeMaxDynamicSharedMemorySize, MM_SMEM);
    cudaFuncSetAttribute((const void*)mm_k<1>, cudaFuncAttributeMaxDynamicSharedMemorySize, MM_SMEM);
    cudaFuncSetAttribute((const void*)mm_k<2>, cudaFuncAttributeMaxDynamicSharedMemorySize, MM_SMEM);
    cudaFuncSetAttribute((const void*)rec_k, cudaFuncAttributeMaxDynamicSharedMemorySize, REC_SMEM);

    k_gather<<<dim3(Bdim, Tdim), 128>>>(caps, emb);                          // 1
    k_convWC<<<dim3(16, 8, 4), 256>>>(Wa, p_WaC);                             // 2
    gemm_k<32,64,16,4,4><<<dim3(8,4,8), 128>>>(tags, Wb, Ub, p_t2, p_t5,      // 3
        Bdim, Rdim, NTG, (long)NTG*Rdim, (long)Bdim*Rdim);
    mm_k<1><<<dim3(24,4,4), 256, MM_SMEM>>>(p_x2C, p_WaC, nullptr,            // 4 (profiled)
        p_t1C, p_t2, 0L, 8L*512*64, 512);
    k_convWC<<<dim3(16, 8, 4), 256>>>(Wc, p_WcC);                             // 5
    k_init<<<256, 256>>>(h0, c0);                                             // 6
    mm_k<2><<<dim3(24,4,4), 256, MM_SMEM>>>(p_t1C, p_WcC, p_gx,               // 7
        nullptr, bi, 8L*TBdim*64, 8L*512*64, 512);
    k_convB<<<dim3(NPAD/32, 8), 256>>>(Wout);                                 // 8
    rec_k<<<RC, 256, REC_SMEM>>>(Ua, Uc);                                     // 9
    mm_k<0><<<dim3(TBdim/128, NPAD/128), 256, MM_SMEM>>>(                     // 10
        p_hsC, p_WoC, out, nullptr, bout, 0L, 0L, NPAD);
}

// round 15
// speedup vs baseline: 6.4374x; 1.0406x over previous
#include <cuda_runtime.h>
#include <cuda_fp16.h>
#include <math.h>
#include <cstdint>

#define Bdim 128
#define Tdim 24
#define Edim 512
#define Hdim 512
#define Rdim 512
#define NTG 400
#define Vdim 20000
#define NPAD 20224          // 158*128
#define TBdim (Tdim*Bdim)   // 3072
#define RC 128              // persistent recurrence CTAs

// ---------------- scratch (device globals; no allocation allowed) ----------
__device__ float g_t2[4*Bdim*Rdim];
__device__ float g_t5[4*Bdim*Rdim];
__device__ float g_gx[4L*TBdim*Hdim];
__device__ float g_gh[4*Bdim*Hdim];
__device__ float g_c[Bdim*Hdim];
__device__ unsigned g_sync;
// chunk-major swizzled fp16 layouts (hi-only): [.. chunk ..][rows][64]
__device__ __half g_x2C[8L*TBdim*64];           // xs hi
__device__ __half g_t1C[4L*8*TBdim*64];         // t1 hi per gate
__device__ __half g_hC[8L*Bdim*64];             // h hi
__device__ __half g_t6C[4L*8*Bdim*64];          // t6 hi per gate
__device__ __half g_WaC[4L*8*Rdim*64];          // Wa^T hi per gate
__device__ __half g_WcC[4L*8*Rdim*64];          // Wc^T hi per gate
__device__ __half g_hsC[8L*TBdim*64];           // hs hi (out GEMM A)
__device__ __half g_WoC[8L*NPAD*64];            // Wout^T hi (out GEMM B)

__device__ __forceinline__ uint32_t smem_u32(const void* p) {
    uint32_t a;
    asm("{ .reg .u64 t; cvta.to.shared.u64 t, %1; cvt.u32.u64 %0, t; }" : "=r"(a) : "l"(p));
    return a;
}

__device__ __forceinline__ void ldm_x4(uint32_t* r, uint32_t addr)
{
    asm volatile("ldmatrix.sync.aligned.m8n8.x4.shared.b16 {%0,%1,%2,%3}, [%4];"
        : "=r"(r[0]), "=r"(r[1]), "=r"(r[2]), "=r"(r[3]) : "r"(addr));
}

__device__ __forceinline__ void mma16816(float* c, const uint32_t* a, const uint32_t* b)
{
    asm volatile("mma.sync.aligned.m16n8k16.row.col.f32.f16.f16.f32 "
        "{%0,%1,%2,%3}, {%4,%5,%6,%7}, {%8,%9}, {%0,%1,%2,%3};"
        : "+f"(c[0]), "+f"(c[1]), "+f"(c[2]), "+f"(c[3])
        : "r"(a[0]), "r"(a[1]), "r"(a[2]), "r"(a[3]), "r"(b[0]), "r"(b[1]));
}

#define MBARRIER_INIT(mbar, cnt) \
    asm volatile("mbarrier.init.shared.b64 [%0], %1;" :: "r"((uint32_t)(mbar)), "r"((uint32_t)(cnt)) : "memory")
#define MBARRIER_ARRIVE(mbar) \
    asm volatile("mbarrier.arrive.shared.b64 _, [%0];" :: "r"((uint32_t)(mbar)) : "memory")
#define MBARRIER_WAIT_PARITY(mbar, par) do { \
    uint32_t _m = (uint32_t)(mbar), _p = (uint32_t)(par), _d; \
    asm volatile("{\n\t.reg .pred p;\n\t" \
        "mbarrier.try_wait.parity.acquire.cta.shared::cta.b64 p, [%1], %2;\n\t" \
        "selp.b32 %0, 1, 0, p;\n\t}" : "=r"(_d) : "r"(_m), "r"(_p) : "memory"); \
    if (!_d) { \
        asm volatile("{\n\t.reg .pred P1;\n\t" \
            "WL_%=:\n\t" \
            "mbarrier.try_wait.parity.acquire.cta.shared::cta.b64 P1, [%0], %1, 0x989680;\n\t" \
            "@P1 bra.uni WD_%=;\n\t" \
            "bra.uni WL_%=;\n\t" \
            "WD_%=:\n\t}" :: "r"(_m), "r"(_p) : "memory"); \
    } \
} while (0)
#define BULK_CP(dst, src, bytes, bar) \
    asm volatile("cp.async.bulk.shared::cluster.global.mbarrier::complete_tx::bytes " \
        "[%0], [%1], %2, [%3];" :: "r"(dst), "l"(src), "r"((uint32_t)(bytes)), "r"(bar) : "memory")
#define BAR_EXPECT(bar, bytes) \
    asm volatile("mbarrier.arrive.expect_tx.shared.b64 _, [%0], %1;" \
        :: "r"(bar), "r"((uint32_t)(bytes)) : "memory")

// ================= unified hi-only MMA GEMM (out / t1 / gx) =================
// 256 threads, 8 warps (2 x 4), CTA tile 128x128, warp tile 64x32. 2 CTAs/SM.
#define MM_STAGE 32768
#define MM_SMEM  (3*MM_STAGE + 64)

__device__ __forceinline__ void mm_issue(uint32_t sb, uint32_t mb, int k,
                                         const __half* Ac, const __half* Bc,
                                         int mtile, int ntile, int bRows)
{
    int slot = k % 3;
    uint32_t dst = sb + slot*MM_STAGE;
    uint32_t bar = mb + slot*8;
    BAR_EXPECT(bar, 32768u);
    BULK_CP(dst, Ac + ((long)k*TBdim + mtile*128)*64, 16384u, bar);
    BULK_CP(dst + 16384, Bc + ((long)k*bRows + ntile*128)*64, 16384u, bar);
}

template<int MODE>
__global__ void __launch_bounds__(256, 2) mm_k(
    const __half* __restrict__ A, const __half* __restrict__ B,
    float* __restrict__ Cf, __half* __restrict__ Cb,
    const float* __restrict__ X, long aS, long bS, int bRows)
{
    extern __shared__ char smem[];
    const uint32_t sb = smem_u32(smem);
    const uint32_t mb = sb + 3*MM_STAGE;
    const int tid = threadIdx.x, wid = tid >> 5, lane = tid & 31;
    const int wm = wid & 1, wn = wid >> 1;
    const int mtile = blockIdx.x, ntile = blockIdx.y, z = blockIdx.z;

    const __half* Az = A + (long)z*aS;
    const __half* Bz = B + (long)z*bS;

    if (tid == 0) {
#pragma unroll
        for (int s = 0; s < 3; s++) {
            MBARRIER_INIT(mb + s*8, 1);
            MBARRIER_INIT(mb + 24 + s*8, 256);
        }
    }
    __syncthreads();
    if (tid == 0) {
        mm_issue(sb, mb, 0, Az, Bz, mtile, ntile, bRows);
        mm_issue(sb, mb, 1, Az, Bz, mtile, ntile, bRows);
        mm_issue(sb, mb, 2, Az, Bz, mtile, ntile, bRows);
    }

    float acc[4][4][4];
#pragma unroll
    for (int i = 0; i < 4; i++)
#pragma unroll
        for (int j = 0; j < 4; j++)
#pragma unroll
            for (int q = 0; q < 4; q++) acc[i][j][q] = 0.f;

    for (int k = 0; k < 8; k++) {
        int slot = k % 3;
        MBARRIER_WAIT_PARITY(mb + slot*8, (k/3) & 1);

        uint32_t sA = sb + slot*MM_STAGE;
        uint32_t sB = sA + 16384;
#pragma unroll
        for (int ks = 0; ks < 4; ks++) {
            uint32_t b[4][2];
#pragma unroll
            for (int np = 0; np < 2; np++) {
                uint32_t n = wn*32 + np*16 + (lane & 7) + ((lane >> 4) & 1)*8;
                uint32_t q = ks*2 + ((lane >> 3) & 1);
                uint32_t r[4];
                ldm_x4(r, sB + n*128 + (q ^ (n & 7))*16);
                b[np*2][0] = r[0];   b[np*2][1] = r[1];
                b[np*2+1][0] = r[2]; b[np*2+1][1] = r[3];
            }
            uint32_t a[4][4];
#pragma unroll
            for (int mi = 0; mi < 4; mi++) {
                uint32_t m = wm*64 + mi*16 + (lane & 15);
                uint32_t q = ks*2 + (lane >> 4);
                ldm_x4(a[mi], sA + m*128 + (q ^ (m & 7))*16);
            }
#pragma unroll
            for (int mi = 0; mi < 4; mi++)
#pragma unroll
                for (int ni = 0; ni < 4; ni++)
                    mma16816(acc[mi][ni], a[mi], b[ni]);
        }
        MBARRIER_ARRIVE(mb + 24 + slot*8);
        if (tid == 0 && k < 5) {
            MBARRIER_WAIT_PARITY(mb + 24 + slot*8, (k/3) & 1);
            mm_issue(sb, mb, k + 3, Az, Bz, mtile, ntile, bRows);
        }
    }

#pragma unroll
    for (int mi = 0; mi < 4; mi++) {
#pragma unroll
        for (int ni = 0; ni < 4; ni++) {
            int n = ntile*128 + wn*32 + ni*8 + (lane & 3)*2;
            int gr0 = mtile*128 + wm*64 + mi*16 + (lane >> 2);
            int gr1 = gr0 + 8;
            if (MODE == 0) {
                if (n < Vdim) {
                    float2 bv = *(const float2*)(X + n);
                    long o0 = ((long)(gr0 & 127)*Tdim + (gr0 >> 7))*Vdim + n;
                    long o1 = ((long)(gr1 & 127)*Tdim + (gr1 >> 7))*Vdim + n;
                    *(float2*)(Cf + o0) = make_float2(acc[mi][ni][0] + bv.x, acc[mi][ni][1] + bv.y);
                    *(float2*)(Cf + o1) = make_float2(acc[mi][ni][2] + bv.x, acc[mi][ni][3] + bv.y);
                }
            } else if (MODE == 1) {
                const float* Xg = X + (long)z*Bdim*Rdim;
                __half* Cz = Cb + (long)z*(8L*TBdim*64);
                int chunk = n >> 6, q = (n & 63) >> 3;
                __half2 h0 = __floats2half2_rn(acc[mi][ni][0]*Xg[(gr0 & 127)*512 + n],
                                               acc[mi][ni][1]*Xg[(gr0 & 127)*512 + n + 1]);
                __half2 h1 = __floats2half2_rn(acc[mi][ni][2]*Xg[(gr1 & 127)*512 + n],
                                               acc[mi][ni][3]*Xg[(gr1 & 127)*512 + n + 1]);
                *(__half2*)(Cz + ((long)chunk*TBdim + gr0)*64 + (q ^ (gr0 & 7))*8 + (n & 7)) = h0;
                *(__half2*)(Cz + ((long)chunk*TBdim + gr1)*64 + (q ^ (gr1 & 7))*8 + (n & 7)) = h1;
            } else {
                const float* Xg = X + z*512;
                float* Cz = Cf + (long)z*TBdim*512;
                float2 bv = make_float2(Xg[n], Xg[n + 1]);
                *(float2*)(Cz + (long)gr0*512 + n) = make_float2(acc[mi][ni][0] + bv.x, acc[mi][ni][1] + bv.y);
                *(float2*)(Cz + (long)gr1*512 + n) = make_float2(acc[mi][ni][2] + bv.x, acc[mi][ni][3] + bv.y);
            }
        }
    }
}

// ---------------- conversions ------------------------------------------------
// fused Wa/Wc conversion: z in [0,8): g = z&3, src = z<4 ? Wa : Wc
__global__ void __launch_bounds__(256) k_convWC(const float* __restrict__ Wa,
                                                const float* __restrict__ Wc)
{
    __shared__ float t[64][33];
    const int tid = threadIdx.x;
    const int z = blockIdx.z;
    const int g = z & 3;
    const float* W = (z < 4) ? Wa : Wc;
    __half* Bp = (z < 4) ? g_WaC : g_WcC;
    const int n0 = blockIdx.x*32;
    const int k0 = blockIdx.y*64;
    for (int e = tid; e < 64*32; e += 256) {
        int kk = e >> 5, nn = e & 31;
        t[kk][nn] = W[((long)g*512 + k0 + kk)*512 + n0 + nn];
    }
    __syncthreads();
    int nn = tid >> 3, q = tid & 7;
    int n = n0 + nn;
    __half h[8];
#pragma unroll
    for (int i = 0; i < 8; i++) h[i] = __float2half_rn(t[q*8 + i][nn]);
    int qs = q ^ (n & 7);
    *(uint4*)(Bp + (((long)g*8 + blockIdx.y)*512 + n)*64 + qs*8) = *(uint4*)h;
}

// streaming Wout conversion: block = 128 n x 64 k, float4 loads, uint4 stores
__global__ void __launch_bounds__(256) k_convB(const float* __restrict__ Wout)
{
    __shared__ float t[64][132];
    const int tid = threadIdx.x;
    const int n0 = blockIdx.x*128;
    const int k0 = blockIdx.y*64;
#pragma unroll
    for (int i = 0; i < 8; i++) {
        int e = tid + i*256;          // 2048 float4 units
        int kk = e >> 5;
        int nf = (e & 31)*4;
        int n = n0 + nf;
        float4 v;
        if (n + 3 < Vdim) {
            v = *(const float4*)(Wout + (long)(k0 + kk)*Vdim + n);
        } else {
            v.x = (n + 0 < Vdim) ? Wout[(long)(k0+kk)*Vdim + n + 0] : 0.f;
            v.y = (n + 1 < Vdim) ? Wout[(long)(k0+kk)*Vdim + n + 1] : 0.f;
            v.z = (n + 2 < Vdim) ? Wout[(long)(k0+kk)*Vdim + n + 2] : 0.f;
            v.w = (n + 3 < Vdim) ? Wout[(long)(k0+kk)*Vdim + n + 3] : 0.f;
        }
        *(float4*)&t[kk][nf] = v;
    }
    __syncthreads();
    int nn = tid >> 1;
    int n = n0 + nn;
    int hs = (tid & 1)*4;
#pragma unroll
    for (int j = 0; j < 4; j++) {
        int q = hs + j;
        __half h[8];
#pragma unroll
        for (int i = 0; i < 8; i++) h[i] = __float2half_rn(t[q*8 + i][nn]);
        int qs = q ^ (n & 7);
        *(uint4*)(g_WoC + ((long)blockIdx.y*NPAD + n)*64 + qs*8) = *(uint4*)h;
    }
}

// ---------------- embedding gather -> x2C hi-only ----------------------------
__global__ void k_gather(const int* __restrict__ caps, const float* __restrict__ emb)
{
    const int b = blockIdx.x, t = blockIdx.y;
    float4 v = make_float4(0.f, 0.f, 0.f, 0.f);
    if (t > 0) {
        int tok = caps[b*Tdim + (t-1)];
        v = ((const float4*)(emb + (long)tok*Edim))[threadIdx.x];
    }
    __half hv[4];
    hv[0] = __float2half_rn(v.x); hv[1] = __float2half_rn(v.y);
    hv[2] = __float2half_rn(v.z); hv[3] = __float2half_rn(v.w);
    int col = threadIdx.x*4;
    int row = t*Bdim + b;
    int chunk = col >> 6, q = (col & 63) >> 3;
    *(uint2*)(g_x2C + ((long)chunk*TBdim + row)*64 + (q ^ (row & 7))*8 + (col & 7)) = *(uint2*)hv;
}

__global__ void k_init(const float* __restrict__ h0, const float* __restrict__ c0)
{
    int i = blockIdx.x*blockDim.x + threadIdx.x;
    int b = i >> 9, col = i & 511;
    int chunk = col >> 6, q = (col & 63) >> 3;
    g_hC[((long)chunk*Bdim + b)*64 + (q ^ (b & 7))*8 + (col & 7)] = __float2half_rn(h0[i]);
    g_c[i] = c0[i];
    if (i == 0) g_sync = 0;
}

// ---------------- fp32 tiled SGEMM (t2 and t5 in one launch) -----------------
template<int BM,int BN,int BK,int TM,int TN>
__global__ void gemm_k(const float* __restrict__ A,
                       const float* __restrict__ Bm, const float* __restrict__ Bm2,
                       float* __restrict__ C, float* __restrict__ C2,
                       int M, int N, int K, long sB, long sC)
{
    constexpr int THREADS = (BM/TM)*(BN/TN);
    __shared__ float As[BK][BM];
    __shared__ float Bs[BK][BN];
    const int z = blockIdx.z;
    const int g = z & 3;
    const float* Bg = (z < 4 ? Bm : Bm2) + (long)g*sB;
    float* Cg = (z < 4 ? C : C2) + (long)g*sC;
    const int m0 = blockIdx.y*BM;
    const int n0 = blockIdx.x*BN;
    const int tid = threadIdx.x;
    constexpr int AK4 = BK/4;
    const int aRow = tid / AK4, aCol = (tid % AK4)*4;
    constexpr int AROWS = THREADS/AK4;
    constexpr int BN4 = BN/4;
    const int bRow = tid / BN4, bCol = (tid % BN4)*4;
    constexpr int BROWS = THREADS/BN4;
    const int tr = (tid/(BN/TN))*TM, tc = (tid%(BN/TN))*TN;

    float acc[TM][TN];
#pragma unroll
    for (int i = 0; i < TM; i++)
#pragma unroll
        for (int j = 0; j < TN; j++) acc[i][j] = 0.f;

    for (int k0 = 0; k0 < K; k0 += BK) {
#pragma unroll
        for (int i = 0; i < BM; i += AROWS) {
            float4 v = *(const float4*)(A + (long)(m0 + aRow + i)*K + (k0 + aCol));
            As[aCol+0][aRow+i] = v.x; As[aCol+1][aRow+i] = v.y;
            As[aCol+2][aRow+i] = v.z; As[aCol+3][aRow+i] = v.w;
        }
#pragma unroll
        for (int i = 0; i < BK; i += BROWS) {
            float4 v = *(const float4*)(Bg + (long)(k0 + bRow + i)*N + (n0 + bCol));
            *(float4*)&Bs[bRow+i][bCol] = v;
        }
        __syncthreads();
#pragma unroll
        for (int kk = 0; kk < BK; kk++) {
            float rm[TM], rn[TN];
#pragma unroll
            for (int i = 0; i < TM; i++) rm[i] = As[kk][tr+i];
#pragma unroll
            for (int j = 0; j < TN; j++) rn[j] = Bs[kk][tc+j];
#pragma unroll
            for (int i = 0; i < TM; i++)
#pragma unroll
                for (int j = 0; j < TN; j++)
                    acc[i][j] = fmaf(rm[i], rn[j], acc[i][j]);
        }
        __syncthreads();
    }
#pragma unroll
    for (int i = 0; i < TM; i++)
#pragma unroll
        for (int j = 0; j < TN; j++)
            Cg[(long)(m0 + tr + i)*N + n0 + tc + j] = acc[i][j];
}

// ---------------- persistent tensor-core recurrence (hi A, hi W) -------------
#define RW_STRIDE 1040
#define RW_SLAB   (16*RW_STRIDE)
#define RA_BASE   (2*RW_SLAB)
#define RA_ST     16384
#define REC_SMEM  (RA_BASE + 3*RA_ST + 64)

__device__ __forceinline__ void gbar(unsigned goal)
{
    __syncthreads();
    __threadfence();
    if (threadIdx.x == 0) {
        atomicAdd(&g_sync, 1u);
        unsigned v;
        do {
            asm volatile("ld.global.acquire.gpu.u32 %0, [%1];" : "=r"(v) : "l"(&g_sync));
        } while (v < goal);
    }
    __syncthreads();
}

__device__ __forceinline__ float sig_f(float x)  { return 1.f/(1.f + __expf(-x)); }
__device__ __forceinline__ float tanh_f(float x) { return 2.f/(1.f + __expf(-2.f*x)) - 1.f; }

__device__ __forceinline__ void rec_issue(uint32_t sbase, uint32_t mb, int k,
                                          const __half* Ac)
{
    int slot = k % 3;
    uint32_t bar = mb + slot*8;
    BAR_EXPECT(bar, 16384u);
    BULK_CP(sbase + RA_BASE + slot*RA_ST, Ac + (long)k*Bdim*64, 16384u, bar);
}

__device__ __forceinline__ void rec_phase(uint32_t sbase, uint32_t wbase, uint32_t mb,
                                          const __half* __restrict__ Asrc,
                                          int tid, int wid, int lane,
                                          float acc[2][4],
                                          unsigned* ub, unsigned* ue, bool prime)
{
#pragma unroll
    for (int i = 0; i < 2; i++)
#pragma unroll
        for (int q = 0; q < 4; q++) acc[i][q] = 0.f;

    if (tid == 0) {
#pragma unroll
        for (int j = 0; j < 3; j++) {
            if (!prime) {
                MBARRIER_WAIT_PARITY(mb + 24 + j*8, ue[j] & 1);
                ue[j]++;
            }
            rec_issue(sbase, mb, j, Asrc);
        }
    }

    for (int k = 0; k < 8; k++) {
        int slot = k % 3;
        MBARRIER_WAIT_PARITY(mb + slot*8, ub[slot] & 1);
        ub[slot]++;

        uint32_t st = sbase + RA_BASE + slot*RA_ST;
#pragma unroll
        for (int ks = 0; ks < 4; ks++) {
            int krow = k*64 + ks*16 + ((lane >> 3) & 1)*8;
            uint32_t baddr = wbase + ((lane & 7) + ((lane >> 4) & 1)*8)*RW_STRIDE + krow*2;
            uint32_t rhi[4];
            ldm_x4(rhi, baddr);
            uint32_t bhi[2][2] = {{rhi[0], rhi[1]}, {rhi[2], rhi[3]}};
            uint32_t m = wid*16 + (lane & 15);
            uint32_t q = ks*2 + (lane >> 4);
            uint32_t ahi[4];
            ldm_x4(ahi, st + m*128 + (q ^ (m & 7))*16);
#pragma unroll
            for (int ni = 0; ni < 2; ni++)
                mma16816(acc[ni], ahi, bhi[ni]);
        }
        MBARRIER_ARRIVE(mb + 24 + slot*8);
        if (tid == 0 && k < 5) {
            MBARRIER_WAIT_PARITY(mb + 24 + slot*8, ue[slot] & 1);
            ue[slot]++;
            rec_issue(sbase, mb, k + 3, Asrc);
        }
    }
}

__global__ void __launch_bounds__(256, 1) rec_k(const float* __restrict__ Ua,
                                                const float* __restrict__ Uc)
{
    extern __shared__ char smem[];
    const uint32_t sbase = smem_u32(smem);
    const uint32_t mb = sbase + RA_BASE + 3*RA_ST;
    const int tid = threadIdx.x, wid = tid >> 5, lane = tid & 31;
    const int bx = blockIdx.x;
    const int gg = bx >> 5;
    const int c0 = (bx & 31)*16;

    {
        const float* UaG = Ua + (long)gg*512*512;
        const float* UcG = Uc + (long)gg*512*512;
        for (int e = tid; e < 512*16; e += 256) {
            int k = e >> 4, j = e & 15;
            *(__half*)(smem + j*RW_STRIDE + k*2) =
                __float2half_rn(UaG[(long)k*512 + c0 + j]);
            *(__half*)(smem + RW_SLAB + j*RW_STRIDE + k*2) =
                __float2half_rn(UcG[(long)k*512 + c0 + j]);
        }
    }
    if (tid == 0) {
#pragma unroll
        for (int s = 0; s < 3; s++) {
            MBARRIER_INIT(mb + s*8, 1);
            MBARRIER_INIT(mb + 24 + s*8, 256);
        }
    }
    __syncthreads();

    unsigned goal = RC;
    unsigned ub[3] = {0u, 0u, 0u};
    unsigned ue[3] = {0u, 0u, 0u};
    bool prime = true;
    const long GS = (long)TBdim*Hdim;
    const long GH = (long)Bdim*Hdim;
    const __half* t6src = g_t6C + (long)gg*8*Bdim*64;

    const int ci = bx*512 + tid*2;
    float creg0 = g_c[ci], creg1 = g_c[ci + 1];

    for (int t = 0; t < Tdim; t++) {
        float acc[2][4];

        // phase A: t6[gg][:, c0..] = (h @ Ua[gg]) * t5 -> t6C hi
        rec_phase(sbase, sbase, mb, g_hC, tid, wid, lane, acc, ub, ue, prime);
        prime = false;
        {
            __half* Cz = g_t6C + (long)gg*8*Bdim*64;
            const float* t5g = g_t5 + (long)gg*GH;
#pragma unroll
            for (int ni = 0; ni < 2; ni++) {
                int col = c0 + ni*8 + (lane & 3)*2;
                int r0 = wid*16 + (lane >> 2), r1 = r0 + 8;
                int chunk = col >> 6, q = (col & 63) >> 3;
                float2 m0 = *(const float2*)(t5g + (long)r0*512 + col);
                float2 m1 = *(const float2*)(t5g + (long)r1*512 + col);
                __half2 h0 = __floats2half2_rn(acc[ni][0]*m0.x, acc[ni][1]*m0.y);
                __half2 h1 = __floats2half2_rn(acc[ni][2]*m1.x, acc[ni][3]*m1.y);
                *(__half2*)(Cz + ((long)chunk*Bdim + r0)*64 + (q ^ (r0 & 7))*8 + (col & 7)) = h0;
                *(__half2*)(Cz + ((long)chunk*Bdim + r1)*64 + (q ^ (r1 & 7))*8 + (col & 7)) = h1;
            }
        }
        gbar(goal); goal += RC;

        // phase B: gh[gg][:, c0..] = t6[gg] @ Uc[gg]
        rec_phase(sbase, sbase + RW_SLAB, mb, t6src, tid, wid, lane, acc, ub, ue, false);
        {
            float* Cz = g_gh + (long)gg*GH;
#pragma unroll
            for (int ni = 0; ni < 2; ni++) {
                int col = c0 + ni*8 + (lane & 3)*2;
                int r0 = wid*16 + (lane >> 2), r1 = r0 + 8;
                *(float2*)(Cz + (long)r0*512 + col) = make_float2(acc[ni][0], acc[ni][1]);
                *(float2*)(Cz + (long)r1*512 + col) = make_float2(acc[ni][2], acc[ni][3]);
            }
        }
        gbar(goal); goal += RC;

        // phase C: LSTM pointwise on batch row bx (c in registers)
        {
            const long so = (long)t*Bdim*Hdim;
            int i0 = bx*512 + tid*2;
            float hv[2];
#pragma unroll
            for (int u = 0; u < 2; u++) {
                int i = i0 + u;
                float pi = g_gx[0*GS + so + i] + g_gh[0*GH + i];
                float pf = g_gx[1*GS + so + i] + g_gh[1*GH + i];
                float po = g_gx[2*GS + so + i] + g_gh[2*GH + i];
                float pc = g_gx[3*GS + so + i] + g_gh[3*GH + i];
                float ig = sig_f(pi), fg = sig_f(pf), og = sig_f(po);
                float ct = tanh_f(pc);
                float cprev = u == 0 ? creg0 : creg1;
                float cn = fg*cprev + ig*ct;
                float hn = og*tanh_f(cn);
                if (u == 0) creg0 = cn; else creg1 = cn;
                hv[u] = hn;
            }
            __half2 hh = __floats2half2_rn(hv[0], hv[1]);
            int kcol = tid*2;
            int chunk = kcol >> 6, q = (kcol & 63) >> 3;
            *(__half2*)(g_hC + ((long)chunk*Bdim + bx)*64
                        + (q ^ (bx & 7))*8 + (kcol & 7)) = hh;
            int row = t*Bdim + bx;
            *(__half2*)(g_hsC + ((long)chunk*TBdim + row)*64
                        + (q ^ (row & 7))*8 + (kcol & 7)) = hh;
        }
        gbar(goal); goal += RC;
    }
}

// ---------------- launch ------------------------------------------------------
extern "C" void kernel_launch(void* const* d_in, const int* in_sizes, int n_in,
                              void* d_out, int out_size)
{
    const int*   caps = (const int*)  d_in[0];
    const float* tags = (const float*)d_in[1];
    const float* h0   = (const float*)d_in[2];
    const float* c0   = (const float*)d_in[3];
    const float* Wa   = (const float*)d_in[4];
    const float* Wb   = (const float*)d_in[5];
    const float* Wc   = (const float*)d_in[6];
    const float* Ua   = (const float*)d_in[7];
    const float* Ub   = (const float*)d_in[8];
    const float* Uc   = (const float*)d_in[9];
    const float* bi   = (const float*)d_in[10];
    const float* emb  = (const float*)d_in[11];
    const float* Wout = (const float*)d_in[12];
    const float* bout = (const float*)d_in[13];
    float* out = (float*)d_out;

    float *p_t2, *p_t5, *p_gx;
    __half *p_x2C, *p_t1C, *p_WaC, *p_WcC, *p_hsC, *p_WoC;
    cudaGetSymbolAddress((void**)&p_t2,  g_t2);
    cudaGetSymbolAddress((void**)&p_t5,  g_t5);
    cudaGetSymbolAddress((void**)&p_gx,  g_gx);
    cudaGetSymbolAddress((void**)&p_x2C, g_x2C);
    cudaGetSymbolAddress((void**)&p_t1C, g_t1C);
    cudaGetSymbolAddress((void**)&p_WaC, g_WaC);
    cudaGetSymbolAddress((void**)&p_WcC, g_WcC);
    cudaGetSymbolAddress((void**)&p_hsC, g_hsC);
    cudaGetSymbolAddress((void**)&p_WoC, g_WoC);

    cudaFuncSetAttribute((const void*)mm_k<0>, cudaFuncAttributeMaxDynamicSharedMemorySize, MM_SMEM);
    cudaFuncSetAttribute((const void*)mm_k<1>, cudaFuncAttributeMaxDynamicSharedMemorySize, MM_SMEM);
    cudaFuncSetAttribute((const void*)mm_k<2>, cudaFuncAttributeMaxDynamicSharedMemorySize, MM_SMEM);
    cudaFuncSetAttribute((const void*)rec_k, cudaFuncAttributeMaxDynamicSharedMemorySize, REC_SMEM);

    k_gather<<<dim3(Bdim, Tdim), 128>>>(caps, emb);                          // 1
    k_convWC<<<dim3(16, 8, 8), 256>>>(Wa, Wc);                                // 2 (Wa+Wc fused)
    gemm_k<32,64,16,4,4><<<dim3(8,4,8), 128>>>(tags, Wb, Ub, p_t2, p_t5,      // 3
        Bdim, Rdim, NTG, (long)NTG*Rdim, (long)Bdim*Rdim);
    mm_k<1><<<dim3(24,4,4), 256, MM_SMEM>>>(p_x2C, p_WaC, nullptr,            // 4 (profiled)
        p_t1C, p_t2, 0L, 8L*512*64, 512);
    k_init<<<256, 256>>>(h0, c0);                                             // 5
    k_convB<<<dim3(NPAD/128, 8), 256>>>(Wout);                                // 6 (fast stream)
    mm_k<2><<<dim3(24,4,4), 256, MM_SMEM>>>(p_t1C, p_WcC, p_gx,               // 7
        nullptr, bi, 8L*TBdim*64, 8L*512*64, 512);
    rec_k<<<RC, 256, REC_SMEM>>>(Ua, Uc);                                     // 8
    mm_k<0><<<dim3(TBdim/128, NPAD/128), 256, MM_SMEM>>>(                     // 9
        p_hsC, p_WoC, out, nullptr, bout, 0L, 0L, NPAD);
}